// round 1
// baseline (speedup 1.0000x reference)
#include <cuda_runtime.h>
#include <math.h>

#define D_MODEL 512
#define FF_DIM  2048
#define S_LEN   1024
#define BATCH   4
#define NLAYER  6
#define NHEAD   8
#define DHEAD   64
#define M_ROWS  (S_LEN * BATCH)   // 4096 token rows

// ---------------- scratch (device globals; no runtime allocation) ----------------
__device__ float g_x [M_ROWS * D_MODEL];   // residual stream (B,S,D)
__device__ float g_xn[M_ROWS * D_MODEL];   // layernorm output
__device__ float g_q [M_ROWS * D_MODEL];
__device__ float g_k [M_ROWS * D_MODEL];
__device__ float g_v [M_ROWS * D_MODEL];
__device__ float g_h [M_ROWS * FF_DIM];    // FF hidden

// ---------------- x = (src + pos) transposed (S,B,D) -> (B,S,D) ----------------
__global__ void add_pos_kernel(const float* __restrict__ src,
                               const float* __restrict__ pos,
                               float* __restrict__ x) {
    int idx = blockIdx.x * blockDim.x + threadIdx.x;   // over M_ROWS*D
    if (idx >= M_ROWS * D_MODEL) return;
    int d = idx & (D_MODEL - 1);
    int m = idx >> 9;            // b*S + s
    int b = m >> 10;             // / S_LEN
    int s = m & (S_LEN - 1);
    int src_i = ((s * BATCH + b) << 9) + d;
    x[idx] = src[src_i] + pos[src_i];
}

// ---------------- layernorm: one block (128 thr) per row of 512 ----------------
__global__ void layernorm_kernel(const float* __restrict__ x,
                                 const float* __restrict__ gamma,
                                 const float* __restrict__ beta,
                                 float* __restrict__ y) {
    int row = blockIdx.x;
    int tid = threadIdx.x;                 // 128
    const float4* xr = (const float4*)(x + row * D_MODEL);
    float4 v = xr[tid];
    float s  = v.x + v.y + v.z + v.w;
    float ss = v.x*v.x + v.y*v.y + v.z*v.z + v.w*v.w;
    #pragma unroll
    for (int o = 16; o > 0; o >>= 1) {
        s  += __shfl_down_sync(0xffffffffu, s,  o);
        ss += __shfl_down_sync(0xffffffffu, ss, o);
    }
    __shared__ float shs[4], shss[4];
    __shared__ float s_mean, s_inv;
    int w = tid >> 5, lane = tid & 31;
    if (lane == 0) { shs[w] = s; shss[w] = ss; }
    __syncthreads();
    if (tid == 0) {
        float ts  = shs[0] + shs[1] + shs[2] + shs[3];
        float tss = shss[0] + shss[1] + shss[2] + shss[3];
        float mean = ts * (1.0f / D_MODEL);
        float var  = tss * (1.0f / D_MODEL) - mean * mean;
        s_mean = mean;
        s_inv  = rsqrtf(var + 1e-5f);
    }
    __syncthreads();
    float mean = s_mean, inv = s_inv;
    int c = tid * 4;
    float4 g = *(const float4*)(gamma + c);
    float4 bb = *(const float4*)(beta + c);
    float4 o;
    o.x = (v.x - mean) * inv * g.x + bb.x;
    o.y = (v.y - mean) * inv * g.y + bb.y;
    o.z = (v.z - mean) * inv * g.z + bb.z;
    o.w = (v.w - mean) * inv * g.w + bb.w;
    ((float4*)(y + row * D_MODEL))[tid] = o;
}

// ---------------- final layernorm with transpose back to (S,B,D) ----------------
__global__ void final_ln_kernel(const float* __restrict__ x,
                                const float* __restrict__ gamma,
                                const float* __restrict__ beta,
                                float* __restrict__ out) {
    int row = blockIdx.x;                  // b*S + s
    int tid = threadIdx.x;
    const float4* xr = (const float4*)(x + row * D_MODEL);
    float4 v = xr[tid];
    float s  = v.x + v.y + v.z + v.w;
    float ss = v.x*v.x + v.y*v.y + v.z*v.z + v.w*v.w;
    #pragma unroll
    for (int o = 16; o > 0; o >>= 1) {
        s  += __shfl_down_sync(0xffffffffu, s,  o);
        ss += __shfl_down_sync(0xffffffffu, ss, o);
    }
    __shared__ float shs[4], shss[4];
    __shared__ float s_mean, s_inv;
    int w = tid >> 5, lane = tid & 31;
    if (lane == 0) { shs[w] = s; shss[w] = ss; }
    __syncthreads();
    if (tid == 0) {
        float ts  = shs[0] + shs[1] + shs[2] + shs[3];
        float tss = shss[0] + shss[1] + shss[2] + shss[3];
        float mean = ts * (1.0f / D_MODEL);
        float var  = tss * (1.0f / D_MODEL) - mean * mean;
        s_mean = mean;
        s_inv  = rsqrtf(var + 1e-5f);
    }
    __syncthreads();
    float mean = s_mean, inv = s_inv;
    int c = tid * 4;
    float4 g = *(const float4*)(gamma + c);
    float4 bb = *(const float4*)(beta + c);
    float4 o;
    o.x = (v.x - mean) * inv * g.x + bb.x;
    o.y = (v.y - mean) * inv * g.y + bb.y;
    o.z = (v.z - mean) * inv * g.z + bb.z;
    o.w = (v.w - mean) * inv * g.w + bb.w;
    int b = row >> 10;
    int ss_ = row & (S_LEN - 1);
    ((float4*)(out + ((ss_ * BATCH + b) << 9)))[tid] = o;
}

// ---------------- SGEMM: C[M,N] = A[M,K] @ W[K,N] + bias (+relu / +residual) ----
// 128x128 tile, BK=8, 256 threads, 8x8 per thread.
template<bool RELU, bool RES>
__global__ void sgemm_kernel(const float* __restrict__ A,
                             const float* __restrict__ W,
                             const float* __restrict__ bias,
                             float* __restrict__ C,
                             int M, int N, int K) {
    __shared__ float As[8][128];
    __shared__ float Bs[8][128];
    int tid = threadIdx.x;                 // 256
    int tx = tid & 15, ty = tid >> 4;
    int rowBase = blockIdx.y * 128;
    int colBase = blockIdx.x * 128;

    int aRow = tid >> 1, aCol = (tid & 1) * 4;   // A tile loads: 128x8
    int bRow = tid >> 5, bCol = (tid & 31) * 4;  // B tile loads: 8x128

    const float* Ap = A + (long)rowBase * K;
    float acc[8][8];
    #pragma unroll
    for (int i = 0; i < 8; i++)
        #pragma unroll
        for (int j = 0; j < 8; j++) acc[i][j] = 0.0f;

    for (int k0 = 0; k0 < K; k0 += 8) {
        float4 av = *(const float4*)(Ap + (long)aRow * K + k0 + aCol);
        As[aCol + 0][aRow] = av.x;
        As[aCol + 1][aRow] = av.y;
        As[aCol + 2][aRow] = av.z;
        As[aCol + 3][aRow] = av.w;
        float4 bv = *(const float4*)(W + (long)(k0 + bRow) * N + colBase + bCol);
        *(float4*)&Bs[bRow][bCol] = bv;
        __syncthreads();
        #pragma unroll
        for (int k = 0; k < 8; k++) {
            float a[8], b[8];
            *(float4*)(a)     = *(float4*)&As[k][ty * 8];
            *(float4*)(a + 4) = *(float4*)&As[k][ty * 8 + 4];
            *(float4*)(b)     = *(float4*)&Bs[k][tx * 8];
            *(float4*)(b + 4) = *(float4*)&Bs[k][tx * 8 + 4];
            #pragma unroll
            for (int i = 0; i < 8; i++)
                #pragma unroll
                for (int j = 0; j < 8; j++)
                    acc[i][j] = fmaf(a[i], b[j], acc[i][j]);
        }
        __syncthreads();
    }

    #pragma unroll
    for (int i = 0; i < 8; i++) {
        int row = rowBase + ty * 8 + i;
        #pragma unroll
        for (int j = 0; j < 8; j++) {
            int col = colBase + tx * 8 + j;
            float v = acc[i][j] + bias[col];
            if (RES) v += C[(long)row * N + col];
            if (RELU) v = fmaxf(v, 0.0f);
            C[(long)row * N + col] = v;
        }
    }
}

// ---------------- flash attention + fused residual add --------------------------
// grid: (B*H, S/64), block 256. 64-query tile, DH=64, online softmax.
#define QPAD 65
__global__ void attention_kernel(const float* __restrict__ q,
                                 const float* __restrict__ k,
                                 const float* __restrict__ v,
                                 float* __restrict__ x) {
    extern __shared__ float sm[];
    float* Qs = sm;                 // 64*65
    float* Ks = sm + 64 * QPAD;
    float* Vs = sm + 2 * 64 * QPAD;
    float* Ps = sm + 3 * 64 * QPAD;
    __shared__ float mrow[64], lrow[64], crow[64];

    int bh = blockIdx.x;
    int b = bh >> 3, h = bh & 7;
    int qt = blockIdx.y;
    int tid = threadIdx.x;          // 256
    int tx = tid & 15, ty = tid >> 4;

    const float* qbase = q + ((long)(b * S_LEN + qt * 64) << 9) + h * DHEAD;
    for (int idx = tid; idx < 64 * 64; idx += 256) {
        int r = idx >> 6, c = idx & 63;
        Qs[r * QPAD + c] = qbase[(long)r * D_MODEL + c];
    }
    if (tid < 64) { mrow[tid] = -1e30f; lrow[tid] = 0.0f; }
    float acc[4][4];
    #pragma unroll
    for (int i = 0; i < 4; i++)
        #pragma unroll
        for (int j = 0; j < 4; j++) acc[i][j] = 0.0f;
    __syncthreads();

    for (int kt = 0; kt < S_LEN / 64; kt++) {
        const float* kbase = k + ((long)(b * S_LEN + kt * 64) << 9) + h * DHEAD;
        const float* vbase = v + ((long)(b * S_LEN + kt * 64) << 9) + h * DHEAD;
        for (int idx = tid; idx < 64 * 64; idx += 256) {
            int r = idx >> 6, c = idx & 63;
            Ks[r * QPAD + c] = kbase[(long)r * D_MODEL + c];
            Vs[r * QPAD + c] = vbase[(long)r * D_MODEL + c];
        }
        __syncthreads();

        // S = scale * Q @ K^T   (4x4 per thread)
        float s[4][4];
        #pragma unroll
        for (int i = 0; i < 4; i++)
            #pragma unroll
            for (int j = 0; j < 4; j++) s[i][j] = 0.0f;
        #pragma unroll 8
        for (int d = 0; d < 64; d++) {
            float qv[4], kv[4];
            #pragma unroll
            for (int i = 0; i < 4; i++) qv[i] = Qs[(ty * 4 + i) * QPAD + d];
            #pragma unroll
            for (int j = 0; j < 4; j++) kv[j] = Ks[(tx * 4 + j) * QPAD + d];
            #pragma unroll
            for (int i = 0; i < 4; i++)
                #pragma unroll
                for (int j = 0; j < 4; j++)
                    s[i][j] = fmaf(qv[i], kv[j], s[i][j]);
        }
        #pragma unroll
        for (int i = 0; i < 4; i++)
            #pragma unroll
            for (int j = 0; j < 4; j++)
                Ps[(ty * 4 + i) * QPAD + tx * 4 + j] = s[i][j] * 0.125f;
        __syncthreads();

        // online softmax per row (64 rows by first 64 threads)
        if (tid < 64) {
            float m = mrow[tid];
            float mx = m;
            #pragma unroll 8
            for (int j = 0; j < 64; j++) mx = fmaxf(mx, Ps[tid * QPAD + j]);
            float cr = __expf(m - mx);
            float l = lrow[tid] * cr;
            #pragma unroll 8
            for (int j = 0; j < 64; j++) {
                float p = __expf(Ps[tid * QPAD + j] - mx);
                Ps[tid * QPAD + j] = p;
                l += p;
            }
            mrow[tid] = mx; lrow[tid] = l; crow[tid] = cr;
        }
        __syncthreads();

        // O = O*c + P @ V
        #pragma unroll
        for (int i = 0; i < 4; i++) {
            float cr = crow[ty * 4 + i];
            float o0 = acc[i][0] * cr, o1 = acc[i][1] * cr;
            float o2 = acc[i][2] * cr, o3 = acc[i][3] * cr;
            #pragma unroll 8
            for (int kk = 0; kk < 64; kk++) {
                float p = Ps[(ty * 4 + i) * QPAD + kk];
                o0 = fmaf(p, Vs[kk * QPAD + tx * 4 + 0], o0);
                o1 = fmaf(p, Vs[kk * QPAD + tx * 4 + 1], o1);
                o2 = fmaf(p, Vs[kk * QPAD + tx * 4 + 2], o2);
                o3 = fmaf(p, Vs[kk * QPAD + tx * 4 + 3], o3);
            }
            acc[i][0] = o0; acc[i][1] = o1; acc[i][2] = o2; acc[i][3] = o3;
        }
        __syncthreads();
    }

    // x += O / l  (residual fused)
    float* xbase = x + ((long)(b * S_LEN + qt * 64) << 9) + h * DHEAD;
    #pragma unroll
    for (int i = 0; i < 4; i++) {
        int r = ty * 4 + i;
        float inv = 1.0f / lrow[r];
        #pragma unroll
        for (int j = 0; j < 4; j++) {
            int c = tx * 4 + j;
            xbase[(long)r * D_MODEL + c] += acc[i][j] * inv;
        }
    }
}

// ---------------- host orchestration --------------------------------------------
extern "C" void kernel_launch(void* const* d_in, const int* in_sizes, int n_in,
                              void* d_out, int out_size) {
    const float* src   = (const float*)d_in[0];
    const float* pos   = (const float*)d_in[1];
    const float* Wq    = (const float*)d_in[2];
    const float* bq    = (const float*)d_in[3];
    const float* Wk    = (const float*)d_in[4];
    const float* bk    = (const float*)d_in[5];
    const float* Wv    = (const float*)d_in[6];
    const float* bv    = (const float*)d_in[7];
    const float* W1    = (const float*)d_in[8];
    const float* b1    = (const float*)d_in[9];
    const float* W2    = (const float*)d_in[10];
    const float* b2    = (const float*)d_in[11];
    const float* ln1_g = (const float*)d_in[12];
    const float* ln1_b = (const float*)d_in[13];
    const float* ln2_g = (const float*)d_in[14];
    const float* ln2_b = (const float*)d_in[15];
    const float* lnf_g = (const float*)d_in[16];
    const float* lnf_b = (const float*)d_in[17];
    float* out = (float*)d_out;

    float *px, *pxn, *pq, *pk, *pv, *ph;
    cudaGetSymbolAddress((void**)&px,  g_x);
    cudaGetSymbolAddress((void**)&pxn, g_xn);
    cudaGetSymbolAddress((void**)&pq,  g_q);
    cudaGetSymbolAddress((void**)&pk,  g_k);
    cudaGetSymbolAddress((void**)&pv,  g_v);
    cudaGetSymbolAddress((void**)&ph,  g_h);

    const int ATT_SMEM = 4 * 64 * QPAD * (int)sizeof(float);   // 66560 B
    cudaFuncSetAttribute(attention_kernel,
                         cudaFuncAttributeMaxDynamicSharedMemorySize, ATT_SMEM);

    add_pos_kernel<<<(M_ROWS * D_MODEL + 255) / 256, 256>>>(src, pos, px);

    for (int l = 0; l < NLAYER; l++) {
        const float* wq = Wq + (long)l * D_MODEL * D_MODEL;
        const float* wk = Wk + (long)l * D_MODEL * D_MODEL;
        const float* wv = Wv + (long)l * D_MODEL * D_MODEL;
        const float* w1 = W1 + (long)l * D_MODEL * FF_DIM;
        const float* w2 = W2 + (long)l * FF_DIM * D_MODEL;

        // attention block
        layernorm_kernel<<<M_ROWS, 128>>>(px, ln1_g + l * D_MODEL, ln1_b + l * D_MODEL, pxn);
        sgemm_kernel<false,false><<<dim3(D_MODEL/128, M_ROWS/128), 256>>>(
            pxn, wq, bq + l * D_MODEL, pq, M_ROWS, D_MODEL, D_MODEL);
        sgemm_kernel<false,false><<<dim3(D_MODEL/128, M_ROWS/128), 256>>>(
            pxn, wk, bk + l * D_MODEL, pk, M_ROWS, D_MODEL, D_MODEL);
        sgemm_kernel<false,false><<<dim3(D_MODEL/128, M_ROWS/128), 256>>>(
            pxn, wv, bv + l * D_MODEL, pv, M_ROWS, D_MODEL, D_MODEL);
        attention_kernel<<<dim3(BATCH * NHEAD, S_LEN / 64), 256, ATT_SMEM>>>(pq, pk, pv, px);

        // feed-forward block
        layernorm_kernel<<<M_ROWS, 128>>>(px, ln2_g + l * D_MODEL, ln2_b + l * D_MODEL, pxn);
        sgemm_kernel<true,false><<<dim3(FF_DIM/128, M_ROWS/128), 256>>>(
            pxn, w1, b1 + l * FF_DIM, ph, M_ROWS, FF_DIM, D_MODEL);
        sgemm_kernel<false,true><<<dim3(D_MODEL/128, M_ROWS/128), 256>>>(
            ph, w2, b2 + l * D_MODEL, px, M_ROWS, D_MODEL, FF_DIM);
    }

    final_ln_kernel<<<M_ROWS, 128>>>(px, lnf_g, lnf_b, out);
}

// round 2
// speedup vs baseline: 1.3070x; 1.3070x over previous
#include <cuda_runtime.h>
#include <math.h>
#include <stdint.h>

#define D_MODEL 512
#define FF_DIM  2048
#define S_LEN   1024
#define BATCH   4
#define NLAYER  6
#define NHEAD   8
#define DHEAD   64
#define M_ROWS  (S_LEN * BATCH)   // 4096 token rows

// ---------------- scratch (device globals; no runtime allocation) ----------------
__device__ float g_x [M_ROWS * D_MODEL];   // residual stream (B,S,D)
__device__ float g_xn[M_ROWS * D_MODEL];   // layernorm output
__device__ float g_q [M_ROWS * D_MODEL];
__device__ float g_k [M_ROWS * D_MODEL];
__device__ float g_v [M_ROWS * D_MODEL];
__device__ float g_h [M_ROWS * FF_DIM];    // FF hidden

// ---------------- x = (src + pos) transposed (S,B,D) -> (B,S,D) ----------------
__global__ void add_pos_kernel(const float* __restrict__ src,
                               const float* __restrict__ pos,
                               float* __restrict__ x) {
    int idx = blockIdx.x * blockDim.x + threadIdx.x;   // over M_ROWS*D
    if (idx >= M_ROWS * D_MODEL) return;
    int d = idx & (D_MODEL - 1);
    int m = idx >> 9;            // b*S + s
    int b = m >> 10;             // / S_LEN
    int s = m & (S_LEN - 1);
    int src_i = ((s * BATCH + b) << 9) + d;
    x[idx] = src[src_i] + pos[src_i];
}

// ---------------- layernorm: one block (128 thr) per row of 512 ----------------
__global__ void layernorm_kernel(const float* __restrict__ x,
                                 const float* __restrict__ gamma,
                                 const float* __restrict__ beta,
                                 float* __restrict__ y) {
    int row = blockIdx.x;
    int tid = threadIdx.x;                 // 128
    const float4* xr = (const float4*)(x + row * D_MODEL);
    float4 v = xr[tid];
    float s  = v.x + v.y + v.z + v.w;
    float ss = v.x*v.x + v.y*v.y + v.z*v.z + v.w*v.w;
    #pragma unroll
    for (int o = 16; o > 0; o >>= 1) {
        s  += __shfl_down_sync(0xffffffffu, s,  o);
        ss += __shfl_down_sync(0xffffffffu, ss, o);
    }
    __shared__ float shs[4], shss[4];
    __shared__ float s_mean, s_inv;
    int w = tid >> 5, lane = tid & 31;
    if (lane == 0) { shs[w] = s; shss[w] = ss; }
    __syncthreads();
    if (tid == 0) {
        float ts  = shs[0] + shs[1] + shs[2] + shs[3];
        float tss = shss[0] + shss[1] + shss[2] + shss[3];
        float mean = ts * (1.0f / D_MODEL);
        float var  = tss * (1.0f / D_MODEL) - mean * mean;
        s_mean = mean;
        s_inv  = rsqrtf(var + 1e-5f);
    }
    __syncthreads();
    float mean = s_mean, inv = s_inv;
    int c = tid * 4;
    float4 g = *(const float4*)(gamma + c);
    float4 bb = *(const float4*)(beta + c);
    float4 o;
    o.x = (v.x - mean) * inv * g.x + bb.x;
    o.y = (v.y - mean) * inv * g.y + bb.y;
    o.z = (v.z - mean) * inv * g.z + bb.z;
    o.w = (v.w - mean) * inv * g.w + bb.w;
    ((float4*)(y + row * D_MODEL))[tid] = o;
}

// ---------------- final layernorm with transpose back to (S,B,D) ----------------
__global__ void final_ln_kernel(const float* __restrict__ x,
                                const float* __restrict__ gamma,
                                const float* __restrict__ beta,
                                float* __restrict__ out) {
    int row = blockIdx.x;                  // b*S + s
    int tid = threadIdx.x;
    const float4* xr = (const float4*)(x + row * D_MODEL);
    float4 v = xr[tid];
    float s  = v.x + v.y + v.z + v.w;
    float ss = v.x*v.x + v.y*v.y + v.z*v.z + v.w*v.w;
    #pragma unroll
    for (int o = 16; o > 0; o >>= 1) {
        s  += __shfl_down_sync(0xffffffffu, s,  o);
        ss += __shfl_down_sync(0xffffffffu, ss, o);
    }
    __shared__ float shs[4], shss[4];
    __shared__ float s_mean, s_inv;
    int w = tid >> 5, lane = tid & 31;
    if (lane == 0) { shs[w] = s; shss[w] = ss; }
    __syncthreads();
    if (tid == 0) {
        float ts  = shs[0] + shs[1] + shs[2] + shs[3];
        float tss = shss[0] + shss[1] + shss[2] + shss[3];
        float mean = ts * (1.0f / D_MODEL);
        float var  = tss * (1.0f / D_MODEL) - mean * mean;
        s_mean = mean;
        s_inv  = rsqrtf(var + 1e-5f);
    }
    __syncthreads();
    float mean = s_mean, inv = s_inv;
    int c = tid * 4;
    float4 g = *(const float4*)(gamma + c);
    float4 bb = *(const float4*)(beta + c);
    float4 o;
    o.x = (v.x - mean) * inv * g.x + bb.x;
    o.y = (v.y - mean) * inv * g.y + bb.y;
    o.z = (v.z - mean) * inv * g.z + bb.z;
    o.w = (v.w - mean) * inv * g.w + bb.w;
    int b = row >> 10;
    int ss_ = row & (S_LEN - 1);
    ((float4*)(out + ((ss_ * BATCH + b) << 9)))[tid] = o;
}

// ---------------- 3xTF32 tensor-core GEMM ---------------------------------------
// C[M,N] = A[M,K] @ W[K,N] + bias (+relu / +residual), fp32-accurate via hi/lo split.
// 128x128 block tile, BK=16, 256 threads = 8 warps (4 x 2), warp tile 32x64.

#define BM 128
#define BN 128
#define BK 16
#define APAD 20    // As row stride (floats): conflict-free A-fragment reads
#define BPAD 136   // Bs row stride (floats): conflict-free B-fragment reads

__device__ __forceinline__ void split_tf32(float x, uint32_t& hi, uint32_t& lo) {
    asm("cvt.rna.tf32.f32 %0, %1;" : "=r"(hi) : "f"(x));
    float r = x - __uint_as_float(hi);
    asm("cvt.rna.tf32.f32 %0, %1;" : "=r"(lo) : "f"(r));
}

__device__ __forceinline__ void mma_tf32(float* d, const uint32_t* a, const uint32_t* b) {
    asm volatile(
        "mma.sync.aligned.m16n8k8.row.col.f32.tf32.tf32.f32 "
        "{%0,%1,%2,%3}, {%4,%5,%6,%7}, {%8,%9}, {%0,%1,%2,%3};"
        : "+f"(d[0]), "+f"(d[1]), "+f"(d[2]), "+f"(d[3])
        : "r"(a[0]), "r"(a[1]), "r"(a[2]), "r"(a[3]), "r"(b[0]), "r"(b[1]));
}

template<bool RELU, bool RES>
__global__ __launch_bounds__(256, 1)
void mma_gemm_kernel(const float* __restrict__ A,
                     const float* __restrict__ W,
                     const float* __restrict__ bias,
                     float* __restrict__ C,
                     int M, int N, int K) {
    __shared__ float As[2][BM * APAD];
    __shared__ float Bs[2][BK * BPAD];

    int tid  = threadIdx.x;
    int lane = tid & 31;
    int warp = tid >> 5;
    int warpM = warp >> 1;     // 0..3 -> +32 rows
    int warpN = warp & 1;      // 0..1 -> +64 cols
    int rowBase = blockIdx.y * BM;
    int colBase = blockIdx.x * BN;
    int g = lane >> 2;         // 0..7
    int t = lane & 3;          // 0..3

    // global load mapping
    int am = tid >> 2;                 // A rows 0..63 (+64 for second half)
    int ak = (tid & 3) * 4;            // A cols within BK
    int bk = tid >> 5;                 // B rows 0..7 (+8 for second half)
    int bn = (tid & 31) * 4;           // B cols within BN

    const float* Ag = A + (long)(rowBase + am) * K + ak;
    const float* Bg = W + (long)bk * N + colBase + bn;

    float acc[2][8][4];
    #pragma unroll
    for (int mi = 0; mi < 2; mi++)
        #pragma unroll
        for (int nj = 0; nj < 8; nj++)
            #pragma unroll
            for (int r = 0; r < 4; r++) acc[mi][nj][r] = 0.0f;

    // prefetch iter 0 into buffer 0
    float4 pa0 = *(const float4*)(Ag);
    float4 pa1 = *(const float4*)(Ag + 64 * (long)K);
    float4 pb0 = *(const float4*)(Bg);
    float4 pb1 = *(const float4*)(Bg + 8 * (long)N);
    *(float4*)&As[0][am * APAD + ak]        = pa0;
    *(float4*)&As[0][(am + 64) * APAD + ak] = pa1;
    *(float4*)&Bs[0][bk * BPAD + bn]        = pb0;
    *(float4*)&Bs[0][(bk + 8) * BPAD + bn]  = pb1;

    int niter = K / BK;
    for (int it = 0; it < niter; it++) {
        __syncthreads();
        int cur = it & 1;

        if (it + 1 < niter) {
            const float* Ag2 = Ag + (it + 1) * BK;
            const float* Bg2 = Bg + (long)(it + 1) * BK * N;
            pa0 = *(const float4*)(Ag2);
            pa1 = *(const float4*)(Ag2 + 64 * (long)K);
            pb0 = *(const float4*)(Bg2);
            pb1 = *(const float4*)(Bg2 + 8 * (long)N);
        }

        const float* Asc = As[cur];
        const float* Bsc = Bs[cur];

        #pragma unroll
        for (int ks = 0; ks < 2; ks++) {
            int k0 = ks * 8;
            // A fragments (hi/lo) for 2 m-tiles
            uint32_t ahi[2][4], alo[2][4];
            #pragma unroll
            for (int mi = 0; mi < 2; mi++) {
                int r0 = warpM * 32 + mi * 16 + g;
                float f0 = Asc[r0 * APAD + k0 + t];
                float f1 = Asc[(r0 + 8) * APAD + k0 + t];
                float f2 = Asc[r0 * APAD + k0 + 4 + t];
                float f3 = Asc[(r0 + 8) * APAD + k0 + 4 + t];
                split_tf32(f0, ahi[mi][0], alo[mi][0]);
                split_tf32(f1, ahi[mi][1], alo[mi][1]);
                split_tf32(f2, ahi[mi][2], alo[mi][2]);
                split_tf32(f3, ahi[mi][3], alo[mi][3]);
            }
            // B fragments in two halves of 4 n-tiles (register pressure)
            #pragma unroll
            for (int half = 0; half < 2; half++) {
                uint32_t bhi[4][2], blo[4][2];
                #pragma unroll
                for (int j = 0; j < 4; j++) {
                    int nj = half * 4 + j;
                    int c = warpN * 64 + nj * 8 + g;
                    float g0 = Bsc[(k0 + t) * BPAD + c];
                    float g1 = Bsc[(k0 + 4 + t) * BPAD + c];
                    split_tf32(g0, bhi[j][0], blo[j][0]);
                    split_tf32(g1, bhi[j][1], blo[j][1]);
                }
                #pragma unroll
                for (int mi = 0; mi < 2; mi++)
                    #pragma unroll
                    for (int j = 0; j < 4; j++) {
                        int nj = half * 4 + j;
                        mma_tf32(acc[mi][nj], ahi[mi], blo[j]);
                        mma_tf32(acc[mi][nj], alo[mi], bhi[j]);
                        mma_tf32(acc[mi][nj], ahi[mi], bhi[j]);
                    }
            }
        }

        if (it + 1 < niter) {
            int nxt = 1 - cur;
            *(float4*)&As[nxt][am * APAD + ak]        = pa0;
            *(float4*)&As[nxt][(am + 64) * APAD + ak] = pa1;
            *(float4*)&Bs[nxt][bk * BPAD + bn]        = pb0;
            *(float4*)&Bs[nxt][(bk + 8) * BPAD + bn]  = pb1;
        }
    }

    // epilogue
    #pragma unroll
    for (int mi = 0; mi < 2; mi++) {
        int r0 = rowBase + warpM * 32 + mi * 16 + g;
        #pragma unroll
        for (int nj = 0; nj < 8; nj++) {
            int c = colBase + warpN * 64 + nj * 8 + t * 2;
            float b0 = bias[c], b1 = bias[c + 1];
            float v0 = acc[mi][nj][0] + b0;
            float v1 = acc[mi][nj][1] + b1;
            float v2 = acc[mi][nj][2] + b0;
            float v3 = acc[mi][nj][3] + b1;
            float* p0 = C + (long)r0 * N + c;
            float* p1 = C + (long)(r0 + 8) * N + c;
            if (RES) { v0 += p0[0]; v1 += p0[1]; v2 += p1[0]; v3 += p1[1]; }
            if (RELU) {
                v0 = fmaxf(v0, 0.0f); v1 = fmaxf(v1, 0.0f);
                v2 = fmaxf(v2, 0.0f); v3 = fmaxf(v3, 0.0f);
            }
            p0[0] = v0; p0[1] = v1; p1[0] = v2; p1[1] = v3;
        }
    }
}

// ---------------- flash attention + fused residual add --------------------------
// grid: (B*H, S/64), block 256. 64-query tile, DH=64, online softmax.
#define QPAD 65
__global__ void attention_kernel(const float* __restrict__ q,
                                 const float* __restrict__ k,
                                 const float* __restrict__ v,
                                 float* __restrict__ x) {
    extern __shared__ float sm[];
    float* Qs = sm;                 // 64*65
    float* Ks = sm + 64 * QPAD;
    float* Vs = sm + 2 * 64 * QPAD;
    float* Ps = sm + 3 * 64 * QPAD;
    __shared__ float mrow[64], lrow[64], crow[64];

    int bh = blockIdx.x;
    int b = bh >> 3, h = bh & 7;
    int qt = blockIdx.y;
    int tid = threadIdx.x;          // 256
    int tx = tid & 15, ty = tid >> 4;

    const float* qbase = q + ((long)(b * S_LEN + qt * 64) << 9) + h * DHEAD;
    for (int idx = tid; idx < 64 * 64; idx += 256) {
        int r = idx >> 6, c = idx & 63;
        Qs[r * QPAD + c] = qbase[(long)r * D_MODEL + c];
    }
    if (tid < 64) { mrow[tid] = -1e30f; lrow[tid] = 0.0f; }
    float acc[4][4];
    #pragma unroll
    for (int i = 0; i < 4; i++)
        #pragma unroll
        for (int j = 0; j < 4; j++) acc[i][j] = 0.0f;
    __syncthreads();

    for (int kt = 0; kt < S_LEN / 64; kt++) {
        const float* kbase = k + ((long)(b * S_LEN + kt * 64) << 9) + h * DHEAD;
        const float* vbase = v + ((long)(b * S_LEN + kt * 64) << 9) + h * DHEAD;
        for (int idx = tid; idx < 64 * 64; idx += 256) {
            int r = idx >> 6, c = idx & 63;
            Ks[r * QPAD + c] = kbase[(long)r * D_MODEL + c];
            Vs[r * QPAD + c] = vbase[(long)r * D_MODEL + c];
        }
        __syncthreads();

        // S = scale * Q @ K^T   (4x4 per thread)
        float s[4][4];
        #pragma unroll
        for (int i = 0; i < 4; i++)
            #pragma unroll
            for (int j = 0; j < 4; j++) s[i][j] = 0.0f;
        #pragma unroll 8
        for (int d = 0; d < 64; d++) {
            float qv[4], kv[4];
            #pragma unroll
            for (int i = 0; i < 4; i++) qv[i] = Qs[(ty * 4 + i) * QPAD + d];
            #pragma unroll
            for (int j = 0; j < 4; j++) kv[j] = Ks[(tx * 4 + j) * QPAD + d];
            #pragma unroll
            for (int i = 0; i < 4; i++)
                #pragma unroll
                for (int j = 0; j < 4; j++)
                    s[i][j] = fmaf(qv[i], kv[j], s[i][j]);
        }
        #pragma unroll
        for (int i = 0; i < 4; i++)
            #pragma unroll
            for (int j = 0; j < 4; j++)
                Ps[(ty * 4 + i) * QPAD + tx * 4 + j] = s[i][j] * 0.125f;
        __syncthreads();

        // online softmax per row (64 rows by first 64 threads)
        if (tid < 64) {
            float m = mrow[tid];
            float mx = m;
            #pragma unroll 8
            for (int j = 0; j < 64; j++) mx = fmaxf(mx, Ps[tid * QPAD + j]);
            float cr = __expf(m - mx);
            float l = lrow[tid] * cr;
            #pragma unroll 8
            for (int j = 0; j < 64; j++) {
                float p = __expf(Ps[tid * QPAD + j] - mx);
                Ps[tid * QPAD + j] = p;
                l += p;
            }
            mrow[tid] = mx; lrow[tid] = l; crow[tid] = cr;
        }
        __syncthreads();

        // O = O*c + P @ V
        #pragma unroll
        for (int i = 0; i < 4; i++) {
            float cr = crow[ty * 4 + i];
            float o0 = acc[i][0] * cr, o1 = acc[i][1] * cr;
            float o2 = acc[i][2] * cr, o3 = acc[i][3] * cr;
            #pragma unroll 8
            for (int kk = 0; kk < 64; kk++) {
                float p = Ps[(ty * 4 + i) * QPAD + kk];
                o0 = fmaf(p, Vs[kk * QPAD + tx * 4 + 0], o0);
                o1 = fmaf(p, Vs[kk * QPAD + tx * 4 + 1], o1);
                o2 = fmaf(p, Vs[kk * QPAD + tx * 4 + 2], o2);
                o3 = fmaf(p, Vs[kk * QPAD + tx * 4 + 3], o3);
            }
            acc[i][0] = o0; acc[i][1] = o1; acc[i][2] = o2; acc[i][3] = o3;
        }
        __syncthreads();
    }

    // x += O / l  (residual fused)
    float* xbase = x + ((long)(b * S_LEN + qt * 64) << 9) + h * DHEAD;
    #pragma unroll
    for (int i = 0; i < 4; i++) {
        int r = ty * 4 + i;
        float inv = 1.0f / lrow[r];
        #pragma unroll
        for (int j = 0; j < 4; j++) {
            int c = tx * 4 + j;
            xbase[(long)r * D_MODEL + c] += acc[i][j] * inv;
        }
    }
}

// ---------------- host orchestration --------------------------------------------
extern "C" void kernel_launch(void* const* d_in, const int* in_sizes, int n_in,
                              void* d_out, int out_size) {
    const float* src   = (const float*)d_in[0];
    const float* pos   = (const float*)d_in[1];
    const float* Wq    = (const float*)d_in[2];
    const float* bq    = (const float*)d_in[3];
    const float* Wk    = (const float*)d_in[4];
    const float* bk    = (const float*)d_in[5];
    const float* Wv    = (const float*)d_in[6];
    const float* bv    = (const float*)d_in[7];
    const float* W1    = (const float*)d_in[8];
    const float* b1    = (const float*)d_in[9];
    const float* W2    = (const float*)d_in[10];
    const float* b2    = (const float*)d_in[11];
    const float* ln1_g = (const float*)d_in[12];
    const float* ln1_b = (const float*)d_in[13];
    const float* ln2_g = (const float*)d_in[14];
    const float* ln2_b = (const float*)d_in[15];
    const float* lnf_g = (const float*)d_in[16];
    const float* lnf_b = (const float*)d_in[17];
    float* out = (float*)d_out;

    float *px, *pxn, *pq, *pk, *pv, *ph;
    cudaGetSymbolAddress((void**)&px,  g_x);
    cudaGetSymbolAddress((void**)&pxn, g_xn);
    cudaGetSymbolAddress((void**)&pq,  g_q);
    cudaGetSymbolAddress((void**)&pk,  g_k);
    cudaGetSymbolAddress((void**)&pv,  g_v);
    cudaGetSymbolAddress((void**)&ph,  g_h);

    const int ATT_SMEM = 4 * 64 * QPAD * (int)sizeof(float);   // 66560 B
    cudaFuncSetAttribute(attention_kernel,
                         cudaFuncAttributeMaxDynamicSharedMemorySize, ATT_SMEM);

    add_pos_kernel<<<(M_ROWS * D_MODEL + 255) / 256, 256>>>(src, pos, px);

    for (int l = 0; l < NLAYER; l++) {
        const float* wq = Wq + (long)l * D_MODEL * D_MODEL;
        const float* wk = Wk + (long)l * D_MODEL * D_MODEL;
        const float* wv = Wv + (long)l * D_MODEL * D_MODEL;
        const float* w1 = W1 + (long)l * D_MODEL * FF_DIM;
        const float* w2 = W2 + (long)l * FF_DIM * D_MODEL;

        // attention block
        layernorm_kernel<<<M_ROWS, 128>>>(px, ln1_g + l * D_MODEL, ln1_b + l * D_MODEL, pxn);
        mma_gemm_kernel<false,false><<<dim3(D_MODEL/BN, M_ROWS/BM), 256>>>(
            pxn, wq, bq + l * D_MODEL, pq, M_ROWS, D_MODEL, D_MODEL);
        mma_gemm_kernel<false,false><<<dim3(D_MODEL/BN, M_ROWS/BM), 256>>>(
            pxn, wk, bk + l * D_MODEL, pk, M_ROWS, D_MODEL, D_MODEL);
        mma_gemm_kernel<false,false><<<dim3(D_MODEL/BN, M_ROWS/BM), 256>>>(
            pxn, wv, bv + l * D_MODEL, pv, M_ROWS, D_MODEL, D_MODEL);
        attention_kernel<<<dim3(BATCH * NHEAD, S_LEN / 64), 256, ATT_SMEM>>>(pq, pk, pv, px);

        // feed-forward block
        layernorm_kernel<<<M_ROWS, 128>>>(px, ln2_g + l * D_MODEL, ln2_b + l * D_MODEL, pxn);
        mma_gemm_kernel<true,false><<<dim3(FF_DIM/BN, M_ROWS/BM), 256>>>(
            pxn, w1, b1 + l * FF_DIM, ph, M_ROWS, FF_DIM, D_MODEL);
        mma_gemm_kernel<false,true><<<dim3(D_MODEL/BN, M_ROWS/BM), 256>>>(
            ph, w2, b2 + l * D_MODEL, px, M_ROWS, D_MODEL, FF_DIM);
    }

    final_ln_kernel<<<M_ROWS, 128>>>(px, lnf_g, lnf_b, out);
}

// round 3
// speedup vs baseline: 2.1732x; 1.6628x over previous
#include <cuda_runtime.h>
#include <math.h>
#include <stdint.h>

#define D_MODEL 512
#define FF_DIM  2048
#define S_LEN   1024
#define BATCH   4
#define NLAYER  6
#define NHEAD   8
#define DHEAD   64
#define M_ROWS  (S_LEN * BATCH)   // 4096 token rows

// ---------------- scratch (device globals; no runtime allocation) ----------------
__device__ float g_x [M_ROWS * D_MODEL];   // residual stream (B,S,D)
__device__ float g_xn[M_ROWS * D_MODEL];   // layernorm output
__device__ float g_q [M_ROWS * D_MODEL];
__device__ float g_k [M_ROWS * D_MODEL];
__device__ float g_v [M_ROWS * D_MODEL];
__device__ float g_h [M_ROWS * FF_DIM];    // FF hidden

// ---------------- tf32 helpers ----------------------------------------------------
__device__ __forceinline__ void split_tf32(float x, uint32_t& hi, uint32_t& lo) {
    asm("cvt.rna.tf32.f32 %0, %1;" : "=r"(hi) : "f"(x));
    float r = x - __uint_as_float(hi);
    asm("cvt.rna.tf32.f32 %0, %1;" : "=r"(lo) : "f"(r));
}

__device__ __forceinline__ void mma_tf32(float* d, const uint32_t* a, const uint32_t* b) {
    asm volatile(
        "mma.sync.aligned.m16n8k8.row.col.f32.tf32.tf32.f32 "
        "{%0,%1,%2,%3}, {%4,%5,%6,%7}, {%8,%9}, {%0,%1,%2,%3};"
        : "+f"(d[0]), "+f"(d[1]), "+f"(d[2]), "+f"(d[3])
        : "r"(a[0]), "r"(a[1]), "r"(a[2]), "r"(a[3]), "r"(b[0]), "r"(b[1]));
}

// ---------------- x = (src + pos) transposed (S,B,D) -> (B,S,D) ----------------
__global__ void add_pos_kernel(const float* __restrict__ src,
                               const float* __restrict__ pos,
                               float* __restrict__ x) {
    int idx = blockIdx.x * blockDim.x + threadIdx.x;   // over M_ROWS*D
    if (idx >= M_ROWS * D_MODEL) return;
    int d = idx & (D_MODEL - 1);
    int m = idx >> 9;            // b*S + s
    int b = m >> 10;             // / S_LEN
    int s = m & (S_LEN - 1);
    int src_i = ((s * BATCH + b) << 9) + d;
    x[idx] = src[src_i] + pos[src_i];
}

// ---------------- layernorm: one block (128 thr) per row of 512 ----------------
__global__ void layernorm_kernel(const float* __restrict__ x,
                                 const float* __restrict__ gamma,
                                 const float* __restrict__ beta,
                                 float* __restrict__ y) {
    int row = blockIdx.x;
    int tid = threadIdx.x;                 // 128
    const float4* xr = (const float4*)(x + row * D_MODEL);
    float4 v = xr[tid];
    float s  = v.x + v.y + v.z + v.w;
    float ss = v.x*v.x + v.y*v.y + v.z*v.z + v.w*v.w;
    #pragma unroll
    for (int o = 16; o > 0; o >>= 1) {
        s  += __shfl_down_sync(0xffffffffu, s,  o);
        ss += __shfl_down_sync(0xffffffffu, ss, o);
    }
    __shared__ float shs[4], shss[4];
    __shared__ float s_mean, s_inv;
    int w = tid >> 5, lane = tid & 31;
    if (lane == 0) { shs[w] = s; shss[w] = ss; }
    __syncthreads();
    if (tid == 0) {
        float ts  = shs[0] + shs[1] + shs[2] + shs[3];
        float tss = shss[0] + shss[1] + shss[2] + shss[3];
        float mean = ts * (1.0f / D_MODEL);
        float var  = tss * (1.0f / D_MODEL) - mean * mean;
        s_mean = mean;
        s_inv  = rsqrtf(var + 1e-5f);
    }
    __syncthreads();
    float mean = s_mean, inv = s_inv;
    int c = tid * 4;
    float4 g = *(const float4*)(gamma + c);
    float4 bb = *(const float4*)(beta + c);
    float4 o;
    o.x = (v.x - mean) * inv * g.x + bb.x;
    o.y = (v.y - mean) * inv * g.y + bb.y;
    o.z = (v.z - mean) * inv * g.z + bb.z;
    o.w = (v.w - mean) * inv * g.w + bb.w;
    ((float4*)(y + row * D_MODEL))[tid] = o;
}

// ---------------- final layernorm with transpose back to (S,B,D) ----------------
__global__ void final_ln_kernel(const float* __restrict__ x,
                                const float* __restrict__ gamma,
                                const float* __restrict__ beta,
                                float* __restrict__ out) {
    int row = blockIdx.x;                  // b*S + s
    int tid = threadIdx.x;
    const float4* xr = (const float4*)(x + row * D_MODEL);
    float4 v = xr[tid];
    float s  = v.x + v.y + v.z + v.w;
    float ss = v.x*v.x + v.y*v.y + v.z*v.z + v.w*v.w;
    #pragma unroll
    for (int o = 16; o > 0; o >>= 1) {
        s  += __shfl_down_sync(0xffffffffu, s,  o);
        ss += __shfl_down_sync(0xffffffffu, ss, o);
    }
    __shared__ float shs[4], shss[4];
    __shared__ float s_mean, s_inv;
    int w = tid >> 5, lane = tid & 31;
    if (lane == 0) { shs[w] = s; shss[w] = ss; }
    __syncthreads();
    if (tid == 0) {
        float ts  = shs[0] + shs[1] + shs[2] + shs[3];
        float tss = shss[0] + shss[1] + shss[2] + shss[3];
        float mean = ts * (1.0f / D_MODEL);
        float var  = tss * (1.0f / D_MODEL) - mean * mean;
        s_mean = mean;
        s_inv  = rsqrtf(var + 1e-5f);
    }
    __syncthreads();
    float mean = s_mean, inv = s_inv;
    int c = tid * 4;
    float4 g = *(const float4*)(gamma + c);
    float4 bb = *(const float4*)(beta + c);
    float4 o;
    o.x = (v.x - mean) * inv * g.x + bb.x;
    o.y = (v.y - mean) * inv * g.y + bb.y;
    o.z = (v.z - mean) * inv * g.z + bb.z;
    o.w = (v.w - mean) * inv * g.w + bb.w;
    int b = row >> 10;
    int ss_ = row & (S_LEN - 1);
    ((float4*)(out + ((ss_ * BATCH + b) << 9)))[tid] = o;
}

// ---------------- 3xTF32 tensor-core GEMM ---------------------------------------
#define BM 128
#define BN 128
#define BK 16
#define APAD 20
#define BPAD 136

template<bool RELU, bool RES>
__global__ __launch_bounds__(256, 1)
void mma_gemm_kernel(const float* __restrict__ A,
                     const float* __restrict__ W,
                     const float* __restrict__ bias,
                     float* __restrict__ C,
                     int M, int N, int K) {
    __shared__ float As[2][BM * APAD];
    __shared__ float Bs[2][BK * BPAD];

    int tid  = threadIdx.x;
    int lane = tid & 31;
    int warp = tid >> 5;
    int warpM = warp >> 1;
    int warpN = warp & 1;
    int rowBase = blockIdx.y * BM;
    int colBase = blockIdx.x * BN;
    int g = lane >> 2;
    int t = lane & 3;

    int am = tid >> 2;
    int ak = (tid & 3) * 4;
    int bk = tid >> 5;
    int bn = (tid & 31) * 4;

    const float* Ag = A + (long)(rowBase + am) * K + ak;
    const float* Bg = W + (long)bk * N + colBase + bn;

    float acc[2][8][4];
    #pragma unroll
    for (int mi = 0; mi < 2; mi++)
        #pragma unroll
        for (int nj = 0; nj < 8; nj++)
            #pragma unroll
            for (int r = 0; r < 4; r++) acc[mi][nj][r] = 0.0f;

    float4 pa0 = *(const float4*)(Ag);
    float4 pa1 = *(const float4*)(Ag + 64 * (long)K);
    float4 pb0 = *(const float4*)(Bg);
    float4 pb1 = *(const float4*)(Bg + 8 * (long)N);
    *(float4*)&As[0][am * APAD + ak]        = pa0;
    *(float4*)&As[0][(am + 64) * APAD + ak] = pa1;
    *(float4*)&Bs[0][bk * BPAD + bn]        = pb0;
    *(float4*)&Bs[0][(bk + 8) * BPAD + bn]  = pb1;

    int niter = K / BK;
    for (int it = 0; it < niter; it++) {
        __syncthreads();
        int cur = it & 1;

        if (it + 1 < niter) {
            const float* Ag2 = Ag + (it + 1) * BK;
            const float* Bg2 = Bg + (long)(it + 1) * BK * N;
            pa0 = *(const float4*)(Ag2);
            pa1 = *(const float4*)(Ag2 + 64 * (long)K);
            pb0 = *(const float4*)(Bg2);
            pb1 = *(const float4*)(Bg2 + 8 * (long)N);
        }

        const float* Asc = As[cur];
        const float* Bsc = Bs[cur];

        #pragma unroll
        for (int ks = 0; ks < 2; ks++) {
            int k0 = ks * 8;
            uint32_t ahi[2][4], alo[2][4];
            #pragma unroll
            for (int mi = 0; mi < 2; mi++) {
                int r0 = warpM * 32 + mi * 16 + g;
                float f0 = Asc[r0 * APAD + k0 + t];
                float f1 = Asc[(r0 + 8) * APAD + k0 + t];
                float f2 = Asc[r0 * APAD + k0 + 4 + t];
                float f3 = Asc[(r0 + 8) * APAD + k0 + 4 + t];
                split_tf32(f0, ahi[mi][0], alo[mi][0]);
                split_tf32(f1, ahi[mi][1], alo[mi][1]);
                split_tf32(f2, ahi[mi][2], alo[mi][2]);
                split_tf32(f3, ahi[mi][3], alo[mi][3]);
            }
            #pragma unroll
            for (int half = 0; half < 2; half++) {
                uint32_t bhi[4][2], blo[4][2];
                #pragma unroll
                for (int j = 0; j < 4; j++) {
                    int nj = half * 4 + j;
                    int c = warpN * 64 + nj * 8 + g;
                    float g0 = Bsc[(k0 + t) * BPAD + c];
                    float g1 = Bsc[(k0 + 4 + t) * BPAD + c];
                    split_tf32(g0, bhi[j][0], blo[j][0]);
                    split_tf32(g1, bhi[j][1], blo[j][1]);
                }
                #pragma unroll
                for (int mi = 0; mi < 2; mi++)
                    #pragma unroll
                    for (int j = 0; j < 4; j++) {
                        int nj = half * 4 + j;
                        mma_tf32(acc[mi][nj], ahi[mi], blo[j]);
                        mma_tf32(acc[mi][nj], alo[mi], bhi[j]);
                        mma_tf32(acc[mi][nj], ahi[mi], bhi[j]);
                    }
            }
        }

        if (it + 1 < niter) {
            int nxt = 1 - cur;
            *(float4*)&As[nxt][am * APAD + ak]        = pa0;
            *(float4*)&As[nxt][(am + 64) * APAD + ak] = pa1;
            *(float4*)&Bs[nxt][bk * BPAD + bn]        = pb0;
            *(float4*)&Bs[nxt][(bk + 8) * BPAD + bn]  = pb1;
        }
    }

    #pragma unroll
    for (int mi = 0; mi < 2; mi++) {
        int r0 = rowBase + warpM * 32 + mi * 16 + g;
        #pragma unroll
        for (int nj = 0; nj < 8; nj++) {
            int c = colBase + warpN * 64 + nj * 8 + t * 2;
            float b0 = bias[c], b1 = bias[c + 1];
            float v0 = acc[mi][nj][0] + b0;
            float v1 = acc[mi][nj][1] + b1;
            float v2 = acc[mi][nj][2] + b0;
            float v3 = acc[mi][nj][3] + b1;
            float* p0 = C + (long)r0 * N + c;
            float* p1 = C + (long)(r0 + 8) * N + c;
            if (RES) { v0 += p0[0]; v1 += p0[1]; v2 += p1[0]; v3 += p1[1]; }
            if (RELU) {
                v0 = fmaxf(v0, 0.0f); v1 = fmaxf(v1, 0.0f);
                v2 = fmaxf(v2, 0.0f); v3 = fmaxf(v3, 0.0f);
            }
            p0[0] = v0; p0[1] = v1; p1[0] = v2; p1[1] = v3;
        }
    }
}

// ---------------- tensor-core flash attention (3xTF32) + fused residual --------
// CTA per (b*h, 128-query tile). 8 warps x 16 exclusive query rows.
// KV streamed in 64-key tiles. Softmax fully in-warp (quad shuffles).
#define QP 68   // pad for A-operand arrays (Q, P): pad % 32 == 4
#define VP 72   // pad for V (B-operand, n=dh):     pad % 32 == 8

__global__ __launch_bounds__(256, 1)
void attention_mma_kernel(const float* __restrict__ q,
                          const float* __restrict__ k,
                          const float* __restrict__ v,
                          float* __restrict__ x) {
    extern __shared__ float sm[];
    float* Qh = sm;                      // [128][QP]
    float* Ql = Qh + 128 * QP;
    float* Kh = Ql + 128 * QP;           // [64][QP]  (keys x dh)
    float* Kl = Kh + 64 * QP;
    float* Vh = Kl + 64 * QP;            // [64][VP]  (keys x dh)
    float* Vl = Vh + 64 * VP;
    float* Ph = Vl + 64 * VP;            // [128][QP] (queries x keys)
    float* Pl = Ph + 128 * QP;

    int tid = threadIdx.x;
    int lane = tid & 31, warp = tid >> 5;
    int g = lane >> 2, t = lane & 3;
    int bh = blockIdx.x;
    int b = bh >> 3, h = bh & 7;
    int qt = blockIdx.y;
    int qr = warp * 16;                  // this warp's query-row base within tile

    // ---- stage Q (scaled by 1/8, split hi/lo) ----
    {
        const float* qg = q + ((long)(b * S_LEN + qt * 128) << 9) + h * DHEAD;
        int r = tid >> 4;                // 16 rows per pass
        int c = (tid & 15) * 4;
        #pragma unroll
        for (int p = 0; p < 8; p++) {
            int rr = p * 16 + r;
            float4 v4 = *(const float4*)(qg + (long)rr * D_MODEL + c);
            v4.x *= 0.125f; v4.y *= 0.125f; v4.z *= 0.125f; v4.w *= 0.125f;
            uint32_t h0,l0,h1,l1,h2,l2,h3,l3;
            split_tf32(v4.x, h0, l0); split_tf32(v4.y, h1, l1);
            split_tf32(v4.z, h2, l2); split_tf32(v4.w, h3, l3);
            *(float4*)&Qh[rr * QP + c] = make_float4(__uint_as_float(h0), __uint_as_float(h1),
                                                     __uint_as_float(h2), __uint_as_float(h3));
            *(float4*)&Ql[rr * QP + c] = make_float4(__uint_as_float(l0), __uint_as_float(l1),
                                                     __uint_as_float(l2), __uint_as_float(l3));
        }
    }

    float o[8][4];
    #pragma unroll
    for (int j = 0; j < 8; j++)
        #pragma unroll
        for (int r = 0; r < 4; r++) o[j][r] = 0.0f;
    float m0 = -1e30f, m1 = -1e30f, l0s = 0.0f, l1s = 0.0f;

    for (int kt = 0; kt < S_LEN / 64; kt++) {
        __syncthreads();
        // ---- stage K, V tile (split hi/lo) ----
        {
            const float* kg = k + ((long)(b * S_LEN + kt * 64) << 9) + h * DHEAD;
            const float* vg = v + ((long)(b * S_LEN + kt * 64) << 9) + h * DHEAD;
            int r = tid >> 4;
            int c = (tid & 15) * 4;
            #pragma unroll
            for (int p = 0; p < 4; p++) {
                int rr = p * 16 + r;
                float4 kv4 = *(const float4*)(kg + (long)rr * D_MODEL + c);
                uint32_t h0,lo0,h1,lo1,h2,lo2,h3,lo3;
                split_tf32(kv4.x, h0, lo0); split_tf32(kv4.y, h1, lo1);
                split_tf32(kv4.z, h2, lo2); split_tf32(kv4.w, h3, lo3);
                *(float4*)&Kh[rr * QP + c] = make_float4(__uint_as_float(h0), __uint_as_float(h1),
                                                         __uint_as_float(h2), __uint_as_float(h3));
                *(float4*)&Kl[rr * QP + c] = make_float4(__uint_as_float(lo0), __uint_as_float(lo1),
                                                         __uint_as_float(lo2), __uint_as_float(lo3));
                float4 vv4 = *(const float4*)(vg + (long)rr * D_MODEL + c);
                split_tf32(vv4.x, h0, lo0); split_tf32(vv4.y, h1, lo1);
                split_tf32(vv4.z, h2, lo2); split_tf32(vv4.w, h3, lo3);
                *(float4*)&Vh[rr * VP + c] = make_float4(__uint_as_float(h0), __uint_as_float(h1),
                                                         __uint_as_float(h2), __uint_as_float(h3));
                *(float4*)&Vl[rr * VP + c] = make_float4(__uint_as_float(lo0), __uint_as_float(lo1),
                                                         __uint_as_float(lo2), __uint_as_float(lo3));
            }
        }
        __syncthreads();

        // ---- S = (Q/8) @ K^T : warp computes 16 x 64 ----
        float s[8][4];
        #pragma unroll
        for (int j = 0; j < 8; j++)
            #pragma unroll
            for (int r = 0; r < 4; r++) s[j][r] = 0.0f;

        #pragma unroll
        for (int k8 = 0; k8 < 8; k8++) {
            int kc = k8 * 8;
            uint32_t qh_[4], ql_[4];
            qh_[0] = __float_as_uint(Qh[(qr + g)     * QP + kc + t]);
            qh_[1] = __float_as_uint(Qh[(qr + g + 8) * QP + kc + t]);
            qh_[2] = __float_as_uint(Qh[(qr + g)     * QP + kc + 4 + t]);
            qh_[3] = __float_as_uint(Qh[(qr + g + 8) * QP + kc + 4 + t]);
            ql_[0] = __float_as_uint(Ql[(qr + g)     * QP + kc + t]);
            ql_[1] = __float_as_uint(Ql[(qr + g + 8) * QP + kc + t]);
            ql_[2] = __float_as_uint(Ql[(qr + g)     * QP + kc + 4 + t]);
            ql_[3] = __float_as_uint(Ql[(qr + g + 8) * QP + kc + 4 + t]);
            #pragma unroll
            for (int j = 0; j < 8; j++) {
                uint32_t kh_[2], kl_[2];
                kh_[0] = __float_as_uint(Kh[(j * 8 + g) * QP + kc + t]);
                kh_[1] = __float_as_uint(Kh[(j * 8 + g) * QP + kc + 4 + t]);
                kl_[0] = __float_as_uint(Kl[(j * 8 + g) * QP + kc + t]);
                kl_[1] = __float_as_uint(Kl[(j * 8 + g) * QP + kc + 4 + t]);
                mma_tf32(s[j], qh_, kl_);
                mma_tf32(s[j], ql_, kh_);
                mma_tf32(s[j], qh_, kh_);
            }
        }

        // ---- online softmax (warp-local rows g and g+8) ----
        float mx0 = -1e30f, mx1 = -1e30f;
        #pragma unroll
        for (int j = 0; j < 8; j++) {
            mx0 = fmaxf(mx0, fmaxf(s[j][0], s[j][1]));
            mx1 = fmaxf(mx1, fmaxf(s[j][2], s[j][3]));
        }
        mx0 = fmaxf(mx0, __shfl_xor_sync(0xffffffffu, mx0, 1));
        mx0 = fmaxf(mx0, __shfl_xor_sync(0xffffffffu, mx0, 2));
        mx1 = fmaxf(mx1, __shfl_xor_sync(0xffffffffu, mx1, 1));
        mx1 = fmaxf(mx1, __shfl_xor_sync(0xffffffffu, mx1, 2));
        float mn0 = fmaxf(m0, mx0), mn1 = fmaxf(m1, mx1);
        float c0 = __expf(m0 - mn0), c1 = __expf(m1 - mn1);
        l0s *= c0; l1s *= c1;
        #pragma unroll
        for (int j = 0; j < 8; j++) {
            float p0 = __expf(s[j][0] - mn0);
            float p1 = __expf(s[j][1] - mn0);
            float p2 = __expf(s[j][2] - mn1);
            float p3 = __expf(s[j][3] - mn1);
            l0s += p0 + p1; l1s += p2 + p3;
            uint32_t ph0,pl0,ph1,pl1,ph2,pl2,ph3,pl3;
            split_tf32(p0, ph0, pl0); split_tf32(p1, ph1, pl1);
            split_tf32(p2, ph2, pl2); split_tf32(p3, ph3, pl3);
            int cc = j * 8 + 2 * t;
            *(float2*)&Ph[(qr + g)     * QP + cc] = make_float2(__uint_as_float(ph0), __uint_as_float(ph1));
            *(float2*)&Ph[(qr + g + 8) * QP + cc] = make_float2(__uint_as_float(ph2), __uint_as_float(ph3));
            *(float2*)&Pl[(qr + g)     * QP + cc] = make_float2(__uint_as_float(pl0), __uint_as_float(pl1));
            *(float2*)&Pl[(qr + g + 8) * QP + cc] = make_float2(__uint_as_float(pl2), __uint_as_float(pl3));
            o[j][0] *= c0; o[j][1] *= c0; o[j][2] *= c1; o[j][3] *= c1;
        }
        m0 = mn0; m1 = mn1;
        __syncwarp();

        // ---- O += P @ V : warp computes 16 x 64 over 64 keys ----
        #pragma unroll
        for (int k8 = 0; k8 < 8; k8++) {
            int kc = k8 * 8;
            uint32_t ph_[4], pl_[4];
            ph_[0] = __float_as_uint(Ph[(qr + g)     * QP + kc + t]);
            ph_[1] = __float_as_uint(Ph[(qr + g + 8) * QP + kc + t]);
            ph_[2] = __float_as_uint(Ph[(qr + g)     * QP + kc + 4 + t]);
            ph_[3] = __float_as_uint(Ph[(qr + g + 8) * QP + kc + 4 + t]);
            pl_[0] = __float_as_uint(Pl[(qr + g)     * QP + kc + t]);
            pl_[1] = __float_as_uint(Pl[(qr + g + 8) * QP + kc + t]);
            pl_[2] = __float_as_uint(Pl[(qr + g)     * QP + kc + 4 + t]);
            pl_[3] = __float_as_uint(Pl[(qr + g + 8) * QP + kc + 4 + t]);
            #pragma unroll
            for (int j = 0; j < 8; j++) {
                uint32_t vh_[2], vl_[2];
                vh_[0] = __float_as_uint(Vh[(kc + t)     * VP + j * 8 + g]);
                vh_[1] = __float_as_uint(Vh[(kc + 4 + t) * VP + j * 8 + g]);
                vl_[0] = __float_as_uint(Vl[(kc + t)     * VP + j * 8 + g]);
                vl_[1] = __float_as_uint(Vl[(kc + 4 + t) * VP + j * 8 + g]);
                mma_tf32(o[j], ph_, vl_);
                mma_tf32(o[j], pl_, vh_);
                mma_tf32(o[j], ph_, vh_);
            }
        }
    }

    // ---- finalize: x += O / l ----
    l0s += __shfl_xor_sync(0xffffffffu, l0s, 1);
    l0s += __shfl_xor_sync(0xffffffffu, l0s, 2);
    l1s += __shfl_xor_sync(0xffffffffu, l1s, 1);
    l1s += __shfl_xor_sync(0xffffffffu, l1s, 2);
    float i0 = 1.0f / l0s, i1 = 1.0f / l1s;

    float* xr0 = x + ((long)(b * S_LEN + qt * 128 + qr + g)     << 9) + h * DHEAD;
    float* xr1 = x + ((long)(b * S_LEN + qt * 128 + qr + g + 8) << 9) + h * DHEAD;
    #pragma unroll
    for (int j = 0; j < 8; j++) {
        int cc = j * 8 + 2 * t;
        float2 r0 = *(float2*)(xr0 + cc);
        r0.x += o[j][0] * i0; r0.y += o[j][1] * i0;
        *(float2*)(xr0 + cc) = r0;
        float2 r1 = *(float2*)(xr1 + cc);
        r1.x += o[j][2] * i1; r1.y += o[j][3] * i1;
        *(float2*)(xr1 + cc) = r1;
    }
}

// ---------------- host orchestration --------------------------------------------
extern "C" void kernel_launch(void* const* d_in, const int* in_sizes, int n_in,
                              void* d_out, int out_size) {
    const float* src   = (const float*)d_in[0];
    const float* pos   = (const float*)d_in[1];
    const float* Wq    = (const float*)d_in[2];
    const float* bq    = (const float*)d_in[3];
    const float* Wk    = (const float*)d_in[4];
    const float* bk    = (const float*)d_in[5];
    const float* Wv    = (const float*)d_in[6];
    const float* bv    = (const float*)d_in[7];
    const float* W1    = (const float*)d_in[8];
    const float* b1    = (const float*)d_in[9];
    const float* W2    = (const float*)d_in[10];
    const float* b2    = (const float*)d_in[11];
    const float* ln1_g = (const float*)d_in[12];
    const float* ln1_b = (const float*)d_in[13];
    const float* ln2_g = (const float*)d_in[14];
    const float* ln2_b = (const float*)d_in[15];
    const float* lnf_g = (const float*)d_in[16];
    const float* lnf_b = (const float*)d_in[17];
    float* out = (float*)d_out;

    float *px, *pxn, *pq, *pk, *pv, *ph;
    cudaGetSymbolAddress((void**)&px,  g_x);
    cudaGetSymbolAddress((void**)&pxn, g_xn);
    cudaGetSymbolAddress((void**)&pq,  g_q);
    cudaGetSymbolAddress((void**)&pk,  g_k);
    cudaGetSymbolAddress((void**)&pv,  g_v);
    cudaGetSymbolAddress((void**)&ph,  g_h);

    const int ATT_SMEM = (2 * 128 * QP + 2 * 64 * QP + 2 * 64 * VP + 2 * 128 * QP)
                         * (int)sizeof(float);   // 210944 B
    cudaFuncSetAttribute(attention_mma_kernel,
                         cudaFuncAttributeMaxDynamicSharedMemorySize, ATT_SMEM);

    add_pos_kernel<<<(M_ROWS * D_MODEL + 255) / 256, 256>>>(src, pos, px);

    for (int l = 0; l < NLAYER; l++) {
        const float* wq = Wq + (long)l * D_MODEL * D_MODEL;
        const float* wk = Wk + (long)l * D_MODEL * D_MODEL;
        const float* wv = Wv + (long)l * D_MODEL * D_MODEL;
        const float* w1 = W1 + (long)l * D_MODEL * FF_DIM;
        const float* w2 = W2 + (long)l * FF_DIM * D_MODEL;

        // attention block
        layernorm_kernel<<<M_ROWS, 128>>>(px, ln1_g + l * D_MODEL, ln1_b + l * D_MODEL, pxn);
        mma_gemm_kernel<false,false><<<dim3(D_MODEL/BN, M_ROWS/BM), 256>>>(
            pxn, wq, bq + l * D_MODEL, pq, M_ROWS, D_MODEL, D_MODEL);
        mma_gemm_kernel<false,false><<<dim3(D_MODEL/BN, M_ROWS/BM), 256>>>(
            pxn, wk, bk + l * D_MODEL, pk, M_ROWS, D_MODEL, D_MODEL);
        mma_gemm_kernel<false,false><<<dim3(D_MODEL/BN, M_ROWS/BM), 256>>>(
            pxn, wv, bv + l * D_MODEL, pv, M_ROWS, D_MODEL, D_MODEL);
        attention_mma_kernel<<<dim3(BATCH * NHEAD, S_LEN / 128), 256, ATT_SMEM>>>(pq, pk, pv, px);

        // feed-forward block
        layernorm_kernel<<<M_ROWS, 128>>>(px, ln2_g + l * D_MODEL, ln2_b + l * D_MODEL, pxn);
        mma_gemm_kernel<true,false><<<dim3(FF_DIM/BN, M_ROWS/BM), 256>>>(
            pxn, w1, b1 + l * FF_DIM, ph, M_ROWS, FF_DIM, D_MODEL);
        mma_gemm_kernel<false,true><<<dim3(D_MODEL/BN, M_ROWS/BM), 256>>>(
            ph, w2, b2 + l * D_MODEL, px, M_ROWS, D_MODEL, FF_DIM);
    }

    final_ln_kernel<<<M_ROWS, 128>>>(px, lnf_g, lnf_b, out);
}

// round 4
// speedup vs baseline: 2.2088x; 1.0164x over previous
#include <cuda_runtime.h>
#include <math.h>
#include <stdint.h>

#define D_MODEL 512
#define FF_DIM  2048
#define S_LEN   1024
#define BATCH   4
#define NLAYER  6
#define NHEAD   8
#define DHEAD   64
#define M_ROWS  (S_LEN * BATCH)   // 4096 token rows

// weight split layout inside g_wh / g_wl
#define WQ_OFF 0
#define WK_OFF (NLAYER * D_MODEL * D_MODEL)            // 1572864
#define WV_OFF (2 * NLAYER * D_MODEL * D_MODEL)        // 3145728
#define W1_OFF (3 * NLAYER * D_MODEL * D_MODEL)        // 4718592
#define W2_OFF (W1_OFF + NLAYER * D_MODEL * FF_DIM)    // 11010048
#define W_TOTAL (W2_OFF + NLAYER * FF_DIM * D_MODEL)   // 17301504

// ---------------- scratch (device globals; no runtime allocation) ----------------
__device__ float g_x   [M_ROWS * D_MODEL];   // residual stream (B,S,D)
__device__ float g_xn_h[M_ROWS * D_MODEL];   // layernorm output hi
__device__ float g_xn_l[M_ROWS * D_MODEL];   // layernorm output lo
__device__ float g_q   [M_ROWS * D_MODEL];
__device__ float g_k   [M_ROWS * D_MODEL];
__device__ float g_v   [M_ROWS * D_MODEL];
__device__ float g_h_h [M_ROWS * FF_DIM];    // FF hidden hi
__device__ float g_h_l [M_ROWS * FF_DIM];    // FF hidden lo
__device__ float g_wh  [W_TOTAL];            // all weights hi
__device__ float g_wl  [W_TOTAL];            // all weights lo

// ---------------- tf32 helpers ----------------------------------------------------
__device__ __forceinline__ void split_tf32(float x, uint32_t& hi, uint32_t& lo) {
    asm("cvt.rna.tf32.f32 %0, %1;" : "=r"(hi) : "f"(x));
    float r = x - __uint_as_float(hi);
    asm("cvt.rna.tf32.f32 %0, %1;" : "=r"(lo) : "f"(r));
}

__device__ __forceinline__ void mma_tf32(float* d, const uint32_t* a, const uint32_t* b) {
    asm volatile(
        "mma.sync.aligned.m16n8k8.row.col.f32.tf32.tf32.f32 "
        "{%0,%1,%2,%3}, {%4,%5,%6,%7}, {%8,%9}, {%0,%1,%2,%3};"
        : "+f"(d[0]), "+f"(d[1]), "+f"(d[2]), "+f"(d[3])
        : "r"(a[0]), "r"(a[1]), "r"(a[2]), "r"(a[3]), "r"(b[0]), "r"(b[1]));
}

__device__ __forceinline__ void cp_async16(uint32_t dst, const void* src) {
    asm volatile("cp.async.ca.shared.global [%0], [%1], 16;" :: "r"(dst), "l"(src));
}
__device__ __forceinline__ void cp_commit() {
    asm volatile("cp.async.commit_group;");
}
template<int N>
__device__ __forceinline__ void cp_wait() {
    asm volatile("cp.async.wait_group %0;" :: "n"(N));
}
__device__ __forceinline__ uint32_t smem_u32(const void* p) {
    return (uint32_t)__cvta_generic_to_shared(p);
}

// ---------------- weight split: src -> (hi, lo), vectorized -----------------------
__global__ void split_kernel(const float* __restrict__ src,
                             float* __restrict__ hi, float* __restrict__ lo, int n4) {
    int i = blockIdx.x * blockDim.x + threadIdx.x;
    if (i >= n4) return;
    float4 v = ((const float4*)src)[i];
    uint32_t h0,l0,h1,l1,h2,l2,h3,l3;
    split_tf32(v.x, h0, l0); split_tf32(v.y, h1, l1);
    split_tf32(v.z, h2, l2); split_tf32(v.w, h3, l3);
    ((float4*)hi)[i] = make_float4(__uint_as_float(h0), __uint_as_float(h1),
                                   __uint_as_float(h2), __uint_as_float(h3));
    ((float4*)lo)[i] = make_float4(__uint_as_float(l0), __uint_as_float(l1),
                                   __uint_as_float(l2), __uint_as_float(l3));
}

// ---------------- x = (src + pos) transposed (S,B,D) -> (B,S,D) ----------------
__global__ void add_pos_kernel(const float* __restrict__ src,
                               const float* __restrict__ pos,
                               float* __restrict__ x) {
    int idx = blockIdx.x * blockDim.x + threadIdx.x;
    if (idx >= M_ROWS * D_MODEL) return;
    int d = idx & (D_MODEL - 1);
    int m = idx >> 9;
    int b = m >> 10;
    int s = m & (S_LEN - 1);
    int src_i = ((s * BATCH + b) << 9) + d;
    x[idx] = src[src_i] + pos[src_i];
}

// ---------------- layernorm -> split hi/lo output --------------------------------
__global__ void layernorm_split_kernel(const float* __restrict__ x,
                                       const float* __restrict__ gamma,
                                       const float* __restrict__ beta,
                                       float* __restrict__ yh,
                                       float* __restrict__ yl) {
    int row = blockIdx.x;
    int tid = threadIdx.x;                 // 128
    const float4* xr = (const float4*)(x + row * D_MODEL);
    float4 v = xr[tid];
    float s  = v.x + v.y + v.z + v.w;
    float ss = v.x*v.x + v.y*v.y + v.z*v.z + v.w*v.w;
    #pragma unroll
    for (int o = 16; o > 0; o >>= 1) {
        s  += __shfl_down_sync(0xffffffffu, s,  o);
        ss += __shfl_down_sync(0xffffffffu, ss, o);
    }
    __shared__ float shs[4], shss[4];
    __shared__ float s_mean, s_inv;
    int w = tid >> 5, lane = tid & 31;
    if (lane == 0) { shs[w] = s; shss[w] = ss; }
    __syncthreads();
    if (tid == 0) {
        float ts  = shs[0] + shs[1] + shs[2] + shs[3];
        float tss = shss[0] + shss[1] + shss[2] + shss[3];
        float mean = ts * (1.0f / D_MODEL);
        float var  = tss * (1.0f / D_MODEL) - mean * mean;
        s_mean = mean;
        s_inv  = rsqrtf(var + 1e-5f);
    }
    __syncthreads();
    float mean = s_mean, inv = s_inv;
    int c = tid * 4;
    float4 g = *(const float4*)(gamma + c);
    float4 bb = *(const float4*)(beta + c);
    float4 o;
    o.x = (v.x - mean) * inv * g.x + bb.x;
    o.y = (v.y - mean) * inv * g.y + bb.y;
    o.z = (v.z - mean) * inv * g.z + bb.z;
    o.w = (v.w - mean) * inv * g.w + bb.w;
    uint32_t h0,l0,h1,l1,h2,l2,h3,l3;
    split_tf32(o.x, h0, l0); split_tf32(o.y, h1, l1);
    split_tf32(o.z, h2, l2); split_tf32(o.w, h3, l3);
    ((float4*)(yh + row * D_MODEL))[tid] = make_float4(__uint_as_float(h0), __uint_as_float(h1),
                                                       __uint_as_float(h2), __uint_as_float(h3));
    ((float4*)(yl + row * D_MODEL))[tid] = make_float4(__uint_as_float(l0), __uint_as_float(l1),
                                                       __uint_as_float(l2), __uint_as_float(l3));
}

// ---------------- final layernorm with transpose back to (S,B,D) ----------------
__global__ void final_ln_kernel(const float* __restrict__ x,
                                const float* __restrict__ gamma,
                                const float* __restrict__ beta,
                                float* __restrict__ out) {
    int row = blockIdx.x;
    int tid = threadIdx.x;
    const float4* xr = (const float4*)(x + row * D_MODEL);
    float4 v = xr[tid];
    float s  = v.x + v.y + v.z + v.w;
    float ss = v.x*v.x + v.y*v.y + v.z*v.z + v.w*v.w;
    #pragma unroll
    for (int o = 16; o > 0; o >>= 1) {
        s  += __shfl_down_sync(0xffffffffu, s,  o);
        ss += __shfl_down_sync(0xffffffffu, ss, o);
    }
    __shared__ float shs[4], shss[4];
    __shared__ float s_mean, s_inv;
    int w = tid >> 5, lane = tid & 31;
    if (lane == 0) { shs[w] = s; shss[w] = ss; }
    __syncthreads();
    if (tid == 0) {
        float ts  = shs[0] + shs[1] + shs[2] + shs[3];
        float tss = shss[0] + shss[1] + shss[2] + shss[3];
        float mean = ts * (1.0f / D_MODEL);
        float var  = tss * (1.0f / D_MODEL) - mean * mean;
        s_mean = mean;
        s_inv  = rsqrtf(var + 1e-5f);
    }
    __syncthreads();
    float mean = s_mean, inv = s_inv;
    int c = tid * 4;
    float4 g = *(const float4*)(gamma + c);
    float4 bb = *(const float4*)(beta + c);
    float4 o;
    o.x = (v.x - mean) * inv * g.x + bb.x;
    o.y = (v.y - mean) * inv * g.y + bb.y;
    o.z = (v.z - mean) * inv * g.z + bb.z;
    o.w = (v.w - mean) * inv * g.w + bb.w;
    int b = row >> 10;
    int ss_ = row & (S_LEN - 1);
    ((float4*)(out + ((ss_ * BATCH + b) << 9)))[tid] = o;
}

// ---------------- pre-split 3xTF32 GEMM body --------------------------------------
// C[M,N] = A @ W + bias. A and W given as hi/lo tf32 pairs. cp.async double buffer.
#define BM 128
#define BN 128
#define BK 16
#define APAD 20
#define BPAD 136
#define A_BUF (BM * APAD)       // 2560 floats
#define B_BUF (BK * BPAD)       // 2176 floats
#define GEMM_SMEM ((2 * A_BUF * 2 + 2 * B_BUF * 2) * 4)   // 75776 bytes

template<bool RELU, bool RES, bool SPLIT>
__device__ __forceinline__ void gemm_body(const float* __restrict__ Ah,
                                          const float* __restrict__ Al,
                                          const float* __restrict__ Wh,
                                          const float* __restrict__ Wl,
                                          const float* __restrict__ bias,
                                          float* __restrict__ C,
                                          float* __restrict__ Ch,
                                          float* __restrict__ Cl,
                                          int M, int N, int K) {
    extern __shared__ float sm[];
    float* Ash = sm;                       // [2][A_BUF]
    float* Asl = Ash + 2 * A_BUF;
    float* Bsh = Asl + 2 * A_BUF;          // [2][B_BUF]
    float* Bsl = Bsh + 2 * B_BUF;

    int tid  = threadIdx.x;
    int lane = tid & 31;
    int warp = tid >> 5;
    int warpM = warp >> 1;
    int warpN = warp & 1;
    int rowBase = blockIdx.y * BM;
    int colBase = blockIdx.x * BN;
    int g = lane >> 2;
    int t = lane & 3;

    int am = tid >> 2;                 // 0..63
    int ak = (tid & 3) * 4;
    int bk = tid >> 5;                 // 0..7
    int bn = (tid & 31) * 4;

    const float* Agh = Ah + (long)(rowBase + am) * K + ak;
    const float* Agl = Al + (long)(rowBase + am) * K + ak;
    const float* Bgh = Wh + (long)bk * N + colBase + bn;
    const float* Bgl = Wl + (long)bk * N + colBase + bn;

    uint32_t sAh0 = smem_u32(&Ash[am * APAD + ak]);
    uint32_t sAh1 = smem_u32(&Ash[(am + 64) * APAD + ak]);
    uint32_t sAl0 = smem_u32(&Asl[am * APAD + ak]);
    uint32_t sAl1 = smem_u32(&Asl[(am + 64) * APAD + ak]);
    uint32_t sBh0 = smem_u32(&Bsh[bk * BPAD + bn]);
    uint32_t sBh1 = smem_u32(&Bsh[(bk + 8) * BPAD + bn]);
    uint32_t sBl0 = smem_u32(&Bsl[bk * BPAD + bn]);
    uint32_t sBl1 = smem_u32(&Bsl[(bk + 8) * BPAD + bn]);

    float acc[2][8][4];
    #pragma unroll
    for (int mi = 0; mi < 2; mi++)
        #pragma unroll
        for (int nj = 0; nj < 8; nj++)
            #pragma unroll
            for (int r = 0; r < 4; r++) acc[mi][nj][r] = 0.0f;

    const int ABUFB = A_BUF * 4;   // bytes
    const int BBUFB = B_BUF * 4;

    // stage iter 0 into buffer 0
    {
        cp_async16(sAh0, Agh);
        cp_async16(sAh1, Agh + 64 * (long)K);
        cp_async16(sAl0, Agl);
        cp_async16(sAl1, Agl + 64 * (long)K);
        cp_async16(sBh0, Bgh);
        cp_async16(sBh1, Bgh + 8 * (long)N);
        cp_async16(sBl0, Bgl);
        cp_async16(sBl1, Bgl + 8 * (long)N);
        cp_commit();
    }

    int niter = K / BK;
    for (int it = 0; it < niter; it++) {
        int cur = it & 1;
        int nxt = cur ^ 1;
        if (it + 1 < niter) {
            long ka = (long)(it + 1) * BK;
            const float* agh = Agh + ka;
            const float* agl = Agl + ka;
            const float* bgh = Bgh + ka * N;
            const float* bgl = Bgl + ka * N;
            int ao = nxt * ABUFB, bo = nxt * BBUFB;
            cp_async16(sAh0 + ao, agh);
            cp_async16(sAh1 + ao, agh + 64 * (long)K);
            cp_async16(sAl0 + ao, agl);
            cp_async16(sAl1 + ao, agl + 64 * (long)K);
            cp_async16(sBh0 + bo, bgh);
            cp_async16(sBh1 + bo, bgh + 8 * (long)N);
            cp_async16(sBl0 + bo, bgl);
            cp_async16(sBl1 + bo, bgl + 8 * (long)N);
            cp_commit();
            cp_wait<1>();
        } else {
            cp_wait<0>();
        }
        __syncthreads();

        const float* Ahc = Ash + cur * A_BUF;
        const float* Alc = Asl + cur * A_BUF;
        const float* Bhc = Bsh + cur * B_BUF;
        const float* Blc = Bsl + cur * B_BUF;

        #pragma unroll
        for (int ks = 0; ks < 2; ks++) {
            int k0 = ks * 8;
            uint32_t ahi[2][4], alo[2][4];
            #pragma unroll
            for (int mi = 0; mi < 2; mi++) {
                int r0 = warpM * 32 + mi * 16 + g;
                ahi[mi][0] = __float_as_uint(Ahc[r0 * APAD + k0 + t]);
                ahi[mi][1] = __float_as_uint(Ahc[(r0 + 8) * APAD + k0 + t]);
                ahi[mi][2] = __float_as_uint(Ahc[r0 * APAD + k0 + 4 + t]);
                ahi[mi][3] = __float_as_uint(Ahc[(r0 + 8) * APAD + k0 + 4 + t]);
                alo[mi][0] = __float_as_uint(Alc[r0 * APAD + k0 + t]);
                alo[mi][1] = __float_as_uint(Alc[(r0 + 8) * APAD + k0 + t]);
                alo[mi][2] = __float_as_uint(Alc[r0 * APAD + k0 + 4 + t]);
                alo[mi][3] = __float_as_uint(Alc[(r0 + 8) * APAD + k0 + 4 + t]);
            }
            #pragma unroll
            for (int half = 0; half < 2; half++) {
                uint32_t bhi[4][2], blo[4][2];
                #pragma unroll
                for (int j = 0; j < 4; j++) {
                    int c = warpN * 64 + (half * 4 + j) * 8 + g;
                    bhi[j][0] = __float_as_uint(Bhc[(k0 + t) * BPAD + c]);
                    bhi[j][1] = __float_as_uint(Bhc[(k0 + 4 + t) * BPAD + c]);
                    blo[j][0] = __float_as_uint(Blc[(k0 + t) * BPAD + c]);
                    blo[j][1] = __float_as_uint(Blc[(k0 + 4 + t) * BPAD + c]);
                }
                #pragma unroll
                for (int mi = 0; mi < 2; mi++)
                    #pragma unroll
                    for (int j = 0; j < 4; j++) {
                        int nj = half * 4 + j;
                        mma_tf32(acc[mi][nj], ahi[mi], blo[j]);
                        mma_tf32(acc[mi][nj], alo[mi], bhi[j]);
                        mma_tf32(acc[mi][nj], ahi[mi], bhi[j]);
                    }
            }
        }
        __syncthreads();
    }

    // epilogue
    #pragma unroll
    for (int mi = 0; mi < 2; mi++) {
        int r0 = rowBase + warpM * 32 + mi * 16 + g;
        #pragma unroll
        for (int nj = 0; nj < 8; nj++) {
            int c = colBase + warpN * 64 + nj * 8 + t * 2;
            float b0 = bias[c], b1 = bias[c + 1];
            float v0 = acc[mi][nj][0] + b0;
            float v1 = acc[mi][nj][1] + b1;
            float v2 = acc[mi][nj][2] + b0;
            float v3 = acc[mi][nj][3] + b1;
            long o0 = (long)r0 * N + c;
            long o1 = (long)(r0 + 8) * N + c;
            if (RES) {
                v0 += C[o0]; v1 += C[o0 + 1];
                v2 += C[o1]; v3 += C[o1 + 1];
            }
            if (RELU) {
                v0 = fmaxf(v0, 0.0f); v1 = fmaxf(v1, 0.0f);
                v2 = fmaxf(v2, 0.0f); v3 = fmaxf(v3, 0.0f);
            }
            if (SPLIT) {
                uint32_t h0,l0,h1,l1,h2,l2,h3,l3;
                split_tf32(v0, h0, l0); split_tf32(v1, h1, l1);
                split_tf32(v2, h2, l2); split_tf32(v3, h3, l3);
                Ch[o0] = __uint_as_float(h0); Ch[o0 + 1] = __uint_as_float(h1);
                Ch[o1] = __uint_as_float(h2); Ch[o1 + 1] = __uint_as_float(h3);
                Cl[o0] = __uint_as_float(l0); Cl[o0 + 1] = __uint_as_float(l1);
                Cl[o1] = __uint_as_float(l2); Cl[o1 + 1] = __uint_as_float(l3);
            } else {
                C[o0] = v0; C[o0 + 1] = v1;
                C[o1] = v2; C[o1 + 1] = v3;
            }
        }
    }
}

template<bool RELU, bool RES, bool SPLIT>
__global__ __launch_bounds__(256, 2)
void gemm_kernel(const float* __restrict__ Ah, const float* __restrict__ Al,
                 const float* __restrict__ Wh, const float* __restrict__ Wl,
                 const float* __restrict__ bias,
                 float* __restrict__ C, float* __restrict__ Ch, float* __restrict__ Cl,
                 int M, int N, int K) {
    gemm_body<RELU, RES, SPLIT>(Ah, Al, Wh, Wl, bias, C, Ch, Cl, M, N, K);
}

// fused QKV: blockIdx.z selects weight/bias/output
__global__ __launch_bounds__(256, 2)
void qkv_gemm_kernel(const float* __restrict__ Ah, const float* __restrict__ Al,
                     const float* __restrict__ Wh_base, const float* __restrict__ Wl_base,
                     const float* __restrict__ bq, const float* __restrict__ bk,
                     const float* __restrict__ bv,
                     float* __restrict__ q, float* __restrict__ k, float* __restrict__ v) {
    int z = blockIdx.z;
    const float* Wh = Wh_base + (long)z * (NLAYER * D_MODEL * D_MODEL);
    const float* Wl = Wl_base + (long)z * (NLAYER * D_MODEL * D_MODEL);
    const float* bias = (z == 0) ? bq : (z == 1) ? bk : bv;
    float* C = (z == 0) ? q : (z == 1) ? k : v;
    gemm_body<false, false, false>(Ah, Al, Wh, Wl, bias, C, nullptr, nullptr,
                                   M_ROWS, D_MODEL, D_MODEL);
}

// ---------------- tensor-core flash attention (3xTF32) + fused residual --------
#define QP 68
#define VP 72

__global__ __launch_bounds__(256, 1)
void attention_mma_kernel(const float* __restrict__ q,
                          const float* __restrict__ k,
                          const float* __restrict__ v,
                          float* __restrict__ x) {
    extern __shared__ float sm[];
    float* Qh = sm;
    float* Ql = Qh + 128 * QP;
    float* Kh = Ql + 128 * QP;
    float* Kl = Kh + 64 * QP;
    float* Vh = Kl + 64 * QP;
    float* Vl = Vh + 64 * VP;
    float* Ph = Vl + 64 * VP;
    float* Pl = Ph + 128 * QP;

    int tid = threadIdx.x;
    int lane = tid & 31, warp = tid >> 5;
    int g = lane >> 2, t = lane & 3;
    int bh = blockIdx.x;
    int b = bh >> 3, h = bh & 7;
    int qt = blockIdx.y;
    int qr = warp * 16;

    {
        const float* qg = q + ((long)(b * S_LEN + qt * 128) << 9) + h * DHEAD;
        int r = tid >> 4;
        int c = (tid & 15) * 4;
        #pragma unroll
        for (int p = 0; p < 8; p++) {
            int rr = p * 16 + r;
            float4 v4 = *(const float4*)(qg + (long)rr * D_MODEL + c);
            v4.x *= 0.125f; v4.y *= 0.125f; v4.z *= 0.125f; v4.w *= 0.125f;
            uint32_t h0,l0,h1,l1,h2,l2,h3,l3;
            split_tf32(v4.x, h0, l0); split_tf32(v4.y, h1, l1);
            split_tf32(v4.z, h2, l2); split_tf32(v4.w, h3, l3);
            *(float4*)&Qh[rr * QP + c] = make_float4(__uint_as_float(h0), __uint_as_float(h1),
                                                     __uint_as_float(h2), __uint_as_float(h3));
            *(float4*)&Ql[rr * QP + c] = make_float4(__uint_as_float(l0), __uint_as_float(l1),
                                                     __uint_as_float(l2), __uint_as_float(l3));
        }
    }

    float o[8][4];
    #pragma unroll
    for (int j = 0; j < 8; j++)
        #pragma unroll
        for (int r = 0; r < 4; r++) o[j][r] = 0.0f;
    float m0 = -1e30f, m1 = -1e30f, l0s = 0.0f, l1s = 0.0f;

    for (int kt = 0; kt < S_LEN / 64; kt++) {
        __syncthreads();
        {
            const float* kg = k + ((long)(b * S_LEN + kt * 64) << 9) + h * DHEAD;
            const float* vg = v + ((long)(b * S_LEN + kt * 64) << 9) + h * DHEAD;
            int r = tid >> 4;
            int c = (tid & 15) * 4;
            #pragma unroll
            for (int p = 0; p < 4; p++) {
                int rr = p * 16 + r;
                float4 kv4 = *(const float4*)(kg + (long)rr * D_MODEL + c);
                uint32_t h0,lo0,h1,lo1,h2,lo2,h3,lo3;
                split_tf32(kv4.x, h0, lo0); split_tf32(kv4.y, h1, lo1);
                split_tf32(kv4.z, h2, lo2); split_tf32(kv4.w, h3, lo3);
                *(float4*)&Kh[rr * QP + c] = make_float4(__uint_as_float(h0), __uint_as_float(h1),
                                                         __uint_as_float(h2), __uint_as_float(h3));
                *(float4*)&Kl[rr * QP + c] = make_float4(__uint_as_float(lo0), __uint_as_float(lo1),
                                                         __uint_as_float(lo2), __uint_as_float(lo3));
                float4 vv4 = *(const float4*)(vg + (long)rr * D_MODEL + c);
                split_tf32(vv4.x, h0, lo0); split_tf32(vv4.y, h1, lo1);
                split_tf32(vv4.z, h2, lo2); split_tf32(vv4.w, h3, lo3);
                *(float4*)&Vh[rr * VP + c] = make_float4(__uint_as_float(h0), __uint_as_float(h1),
                                                         __uint_as_float(h2), __uint_as_float(h3));
                *(float4*)&Vl[rr * VP + c] = make_float4(__uint_as_float(lo0), __uint_as_float(lo1),
                                                         __uint_as_float(lo2), __uint_as_float(lo3));
            }
        }
        __syncthreads();

        float s[8][4];
        #pragma unroll
        for (int j = 0; j < 8; j++)
            #pragma unroll
            for (int r = 0; r < 4; r++) s[j][r] = 0.0f;

        #pragma unroll
        for (int k8 = 0; k8 < 8; k8++) {
            int kc = k8 * 8;
            uint32_t qh_[4], ql_[4];
            qh_[0] = __float_as_uint(Qh[(qr + g)     * QP + kc + t]);
            qh_[1] = __float_as_uint(Qh[(qr + g + 8) * QP + kc + t]);
            qh_[2] = __float_as_uint(Qh[(qr + g)     * QP + kc + 4 + t]);
            qh_[3] = __float_as_uint(Qh[(qr + g + 8) * QP + kc + 4 + t]);
            ql_[0] = __float_as_uint(Ql[(qr + g)     * QP + kc + t]);
            ql_[1] = __float_as_uint(Ql[(qr + g + 8) * QP + kc + t]);
            ql_[2] = __float_as_uint(Ql[(qr + g)     * QP + kc + 4 + t]);
            ql_[3] = __float_as_uint(Ql[(qr + g + 8) * QP + kc + 4 + t]);
            #pragma unroll
            for (int j = 0; j < 8; j++) {
                uint32_t kh_[2], kl_[2];
                kh_[0] = __float_as_uint(Kh[(j * 8 + g) * QP + kc + t]);
                kh_[1] = __float_as_uint(Kh[(j * 8 + g) * QP + kc + 4 + t]);
                kl_[0] = __float_as_uint(Kl[(j * 8 + g) * QP + kc + t]);
                kl_[1] = __float_as_uint(Kl[(j * 8 + g) * QP + kc + 4 + t]);
                mma_tf32(s[j], qh_, kl_);
                mma_tf32(s[j], ql_, kh_);
                mma_tf32(s[j], qh_, kh_);
            }
        }

        float mx0 = -1e30f, mx1 = -1e30f;
        #pragma unroll
        for (int j = 0; j < 8; j++) {
            mx0 = fmaxf(mx0, fmaxf(s[j][0], s[j][1]));
            mx1 = fmaxf(mx1, fmaxf(s[j][2], s[j][3]));
        }
        mx0 = fmaxf(mx0, __shfl_xor_sync(0xffffffffu, mx0, 1));
        mx0 = fmaxf(mx0, __shfl_xor_sync(0xffffffffu, mx0, 2));
        mx1 = fmaxf(mx1, __shfl_xor_sync(0xffffffffu, mx1, 1));
        mx1 = fmaxf(mx1, __shfl_xor_sync(0xffffffffu, mx1, 2));
        float mn0 = fmaxf(m0, mx0), mn1 = fmaxf(m1, mx1);
        float c0 = __expf(m0 - mn0), c1 = __expf(m1 - mn1);
        l0s *= c0; l1s *= c1;
        #pragma unroll
        for (int j = 0; j < 8; j++) {
            float p0 = __expf(s[j][0] - mn0);
            float p1 = __expf(s[j][1] - mn0);
            float p2 = __expf(s[j][2] - mn1);
            float p3 = __expf(s[j][3] - mn1);
            l0s += p0 + p1; l1s += p2 + p3;
            uint32_t ph0,pl0,ph1,pl1,ph2,pl2,ph3,pl3;
            split_tf32(p0, ph0, pl0); split_tf32(p1, ph1, pl1);
            split_tf32(p2, ph2, pl2); split_tf32(p3, ph3, pl3);
            int cc = j * 8 + 2 * t;
            *(float2*)&Ph[(qr + g)     * QP + cc] = make_float2(__uint_as_float(ph0), __uint_as_float(ph1));
            *(float2*)&Ph[(qr + g + 8) * QP + cc] = make_float2(__uint_as_float(ph2), __uint_as_float(ph3));
            *(float2*)&Pl[(qr + g)     * QP + cc] = make_float2(__uint_as_float(pl0), __uint_as_float(pl1));
            *(float2*)&Pl[(qr + g + 8) * QP + cc] = make_float2(__uint_as_float(pl2), __uint_as_float(pl3));
            o[j][0] *= c0; o[j][1] *= c0; o[j][2] *= c1; o[j][3] *= c1;
        }
        m0 = mn0; m1 = mn1;
        __syncwarp();

        #pragma unroll
        for (int k8 = 0; k8 < 8; k8++) {
            int kc = k8 * 8;
            uint32_t ph_[4], pl_[4];
            ph_[0] = __float_as_uint(Ph[(qr + g)     * QP + kc + t]);
            ph_[1] = __float_as_uint(Ph[(qr + g + 8) * QP + kc + t]);
            ph_[2] = __float_as_uint(Ph[(qr + g)     * QP + kc + 4 + t]);
            ph_[3] = __float_as_uint(Ph[(qr + g + 8) * QP + kc + 4 + t]);
            pl_[0] = __float_as_uint(Pl[(qr + g)     * QP + kc + t]);
            pl_[1] = __float_as_uint(Pl[(qr + g + 8) * QP + kc + t]);
            pl_[2] = __float_as_uint(Pl[(qr + g)     * QP + kc + 4 + t]);
            pl_[3] = __float_as_uint(Pl[(qr + g + 8) * QP + kc + 4 + t]);
            #pragma unroll
            for (int j = 0; j < 8; j++) {
                uint32_t vh_[2], vl_[2];
                vh_[0] = __float_as_uint(Vh[(kc + t)     * VP + j * 8 + g]);
                vh_[1] = __float_as_uint(Vh[(kc + 4 + t) * VP + j * 8 + g]);
                vl_[0] = __float_as_uint(Vl[(kc + t)     * VP + j * 8 + g]);
                vl_[1] = __float_as_uint(Vl[(kc + 4 + t) * VP + j * 8 + g]);
                mma_tf32(o[j], ph_, vl_);
                mma_tf32(o[j], pl_, vh_);
                mma_tf32(o[j], ph_, vh_);
            }
        }
    }

    l0s += __shfl_xor_sync(0xffffffffu, l0s, 1);
    l0s += __shfl_xor_sync(0xffffffffu, l0s, 2);
    l1s += __shfl_xor_sync(0xffffffffu, l1s, 1);
    l1s += __shfl_xor_sync(0xffffffffu, l1s, 2);
    float i0 = 1.0f / l0s, i1 = 1.0f / l1s;

    float* xr0 = x + ((long)(b * S_LEN + qt * 128 + qr + g)     << 9) + h * DHEAD;
    float* xr1 = x + ((long)(b * S_LEN + qt * 128 + qr + g + 8) << 9) + h * DHEAD;
    #pragma unroll
    for (int j = 0; j < 8; j++) {
        int cc = j * 8 + 2 * t;
        float2 r0 = *(float2*)(xr0 + cc);
        r0.x += o[j][0] * i0; r0.y += o[j][1] * i0;
        *(float2*)(xr0 + cc) = r0;
        float2 r1 = *(float2*)(xr1 + cc);
        r1.x += o[j][2] * i1; r1.y += o[j][3] * i1;
        *(float2*)(xr1 + cc) = r1;
    }
}

// ---------------- host orchestration --------------------------------------------
extern "C" void kernel_launch(void* const* d_in, const int* in_sizes, int n_in,
                              void* d_out, int out_size) {
    const float* src   = (const float*)d_in[0];
    const float* pos   = (const float*)d_in[1];
    const float* Wq    = (const float*)d_in[2];
    const float* bq    = (const float*)d_in[3];
    const float* Wk    = (const float*)d_in[4];
    const float* bk    = (const float*)d_in[5];
    const float* Wv    = (const float*)d_in[6];
    const float* bv    = (const float*)d_in[7];
    const float* W1    = (const float*)d_in[8];
    const float* b1    = (const float*)d_in[9];
    const float* W2    = (const float*)d_in[10];
    const float* b2    = (const float*)d_in[11];
    const float* ln1_g = (const float*)d_in[12];
    const float* ln1_b = (const float*)d_in[13];
    const float* ln2_g = (const float*)d_in[14];
    const float* ln2_b = (const float*)d_in[15];
    const float* lnf_g = (const float*)d_in[16];
    const float* lnf_b = (const float*)d_in[17];
    float* out = (float*)d_out;

    float *px, *pxnh, *pxnl, *pq, *pk, *pv, *phh, *phl, *pwh, *pwl;
    cudaGetSymbolAddress((void**)&px,   g_x);
    cudaGetSymbolAddress((void**)&pxnh, g_xn_h);
    cudaGetSymbolAddress((void**)&pxnl, g_xn_l);
    cudaGetSymbolAddress((void**)&pq,   g_q);
    cudaGetSymbolAddress((void**)&pk,   g_k);
    cudaGetSymbolAddress((void**)&pv,   g_v);
    cudaGetSymbolAddress((void**)&phh,  g_h_h);
    cudaGetSymbolAddress((void**)&phl,  g_h_l);
    cudaGetSymbolAddress((void**)&pwh,  g_wh);
    cudaGetSymbolAddress((void**)&pwl,  g_wl);

    const int ATT_SMEM = (2 * 128 * QP + 2 * 64 * QP + 2 * 64 * VP + 2 * 128 * QP)
                         * (int)sizeof(float);
    cudaFuncSetAttribute(attention_mma_kernel,
                         cudaFuncAttributeMaxDynamicSharedMemorySize, ATT_SMEM);
    cudaFuncSetAttribute(qkv_gemm_kernel,
                         cudaFuncAttributeMaxDynamicSharedMemorySize, GEMM_SMEM);
    cudaFuncSetAttribute(gemm_kernel<true, false, true>,
                         cudaFuncAttributeMaxDynamicSharedMemorySize, GEMM_SMEM);
    cudaFuncSetAttribute(gemm_kernel<false, true, false>,
                         cudaFuncAttributeMaxDynamicSharedMemorySize, GEMM_SMEM);

    // ---- pre-split all weights into tf32 hi/lo ----
    {
        int nqkv4 = (NLAYER * D_MODEL * D_MODEL) / 4;
        int nff4  = (NLAYER * D_MODEL * FF_DIM) / 4;
        split_kernel<<<(nqkv4 + 255) / 256, 256>>>(Wq, pwh + WQ_OFF, pwl + WQ_OFF, nqkv4);
        split_kernel<<<(nqkv4 + 255) / 256, 256>>>(Wk, pwh + WK_OFF, pwl + WK_OFF, nqkv4);
        split_kernel<<<(nqkv4 + 255) / 256, 256>>>(Wv, pwh + WV_OFF, pwl + WV_OFF, nqkv4);
        split_kernel<<<(nff4  + 255) / 256, 256>>>(W1, pwh + W1_OFF, pwl + W1_OFF, nff4);
        split_kernel<<<(nff4  + 255) / 256, 256>>>(W2, pwh + W2_OFF, pwl + W2_OFF, nff4);
    }

    add_pos_kernel<<<(M_ROWS * D_MODEL + 255) / 256, 256>>>(src, pos, px);

    for (int l = 0; l < NLAYER; l++) {
        long wqkv = (long)l * D_MODEL * D_MODEL;
        long wff1 = (long)l * D_MODEL * FF_DIM;
        long wff2 = (long)l * FF_DIM * D_MODEL;

        // attention block
        layernorm_split_kernel<<<M_ROWS, 128>>>(px, ln1_g + l * D_MODEL, ln1_b + l * D_MODEL,
                                                pxnh, pxnl);
        qkv_gemm_kernel<<<dim3(D_MODEL / BN, M_ROWS / BM, 3), 256, GEMM_SMEM>>>(
            pxnh, pxnl, pwh + WQ_OFF + wqkv, pwl + WQ_OFF + wqkv,
            bq + l * D_MODEL, bk + l * D_MODEL, bv + l * D_MODEL, pq, pk, pv);
        attention_mma_kernel<<<dim3(BATCH * NHEAD, S_LEN / 128), 256, ATT_SMEM>>>(pq, pk, pv, px);

        // feed-forward block
        layernorm_split_kernel<<<M_ROWS, 128>>>(px, ln2_g + l * D_MODEL, ln2_b + l * D_MODEL,
                                                pxnh, pxnl);
        gemm_kernel<true, false, true><<<dim3(FF_DIM / BN, M_ROWS / BM), 256, GEMM_SMEM>>>(
            pxnh, pxnl, pwh + W1_OFF + wff1, pwl + W1_OFF + wff1, b1 + l * FF_DIM,
            nullptr, phh, phl, M_ROWS, FF_DIM, D_MODEL);
        gemm_kernel<false, true, false><<<dim3(D_MODEL / BN, M_ROWS / BM), 256, GEMM_SMEM>>>(
            phh, phl, pwh + W2_OFF + wff2, pwl + W2_OFF + wff2, b2 + l * D_MODEL,
            px, nullptr, nullptr, M_ROWS, D_MODEL, FF_DIM);
    }

    final_ln_kernel<<<M_ROWS, 128>>>(px, lnf_g, lnf_b, out);
}

// round 5
// speedup vs baseline: 3.1636x; 1.4323x over previous
#include <cuda_runtime.h>
#include <cuda_bf16.h>
#include <math.h>
#include <stdint.h>

#define D_MODEL 512
#define FF_DIM  2048
#define S_LEN   1024
#define BATCH   4
#define NLAYER  6
#define NHEAD   8
#define DHEAD   64
#define M_ROWS  (S_LEN * BATCH)   // 4096 token rows

// weight split layout inside g_wth / g_wtl (element offsets; arrays are transposed [N][K])
#define WQ_OFF 0
#define WK_OFF (NLAYER * D_MODEL * D_MODEL)
#define WV_OFF (2 * NLAYER * D_MODEL * D_MODEL)
#define W1_OFF (3 * NLAYER * D_MODEL * D_MODEL)
#define W2_OFF (W1_OFF + NLAYER * D_MODEL * FF_DIM)
#define W_TOTAL (W2_OFF + NLAYER * FF_DIM * D_MODEL)

// ---------------- scratch (device globals; no runtime allocation) ----------------
__device__ float g_x [M_ROWS * D_MODEL];            // residual stream (B,S,D)
__device__ __nv_bfloat16 g_xn_h[M_ROWS * D_MODEL];  // layernorm out hi (bf16)
__device__ __nv_bfloat16 g_xn_l[M_ROWS * D_MODEL];  // layernorm out lo
__device__ float g_q [M_ROWS * D_MODEL];
__device__ float g_k [M_ROWS * D_MODEL];
__device__ float g_v [M_ROWS * D_MODEL];
__device__ __nv_bfloat16 g_h_h[M_ROWS * FF_DIM];    // FF hidden hi
__device__ __nv_bfloat16 g_h_l[M_ROWS * FF_DIM];    // FF hidden lo
__device__ __nv_bfloat16 g_wth[W_TOTAL];            // weights transposed [N][K], hi
__device__ __nv_bfloat16 g_wtl[W_TOTAL];            // weights transposed [N][K], lo

// ---------------- helpers ----------------------------------------------------------
__device__ __forceinline__ void split_tf32(float x, uint32_t& hi, uint32_t& lo) {
    asm("cvt.rna.tf32.f32 %0, %1;" : "=r"(hi) : "f"(x));
    float r = x - __uint_as_float(hi);
    asm("cvt.rna.tf32.f32 %0, %1;" : "=r"(lo) : "f"(r));
}

__device__ __forceinline__ void mma_tf32(float* d, const uint32_t* a, const uint32_t* b) {
    asm volatile(
        "mma.sync.aligned.m16n8k8.row.col.f32.tf32.tf32.f32 "
        "{%0,%1,%2,%3}, {%4,%5,%6,%7}, {%8,%9}, {%0,%1,%2,%3};"
        : "+f"(d[0]), "+f"(d[1]), "+f"(d[2]), "+f"(d[3])
        : "r"(a[0]), "r"(a[1]), "r"(a[2]), "r"(a[3]), "r"(b[0]), "r"(b[1]));
}

__device__ __forceinline__ void mma_bf16(float* d, const uint32_t* a, const uint32_t* b) {
    asm volatile(
        "mma.sync.aligned.m16n8k16.row.col.f32.bf16.bf16.f32 "
        "{%0,%1,%2,%3}, {%4,%5,%6,%7}, {%8,%9}, {%0,%1,%2,%3};"
        : "+f"(d[0]), "+f"(d[1]), "+f"(d[2]), "+f"(d[3])
        : "r"(a[0]), "r"(a[1]), "r"(a[2]), "r"(a[3]), "r"(b[0]), "r"(b[1]));
}

__device__ __forceinline__ void split_bf16(float x, __nv_bfloat16& hi, __nv_bfloat16& lo) {
    hi = __float2bfloat16_rn(x);
    lo = __float2bfloat16_rn(x - __bfloat162float(hi));
}

__device__ __forceinline__ void cp_async16(uint32_t dst, const void* src) {
    asm volatile("cp.async.ca.shared.global [%0], [%1], 16;" :: "r"(dst), "l"(src));
}
__device__ __forceinline__ void cp_commit() {
    asm volatile("cp.async.commit_group;");
}
template<int N>
__device__ __forceinline__ void cp_wait() {
    asm volatile("cp.async.wait_group %0;" :: "n"(N));
}
__device__ __forceinline__ uint32_t smem_u32(const void* p) {
    return (uint32_t)__cvta_generic_to_shared(p);
}

// ---------------- weight transpose + bf16 split: W[K][N] -> Wt[N][K] hi/lo ---------
__global__ void wsplit_t_kernel(const float* __restrict__ src,
                                __nv_bfloat16* __restrict__ oh,
                                __nv_bfloat16* __restrict__ ol,
                                int K, int N) {
    __shared__ float tile[32][33];
    int l = blockIdx.z;
    src += (long)l * K * N;
    oh  += (long)l * N * K;
    ol  += (long)l * N * K;
    int n0 = blockIdx.x * 32, k0 = blockIdx.y * 32;
    int tx = threadIdx.x, ty = threadIdx.y;      // 32 x 8
    #pragma unroll
    for (int i = ty; i < 32; i += 8)
        tile[i][tx] = src[(long)(k0 + i) * N + n0 + tx];
    __syncthreads();
    #pragma unroll
    for (int i = ty; i < 32; i += 8) {
        float x = tile[tx][i];                   // src[k0+tx][n0+i]
        __nv_bfloat16 h, lo;
        split_bf16(x, h, lo);
        long o = (long)(n0 + i) * K + k0 + tx;
        oh[o] = h; ol[o] = lo;
    }
}

// ---------------- x = (src + pos) transposed (S,B,D) -> (B,S,D) ----------------
__global__ void add_pos_kernel(const float* __restrict__ src,
                               const float* __restrict__ pos,
                               float* __restrict__ x) {
    int idx = blockIdx.x * blockDim.x + threadIdx.x;
    if (idx >= M_ROWS * D_MODEL) return;
    int d = idx & (D_MODEL - 1);
    int m = idx >> 9;
    int b = m >> 10;
    int s = m & (S_LEN - 1);
    int src_i = ((s * BATCH + b) << 9) + d;
    x[idx] = src[src_i] + pos[src_i];
}

// ---------------- layernorm -> split bf16 hi/lo output ---------------------------
__global__ void layernorm_split_kernel(const float* __restrict__ x,
                                       const float* __restrict__ gamma,
                                       const float* __restrict__ beta,
                                       __nv_bfloat16* __restrict__ yh,
                                       __nv_bfloat16* __restrict__ yl) {
    int row = blockIdx.x;
    int tid = threadIdx.x;                 // 128
    const float4* xr = (const float4*)(x + row * D_MODEL);
    float4 v = xr[tid];
    float s  = v.x + v.y + v.z + v.w;
    float ss = v.x*v.x + v.y*v.y + v.z*v.z + v.w*v.w;
    #pragma unroll
    for (int o = 16; o > 0; o >>= 1) {
        s  += __shfl_down_sync(0xffffffffu, s,  o);
        ss += __shfl_down_sync(0xffffffffu, ss, o);
    }
    __shared__ float shs[4], shss[4];
    __shared__ float s_mean, s_inv;
    int w = tid >> 5, lane = tid & 31;
    if (lane == 0) { shs[w] = s; shss[w] = ss; }
    __syncthreads();
    if (tid == 0) {
        float ts  = shs[0] + shs[1] + shs[2] + shs[3];
        float tss = shss[0] + shss[1] + shss[2] + shss[3];
        float mean = ts * (1.0f / D_MODEL);
        float var  = tss * (1.0f / D_MODEL) - mean * mean;
        s_mean = mean;
        s_inv  = rsqrtf(var + 1e-5f);
    }
    __syncthreads();
    float mean = s_mean, inv = s_inv;
    int c = tid * 4;
    float4 g = *(const float4*)(gamma + c);
    float4 bb = *(const float4*)(beta + c);
    float o0 = (v.x - mean) * inv * g.x + bb.x;
    float o1 = (v.y - mean) * inv * g.y + bb.y;
    float o2 = (v.z - mean) * inv * g.z + bb.z;
    float o3 = (v.w - mean) * inv * g.w + bb.w;
    __nv_bfloat16 h0,l0,h1,l1,h2,l2,h3,l3;
    split_bf16(o0, h0, l0); split_bf16(o1, h1, l1);
    split_bf16(o2, h2, l2); split_bf16(o3, h3, l3);
    __nv_bfloat162* yh2 = (__nv_bfloat162*)(yh + row * D_MODEL);
    __nv_bfloat162* yl2 = (__nv_bfloat162*)(yl + row * D_MODEL);
    yh2[tid * 2]     = __nv_bfloat162{h0, h1};
    yh2[tid * 2 + 1] = __nv_bfloat162{h2, h3};
    yl2[tid * 2]     = __nv_bfloat162{l0, l1};
    yl2[tid * 2 + 1] = __nv_bfloat162{l2, l3};
}

// ---------------- final layernorm with transpose back to (S,B,D) ----------------
__global__ void final_ln_kernel(const float* __restrict__ x,
                                const float* __restrict__ gamma,
                                const float* __restrict__ beta,
                                float* __restrict__ out) {
    int row = blockIdx.x;
    int tid = threadIdx.x;
    const float4* xr = (const float4*)(x + row * D_MODEL);
    float4 v = xr[tid];
    float s  = v.x + v.y + v.z + v.w;
    float ss = v.x*v.x + v.y*v.y + v.z*v.z + v.w*v.w;
    #pragma unroll
    for (int o = 16; o > 0; o >>= 1) {
        s  += __shfl_down_sync(0xffffffffu, s,  o);
        ss += __shfl_down_sync(0xffffffffu, ss, o);
    }
    __shared__ float shs[4], shss[4];
    __shared__ float s_mean, s_inv;
    int w = tid >> 5, lane = tid & 31;
    if (lane == 0) { shs[w] = s; shss[w] = ss; }
    __syncthreads();
    if (tid == 0) {
        float ts  = shs[0] + shs[1] + shs[2] + shs[3];
        float tss = shss[0] + shss[1] + shss[2] + shss[3];
        float mean = ts * (1.0f / D_MODEL);
        float var  = tss * (1.0f / D_MODEL) - mean * mean;
        s_mean = mean;
        s_inv  = rsqrtf(var + 1e-5f);
    }
    __syncthreads();
    float mean = s_mean, inv = s_inv;
    int c = tid * 4;
    float4 g = *(const float4*)(gamma + c);
    float4 bb = *(const float4*)(beta + c);
    float4 o;
    o.x = (v.x - mean) * inv * g.x + bb.x;
    o.y = (v.y - mean) * inv * g.y + bb.y;
    o.z = (v.z - mean) * inv * g.z + bb.z;
    o.w = (v.w - mean) * inv * g.w + bb.w;
    int b = row >> 10;
    int ss_ = row & (S_LEN - 1);
    ((float4*)(out + ((ss_ * BATCH + b) << 9)))[tid] = o;
}

// ---------------- split-BF16 3-term GEMM (m16n8k16) --------------------------------
// C[M,N] = A[M,K] @ W[K,N] + bias; A given row-major bf16 hi/lo, W transposed [N][K].
#define BM 128
#define BN 128
#define BK 32
#define SPAD 40                    // bf16 row stride: 20 banks -> conflict-free
#define TBUF (128 * SPAD)          // bf16 elems per buffer (A or B, one stage)
#define GEMM_SMEM (8 * TBUF * 2)   // bytes: 4 arrays x 2 buffers x TBUF x 2B = 81920

template<bool RELU, bool RES, bool SPLIT>
__device__ __forceinline__ void gemm_body(const __nv_bfloat16* __restrict__ Ah,
                                          const __nv_bfloat16* __restrict__ Al,
                                          const __nv_bfloat16* __restrict__ Wh,
                                          const __nv_bfloat16* __restrict__ Wl,
                                          const float* __restrict__ bias,
                                          float* __restrict__ C,
                                          __nv_bfloat16* __restrict__ Ch,
                                          __nv_bfloat16* __restrict__ Cl,
                                          int M, int N, int K) {
    extern __shared__ __nv_bfloat16 smb[];
    __nv_bfloat16* Ash = smb;                  // [2][TBUF]
    __nv_bfloat16* Asl = Ash + 2 * TBUF;
    __nv_bfloat16* Bsh = Asl + 2 * TBUF;
    __nv_bfloat16* Bsl = Bsh + 2 * TBUF;

    int tid  = threadIdx.x;
    int lane = tid & 31;
    int warp = tid >> 5;
    int warpM = warp >> 1;         // 0..3 -> +32 rows
    int warpN = warp & 1;          // 0..1 -> +64 cols
    int rowBase = blockIdx.y * BM;
    int colBase = blockIdx.x * BN;
    int g = lane >> 2;
    int t = lane & 3;

    // staging: 512 16B-chunks per array; thread does chunks tid, tid+256
    int r0c = tid >> 2;            // row of chunk 0 (0..63)
    int o0c = (tid & 3) * 8;       // bf16 offset of chunk 0
    int r1c = (tid + 256) >> 2;    // 64..127
    // global srcs (row-major, stride K)
    const __nv_bfloat16* Ag0 = Ah + (long)(rowBase + r0c) * K + o0c;
    const __nv_bfloat16* Ag1 = Ah + (long)(rowBase + r1c) * K + o0c;
    const __nv_bfloat16* Al0 = Al + (long)(rowBase + r0c) * K + o0c;
    const __nv_bfloat16* Al1 = Al + (long)(rowBase + r1c) * K + o0c;
    const __nv_bfloat16* Bg0 = Wh + (long)(colBase + r0c) * K + o0c;
    const __nv_bfloat16* Bg1 = Wh + (long)(colBase + r1c) * K + o0c;
    const __nv_bfloat16* Bl0 = Wl + (long)(colBase + r0c) * K + o0c;
    const __nv_bfloat16* Bl1 = Wl + (long)(colBase + r1c) * K + o0c;
    // smem dsts
    uint32_t dA0 = smem_u32(&Ash[r0c * SPAD + o0c]);
    uint32_t dA1 = smem_u32(&Ash[r1c * SPAD + o0c]);
    uint32_t dAl0 = smem_u32(&Asl[r0c * SPAD + o0c]);
    uint32_t dAl1 = smem_u32(&Asl[r1c * SPAD + o0c]);
    uint32_t dB0 = smem_u32(&Bsh[r0c * SPAD + o0c]);
    uint32_t dB1 = smem_u32(&Bsh[r1c * SPAD + o0c]);
    uint32_t dBl0 = smem_u32(&Bsl[r0c * SPAD + o0c]);
    uint32_t dBl1 = smem_u32(&Bsl[r1c * SPAD + o0c]);
    const int BUFB = TBUF * 2;     // buffer stride in bytes

    float acc[2][8][4];
    #pragma unroll
    for (int mi = 0; mi < 2; mi++)
        #pragma unroll
        for (int nj = 0; nj < 8; nj++)
            #pragma unroll
            for (int r = 0; r < 4; r++) acc[mi][nj][r] = 0.0f;

    // stage iter 0
    cp_async16(dA0, Ag0);  cp_async16(dA1, Ag1);
    cp_async16(dAl0, Al0); cp_async16(dAl1, Al1);
    cp_async16(dB0, Bg0);  cp_async16(dB1, Bg1);
    cp_async16(dBl0, Bl0); cp_async16(dBl1, Bl1);
    cp_commit();

    int niter = K / BK;
    for (int it = 0; it < niter; it++) {
        int cur = it & 1;
        int nxt = cur ^ 1;
        if (it + 1 < niter) {
            int ka = (it + 1) * BK;
            int bo = nxt * BUFB;
            cp_async16(dA0 + bo, Ag0 + ka);  cp_async16(dA1 + bo, Ag1 + ka);
            cp_async16(dAl0 + bo, Al0 + ka); cp_async16(dAl1 + bo, Al1 + ka);
            cp_async16(dB0 + bo, Bg0 + ka);  cp_async16(dB1 + bo, Bg1 + ka);
            cp_async16(dBl0 + bo, Bl0 + ka); cp_async16(dBl1 + bo, Bl1 + ka);
            cp_commit();
            cp_wait<1>();
        } else {
            cp_wait<0>();
        }
        __syncthreads();

        const __nv_bfloat16* Ahc = Ash + cur * TBUF;
        const __nv_bfloat16* Alc = Asl + cur * TBUF;
        const __nv_bfloat16* Bhc = Bsh + cur * TBUF;
        const __nv_bfloat16* Blc = Bsl + cur * TBUF;

        #pragma unroll
        for (int ks = 0; ks < 2; ks++) {
            int k0 = ks * 16;
            uint32_t ahi[2][4], alo[2][4];
            #pragma unroll
            for (int mi = 0; mi < 2; mi++) {
                int rr = warpM * 32 + mi * 16 + g;
                ahi[mi][0] = *(const uint32_t*)&Ahc[rr * SPAD + k0 + 2 * t];
                ahi[mi][1] = *(const uint32_t*)&Ahc[(rr + 8) * SPAD + k0 + 2 * t];
                ahi[mi][2] = *(const uint32_t*)&Ahc[rr * SPAD + k0 + 8 + 2 * t];
                ahi[mi][3] = *(const uint32_t*)&Ahc[(rr + 8) * SPAD + k0 + 8 + 2 * t];
                alo[mi][0] = *(const uint32_t*)&Alc[rr * SPAD + k0 + 2 * t];
                alo[mi][1] = *(const uint32_t*)&Alc[(rr + 8) * SPAD + k0 + 2 * t];
                alo[mi][2] = *(const uint32_t*)&Alc[rr * SPAD + k0 + 8 + 2 * t];
                alo[mi][3] = *(const uint32_t*)&Alc[(rr + 8) * SPAD + k0 + 8 + 2 * t];
            }
            #pragma unroll
            for (int half = 0; half < 2; half++) {
                uint32_t bhi[4][2], blo[4][2];
                #pragma unroll
                for (int j = 0; j < 4; j++) {
                    int c = warpN * 64 + (half * 4 + j) * 8 + g;
                    bhi[j][0] = *(const uint32_t*)&Bhc[c * SPAD + k0 + 2 * t];
                    bhi[j][1] = *(const uint32_t*)&Bhc[c * SPAD + k0 + 8 + 2 * t];
                    blo[j][0] = *(const uint32_t*)&Blc[c * SPAD + k0 + 2 * t];
                    blo[j][1] = *(const uint32_t*)&Blc[c * SPAD + k0 + 8 + 2 * t];
                }
                #pragma unroll
                for (int mi = 0; mi < 2; mi++)
                    #pragma unroll
                    for (int j = 0; j < 4; j++) {
                        int nj = half * 4 + j;
                        mma_bf16(acc[mi][nj], ahi[mi], blo[j]);
                        mma_bf16(acc[mi][nj], alo[mi], bhi[j]);
                        mma_bf16(acc[mi][nj], ahi[mi], bhi[j]);
                    }
            }
        }
        __syncthreads();
    }

    // epilogue
    #pragma unroll
    for (int mi = 0; mi < 2; mi++) {
        int r0 = rowBase + warpM * 32 + mi * 16 + g;
        #pragma unroll
        for (int nj = 0; nj < 8; nj++) {
            int c = colBase + warpN * 64 + nj * 8 + t * 2;
            float b0 = bias[c], b1 = bias[c + 1];
            float v0 = acc[mi][nj][0] + b0;
            float v1 = acc[mi][nj][1] + b1;
            float v2 = acc[mi][nj][2] + b0;
            float v3 = acc[mi][nj][3] + b1;
            long o0 = (long)r0 * N + c;
            long o1 = (long)(r0 + 8) * N + c;
            if (RES) {
                v0 += C[o0]; v1 += C[o0 + 1];
                v2 += C[o1]; v3 += C[o1 + 1];
            }
            if (RELU) {
                v0 = fmaxf(v0, 0.0f); v1 = fmaxf(v1, 0.0f);
                v2 = fmaxf(v2, 0.0f); v3 = fmaxf(v3, 0.0f);
            }
            if (SPLIT) {
                __nv_bfloat16 h0,l0,h1,l1,h2,l2,h3,l3;
                split_bf16(v0, h0, l0); split_bf16(v1, h1, l1);
                split_bf16(v2, h2, l2); split_bf16(v3, h3, l3);
                *(__nv_bfloat162*)(Ch + o0) = __nv_bfloat162{h0, h1};
                *(__nv_bfloat162*)(Ch + o1) = __nv_bfloat162{h2, h3};
                *(__nv_bfloat162*)(Cl + o0) = __nv_bfloat162{l0, l1};
                *(__nv_bfloat162*)(Cl + o1) = __nv_bfloat162{l2, l3};
            } else {
                C[o0] = v0; C[o0 + 1] = v1;
                C[o1] = v2; C[o1 + 1] = v3;
            }
        }
    }
}

template<bool RELU, bool RES, bool SPLIT>
__global__ __launch_bounds__(256, 2)
void gemm_kernel(const __nv_bfloat16* __restrict__ Ah, const __nv_bfloat16* __restrict__ Al,
                 const __nv_bfloat16* __restrict__ Wh, const __nv_bfloat16* __restrict__ Wl,
                 const float* __restrict__ bias,
                 float* __restrict__ C, __nv_bfloat16* __restrict__ Ch,
                 __nv_bfloat16* __restrict__ Cl,
                 int M, int N, int K) {
    gemm_body<RELU, RES, SPLIT>(Ah, Al, Wh, Wl, bias, C, Ch, Cl, M, N, K);
}

// fused QKV: blockIdx.z selects weight/bias/output
__global__ __launch_bounds__(256, 2)
void qkv_gemm_kernel(const __nv_bfloat16* __restrict__ Ah, const __nv_bfloat16* __restrict__ Al,
                     const __nv_bfloat16* __restrict__ Wh_base,
                     const __nv_bfloat16* __restrict__ Wl_base,
                     const float* __restrict__ bq, const float* __restrict__ bk,
                     const float* __restrict__ bv,
                     float* __restrict__ q, float* __restrict__ k, float* __restrict__ v) {
    int z = blockIdx.z;
    const __nv_bfloat16* Wh = Wh_base + (long)z * (NLAYER * D_MODEL * D_MODEL);
    const __nv_bfloat16* Wl = Wl_base + (long)z * (NLAYER * D_MODEL * D_MODEL);
    const float* bias = (z == 0) ? bq : (z == 1) ? bk : bv;
    float* C = (z == 0) ? q : (z == 1) ? k : v;
    gemm_body<false, false, false>(Ah, Al, Wh, Wl, bias, C, nullptr, nullptr,
                                   M_ROWS, D_MODEL, D_MODEL);
}

// ---------------- tensor-core flash attention (3xTF32) + fused residual --------
#define QP 68
#define VP 72

__global__ __launch_bounds__(256, 1)
void attention_mma_kernel(const float* __restrict__ q,
                          const float* __restrict__ k,
                          const float* __restrict__ v,
                          float* __restrict__ x) {
    extern __shared__ float sm[];
    float* Qh = sm;
    float* Ql = Qh + 128 * QP;
    float* Kh = Ql + 128 * QP;
    float* Kl = Kh + 64 * QP;
    float* Vh = Kl + 64 * QP;
    float* Vl = Vh + 64 * VP;
    float* Ph = Vl + 64 * VP;
    float* Pl = Ph + 128 * QP;

    int tid = threadIdx.x;
    int lane = tid & 31, warp = tid >> 5;
    int g = lane >> 2, t = lane & 3;
    int bh = blockIdx.x;
    int b = bh >> 3, h = bh & 7;
    int qt = blockIdx.y;
    int qr = warp * 16;

    {
        const float* qg = q + ((long)(b * S_LEN + qt * 128) << 9) + h * DHEAD;
        int r = tid >> 4;
        int c = (tid & 15) * 4;
        #pragma unroll
        for (int p = 0; p < 8; p++) {
            int rr = p * 16 + r;
            float4 v4 = *(const float4*)(qg + (long)rr * D_MODEL + c);
            v4.x *= 0.125f; v4.y *= 0.125f; v4.z *= 0.125f; v4.w *= 0.125f;
            uint32_t h0,l0,h1,l1,h2,l2,h3,l3;
            split_tf32(v4.x, h0, l0); split_tf32(v4.y, h1, l1);
            split_tf32(v4.z, h2, l2); split_tf32(v4.w, h3, l3);
            *(float4*)&Qh[rr * QP + c] = make_float4(__uint_as_float(h0), __uint_as_float(h1),
                                                     __uint_as_float(h2), __uint_as_float(h3));
            *(float4*)&Ql[rr * QP + c] = make_float4(__uint_as_float(l0), __uint_as_float(l1),
                                                     __uint_as_float(l2), __uint_as_float(l3));
        }
    }

    float o[8][4];
    #pragma unroll
    for (int j = 0; j < 8; j++)
        #pragma unroll
        for (int r = 0; r < 4; r++) o[j][r] = 0.0f;
    float m0 = -1e30f, m1 = -1e30f, l0s = 0.0f, l1s = 0.0f;

    for (int kt = 0; kt < S_LEN / 64; kt++) {
        __syncthreads();
        {
            const float* kg = k + ((long)(b * S_LEN + kt * 64) << 9) + h * DHEAD;
            const float* vg = v + ((long)(b * S_LEN + kt * 64) << 9) + h * DHEAD;
            int r = tid >> 4;
            int c = (tid & 15) * 4;
            #pragma unroll
            for (int p = 0; p < 4; p++) {
                int rr = p * 16 + r;
                float4 kv4 = *(const float4*)(kg + (long)rr * D_MODEL + c);
                uint32_t h0,lo0,h1,lo1,h2,lo2,h3,lo3;
                split_tf32(kv4.x, h0, lo0); split_tf32(kv4.y, h1, lo1);
                split_tf32(kv4.z, h2, lo2); split_tf32(kv4.w, h3, lo3);
                *(float4*)&Kh[rr * QP + c] = make_float4(__uint_as_float(h0), __uint_as_float(h1),
                                                         __uint_as_float(h2), __uint_as_float(h3));
                *(float4*)&Kl[rr * QP + c] = make_float4(__uint_as_float(lo0), __uint_as_float(lo1),
                                                         __uint_as_float(lo2), __uint_as_float(lo3));
                float4 vv4 = *(const float4*)(vg + (long)rr * D_MODEL + c);
                split_tf32(vv4.x, h0, lo0); split_tf32(vv4.y, h1, lo1);
                split_tf32(vv4.z, h2, lo2); split_tf32(vv4.w, h3, lo3);
                *(float4*)&Vh[rr * VP + c] = make_float4(__uint_as_float(h0), __uint_as_float(h1),
                                                         __uint_as_float(h2), __uint_as_float(h3));
                *(float4*)&Vl[rr * VP + c] = make_float4(__uint_as_float(lo0), __uint_as_float(lo1),
                                                         __uint_as_float(lo2), __uint_as_float(lo3));
            }
        }
        __syncthreads();

        float s[8][4];
        #pragma unroll
        for (int j = 0; j < 8; j++)
            #pragma unroll
            for (int r = 0; r < 4; r++) s[j][r] = 0.0f;

        #pragma unroll
        for (int k8 = 0; k8 < 8; k8++) {
            int kc = k8 * 8;
            uint32_t qh_[4], ql_[4];
            qh_[0] = __float_as_uint(Qh[(qr + g)     * QP + kc + t]);
            qh_[1] = __float_as_uint(Qh[(qr + g + 8) * QP + kc + t]);
            qh_[2] = __float_as_uint(Qh[(qr + g)     * QP + kc + 4 + t]);
            qh_[3] = __float_as_uint(Qh[(qr + g + 8) * QP + kc + 4 + t]);
            ql_[0] = __float_as_uint(Ql[(qr + g)     * QP + kc + t]);
            ql_[1] = __float_as_uint(Ql[(qr + g + 8) * QP + kc + t]);
            ql_[2] = __float_as_uint(Ql[(qr + g)     * QP + kc + 4 + t]);
            ql_[3] = __float_as_uint(Ql[(qr + g + 8) * QP + kc + 4 + t]);
            #pragma unroll
            for (int j = 0; j < 8; j++) {
                uint32_t kh_[2], kl_[2];
                kh_[0] = __float_as_uint(Kh[(j * 8 + g) * QP + kc + t]);
                kh_[1] = __float_as_uint(Kh[(j * 8 + g) * QP + kc + 4 + t]);
                kl_[0] = __float_as_uint(Kl[(j * 8 + g) * QP + kc + t]);
                kl_[1] = __float_as_uint(Kl[(j * 8 + g) * QP + kc + 4 + t]);
                mma_tf32(s[j], qh_, kl_);
                mma_tf32(s[j], ql_, kh_);
                mma_tf32(s[j], qh_, kh_);
            }
        }

        float mx0 = -1e30f, mx1 = -1e30f;
        #pragma unroll
        for (int j = 0; j < 8; j++) {
            mx0 = fmaxf(mx0, fmaxf(s[j][0], s[j][1]));
            mx1 = fmaxf(mx1, fmaxf(s[j][2], s[j][3]));
        }
        mx0 = fmaxf(mx0, __shfl_xor_sync(0xffffffffu, mx0, 1));
        mx0 = fmaxf(mx0, __shfl_xor_sync(0xffffffffu, mx0, 2));
        mx1 = fmaxf(mx1, __shfl_xor_sync(0xffffffffu, mx1, 1));
        mx1 = fmaxf(mx1, __shfl_xor_sync(0xffffffffu, mx1, 2));
        float mn0 = fmaxf(m0, mx0), mn1 = fmaxf(m1, mx1);
        float c0 = __expf(m0 - mn0), c1 = __expf(m1 - mn1);
        l0s *= c0; l1s *= c1;
        #pragma unroll
        for (int j = 0; j < 8; j++) {
            float p0 = __expf(s[j][0] - mn0);
            float p1 = __expf(s[j][1] - mn0);
            float p2 = __expf(s[j][2] - mn1);
            float p3 = __expf(s[j][3] - mn1);
            l0s += p0 + p1; l1s += p2 + p3;
            uint32_t ph0,pl0,ph1,pl1,ph2,pl2,ph3,pl3;
            split_tf32(p0, ph0, pl0); split_tf32(p1, ph1, pl1);
            split_tf32(p2, ph2, pl2); split_tf32(p3, ph3, pl3);
            int cc = j * 8 + 2 * t;
            *(float2*)&Ph[(qr + g)     * QP + cc] = make_float2(__uint_as_float(ph0), __uint_as_float(ph1));
            *(float2*)&Ph[(qr + g + 8) * QP + cc] = make_float2(__uint_as_float(ph2), __uint_as_float(ph3));
            *(float2*)&Pl[(qr + g)     * QP + cc] = make_float2(__uint_as_float(pl0), __uint_as_float(pl1));
            *(float2*)&Pl[(qr + g + 8) * QP + cc] = make_float2(__uint_as_float(pl2), __uint_as_float(pl3));
            o[j][0] *= c0; o[j][1] *= c0; o[j][2] *= c1; o[j][3] *= c1;
        }
        m0 = mn0; m1 = mn1;
        __syncwarp();

        #pragma unroll
        for (int k8 = 0; k8 < 8; k8++) {
            int kc = k8 * 8;
            uint32_t ph_[4], pl_[4];
            ph_[0] = __float_as_uint(Ph[(qr + g)     * QP + kc + t]);
            ph_[1] = __float_as_uint(Ph[(qr + g + 8) * QP + kc + t]);
            ph_[2] = __float_as_uint(Ph[(qr + g)     * QP + kc + 4 + t]);
            ph_[3] = __float_as_uint(Ph[(qr + g + 8) * QP + kc + 4 + t]);
            pl_[0] = __float_as_uint(Pl[(qr + g)     * QP + kc + t]);
            pl_[1] = __float_as_uint(Pl[(qr + g + 8) * QP + kc + t]);
            pl_[2] = __float_as_uint(Pl[(qr + g)     * QP + kc + 4 + t]);
            pl_[3] = __float_as_uint(Pl[(qr + g + 8) * QP + kc + 4 + t]);
            #pragma unroll
            for (int j = 0; j < 8; j++) {
                uint32_t vh_[2], vl_[2];
                vh_[0] = __float_as_uint(Vh[(kc + t)     * VP + j * 8 + g]);
                vh_[1] = __float_as_uint(Vh[(kc + 4 + t) * VP + j * 8 + g]);
                vl_[0] = __float_as_uint(Vl[(kc + t)     * VP + j * 8 + g]);
                vl_[1] = __float_as_uint(Vl[(kc + 4 + t) * VP + j * 8 + g]);
                mma_tf32(o[j], ph_, vl_);
                mma_tf32(o[j], pl_, vh_);
                mma_tf32(o[j], ph_, vh_);
            }
        }
    }

    l0s += __shfl_xor_sync(0xffffffffu, l0s, 1);
    l0s += __shfl_xor_sync(0xffffffffu, l0s, 2);
    l1s += __shfl_xor_sync(0xffffffffu, l1s, 1);
    l1s += __shfl_xor_sync(0xffffffffu, l1s, 2);
    float i0 = 1.0f / l0s, i1 = 1.0f / l1s;

    float* xr0 = x + ((long)(b * S_LEN + qt * 128 + qr + g)     << 9) + h * DHEAD;
    float* xr1 = x + ((long)(b * S_LEN + qt * 128 + qr + g + 8) << 9) + h * DHEAD;
    #pragma unroll
    for (int j = 0; j < 8; j++) {
        int cc = j * 8 + 2 * t;
        float2 r0 = *(float2*)(xr0 + cc);
        r0.x += o[j][0] * i0; r0.y += o[j][1] * i0;
        *(float2*)(xr0 + cc) = r0;
        float2 r1 = *(float2*)(xr1 + cc);
        r1.x += o[j][2] * i1; r1.y += o[j][3] * i1;
        *(float2*)(xr1 + cc) = r1;
    }
}

// ---------------- host orchestration --------------------------------------------
extern "C" void kernel_launch(void* const* d_in, const int* in_sizes, int n_in,
                              void* d_out, int out_size) {
    const float* src   = (const float*)d_in[0];
    const float* pos   = (const float*)d_in[1];
    const float* Wq    = (const float*)d_in[2];
    const float* bq    = (const float*)d_in[3];
    const float* Wk    = (const float*)d_in[4];
    const float* bk    = (const float*)d_in[5];
    const float* Wv    = (const float*)d_in[6];
    const float* bv    = (const float*)d_in[7];
    const float* W1    = (const float*)d_in[8];
    const float* b1    = (const float*)d_in[9];
    const float* W2    = (const float*)d_in[10];
    const float* b2    = (const float*)d_in[11];
    const float* ln1_g = (const float*)d_in[12];
    const float* ln1_b = (const float*)d_in[13];
    const float* ln2_g = (const float*)d_in[14];
    const float* ln2_b = (const float*)d_in[15];
    const float* lnf_g = (const float*)d_in[16];
    const float* lnf_b = (const float*)d_in[17];
    float* out = (float*)d_out;

    float *px, *pq, *pk, *pv;
    __nv_bfloat16 *pxnh, *pxnl, *phh, *phl, *pwh, *pwl;
    cudaGetSymbolAddress((void**)&px,   g_x);
    cudaGetSymbolAddress((void**)&pxnh, g_xn_h);
    cudaGetSymbolAddress((void**)&pxnl, g_xn_l);
    cudaGetSymbolAddress((void**)&pq,   g_q);
    cudaGetSymbolAddress((void**)&pk,   g_k);
    cudaGetSymbolAddress((void**)&pv,   g_v);
    cudaGetSymbolAddress((void**)&phh,  g_h_h);
    cudaGetSymbolAddress((void**)&phl,  g_h_l);
    cudaGetSymbolAddress((void**)&pwh,  g_wth);
    cudaGetSymbolAddress((void**)&pwl,  g_wtl);

    const int ATT_SMEM = (2 * 128 * QP + 2 * 64 * QP + 2 * 64 * VP + 2 * 128 * QP)
                         * (int)sizeof(float);
    cudaFuncSetAttribute(attention_mma_kernel,
                         cudaFuncAttributeMaxDynamicSharedMemorySize, ATT_SMEM);
    cudaFuncSetAttribute(qkv_gemm_kernel,
                         cudaFuncAttributeMaxDynamicSharedMemorySize, GEMM_SMEM);
    cudaFuncSetAttribute(gemm_kernel<true, false, true>,
                         cudaFuncAttributeMaxDynamicSharedMemorySize, GEMM_SMEM);
    cudaFuncSetAttribute(gemm_kernel<false, true, false>,
                         cudaFuncAttributeMaxDynamicSharedMemorySize, GEMM_SMEM);

    // ---- transpose + bf16-split all weights: W[K][N] -> Wt[N][K] hi/lo ----
    {
        dim3 blk(32, 8);
        wsplit_t_kernel<<<dim3(D_MODEL / 32, D_MODEL / 32, NLAYER), blk>>>(
            Wq, pwh + WQ_OFF, pwl + WQ_OFF, D_MODEL, D_MODEL);
        wsplit_t_kernel<<<dim3(D_MODEL / 32, D_MODEL / 32, NLAYER), blk>>>(
            Wk, pwh + WK_OFF, pwl + WK_OFF, D_MODEL, D_MODEL);
        wsplit_t_kernel<<<dim3(D_MODEL / 32, D_MODEL / 32, NLAYER), blk>>>(
            Wv, pwh + WV_OFF, pwl + WV_OFF, D_MODEL, D_MODEL);
        wsplit_t_kernel<<<dim3(FF_DIM / 32, D_MODEL / 32, NLAYER), blk>>>(
            W1, pwh + W1_OFF, pwl + W1_OFF, D_MODEL, FF_DIM);
        wsplit_t_kernel<<<dim3(D_MODEL / 32, FF_DIM / 32, NLAYER), blk>>>(
            W2, pwh + W2_OFF, pwl + W2_OFF, FF_DIM, D_MODEL);
    }

    add_pos_kernel<<<(M_ROWS * D_MODEL + 255) / 256, 256>>>(src, pos, px);

    for (int l = 0; l < NLAYER; l++) {
        long wqkv = (long)l * D_MODEL * D_MODEL;
        long wff1 = (long)l * D_MODEL * FF_DIM;
        long wff2 = (long)l * FF_DIM * D_MODEL;

        // attention block
        layernorm_split_kernel<<<M_ROWS, 128>>>(px, ln1_g + l * D_MODEL, ln1_b + l * D_MODEL,
                                                pxnh, pxnl);
        qkv_gemm_kernel<<<dim3(D_MODEL / BN, M_ROWS / BM, 3), 256, GEMM_SMEM>>>(
            pxnh, pxnl, pwh + WQ_OFF + wqkv, pwl + WQ_OFF + wqkv,
            bq + l * D_MODEL, bk + l * D_MODEL, bv + l * D_MODEL, pq, pk, pv);
        attention_mma_kernel<<<dim3(BATCH * NHEAD, S_LEN / 128), 256, ATT_SMEM>>>(pq, pk, pv, px);

        // feed-forward block
        layernorm_split_kernel<<<M_ROWS, 128>>>(px, ln2_g + l * D_MODEL, ln2_b + l * D_MODEL,
                                                pxnh, pxnl);
        gemm_kernel<true, false, true><<<dim3(FF_DIM / BN, M_ROWS / BM), 256, GEMM_SMEM>>>(
            pxnh, pxnl, pwh + W1_OFF + wff1, pwl + W1_OFF + wff1, b1 + l * FF_DIM,
            nullptr, phh, phl, M_ROWS, FF_DIM, D_MODEL);
        gemm_kernel<false, true, false><<<dim3(D_MODEL / BN, M_ROWS / BM), 256, GEMM_SMEM>>>(
            phh, phl, pwh + W2_OFF + wff2, pwl + W2_OFF + wff2, b2 + l * D_MODEL,
            px, nullptr, nullptr, M_ROWS, D_MODEL, FF_DIM);
    }

    final_ln_kernel<<<M_ROWS, 128>>>(px, lnf_g, lnf_b, out);
}

// round 6
// speedup vs baseline: 3.6951x; 1.1680x over previous
#include <cuda_runtime.h>
#include <cuda_bf16.h>
#include <math.h>
#include <stdint.h>

#define D_MODEL 512
#define FF_DIM  2048
#define S_LEN   1024
#define BATCH   4
#define NLAYER  6
#define NHEAD   8
#define DHEAD   64
#define M_ROWS  (S_LEN * BATCH)   // 4096 token rows

// weight split layout inside g_wth / g_wtl (element offsets; arrays are transposed [N][K])
#define WQ_OFF 0
#define WK_OFF (NLAYER * D_MODEL * D_MODEL)
#define WV_OFF (2 * NLAYER * D_MODEL * D_MODEL)
#define W1_OFF (3 * NLAYER * D_MODEL * D_MODEL)
#define W2_OFF (W1_OFF + NLAYER * D_MODEL * FF_DIM)
#define W_TOTAL (W2_OFF + NLAYER * FF_DIM * D_MODEL)

// ---------------- scratch (device globals; no runtime allocation) ----------------
__device__ float g_x [M_ROWS * D_MODEL];            // residual stream (B,S,D)
__device__ __nv_bfloat16 g_xn_h[M_ROWS * D_MODEL];  // layernorm out hi (bf16)
__device__ __nv_bfloat16 g_xn_l[M_ROWS * D_MODEL];  // layernorm out lo
__device__ __nv_bfloat16 g_qh[M_ROWS * D_MODEL];    // Q/8 hi (row-major)
__device__ __nv_bfloat16 g_ql[M_ROWS * D_MODEL];
__device__ __nv_bfloat16 g_kh[M_ROWS * D_MODEL];    // K hi
__device__ __nv_bfloat16 g_kl[M_ROWS * D_MODEL];
__device__ __nv_bfloat16 g_vth[D_MODEL * M_ROWS];   // V hi TRANSPOSED [dh_col][token]
__device__ __nv_bfloat16 g_vtl[D_MODEL * M_ROWS];
__device__ __nv_bfloat16 g_h_h[M_ROWS * FF_DIM];    // FF hidden hi
__device__ __nv_bfloat16 g_h_l[M_ROWS * FF_DIM];    // FF hidden lo
__device__ __nv_bfloat16 g_wth[W_TOTAL];            // weights transposed [N][K], hi
__device__ __nv_bfloat16 g_wtl[W_TOTAL];            // weights transposed [N][K], lo

// ---------------- helpers ----------------------------------------------------------
__device__ __forceinline__ void mma_bf16(float* d, const uint32_t* a, const uint32_t* b) {
    asm volatile(
        "mma.sync.aligned.m16n8k16.row.col.f32.bf16.bf16.f32 "
        "{%0,%1,%2,%3}, {%4,%5,%6,%7}, {%8,%9}, {%0,%1,%2,%3};"
        : "+f"(d[0]), "+f"(d[1]), "+f"(d[2]), "+f"(d[3])
        : "r"(a[0]), "r"(a[1]), "r"(a[2]), "r"(a[3]), "r"(b[0]), "r"(b[1]));
}

__device__ __forceinline__ void split_bf16(float x, __nv_bfloat16& hi, __nv_bfloat16& lo) {
    hi = __float2bfloat16_rn(x);
    lo = __float2bfloat16_rn(x - __bfloat162float(hi));
}

__device__ __forceinline__ void cp_async16(uint32_t dst, const void* src) {
    asm volatile("cp.async.ca.shared.global [%0], [%1], 16;" :: "r"(dst), "l"(src));
}
__device__ __forceinline__ void cp_commit() {
    asm volatile("cp.async.commit_group;");
}
template<int N>
__device__ __forceinline__ void cp_wait() {
    asm volatile("cp.async.wait_group %0;" :: "n"(N));
}
__device__ __forceinline__ uint32_t smem_u32(const void* p) {
    return (uint32_t)__cvta_generic_to_shared(p);
}

// ---------------- weight transpose + bf16 split: W[K][N] -> Wt[N][K] hi/lo ---------
__global__ void wsplit_t_kernel(const float* __restrict__ src,
                                __nv_bfloat16* __restrict__ oh,
                                __nv_bfloat16* __restrict__ ol,
                                int K, int N) {
    __shared__ float tile[32][33];
    int l = blockIdx.z;
    src += (long)l * K * N;
    oh  += (long)l * N * K;
    ol  += (long)l * N * K;
    int n0 = blockIdx.x * 32, k0 = blockIdx.y * 32;
    int tx = threadIdx.x, ty = threadIdx.y;      // 32 x 8
    #pragma unroll
    for (int i = ty; i < 32; i += 8)
        tile[i][tx] = src[(long)(k0 + i) * N + n0 + tx];
    __syncthreads();
    #pragma unroll
    for (int i = ty; i < 32; i += 8) {
        float x = tile[tx][i];                   // src[k0+tx][n0+i]
        __nv_bfloat16 h, lo;
        split_bf16(x, h, lo);
        long o = (long)(n0 + i) * K + k0 + tx;
        oh[o] = h; ol[o] = lo;
    }
}

// ---------------- x = (src + pos) transposed (S,B,D) -> (B,S,D) ----------------
__global__ void add_pos_kernel(const float* __restrict__ src,
                               const float* __restrict__ pos,
                               float* __restrict__ x) {
    int idx = blockIdx.x * blockDim.x + threadIdx.x;
    if (idx >= M_ROWS * D_MODEL) return;
    int d = idx & (D_MODEL - 1);
    int m = idx >> 9;
    int b = m >> 10;
    int s = m & (S_LEN - 1);
    int src_i = ((s * BATCH + b) << 9) + d;
    x[idx] = src[src_i] + pos[src_i];
}

// ---------------- layernorm -> split bf16 hi/lo output ---------------------------
__global__ void layernorm_split_kernel(const float* __restrict__ x,
                                       const float* __restrict__ gamma,
                                       const float* __restrict__ beta,
                                       __nv_bfloat16* __restrict__ yh,
                                       __nv_bfloat16* __restrict__ yl) {
    int row = blockIdx.x;
    int tid = threadIdx.x;                 // 128
    const float4* xr = (const float4*)(x + row * D_MODEL);
    float4 v = xr[tid];
    float s  = v.x + v.y + v.z + v.w;
    float ss = v.x*v.x + v.y*v.y + v.z*v.z + v.w*v.w;
    #pragma unroll
    for (int o = 16; o > 0; o >>= 1) {
        s  += __shfl_down_sync(0xffffffffu, s,  o);
        ss += __shfl_down_sync(0xffffffffu, ss, o);
    }
    __shared__ float shs[4], shss[4];
    __shared__ float s_mean, s_inv;
    int w = tid >> 5, lane = tid & 31;
    if (lane == 0) { shs[w] = s; shss[w] = ss; }
    __syncthreads();
    if (tid == 0) {
        float ts  = shs[0] + shs[1] + shs[2] + shs[3];
        float tss = shss[0] + shss[1] + shss[2] + shss[3];
        float mean = ts * (1.0f / D_MODEL);
        float var  = tss * (1.0f / D_MODEL) - mean * mean;
        s_mean = mean;
        s_inv  = rsqrtf(var + 1e-5f);
    }
    __syncthreads();
    float mean = s_mean, inv = s_inv;
    int c = tid * 4;
    float4 g = *(const float4*)(gamma + c);
    float4 bb = *(const float4*)(beta + c);
    float o0 = (v.x - mean) * inv * g.x + bb.x;
    float o1 = (v.y - mean) * inv * g.y + bb.y;
    float o2 = (v.z - mean) * inv * g.z + bb.z;
    float o3 = (v.w - mean) * inv * g.w + bb.w;
    __nv_bfloat16 h0,l0,h1,l1,h2,l2,h3,l3;
    split_bf16(o0, h0, l0); split_bf16(o1, h1, l1);
    split_bf16(o2, h2, l2); split_bf16(o3, h3, l3);
    __nv_bfloat162* yh2 = (__nv_bfloat162*)(yh + row * D_MODEL);
    __nv_bfloat162* yl2 = (__nv_bfloat162*)(yl + row * D_MODEL);
    yh2[tid * 2]     = __nv_bfloat162{h0, h1};
    yh2[tid * 2 + 1] = __nv_bfloat162{h2, h3};
    yl2[tid * 2]     = __nv_bfloat162{l0, l1};
    yl2[tid * 2 + 1] = __nv_bfloat162{l2, l3};
}

// ---------------- final layernorm with transpose back to (S,B,D) ----------------
__global__ void final_ln_kernel(const float* __restrict__ x,
                                const float* __restrict__ gamma,
                                const float* __restrict__ beta,
                                float* __restrict__ out) {
    int row = blockIdx.x;
    int tid = threadIdx.x;
    const float4* xr = (const float4*)(x + row * D_MODEL);
    float4 v = xr[tid];
    float s  = v.x + v.y + v.z + v.w;
    float ss = v.x*v.x + v.y*v.y + v.z*v.z + v.w*v.w;
    #pragma unroll
    for (int o = 16; o > 0; o >>= 1) {
        s  += __shfl_down_sync(0xffffffffu, s,  o);
        ss += __shfl_down_sync(0xffffffffu, ss, o);
    }
    __shared__ float shs[4], shss[4];
    __shared__ float s_mean, s_inv;
    int w = tid >> 5, lane = tid & 31;
    if (lane == 0) { shs[w] = s; shss[w] = ss; }
    __syncthreads();
    if (tid == 0) {
        float ts  = shs[0] + shs[1] + shs[2] + shs[3];
        float tss = shss[0] + shss[1] + shss[2] + shss[3];
        float mean = ts * (1.0f / D_MODEL);
        float var  = tss * (1.0f / D_MODEL) - mean * mean;
        s_mean = mean;
        s_inv  = rsqrtf(var + 1e-5f);
    }
    __syncthreads();
    float mean = s_mean, inv = s_inv;
    int c = tid * 4;
    float4 g = *(const float4*)(gamma + c);
    float4 bb = *(const float4*)(beta + c);
    float4 o;
    o.x = (v.x - mean) * inv * g.x + bb.x;
    o.y = (v.y - mean) * inv * g.y + bb.y;
    o.z = (v.z - mean) * inv * g.z + bb.z;
    o.w = (v.w - mean) * inv * g.w + bb.w;
    int b = row >> 10;
    int ss_ = row & (S_LEN - 1);
    ((float4*)(out + ((ss_ * BATCH + b) << 9)))[tid] = o;
}

// ---------------- split-BF16 3-term GEMM mainloop (m16n8k16) -----------------------
#define BM 128
#define BN 128
#define BK 32
#define SPAD 40                    // bf16 row stride: 20 banks -> conflict-free
#define TBUF (128 * SPAD)          // bf16 elems per buffer (A or B, one stage)
#define GEMM_SMEM (8 * TBUF * 2)   // bytes

__device__ __forceinline__ void gemm_mainloop(const __nv_bfloat16* __restrict__ Ah,
                                              const __nv_bfloat16* __restrict__ Al,
                                              const __nv_bfloat16* __restrict__ Wh,
                                              const __nv_bfloat16* __restrict__ Wl,
                                              int K, float acc[2][8][4]) {
    extern __shared__ __nv_bfloat16 smb[];
    __nv_bfloat16* Ash = smb;
    __nv_bfloat16* Asl = Ash + 2 * TBUF;
    __nv_bfloat16* Bsh = Asl + 2 * TBUF;
    __nv_bfloat16* Bsl = Bsh + 2 * TBUF;

    int tid  = threadIdx.x;
    int lane = tid & 31;
    int warp = tid >> 5;
    int warpM = warp >> 1;
    int warpN = warp & 1;
    int rowBase = blockIdx.y * BM;
    int colBase = blockIdx.x * BN;
    int g = lane >> 2;
    int t = lane & 3;

    int r0c = tid >> 2;
    int o0c = (tid & 3) * 8;
    int r1c = (tid + 256) >> 2;
    const __nv_bfloat16* Ag0 = Ah + (long)(rowBase + r0c) * K + o0c;
    const __nv_bfloat16* Ag1 = Ah + (long)(rowBase + r1c) * K + o0c;
    const __nv_bfloat16* Al0 = Al + (long)(rowBase + r0c) * K + o0c;
    const __nv_bfloat16* Al1 = Al + (long)(rowBase + r1c) * K + o0c;
    const __nv_bfloat16* Bg0 = Wh + (long)(colBase + r0c) * K + o0c;
    const __nv_bfloat16* Bg1 = Wh + (long)(colBase + r1c) * K + o0c;
    const __nv_bfloat16* Bl0 = Wl + (long)(colBase + r0c) * K + o0c;
    const __nv_bfloat16* Bl1 = Wl + (long)(colBase + r1c) * K + o0c;
    uint32_t dA0 = smem_u32(&Ash[r0c * SPAD + o0c]);
    uint32_t dA1 = smem_u32(&Ash[r1c * SPAD + o0c]);
    uint32_t dAl0 = smem_u32(&Asl[r0c * SPAD + o0c]);
    uint32_t dAl1 = smem_u32(&Asl[r1c * SPAD + o0c]);
    uint32_t dB0 = smem_u32(&Bsh[r0c * SPAD + o0c]);
    uint32_t dB1 = smem_u32(&Bsh[r1c * SPAD + o0c]);
    uint32_t dBl0 = smem_u32(&Bsl[r0c * SPAD + o0c]);
    uint32_t dBl1 = smem_u32(&Bsl[r1c * SPAD + o0c]);
    const int BUFB = TBUF * 2;

    cp_async16(dA0, Ag0);  cp_async16(dA1, Ag1);
    cp_async16(dAl0, Al0); cp_async16(dAl1, Al1);
    cp_async16(dB0, Bg0);  cp_async16(dB1, Bg1);
    cp_async16(dBl0, Bl0); cp_async16(dBl1, Bl1);
    cp_commit();

    int niter = K / BK;
    for (int it = 0; it < niter; it++) {
        int cur = it & 1;
        int nxt = cur ^ 1;
        if (it + 1 < niter) {
            int ka = (it + 1) * BK;
            int bo = nxt * BUFB;
            cp_async16(dA0 + bo, Ag0 + ka);  cp_async16(dA1 + bo, Ag1 + ka);
            cp_async16(dAl0 + bo, Al0 + ka); cp_async16(dAl1 + bo, Al1 + ka);
            cp_async16(dB0 + bo, Bg0 + ka);  cp_async16(dB1 + bo, Bg1 + ka);
            cp_async16(dBl0 + bo, Bl0 + ka); cp_async16(dBl1 + bo, Bl1 + ka);
            cp_commit();
            cp_wait<1>();
        } else {
            cp_wait<0>();
        }
        __syncthreads();

        const __nv_bfloat16* Ahc = Ash + cur * TBUF;
        const __nv_bfloat16* Alc = Asl + cur * TBUF;
        const __nv_bfloat16* Bhc = Bsh + cur * TBUF;
        const __nv_bfloat16* Blc = Bsl + cur * TBUF;

        #pragma unroll
        for (int ks = 0; ks < 2; ks++) {
            int k0 = ks * 16;
            uint32_t ahi[2][4], alo[2][4];
            #pragma unroll
            for (int mi = 0; mi < 2; mi++) {
                int rr = warpM * 32 + mi * 16 + g;
                ahi[mi][0] = *(const uint32_t*)&Ahc[rr * SPAD + k0 + 2 * t];
                ahi[mi][1] = *(const uint32_t*)&Ahc[(rr + 8) * SPAD + k0 + 2 * t];
                ahi[mi][2] = *(const uint32_t*)&Ahc[rr * SPAD + k0 + 8 + 2 * t];
                ahi[mi][3] = *(const uint32_t*)&Ahc[(rr + 8) * SPAD + k0 + 8 + 2 * t];
                alo[mi][0] = *(const uint32_t*)&Alc[rr * SPAD + k0 + 2 * t];
                alo[mi][1] = *(const uint32_t*)&Alc[(rr + 8) * SPAD + k0 + 2 * t];
                alo[mi][2] = *(const uint32_t*)&Alc[rr * SPAD + k0 + 8 + 2 * t];
                alo[mi][3] = *(const uint32_t*)&Alc[(rr + 8) * SPAD + k0 + 8 + 2 * t];
            }
            #pragma unroll
            for (int half = 0; half < 2; half++) {
                uint32_t bhi[4][2], blo[4][2];
                #pragma unroll
                for (int j = 0; j < 4; j++) {
                    int c = warpN * 64 + (half * 4 + j) * 8 + g;
                    bhi[j][0] = *(const uint32_t*)&Bhc[c * SPAD + k0 + 2 * t];
                    bhi[j][1] = *(const uint32_t*)&Bhc[c * SPAD + k0 + 8 + 2 * t];
                    blo[j][0] = *(const uint32_t*)&Blc[c * SPAD + k0 + 2 * t];
                    blo[j][1] = *(const uint32_t*)&Blc[c * SPAD + k0 + 8 + 2 * t];
                }
                #pragma unroll
                for (int mi = 0; mi < 2; mi++)
                    #pragma unroll
                    for (int j = 0; j < 4; j++) {
                        int nj = half * 4 + j;
                        mma_bf16(acc[mi][nj], ahi[mi], blo[j]);
                        mma_bf16(acc[mi][nj], alo[mi], bhi[j]);
                        mma_bf16(acc[mi][nj], ahi[mi], bhi[j]);
                    }
            }
        }
        __syncthreads();
    }
}

// ---- FF GEMMs: standard / split epilogues ----
template<bool RELU, bool RES, bool SPLIT>
__global__ __launch_bounds__(256, 2)
void gemm_kernel(const __nv_bfloat16* __restrict__ Ah, const __nv_bfloat16* __restrict__ Al,
                 const __nv_bfloat16* __restrict__ Wh, const __nv_bfloat16* __restrict__ Wl,
                 const float* __restrict__ bias,
                 float* __restrict__ C, __nv_bfloat16* __restrict__ Ch,
                 __nv_bfloat16* __restrict__ Cl,
                 int M, int N, int K) {
    float acc[2][8][4];
    #pragma unroll
    for (int mi = 0; mi < 2; mi++)
        #pragma unroll
        for (int nj = 0; nj < 8; nj++)
            #pragma unroll
            for (int r = 0; r < 4; r++) acc[mi][nj][r] = 0.0f;
    gemm_mainloop(Ah, Al, Wh, Wl, K, acc);

    int lane = threadIdx.x & 31, warp = threadIdx.x >> 5;
    int warpM = warp >> 1, warpN = warp & 1;
    int g = lane >> 2, t = lane & 3;
    int rowBase = blockIdx.y * BM, colBase = blockIdx.x * BN;
    #pragma unroll
    for (int mi = 0; mi < 2; mi++) {
        int r0 = rowBase + warpM * 32 + mi * 16 + g;
        #pragma unroll
        for (int nj = 0; nj < 8; nj++) {
            int c = colBase + warpN * 64 + nj * 8 + t * 2;
            float b0 = bias[c], b1 = bias[c + 1];
            float v0 = acc[mi][nj][0] + b0;
            float v1 = acc[mi][nj][1] + b1;
            float v2 = acc[mi][nj][2] + b0;
            float v3 = acc[mi][nj][3] + b1;
            long o0 = (long)r0 * N + c;
            long o1 = (long)(r0 + 8) * N + c;
            if (RES) {
                v0 += C[o0]; v1 += C[o0 + 1];
                v2 += C[o1]; v3 += C[o1 + 1];
            }
            if (RELU) {
                v0 = fmaxf(v0, 0.0f); v1 = fmaxf(v1, 0.0f);
                v2 = fmaxf(v2, 0.0f); v3 = fmaxf(v3, 0.0f);
            }
            if (SPLIT) {
                __nv_bfloat16 h0,l0,h1,l1,h2,l2,h3,l3;
                split_bf16(v0, h0, l0); split_bf16(v1, h1, l1);
                split_bf16(v2, h2, l2); split_bf16(v3, h3, l3);
                *(__nv_bfloat162*)(Ch + o0) = __nv_bfloat162{h0, h1};
                *(__nv_bfloat162*)(Ch + o1) = __nv_bfloat162{h2, h3};
                *(__nv_bfloat162*)(Cl + o0) = __nv_bfloat162{l0, l1};
                *(__nv_bfloat162*)(Cl + o1) = __nv_bfloat162{l2, l3};
            } else {
                C[o0] = v0; C[o0 + 1] = v1;
                C[o1] = v2; C[o1 + 1] = v3;
            }
        }
    }
}

// ---- fused QKV GEMM: z selects weight; epilogue emits pre-split bf16 -------------
// z=0: Q scaled by 1/8, row-major hi/lo.  z=1: K row-major.  z=2: V transposed.
__global__ __launch_bounds__(256, 2)
void qkv_gemm_kernel(const __nv_bfloat16* __restrict__ Ah, const __nv_bfloat16* __restrict__ Al,
                     const __nv_bfloat16* __restrict__ Wh_base,
                     const __nv_bfloat16* __restrict__ Wl_base,
                     const float* __restrict__ bq, const float* __restrict__ bk,
                     const float* __restrict__ bv,
                     __nv_bfloat16* __restrict__ qh, __nv_bfloat16* __restrict__ ql,
                     __nv_bfloat16* __restrict__ kh, __nv_bfloat16* __restrict__ kl,
                     __nv_bfloat16* __restrict__ vth, __nv_bfloat16* __restrict__ vtl) {
    int z = blockIdx.z;
    const __nv_bfloat16* Wh = Wh_base + (long)z * (NLAYER * D_MODEL * D_MODEL);
    const __nv_bfloat16* Wl = Wl_base + (long)z * (NLAYER * D_MODEL * D_MODEL);
    const float* bias = (z == 0) ? bq : (z == 1) ? bk : bv;

    float acc[2][8][4];
    #pragma unroll
    for (int mi = 0; mi < 2; mi++)
        #pragma unroll
        for (int nj = 0; nj < 8; nj++)
            #pragma unroll
            for (int r = 0; r < 4; r++) acc[mi][nj][r] = 0.0f;
    gemm_mainloop(Ah, Al, Wh, Wl, D_MODEL, acc);

    int lane = threadIdx.x & 31, warp = threadIdx.x >> 5;
    int warpM = warp >> 1, warpN = warp & 1;
    int g = lane >> 2, t = lane & 3;
    int rowBase = blockIdx.y * BM, colBase = blockIdx.x * BN;
    float scale = (z == 0) ? 0.125f : 1.0f;

    #pragma unroll
    for (int mi = 0; mi < 2; mi++) {
        int r0 = rowBase + warpM * 32 + mi * 16 + g;
        #pragma unroll
        for (int nj = 0; nj < 8; nj++) {
            int c = colBase + warpN * 64 + nj * 8 + t * 2;
            float b0 = bias[c], b1 = bias[c + 1];
            float v0 = (acc[mi][nj][0] + b0) * scale;
            float v1 = (acc[mi][nj][1] + b1) * scale;
            float v2 = (acc[mi][nj][2] + b0) * scale;
            float v3 = (acc[mi][nj][3] + b1) * scale;
            __nv_bfloat16 h0,l0,h1,l1,h2,l2,h3,l3;
            split_bf16(v0, h0, l0); split_bf16(v1, h1, l1);
            split_bf16(v2, h2, l2); split_bf16(v3, h3, l3);
            if (z == 2) {
                // transposed store: vt[col][token]
                long c0 = (long)c * M_ROWS, c1 = (long)(c + 1) * M_ROWS;
                vth[c0 + r0]     = h0; vth[c1 + r0]     = h1;
                vth[c0 + r0 + 8] = h2; vth[c1 + r0 + 8] = h3;
                vtl[c0 + r0]     = l0; vtl[c1 + r0]     = l1;
                vtl[c0 + r0 + 8] = l2; vtl[c1 + r0 + 8] = l3;
            } else {
                __nv_bfloat16* Ch = (z == 0) ? qh : kh;
                __nv_bfloat16* Cl = (z == 0) ? ql : kl;
                long o0 = (long)r0 * D_MODEL + c;
                long o1 = (long)(r0 + 8) * D_MODEL + c;
                *(__nv_bfloat162*)(Ch + o0) = __nv_bfloat162{h0, h1};
                *(__nv_bfloat162*)(Ch + o1) = __nv_bfloat162{h2, h3};
                *(__nv_bfloat162*)(Cl + o0) = __nv_bfloat162{l0, l1};
                *(__nv_bfloat162*)(Cl + o1) = __nv_bfloat162{l2, l3};
            }
        }
    }
}

// ---------------- split-bf16 flash attention (m16n8k16) + fused residual ----------
// CTA per (b*h, 128-query tile), 8 warps x 16 query rows. All operands pre-split.
#define QPB 72   // bf16 row stride (144 B): conflict-free for all fragment patterns
#define ATT_SMEM ((2*128 + 2*64 + 2*64 + 2*128) * QPB * 2)   // 110592 B

__global__ __launch_bounds__(256)
void attention_bf16_kernel(const __nv_bfloat16* __restrict__ qh,
                           const __nv_bfloat16* __restrict__ ql,
                           const __nv_bfloat16* __restrict__ kh,
                           const __nv_bfloat16* __restrict__ kl,
                           const __nv_bfloat16* __restrict__ vth,
                           const __nv_bfloat16* __restrict__ vtl,
                           float* __restrict__ x) {
    extern __shared__ __nv_bfloat16 smb[];
    __nv_bfloat16* Qh = smb;                 // [128][QPB]
    __nv_bfloat16* Ql = Qh + 128 * QPB;
    __nv_bfloat16* Kh = Ql + 128 * QPB;      // [64][QPB]
    __nv_bfloat16* Kl = Kh + 64 * QPB;
    __nv_bfloat16* Vh = Kl + 64 * QPB;       // [64 dh][QPB keys]
    __nv_bfloat16* Vl = Vh + 64 * QPB;
    __nv_bfloat16* Ph = Vl + 64 * QPB;       // [128][QPB]
    __nv_bfloat16* Pl = Ph + 128 * QPB;

    int tid = threadIdx.x;
    int lane = tid & 31, warp = tid >> 5;
    int g = lane >> 2, t = lane & 3;
    int bh = blockIdx.x;
    int b = bh >> 3, h = bh & 7;
    int qt = blockIdx.y;
    int qr = warp * 16;

    // ---- stage Q (2048 x 16B chunks via cp.async) ----
    {
        long qbase = ((long)(b * S_LEN + qt * 128)) * D_MODEL + h * DHEAD;
        #pragma unroll
        for (int p = 0; p < 8; p++) {
            int id = p * 256 + tid;
            int arr = id >> 10;            // 0 = hi, 1 = lo
            int rem = id & 1023;
            int row = rem >> 3, ck = rem & 7;
            const __nv_bfloat16* src = (arr ? ql : qh) + qbase + (long)row * D_MODEL + ck * 8;
            uint32_t dst = smem_u32(&(arr ? Ql : Qh)[row * QPB + ck * 8]);
            cp_async16(dst, src);
        }
        cp_commit();
    }

    float o[8][4];
    #pragma unroll
    for (int j = 0; j < 8; j++)
        #pragma unroll
        for (int r = 0; r < 4; r++) o[j][r] = 0.0f;
    float m0 = -1e30f, m1 = -1e30f, l0s = 0.0f, l1s = 0.0f;

    for (int kt = 0; kt < S_LEN / 64; kt++) {
        __syncthreads();
        // ---- stage K + Vt (2048 chunks) ----
        {
            long kbase = ((long)(b * S_LEN + kt * 64)) * D_MODEL + h * DHEAD;
            long vcol  = (long)b * S_LEN + kt * 64;
            #pragma unroll
            for (int p = 0; p < 8; p++) {
                int id = p * 256 + tid;
                int arr = id >> 9;         // 0=Kh 1=Kl 2=Vh 3=Vl
                int rem = id & 511;
                int row = rem >> 3, ck = rem & 7;
                const __nv_bfloat16* src;
                uint32_t dst;
                if (arr == 0) {
                    src = kh + kbase + (long)row * D_MODEL + ck * 8;
                    dst = smem_u32(&Kh[row * QPB + ck * 8]);
                } else if (arr == 1) {
                    src = kl + kbase + (long)row * D_MODEL + ck * 8;
                    dst = smem_u32(&Kl[row * QPB + ck * 8]);
                } else if (arr == 2) {
                    src = vth + (long)(h * DHEAD + row) * M_ROWS + vcol + ck * 8;
                    dst = smem_u32(&Vh[row * QPB + ck * 8]);
                } else {
                    src = vtl + (long)(h * DHEAD + row) * M_ROWS + vcol + ck * 8;
                    dst = smem_u32(&Vl[row * QPB + ck * 8]);
                }
                cp_async16(dst, src);
            }
            cp_commit();
        }
        cp_wait<0>();
        __syncthreads();

        // ---- S = (Q/8) @ K^T : 16 x 64 per warp, 3-term bf16 ----
        float s[8][4];
        #pragma unroll
        for (int j = 0; j < 8; j++)
            #pragma unroll
            for (int r = 0; r < 4; r++) s[j][r] = 0.0f;

        #pragma unroll
        for (int ks = 0; ks < 4; ks++) {
            int k0 = ks * 16;
            int r0 = (qr + g) * QPB, r1 = (qr + g + 8) * QPB;
            uint32_t a_h[4], a_l[4];
            a_h[0] = *(const uint32_t*)&Qh[r0 + k0 + 2 * t];
            a_h[1] = *(const uint32_t*)&Qh[r1 + k0 + 2 * t];
            a_h[2] = *(const uint32_t*)&Qh[r0 + k0 + 8 + 2 * t];
            a_h[3] = *(const uint32_t*)&Qh[r1 + k0 + 8 + 2 * t];
            a_l[0] = *(const uint32_t*)&Ql[r0 + k0 + 2 * t];
            a_l[1] = *(const uint32_t*)&Ql[r1 + k0 + 2 * t];
            a_l[2] = *(const uint32_t*)&Ql[r0 + k0 + 8 + 2 * t];
            a_l[3] = *(const uint32_t*)&Ql[r1 + k0 + 8 + 2 * t];
            #pragma unroll
            for (int j = 0; j < 8; j++) {
                int kr = (j * 8 + g) * QPB;
                uint32_t b_h[2], b_l[2];
                b_h[0] = *(const uint32_t*)&Kh[kr + k0 + 2 * t];
                b_h[1] = *(const uint32_t*)&Kh[kr + k0 + 8 + 2 * t];
                b_l[0] = *(const uint32_t*)&Kl[kr + k0 + 2 * t];
                b_l[1] = *(const uint32_t*)&Kl[kr + k0 + 8 + 2 * t];
                mma_bf16(s[j], a_h, b_l);
                mma_bf16(s[j], a_l, b_h);
                mma_bf16(s[j], a_h, b_h);
            }
        }

        // ---- online softmax (warp-local rows) ----
        float mx0 = -1e30f, mx1 = -1e30f;
        #pragma unroll
        for (int j = 0; j < 8; j++) {
            mx0 = fmaxf(mx0, fmaxf(s[j][0], s[j][1]));
            mx1 = fmaxf(mx1, fmaxf(s[j][2], s[j][3]));
        }
        mx0 = fmaxf(mx0, __shfl_xor_sync(0xffffffffu, mx0, 1));
        mx0 = fmaxf(mx0, __shfl_xor_sync(0xffffffffu, mx0, 2));
        mx1 = fmaxf(mx1, __shfl_xor_sync(0xffffffffu, mx1, 1));
        mx1 = fmaxf(mx1, __shfl_xor_sync(0xffffffffu, mx1, 2));
        float mn0 = fmaxf(m0, mx0), mn1 = fmaxf(m1, mx1);
        float c0 = __expf(m0 - mn0), c1 = __expf(m1 - mn1);
        l0s *= c0; l1s *= c1;
        #pragma unroll
        for (int j = 0; j < 8; j++) {
            float p0 = __expf(s[j][0] - mn0);
            float p1 = __expf(s[j][1] - mn0);
            float p2 = __expf(s[j][2] - mn1);
            float p3 = __expf(s[j][3] - mn1);
            l0s += p0 + p1; l1s += p2 + p3;
            __nv_bfloat16 h0,lo0,h1,lo1,h2,lo2,h3,lo3;
            split_bf16(p0, h0, lo0); split_bf16(p1, h1, lo1);
            split_bf16(p2, h2, lo2); split_bf16(p3, h3, lo3);
            int cc = j * 8 + 2 * t;
            *(__nv_bfloat162*)&Ph[(qr + g) * QPB + cc]     = __nv_bfloat162{h0, h1};
            *(__nv_bfloat162*)&Ph[(qr + g + 8) * QPB + cc] = __nv_bfloat162{h2, h3};
            *(__nv_bfloat162*)&Pl[(qr + g) * QPB + cc]     = __nv_bfloat162{lo0, lo1};
            *(__nv_bfloat162*)&Pl[(qr + g + 8) * QPB + cc] = __nv_bfloat162{lo2, lo3};
            o[j][0] *= c0; o[j][1] *= c0; o[j][2] *= c1; o[j][3] *= c1;
        }
        m0 = mn0; m1 = mn1;
        __syncwarp();

        // ---- O += P @ V : keys are the k-dim, Vt[dh][keys] is the B operand ----
        #pragma unroll
        for (int ks = 0; ks < 4; ks++) {
            int k0 = ks * 16;
            int r0 = (qr + g) * QPB, r1 = (qr + g + 8) * QPB;
            uint32_t p_h[4], p_l[4];
            p_h[0] = *(const uint32_t*)&Ph[r0 + k0 + 2 * t];
            p_h[1] = *(const uint32_t*)&Ph[r1 + k0 + 2 * t];
            p_h[2] = *(const uint32_t*)&Ph[r0 + k0 + 8 + 2 * t];
            p_h[3] = *(const uint32_t*)&Ph[r1 + k0 + 8 + 2 * t];
            p_l[0] = *(const uint32_t*)&Pl[r0 + k0 + 2 * t];
            p_l[1] = *(const uint32_t*)&Pl[r1 + k0 + 2 * t];
            p_l[2] = *(const uint32_t*)&Pl[r0 + k0 + 8 + 2 * t];
            p_l[3] = *(const uint32_t*)&Pl[r1 + k0 + 8 + 2 * t];
            #pragma unroll
            for (int j = 0; j < 8; j++) {
                int vr = (j * 8 + g) * QPB;
                uint32_t b_h[2], b_l[2];
                b_h[0] = *(const uint32_t*)&Vh[vr + k0 + 2 * t];
                b_h[1] = *(const uint32_t*)&Vh[vr + k0 + 8 + 2 * t];
                b_l[0] = *(const uint32_t*)&Vl[vr + k0 + 2 * t];
                b_l[1] = *(const uint32_t*)&Vl[vr + k0 + 8 + 2 * t];
                mma_bf16(o[j], p_h, b_l);
                mma_bf16(o[j], p_l, b_h);
                mma_bf16(o[j], p_h, b_h);
            }
        }
    }

    // ---- finalize: x += O / l ----
    l0s += __shfl_xor_sync(0xffffffffu, l0s, 1);
    l0s += __shfl_xor_sync(0xffffffffu, l0s, 2);
    l1s += __shfl_xor_sync(0xffffffffu, l1s, 1);
    l1s += __shfl_xor_sync(0xffffffffu, l1s, 2);
    float i0 = 1.0f / l0s, i1 = 1.0f / l1s;

    float* xr0 = x + ((long)(b * S_LEN + qt * 128 + qr + g)     << 9) + h * DHEAD;
    float* xr1 = x + ((long)(b * S_LEN + qt * 128 + qr + g + 8) << 9) + h * DHEAD;
    #pragma unroll
    for (int j = 0; j < 8; j++) {
        int cc = j * 8 + 2 * t;
        float2 r0 = *(float2*)(xr0 + cc);
        r0.x += o[j][0] * i0; r0.y += o[j][1] * i0;
        *(float2*)(xr0 + cc) = r0;
        float2 r1 = *(float2*)(xr1 + cc);
        r1.x += o[j][2] * i1; r1.y += o[j][3] * i1;
        *(float2*)(xr1 + cc) = r1;
    }
}

// ---------------- host orchestration --------------------------------------------
extern "C" void kernel_launch(void* const* d_in, const int* in_sizes, int n_in,
                              void* d_out, int out_size) {
    const float* src   = (const float*)d_in[0];
    const float* pos   = (const float*)d_in[1];
    const float* Wq    = (const float*)d_in[2];
    const float* bq    = (const float*)d_in[3];
    const float* Wk    = (const float*)d_in[4];
    const float* bk    = (const float*)d_in[5];
    const float* Wv    = (const float*)d_in[6];
    const float* bv    = (const float*)d_in[7];
    const float* W1    = (const float*)d_in[8];
    const float* b1    = (const float*)d_in[9];
    const float* W2    = (const float*)d_in[10];
    const float* b2    = (const float*)d_in[11];
    const float* ln1_g = (const float*)d_in[12];
    const float* ln1_b = (const float*)d_in[13];
    const float* ln2_g = (const float*)d_in[14];
    const float* ln2_b = (const float*)d_in[15];
    const float* lnf_g = (const float*)d_in[16];
    const float* lnf_b = (const float*)d_in[17];
    float* out = (float*)d_out;

    float* px;
    __nv_bfloat16 *pxnh, *pxnl, *pqh, *pql, *pkh, *pkl, *pvth, *pvtl, *phh, *phl, *pwh, *pwl;
    cudaGetSymbolAddress((void**)&px,   g_x);
    cudaGetSymbolAddress((void**)&pxnh, g_xn_h);
    cudaGetSymbolAddress((void**)&pxnl, g_xn_l);
    cudaGetSymbolAddress((void**)&pqh,  g_qh);
    cudaGetSymbolAddress((void**)&pql,  g_ql);
    cudaGetSymbolAddress((void**)&pkh,  g_kh);
    cudaGetSymbolAddress((void**)&pkl,  g_kl);
    cudaGetSymbolAddress((void**)&pvth, g_vth);
    cudaGetSymbolAddress((void**)&pvtl, g_vtl);
    cudaGetSymbolAddress((void**)&phh,  g_h_h);
    cudaGetSymbolAddress((void**)&phl,  g_h_l);
    cudaGetSymbolAddress((void**)&pwh,  g_wth);
    cudaGetSymbolAddress((void**)&pwl,  g_wtl);

    cudaFuncSetAttribute(attention_bf16_kernel,
                         cudaFuncAttributeMaxDynamicSharedMemorySize, ATT_SMEM);
    cudaFuncSetAttribute(qkv_gemm_kernel,
                         cudaFuncAttributeMaxDynamicSharedMemorySize, GEMM_SMEM);
    cudaFuncSetAttribute(gemm_kernel<true, false, true>,
                         cudaFuncAttributeMaxDynamicSharedMemorySize, GEMM_SMEM);
    cudaFuncSetAttribute(gemm_kernel<false, true, false>,
                         cudaFuncAttributeMaxDynamicSharedMemorySize, GEMM_SMEM);

    // ---- transpose + bf16-split all weights: W[K][N] -> Wt[N][K] hi/lo ----
    {
        dim3 blk(32, 8);
        wsplit_t_kernel<<<dim3(D_MODEL / 32, D_MODEL / 32, NLAYER), blk>>>(
            Wq, pwh + WQ_OFF, pwl + WQ_OFF, D_MODEL, D_MODEL);
        wsplit_t_kernel<<<dim3(D_MODEL / 32, D_MODEL / 32, NLAYER), blk>>>(
            Wk, pwh + WK_OFF, pwl + WK_OFF, D_MODEL, D_MODEL);
        wsplit_t_kernel<<<dim3(D_MODEL / 32, D_MODEL / 32, NLAYER), blk>>>(
            Wv, pwh + WV_OFF, pwl + WV_OFF, D_MODEL, D_MODEL);
        wsplit_t_kernel<<<dim3(FF_DIM / 32, D_MODEL / 32, NLAYER), blk>>>(
            W1, pwh + W1_OFF, pwl + W1_OFF, D_MODEL, FF_DIM);
        wsplit_t_kernel<<<dim3(D_MODEL / 32, FF_DIM / 32, NLAYER), blk>>>(
            W2, pwh + W2_OFF, pwl + W2_OFF, FF_DIM, D_MODEL);
    }

    add_pos_kernel<<<(M_ROWS * D_MODEL + 255) / 256, 256>>>(src, pos, px);

    for (int l = 0; l < NLAYER; l++) {
        long wqkv = (long)l * D_MODEL * D_MODEL;
        long wff1 = (long)l * D_MODEL * FF_DIM;
        long wff2 = (long)l * FF_DIM * D_MODEL;

        // attention block
        layernorm_split_kernel<<<M_ROWS, 128>>>(px, ln1_g + l * D_MODEL, ln1_b + l * D_MODEL,
                                                pxnh, pxnl);
        qkv_gemm_kernel<<<dim3(D_MODEL / BN, M_ROWS / BM, 3), 256, GEMM_SMEM>>>(
            pxnh, pxnl, pwh + WQ_OFF + wqkv, pwl + WQ_OFF + wqkv,
            bq + l * D_MODEL, bk + l * D_MODEL, bv + l * D_MODEL,
            pqh, pql, pkh, pkl, pvth, pvtl);
        attention_bf16_kernel<<<dim3(BATCH * NHEAD, S_LEN / 128), 256, ATT_SMEM>>>(
            pqh, pql, pkh, pkl, pvth, pvtl, px);

        // feed-forward block
        layernorm_split_kernel<<<M_ROWS, 128>>>(px, ln2_g + l * D_MODEL, ln2_b + l * D_MODEL,
                                                pxnh, pxnl);
        gemm_kernel<true, false, true><<<dim3(FF_DIM / BN, M_ROWS / BM), 256, GEMM_SMEM>>>(
            pxnh, pxnl, pwh + W1_OFF + wff1, pwl + W1_OFF + wff1, b1 + l * FF_DIM,
            nullptr, phh, phl, M_ROWS, FF_DIM, D_MODEL);
        gemm_kernel<false, true, false><<<dim3(D_MODEL / BN, M_ROWS / BM), 256, GEMM_SMEM>>>(
            phh, phl, pwh + W2_OFF + wff2, pwl + W2_OFF + wff2, b2 + l * D_MODEL,
            px, nullptr, nullptr, M_ROWS, D_MODEL, FF_DIM);
    }

    final_ln_kernel<<<M_ROWS, 128>>>(px, lnf_g, lnf_b, out);
}

// round 7
// speedup vs baseline: 4.1124x; 1.1129x over previous
#include <cuda_runtime.h>
#include <cuda_bf16.h>
#include <math.h>
#include <stdint.h>

#define D_MODEL 512
#define FF_DIM  2048
#define S_LEN   1024
#define BATCH   4
#define NLAYER  6
#define NHEAD   8
#define DHEAD   64
#define M_ROWS  (S_LEN * BATCH)   // 4096 token rows

// weight split layout inside g_wth / g_wtl (element offsets; arrays are transposed [N][K])
#define WQ_OFF 0
#define WK_OFF (NLAYER * D_MODEL * D_MODEL)
#define WV_OFF (2 * NLAYER * D_MODEL * D_MODEL)
#define W1_OFF (3 * NLAYER * D_MODEL * D_MODEL)
#define W2_OFF (W1_OFF + NLAYER * D_MODEL * FF_DIM)
#define W_TOTAL (W2_OFF + NLAYER * FF_DIM * D_MODEL)

// ---------------- scratch (device globals; no runtime allocation) ----------------
__device__ float g_x [M_ROWS * D_MODEL];            // residual stream (B,S,D)
__device__ __nv_bfloat16 g_xn_h[M_ROWS * D_MODEL];  // layernorm out hi (bf16)
__device__ __nv_bfloat16 g_xn_l[M_ROWS * D_MODEL];  // layernorm out lo
__device__ __nv_bfloat16 g_qh[M_ROWS * D_MODEL];    // Q/8 hi (row-major)
__device__ __nv_bfloat16 g_ql[M_ROWS * D_MODEL];
__device__ __nv_bfloat16 g_kh[M_ROWS * D_MODEL];    // K hi
__device__ __nv_bfloat16 g_kl[M_ROWS * D_MODEL];
__device__ __nv_bfloat16 g_vth[D_MODEL * M_ROWS];   // V hi TRANSPOSED [dh_col][token]
__device__ __nv_bfloat16 g_vtl[D_MODEL * M_ROWS];
__device__ __nv_bfloat16 g_h_h[M_ROWS * FF_DIM];    // FF hidden hi
__device__ __nv_bfloat16 g_h_l[M_ROWS * FF_DIM];    // FF hidden lo
__device__ __nv_bfloat16 g_wth[W_TOTAL];            // weights transposed [N][K], hi
__device__ __nv_bfloat16 g_wtl[W_TOTAL];            // weights transposed [N][K], lo

// ---------------- helpers ----------------------------------------------------------
__device__ __forceinline__ void mma_bf16(float* d, const uint32_t* a, const uint32_t* b) {
    asm volatile(
        "mma.sync.aligned.m16n8k16.row.col.f32.bf16.bf16.f32 "
        "{%0,%1,%2,%3}, {%4,%5,%6,%7}, {%8,%9}, {%0,%1,%2,%3};"
        : "+f"(d[0]), "+f"(d[1]), "+f"(d[2]), "+f"(d[3])
        : "r"(a[0]), "r"(a[1]), "r"(a[2]), "r"(a[3]), "r"(b[0]), "r"(b[1]));
}

__device__ __forceinline__ void ldsm_x4(uint32_t* r, uint32_t addr) {
    asm volatile("ldmatrix.sync.aligned.m8n8.x4.shared.b16 {%0,%1,%2,%3}, [%4];"
                 : "=r"(r[0]), "=r"(r[1]), "=r"(r[2]), "=r"(r[3]) : "r"(addr));
}

__device__ __forceinline__ void split_bf16(float x, __nv_bfloat16& hi, __nv_bfloat16& lo) {
    hi = __float2bfloat16_rn(x);
    lo = __float2bfloat16_rn(x - __bfloat162float(hi));
}

__device__ __forceinline__ void cp_async16(uint32_t dst, const void* src) {
    asm volatile("cp.async.ca.shared.global [%0], [%1], 16;" :: "r"(dst), "l"(src));
}
__device__ __forceinline__ void cp_commit() {
    asm volatile("cp.async.commit_group;");
}
template<int N>
__device__ __forceinline__ void cp_wait() {
    asm volatile("cp.async.wait_group %0;" :: "n"(N));
}
__device__ __forceinline__ uint32_t smem_u32(const void* p) {
    return (uint32_t)__cvta_generic_to_shared(p);
}

// ---------------- weight transpose + bf16 split: W[K][N] -> Wt[N][K] hi/lo ---------
__global__ void wsplit_t_kernel(const float* __restrict__ src,
                                __nv_bfloat16* __restrict__ oh,
                                __nv_bfloat16* __restrict__ ol,
                                int K, int N) {
    __shared__ float tile[32][33];
    int l = blockIdx.z;
    src += (long)l * K * N;
    oh  += (long)l * N * K;
    ol  += (long)l * N * K;
    int n0 = blockIdx.x * 32, k0 = blockIdx.y * 32;
    int tx = threadIdx.x, ty = threadIdx.y;      // 32 x 8
    #pragma unroll
    for (int i = ty; i < 32; i += 8)
        tile[i][tx] = src[(long)(k0 + i) * N + n0 + tx];
    __syncthreads();
    #pragma unroll
    for (int i = ty; i < 32; i += 8) {
        float x = tile[tx][i];                   // src[k0+tx][n0+i]
        __nv_bfloat16 h, lo;
        split_bf16(x, h, lo);
        long o = (long)(n0 + i) * K + k0 + tx;
        oh[o] = h; ol[o] = lo;
    }
}

// ---------------- x = (src + pos) transposed (S,B,D) -> (B,S,D) ----------------
__global__ void add_pos_kernel(const float* __restrict__ src,
                               const float* __restrict__ pos,
                               float* __restrict__ x) {
    int idx = blockIdx.x * blockDim.x + threadIdx.x;
    if (idx >= M_ROWS * D_MODEL) return;
    int d = idx & (D_MODEL - 1);
    int m = idx >> 9;
    int b = m >> 10;
    int s = m & (S_LEN - 1);
    int src_i = ((s * BATCH + b) << 9) + d;
    x[idx] = src[src_i] + pos[src_i];
}

// ---------------- layernorm -> split bf16 hi/lo output ---------------------------
__global__ void layernorm_split_kernel(const float* __restrict__ x,
                                       const float* __restrict__ gamma,
                                       const float* __restrict__ beta,
                                       __nv_bfloat16* __restrict__ yh,
                                       __nv_bfloat16* __restrict__ yl) {
    int row = blockIdx.x;
    int tid = threadIdx.x;                 // 128
    const float4* xr = (const float4*)(x + row * D_MODEL);
    float4 v = xr[tid];
    float s  = v.x + v.y + v.z + v.w;
    float ss = v.x*v.x + v.y*v.y + v.z*v.z + v.w*v.w;
    #pragma unroll
    for (int o = 16; o > 0; o >>= 1) {
        s  += __shfl_down_sync(0xffffffffu, s,  o);
        ss += __shfl_down_sync(0xffffffffu, ss, o);
    }
    __shared__ float shs[4], shss[4];
    __shared__ float s_mean, s_inv;
    int w = tid >> 5, lane = tid & 31;
    if (lane == 0) { shs[w] = s; shss[w] = ss; }
    __syncthreads();
    if (tid == 0) {
        float ts  = shs[0] + shs[1] + shs[2] + shs[3];
        float tss = shss[0] + shss[1] + shss[2] + shss[3];
        float mean = ts * (1.0f / D_MODEL);
        float var  = tss * (1.0f / D_MODEL) - mean * mean;
        s_mean = mean;
        s_inv  = rsqrtf(var + 1e-5f);
    }
    __syncthreads();
    float mean = s_mean, inv = s_inv;
    int c = tid * 4;
    float4 g = *(const float4*)(gamma + c);
    float4 bb = *(const float4*)(beta + c);
    float o0 = (v.x - mean) * inv * g.x + bb.x;
    float o1 = (v.y - mean) * inv * g.y + bb.y;
    float o2 = (v.z - mean) * inv * g.z + bb.z;
    float o3 = (v.w - mean) * inv * g.w + bb.w;
    __nv_bfloat16 h0,l0,h1,l1,h2,l2,h3,l3;
    split_bf16(o0, h0, l0); split_bf16(o1, h1, l1);
    split_bf16(o2, h2, l2); split_bf16(o3, h3, l3);
    __nv_bfloat162* yh2 = (__nv_bfloat162*)(yh + row * D_MODEL);
    __nv_bfloat162* yl2 = (__nv_bfloat162*)(yl + row * D_MODEL);
    yh2[tid * 2]     = __nv_bfloat162{h0, h1};
    yh2[tid * 2 + 1] = __nv_bfloat162{h2, h3};
    yl2[tid * 2]     = __nv_bfloat162{l0, l1};
    yl2[tid * 2 + 1] = __nv_bfloat162{l2, l3};
}

// ---------------- final layernorm with transpose back to (S,B,D) ----------------
__global__ void final_ln_kernel(const float* __restrict__ x,
                                const float* __restrict__ gamma,
                                const float* __restrict__ beta,
                                float* __restrict__ out) {
    int row = blockIdx.x;
    int tid = threadIdx.x;
    const float4* xr = (const float4*)(x + row * D_MODEL);
    float4 v = xr[tid];
    float s  = v.x + v.y + v.z + v.w;
    float ss = v.x*v.x + v.y*v.y + v.z*v.z + v.w*v.w;
    #pragma unroll
    for (int o = 16; o > 0; o >>= 1) {
        s  += __shfl_down_sync(0xffffffffu, s,  o);
        ss += __shfl_down_sync(0xffffffffu, ss, o);
    }
    __shared__ float shs[4], shss[4];
    __shared__ float s_mean, s_inv;
    int w = tid >> 5, lane = tid & 31;
    if (lane == 0) { shs[w] = s; shss[w] = ss; }
    __syncthreads();
    if (tid == 0) {
        float ts  = shs[0] + shs[1] + shs[2] + shs[3];
        float tss = shss[0] + shss[1] + shss[2] + shss[3];
        float mean = ts * (1.0f / D_MODEL);
        float var  = tss * (1.0f / D_MODEL) - mean * mean;
        s_mean = mean;
        s_inv  = rsqrtf(var + 1e-5f);
    }
    __syncthreads();
    float mean = s_mean, inv = s_inv;
    int c = tid * 4;
    float4 g = *(const float4*)(gamma + c);
    float4 bb = *(const float4*)(beta + c);
    float4 o;
    o.x = (v.x - mean) * inv * g.x + bb.x;
    o.y = (v.y - mean) * inv * g.y + bb.y;
    o.z = (v.z - mean) * inv * g.z + bb.z;
    o.w = (v.w - mean) * inv * g.w + bb.w;
    int b = row >> 10;
    int ss_ = row & (S_LEN - 1);
    ((float4*)(out + ((ss_ * BATCH + b) << 9)))[tid] = o;
}

// ---------------- split-BF16 3-term GEMM mainloop (m16n8k16 + ldmatrix) ------------
#define BM 128
#define BN 128
#define BK 32
#define SPAD 40                    // bf16 row stride: 80 B (conflict-free for LDSM)
#define TBUF (128 * SPAD)          // bf16 elems per buffer
#define BUFB (TBUF * 2)            // bytes per buffer
#define GEMM_SMEM (8 * TBUF * 2)   // bytes

__device__ __forceinline__ void gemm_mainloop(const __nv_bfloat16* __restrict__ Ah,
                                              const __nv_bfloat16* __restrict__ Al,
                                              const __nv_bfloat16* __restrict__ Wh,
                                              const __nv_bfloat16* __restrict__ Wl,
                                              int K, float acc[2][8][4]) {
    extern __shared__ __nv_bfloat16 smb[];
    __nv_bfloat16* Ash = smb;
    __nv_bfloat16* Asl = Ash + 2 * TBUF;
    __nv_bfloat16* Bsh = Asl + 2 * TBUF;
    __nv_bfloat16* Bsl = Bsh + 2 * TBUF;

    int tid  = threadIdx.x;
    int lane = tid & 31;
    int warp = tid >> 5;
    int warpM = warp >> 1;
    int warpN = warp & 1;
    int rowBase = blockIdx.y * BM;
    int colBase = blockIdx.x * BN;

    // ldmatrix per-thread base addresses (bytes); row stride = 80 B
    int lm8  = lane & 7;
    int bit3 = (lane >> 3) & 1;
    int bit4 = lane >> 4;
    uint32_t aOff = (uint32_t)(warpM * 32 + lm8 + 8 * bit3) * 80u + (uint32_t)bit4 * 16u;
    uint32_t bOff = (uint32_t)(warpN * 64 + lm8 + 8 * bit4) * 80u + (uint32_t)bit3 * 16u;
    uint32_t baseAh = smem_u32(Ash) + aOff;
    uint32_t baseAl = smem_u32(Asl) + aOff;
    uint32_t baseBh = smem_u32(Bsh) + bOff;
    uint32_t baseBl = smem_u32(Bsl) + bOff;

    // staging: 512 x 16B chunks per array; thread does chunks tid, tid+256
    int r0c = tid >> 2;
    int o0c = (tid & 3) * 8;
    int r1c = (tid + 256) >> 2;
    const __nv_bfloat16* Ag0 = Ah + (long)(rowBase + r0c) * K + o0c;
    const __nv_bfloat16* Ag1 = Ah + (long)(rowBase + r1c) * K + o0c;
    const __nv_bfloat16* Al0 = Al + (long)(rowBase + r0c) * K + o0c;
    const __nv_bfloat16* Al1 = Al + (long)(rowBase + r1c) * K + o0c;
    const __nv_bfloat16* Bg0 = Wh + (long)(colBase + r0c) * K + o0c;
    const __nv_bfloat16* Bg1 = Wh + (long)(colBase + r1c) * K + o0c;
    const __nv_bfloat16* Bl0 = Wl + (long)(colBase + r0c) * K + o0c;
    const __nv_bfloat16* Bl1 = Wl + (long)(colBase + r1c) * K + o0c;
    uint32_t dA0 = smem_u32(&Ash[r0c * SPAD + o0c]);
    uint32_t dA1 = smem_u32(&Ash[r1c * SPAD + o0c]);
    uint32_t dAl0 = smem_u32(&Asl[r0c * SPAD + o0c]);
    uint32_t dAl1 = smem_u32(&Asl[r1c * SPAD + o0c]);
    uint32_t dB0 = smem_u32(&Bsh[r0c * SPAD + o0c]);
    uint32_t dB1 = smem_u32(&Bsh[r1c * SPAD + o0c]);
    uint32_t dBl0 = smem_u32(&Bsl[r0c * SPAD + o0c]);
    uint32_t dBl1 = smem_u32(&Bsl[r1c * SPAD + o0c]);

    cp_async16(dA0, Ag0);  cp_async16(dA1, Ag1);
    cp_async16(dAl0, Al0); cp_async16(dAl1, Al1);
    cp_async16(dB0, Bg0);  cp_async16(dB1, Bg1);
    cp_async16(dBl0, Bl0); cp_async16(dBl1, Bl1);
    cp_commit();

    int niter = K / BK;
    for (int it = 0; it < niter; it++) {
        int cur = it & 1;
        int nxt = cur ^ 1;
        if (it + 1 < niter) {
            int ka = (it + 1) * BK;
            int bo = nxt * BUFB;
            cp_async16(dA0 + bo, Ag0 + ka);  cp_async16(dA1 + bo, Ag1 + ka);
            cp_async16(dAl0 + bo, Al0 + ka); cp_async16(dAl1 + bo, Al1 + ka);
            cp_async16(dB0 + bo, Bg0 + ka);  cp_async16(dB1 + bo, Bg1 + ka);
            cp_async16(dBl0 + bo, Bl0 + ka); cp_async16(dBl1 + bo, Bl1 + ka);
            cp_commit();
            cp_wait<1>();
        } else {
            cp_wait<0>();
        }
        __syncthreads();

        uint32_t cb = (uint32_t)(cur * BUFB);
        #pragma unroll
        for (int ks = 0; ks < 2; ks++) {
            uint32_t ko = cb + ks * 32;
            uint32_t ahi[2][4], alo[2][4];
            ldsm_x4(ahi[0], baseAh + ko);
            ldsm_x4(ahi[1], baseAh + ko + 16 * 80);
            ldsm_x4(alo[0], baseAl + ko);
            ldsm_x4(alo[1], baseAl + ko + 16 * 80);
            #pragma unroll
            for (int h = 0; h < 4; h++) {
                uint32_t bh[4], bl[4];
                ldsm_x4(bh, baseBh + ko + h * (16 * 80));
                ldsm_x4(bl, baseBl + ko + h * (16 * 80));
                #pragma unroll
                for (int mi = 0; mi < 2; mi++) {
                    mma_bf16(acc[mi][2 * h],     ahi[mi], bl);
                    mma_bf16(acc[mi][2 * h],     alo[mi], bh);
                    mma_bf16(acc[mi][2 * h],     ahi[mi], bh);
                    mma_bf16(acc[mi][2 * h + 1], ahi[mi], bl + 2);
                    mma_bf16(acc[mi][2 * h + 1], alo[mi], bh + 2);
                    mma_bf16(acc[mi][2 * h + 1], ahi[mi], bh + 2);
                }
            }
        }
        __syncthreads();
    }
}

// ---- FF GEMMs: standard / split epilogues ----
template<bool RELU, bool RES, bool SPLIT>
__global__ __launch_bounds__(256, 2)
void gemm_kernel(const __nv_bfloat16* __restrict__ Ah, const __nv_bfloat16* __restrict__ Al,
                 const __nv_bfloat16* __restrict__ Wh, const __nv_bfloat16* __restrict__ Wl,
                 const float* __restrict__ bias,
                 float* __restrict__ C, __nv_bfloat16* __restrict__ Ch,
                 __nv_bfloat16* __restrict__ Cl,
                 int M, int N, int K) {
    float acc[2][8][4];
    #pragma unroll
    for (int mi = 0; mi < 2; mi++)
        #pragma unroll
        for (int nj = 0; nj < 8; nj++)
            #pragma unroll
            for (int r = 0; r < 4; r++) acc[mi][nj][r] = 0.0f;
    gemm_mainloop(Ah, Al, Wh, Wl, K, acc);

    int lane = threadIdx.x & 31, warp = threadIdx.x >> 5;
    int warpM = warp >> 1, warpN = warp & 1;
    int g = lane >> 2, t = lane & 3;
    int rowBase = blockIdx.y * BM, colBase = blockIdx.x * BN;
    #pragma unroll
    for (int mi = 0; mi < 2; mi++) {
        int r0 = rowBase + warpM * 32 + mi * 16 + g;
        #pragma unroll
        for (int nj = 0; nj < 8; nj++) {
            int c = colBase + warpN * 64 + nj * 8 + t * 2;
            float b0 = bias[c], b1 = bias[c + 1];
            float v0 = acc[mi][nj][0] + b0;
            float v1 = acc[mi][nj][1] + b1;
            float v2 = acc[mi][nj][2] + b0;
            float v3 = acc[mi][nj][3] + b1;
            long o0 = (long)r0 * N + c;
            long o1 = (long)(r0 + 8) * N + c;
            if (RES) {
                v0 += C[o0]; v1 += C[o0 + 1];
                v2 += C[o1]; v3 += C[o1 + 1];
            }
            if (RELU) {
                v0 = fmaxf(v0, 0.0f); v1 = fmaxf(v1, 0.0f);
                v2 = fmaxf(v2, 0.0f); v3 = fmaxf(v3, 0.0f);
            }
            if (SPLIT) {
                __nv_bfloat16 h0,l0,h1,l1,h2,l2,h3,l3;
                split_bf16(v0, h0, l0); split_bf16(v1, h1, l1);
                split_bf16(v2, h2, l2); split_bf16(v3, h3, l3);
                *(__nv_bfloat162*)(Ch + o0) = __nv_bfloat162{h0, h1};
                *(__nv_bfloat162*)(Ch + o1) = __nv_bfloat162{h2, h3};
                *(__nv_bfloat162*)(Cl + o0) = __nv_bfloat162{l0, l1};
                *(__nv_bfloat162*)(Cl + o1) = __nv_bfloat162{l2, l3};
            } else {
                C[o0] = v0; C[o0 + 1] = v1;
                C[o1] = v2; C[o1 + 1] = v3;
            }
        }
    }
}

// ---- fused QKV GEMM: z selects weight; epilogue emits pre-split bf16 -------------
__global__ __launch_bounds__(256, 2)
void qkv_gemm_kernel(const __nv_bfloat16* __restrict__ Ah, const __nv_bfloat16* __restrict__ Al,
                     const __nv_bfloat16* __restrict__ Wh_base,
                     const __nv_bfloat16* __restrict__ Wl_base,
                     const float* __restrict__ bq, const float* __restrict__ bk,
                     const float* __restrict__ bv,
                     __nv_bfloat16* __restrict__ qh, __nv_bfloat16* __restrict__ ql,
                     __nv_bfloat16* __restrict__ kh, __nv_bfloat16* __restrict__ kl,
                     __nv_bfloat16* __restrict__ vth, __nv_bfloat16* __restrict__ vtl) {
    int z = blockIdx.z;
    const __nv_bfloat16* Wh = Wh_base + (long)z * (NLAYER * D_MODEL * D_MODEL);
    const __nv_bfloat16* Wl = Wl_base + (long)z * (NLAYER * D_MODEL * D_MODEL);
    const float* bias = (z == 0) ? bq : (z == 1) ? bk : bv;

    float acc[2][8][4];
    #pragma unroll
    for (int mi = 0; mi < 2; mi++)
        #pragma unroll
        for (int nj = 0; nj < 8; nj++)
            #pragma unroll
            for (int r = 0; r < 4; r++) acc[mi][nj][r] = 0.0f;
    gemm_mainloop(Ah, Al, Wh, Wl, D_MODEL, acc);

    int lane = threadIdx.x & 31, warp = threadIdx.x >> 5;
    int warpM = warp >> 1, warpN = warp & 1;
    int g = lane >> 2, t = lane & 3;
    int rowBase = blockIdx.y * BM, colBase = blockIdx.x * BN;
    float scale = (z == 0) ? 0.125f : 1.0f;

    #pragma unroll
    for (int mi = 0; mi < 2; mi++) {
        int r0 = rowBase + warpM * 32 + mi * 16 + g;
        #pragma unroll
        for (int nj = 0; nj < 8; nj++) {
            int c = colBase + warpN * 64 + nj * 8 + t * 2;
            float b0 = bias[c], b1 = bias[c + 1];
            float v0 = (acc[mi][nj][0] + b0) * scale;
            float v1 = (acc[mi][nj][1] + b1) * scale;
            float v2 = (acc[mi][nj][2] + b0) * scale;
            float v3 = (acc[mi][nj][3] + b1) * scale;
            __nv_bfloat16 h0,l0,h1,l1,h2,l2,h3,l3;
            split_bf16(v0, h0, l0); split_bf16(v1, h1, l1);
            split_bf16(v2, h2, l2); split_bf16(v3, h3, l3);
            if (z == 2) {
                long c0 = (long)c * M_ROWS, c1 = (long)(c + 1) * M_ROWS;
                vth[c0 + r0]     = h0; vth[c1 + r0]     = h1;
                vth[c0 + r0 + 8] = h2; vth[c1 + r0 + 8] = h3;
                vtl[c0 + r0]     = l0; vtl[c1 + r0]     = l1;
                vtl[c0 + r0 + 8] = l2; vtl[c1 + r0 + 8] = l3;
            } else {
                __nv_bfloat16* Ch = (z == 0) ? qh : kh;
                __nv_bfloat16* Cl = (z == 0) ? ql : kl;
                long o0 = (long)r0 * D_MODEL + c;
                long o1 = (long)(r0 + 8) * D_MODEL + c;
                *(__nv_bfloat162*)(Ch + o0) = __nv_bfloat162{h0, h1};
                *(__nv_bfloat162*)(Ch + o1) = __nv_bfloat162{h2, h3};
                *(__nv_bfloat162*)(Cl + o0) = __nv_bfloat162{l0, l1};
                *(__nv_bfloat162*)(Cl + o1) = __nv_bfloat162{l2, l3};
            }
        }
    }
}

// ---------------- split-bf16 flash attention (m16n8k16 + ldmatrix) ----------------
#define QPB 72   // bf16 row stride (144 B): conflict-free for LDSM
#define QPBB (QPB * 2)
#define ATT_SMEM ((2*128 + 2*64 + 2*64 + 2*128) * QPB * 2)   // 110592 B

__global__ __launch_bounds__(256)
void attention_bf16_kernel(const __nv_bfloat16* __restrict__ qh,
                           const __nv_bfloat16* __restrict__ ql,
                           const __nv_bfloat16* __restrict__ kh,
                           const __nv_bfloat16* __restrict__ kl,
                           const __nv_bfloat16* __restrict__ vth,
                           const __nv_bfloat16* __restrict__ vtl,
                           float* __restrict__ x) {
    extern __shared__ __nv_bfloat16 smb[];
    __nv_bfloat16* Qh = smb;                 // [128][QPB]
    __nv_bfloat16* Ql = Qh + 128 * QPB;
    __nv_bfloat16* Kh = Ql + 128 * QPB;      // [64][QPB]
    __nv_bfloat16* Kl = Kh + 64 * QPB;
    __nv_bfloat16* Vh = Kl + 64 * QPB;       // [64 dh][QPB keys]
    __nv_bfloat16* Vl = Vh + 64 * QPB;
    __nv_bfloat16* Ph = Vl + 64 * QPB;       // [128][QPB]
    __nv_bfloat16* Pl = Ph + 128 * QPB;

    int tid = threadIdx.x;
    int lane = tid & 31, warp = tid >> 5;
    int g = lane >> 2, t = lane & 3;
    int bh = blockIdx.x;
    int b = bh >> 3, h = bh & 7;
    int qt = blockIdx.y;
    int qr = warp * 16;

    // ldmatrix bases
    int lm8  = lane & 7;
    int bit3 = (lane >> 3) & 1;
    int bit4 = lane >> 4;
    uint32_t aOff = (uint32_t)(qr + lm8 + 8 * bit3) * QPBB + (uint32_t)bit4 * 16u;
    uint32_t bOff = (uint32_t)(lm8 + 8 * bit4) * QPBB + (uint32_t)bit3 * 16u;
    uint32_t baseQh = smem_u32(Qh) + aOff;
    uint32_t baseQl = smem_u32(Ql) + aOff;
    uint32_t basePh = smem_u32(Ph) + aOff;
    uint32_t basePl = smem_u32(Pl) + aOff;
    uint32_t baseKh = smem_u32(Kh) + bOff;
    uint32_t baseKl = smem_u32(Kl) + bOff;
    uint32_t baseVh = smem_u32(Vh) + bOff;
    uint32_t baseVl = smem_u32(Vl) + bOff;

    // ---- stage Q (2048 x 16B chunks via cp.async) ----
    {
        long qbase = ((long)(b * S_LEN + qt * 128)) * D_MODEL + h * DHEAD;
        #pragma unroll
        for (int p = 0; p < 8; p++) {
            int id = p * 256 + tid;
            int arr = id >> 10;            // 0 = hi, 1 = lo
            int rem = id & 1023;
            int row = rem >> 3, ck = rem & 7;
            const __nv_bfloat16* src = (arr ? ql : qh) + qbase + (long)row * D_MODEL + ck * 8;
            uint32_t dst = smem_u32(&(arr ? Ql : Qh)[row * QPB + ck * 8]);
            cp_async16(dst, src);
        }
        cp_commit();
    }

    float o[8][4];
    #pragma unroll
    for (int j = 0; j < 8; j++)
        #pragma unroll
        for (int r = 0; r < 4; r++) o[j][r] = 0.0f;
    float m0 = -1e30f, m1 = -1e30f, l0s = 0.0f, l1s = 0.0f;

    for (int kt = 0; kt < S_LEN / 64; kt++) {
        __syncthreads();
        // ---- stage K + Vt (2048 chunks) ----
        {
            long kbase = ((long)(b * S_LEN + kt * 64)) * D_MODEL + h * DHEAD;
            long vcol  = (long)b * S_LEN + kt * 64;
            #pragma unroll
            for (int p = 0; p < 8; p++) {
                int id = p * 256 + tid;
                int arr = id >> 9;         // 0=Kh 1=Kl 2=Vh 3=Vl
                int rem = id & 511;
                int row = rem >> 3, ck = rem & 7;
                const __nv_bfloat16* src;
                uint32_t dst;
                if (arr == 0) {
                    src = kh + kbase + (long)row * D_MODEL + ck * 8;
                    dst = smem_u32(&Kh[row * QPB + ck * 8]);
                } else if (arr == 1) {
                    src = kl + kbase + (long)row * D_MODEL + ck * 8;
                    dst = smem_u32(&Kl[row * QPB + ck * 8]);
                } else if (arr == 2) {
                    src = vth + (long)(h * DHEAD + row) * M_ROWS + vcol + ck * 8;
                    dst = smem_u32(&Vh[row * QPB + ck * 8]);
                } else {
                    src = vtl + (long)(h * DHEAD + row) * M_ROWS + vcol + ck * 8;
                    dst = smem_u32(&Vl[row * QPB + ck * 8]);
                }
                cp_async16(dst, src);
            }
            cp_commit();
        }
        cp_wait<0>();
        __syncthreads();

        // ---- S = (Q/8) @ K^T : 16 x 64 per warp, 3-term bf16 via ldmatrix ----
        float s[8][4];
        #pragma unroll
        for (int j = 0; j < 8; j++)
            #pragma unroll
            for (int r = 0; r < 4; r++) s[j][r] = 0.0f;

        #pragma unroll
        for (int ks = 0; ks < 4; ks++) {
            uint32_t ko = ks * 32;
            uint32_t a_h[4], a_l[4];
            ldsm_x4(a_h, baseQh + ko);
            ldsm_x4(a_l, baseQl + ko);
            #pragma unroll
            for (int h4 = 0; h4 < 4; h4++) {
                uint32_t b_h[4], b_l[4];
                ldsm_x4(b_h, baseKh + ko + h4 * (16 * QPBB));
                ldsm_x4(b_l, baseKl + ko + h4 * (16 * QPBB));
                mma_bf16(s[2 * h4],     a_h, b_l);
                mma_bf16(s[2 * h4],     a_l, b_h);
                mma_bf16(s[2 * h4],     a_h, b_h);
                mma_bf16(s[2 * h4 + 1], a_h, b_l + 2);
                mma_bf16(s[2 * h4 + 1], a_l, b_h + 2);
                mma_bf16(s[2 * h4 + 1], a_h, b_h + 2);
            }
        }

        // ---- online softmax (warp-local rows) ----
        float mx0 = -1e30f, mx1 = -1e30f;
        #pragma unroll
        for (int j = 0; j < 8; j++) {
            mx0 = fmaxf(mx0, fmaxf(s[j][0], s[j][1]));
            mx1 = fmaxf(mx1, fmaxf(s[j][2], s[j][3]));
        }
        mx0 = fmaxf(mx0, __shfl_xor_sync(0xffffffffu, mx0, 1));
        mx0 = fmaxf(mx0, __shfl_xor_sync(0xffffffffu, mx0, 2));
        mx1 = fmaxf(mx1, __shfl_xor_sync(0xffffffffu, mx1, 1));
        mx1 = fmaxf(mx1, __shfl_xor_sync(0xffffffffu, mx1, 2));
        float mn0 = fmaxf(m0, mx0), mn1 = fmaxf(m1, mx1);
        float c0 = __expf(m0 - mn0), c1 = __expf(m1 - mn1);
        l0s *= c0; l1s *= c1;
        #pragma unroll
        for (int j = 0; j < 8; j++) {
            float p0 = __expf(s[j][0] - mn0);
            float p1 = __expf(s[j][1] - mn0);
            float p2 = __expf(s[j][2] - mn1);
            float p3 = __expf(s[j][3] - mn1);
            l0s += p0 + p1; l1s += p2 + p3;
            __nv_bfloat16 h0,lo0,h1,lo1,h2,lo2,h3,lo3;
            split_bf16(p0, h0, lo0); split_bf16(p1, h1, lo1);
            split_bf16(p2, h2, lo2); split_bf16(p3, h3, lo3);
            int cc = j * 8 + 2 * t;
            *(__nv_bfloat162*)&Ph[(qr + g) * QPB + cc]     = __nv_bfloat162{h0, h1};
            *(__nv_bfloat162*)&Ph[(qr + g + 8) * QPB + cc] = __nv_bfloat162{h2, h3};
            *(__nv_bfloat162*)&Pl[(qr + g) * QPB + cc]     = __nv_bfloat162{lo0, lo1};
            *(__nv_bfloat162*)&Pl[(qr + g + 8) * QPB + cc] = __nv_bfloat162{lo2, lo3};
            o[j][0] *= c0; o[j][1] *= c0; o[j][2] *= c1; o[j][3] *= c1;
        }
        m0 = mn0; m1 = mn1;
        __syncwarp();

        // ---- O += P @ V via ldmatrix ----
        #pragma unroll
        for (int ks = 0; ks < 4; ks++) {
            uint32_t ko = ks * 32;
            uint32_t p_h[4], p_l[4];
            ldsm_x4(p_h, basePh + ko);
            ldsm_x4(p_l, basePl + ko);
            #pragma unroll
            for (int h4 = 0; h4 < 4; h4++) {
                uint32_t b_h[4], b_l[4];
                ldsm_x4(b_h, baseVh + ko + h4 * (16 * QPBB));
                ldsm_x4(b_l, baseVl + ko + h4 * (16 * QPBB));
                mma_bf16(o[2 * h4],     p_h, b_l);
                mma_bf16(o[2 * h4],     p_l, b_h);
                mma_bf16(o[2 * h4],     p_h, b_h);
                mma_bf16(o[2 * h4 + 1], p_h, b_l + 2);
                mma_bf16(o[2 * h4 + 1], p_l, b_h + 2);
                mma_bf16(o[2 * h4 + 1], p_h, b_h + 2);
            }
        }
    }

    // ---- finalize: x += O / l ----
    l0s += __shfl_xor_sync(0xffffffffu, l0s, 1);
    l0s += __shfl_xor_sync(0xffffffffu, l0s, 2);
    l1s += __shfl_xor_sync(0xffffffffu, l1s, 1);
    l1s += __shfl_xor_sync(0xffffffffu, l1s, 2);
    float i0 = 1.0f / l0s, i1 = 1.0f / l1s;

    float* xr0 = x + ((long)(b * S_LEN + qt * 128 + qr + g)     << 9) + h * DHEAD;
    float* xr1 = x + ((long)(b * S_LEN + qt * 128 + qr + g + 8) << 9) + h * DHEAD;
    #pragma unroll
    for (int j = 0; j < 8; j++) {
        int cc = j * 8 + 2 * t;
        float2 r0 = *(float2*)(xr0 + cc);
        r0.x += o[j][0] * i0; r0.y += o[j][1] * i0;
        *(float2*)(xr0 + cc) = r0;
        float2 r1 = *(float2*)(xr1 + cc);
        r1.x += o[j][2] * i1; r1.y += o[j][3] * i1;
        *(float2*)(xr1 + cc) = r1;
    }
}

// ---------------- host orchestration --------------------------------------------
extern "C" void kernel_launch(void* const* d_in, const int* in_sizes, int n_in,
                              void* d_out, int out_size) {
    const float* src   = (const float*)d_in[0];
    const float* pos   = (const float*)d_in[1];
    const float* Wq    = (const float*)d_in[2];
    const float* bq    = (const float*)d_in[3];
    const float* Wk    = (const float*)d_in[4];
    const float* bk    = (const float*)d_in[5];
    const float* Wv    = (const float*)d_in[6];
    const float* bv    = (const float*)d_in[7];
    const float* W1    = (const float*)d_in[8];
    const float* b1    = (const float*)d_in[9];
    const float* W2    = (const float*)d_in[10];
    const float* b2    = (const float*)d_in[11];
    const float* ln1_g = (const float*)d_in[12];
    const float* ln1_b = (const float*)d_in[13];
    const float* ln2_g = (const float*)d_in[14];
    const float* ln2_b = (const float*)d_in[15];
    const float* lnf_g = (const float*)d_in[16];
    const float* lnf_b = (const float*)d_in[17];
    float* out = (float*)d_out;

    float* px;
    __nv_bfloat16 *pxnh, *pxnl, *pqh, *pql, *pkh, *pkl, *pvth, *pvtl, *phh, *phl, *pwh, *pwl;
    cudaGetSymbolAddress((void**)&px,   g_x);
    cudaGetSymbolAddress((void**)&pxnh, g_xn_h);
    cudaGetSymbolAddress((void**)&pxnl, g_xn_l);
    cudaGetSymbolAddress((void**)&pqh,  g_qh);
    cudaGetSymbolAddress((void**)&pql,  g_ql);
    cudaGetSymbolAddress((void**)&pkh,  g_kh);
    cudaGetSymbolAddress((void**)&pkl,  g_kl);
    cudaGetSymbolAddress((void**)&pvth, g_vth);
    cudaGetSymbolAddress((void**)&pvtl, g_vtl);
    cudaGetSymbolAddress((void**)&phh,  g_h_h);
    cudaGetSymbolAddress((void**)&phl,  g_h_l);
    cudaGetSymbolAddress((void**)&pwh,  g_wth);
    cudaGetSymbolAddress((void**)&pwl,  g_wtl);

    cudaFuncSetAttribute(attention_bf16_kernel,
                         cudaFuncAttributeMaxDynamicSharedMemorySize, ATT_SMEM);
    cudaFuncSetAttribute(qkv_gemm_kernel,
                         cudaFuncAttributeMaxDynamicSharedMemorySize, GEMM_SMEM);
    cudaFuncSetAttribute(gemm_kernel<true, false, true>,
                         cudaFuncAttributeMaxDynamicSharedMemorySize, GEMM_SMEM);
    cudaFuncSetAttribute(gemm_kernel<false, true, false>,
                         cudaFuncAttributeMaxDynamicSharedMemorySize, GEMM_SMEM);

    // ---- transpose + bf16-split all weights: W[K][N] -> Wt[N][K] hi/lo ----
    {
        dim3 blk(32, 8);
        wsplit_t_kernel<<<dim3(D_MODEL / 32, D_MODEL / 32, NLAYER), blk>>>(
            Wq, pwh + WQ_OFF, pwl + WQ_OFF, D_MODEL, D_MODEL);
        wsplit_t_kernel<<<dim3(D_MODEL / 32, D_MODEL / 32, NLAYER), blk>>>(
            Wk, pwh + WK_OFF, pwl + WK_OFF, D_MODEL, D_MODEL);
        wsplit_t_kernel<<<dim3(D_MODEL / 32, D_MODEL / 32, NLAYER), blk>>>(
            Wv, pwh + WV_OFF, pwl + WV_OFF, D_MODEL, D_MODEL);
        wsplit_t_kernel<<<dim3(FF_DIM / 32, D_MODEL / 32, NLAYER), blk>>>(
            W1, pwh + W1_OFF, pwl + W1_OFF, D_MODEL, FF_DIM);
        wsplit_t_kernel<<<dim3(D_MODEL / 32, FF_DIM / 32, NLAYER), blk>>>(
            W2, pwh + W2_OFF, pwl + W2_OFF, FF_DIM, D_MODEL);
    }

    add_pos_kernel<<<(M_ROWS * D_MODEL + 255) / 256, 256>>>(src, pos, px);

    for (int l = 0; l < NLAYER; l++) {
        long wqkv = (long)l * D_MODEL * D_MODEL;
        long wff1 = (long)l * D_MODEL * FF_DIM;
        long wff2 = (long)l * FF_DIM * D_MODEL;

        // attention block
        layernorm_split_kernel<<<M_ROWS, 128>>>(px, ln1_g + l * D_MODEL, ln1_b + l * D_MODEL,
                                                pxnh, pxnl);
        qkv_gemm_kernel<<<dim3(D_MODEL / BN, M_ROWS / BM, 3), 256, GEMM_SMEM>>>(
            pxnh, pxnl, pwh + WQ_OFF + wqkv, pwl + WQ_OFF + wqkv,
            bq + l * D_MODEL, bk + l * D_MODEL, bv + l * D_MODEL,
            pqh, pql, pkh, pkl, pvth, pvtl);
        attention_bf16_kernel<<<dim3(BATCH * NHEAD, S_LEN / 128), 256, ATT_SMEM>>>(
            pqh, pql, pkh, pkl, pvth, pvtl, px);

        // feed-forward block
        layernorm_split_kernel<<<M_ROWS, 128>>>(px, ln2_g + l * D_MODEL, ln2_b + l * D_MODEL,
                                                pxnh, pxnl);
        gemm_kernel<true, false, true><<<dim3(FF_DIM / BN, M_ROWS / BM), 256, GEMM_SMEM>>>(
            pxnh, pxnl, pwh + W1_OFF + wff1, pwl + W1_OFF + wff1, b1 + l * FF_DIM,
            nullptr, phh, phl, M_ROWS, FF_DIM, D_MODEL);
        gemm_kernel<false, true, false><<<dim3(D_MODEL / BN, M_ROWS / BM), 256, GEMM_SMEM>>>(
            phh, phl, pwh + W2_OFF + wff2, pwl + W2_OFF + wff2, b2 + l * D_MODEL,
            px, nullptr, nullptr, M_ROWS, D_MODEL, FF_DIM);
    }

    final_ln_kernel<<<M_ROWS, 128>>>(px, lnf_g, lnf_b, out);
}

// round 8
// speedup vs baseline: 4.1459x; 1.0081x over previous
#include <cuda_runtime.h>
#include <cuda_bf16.h>
#include <math.h>
#include <stdint.h>

#define D_MODEL 512
#define FF_DIM  2048
#define S_LEN   1024
#define BATCH   4
#define NLAYER  6
#define NHEAD   8
#define DHEAD   64
#define M_ROWS  (S_LEN * BATCH)   // 4096 token rows

// weight split layout inside g_wth / g_wtl (element offsets; arrays are transposed [N][K])
#define WQ_OFF 0
#define WK_OFF (NLAYER * D_MODEL * D_MODEL)
#define WV_OFF (2 * NLAYER * D_MODEL * D_MODEL)
#define W1_OFF (3 * NLAYER * D_MODEL * D_MODEL)
#define W2_OFF (W1_OFF + NLAYER * D_MODEL * FF_DIM)
#define W_TOTAL (W2_OFF + NLAYER * FF_DIM * D_MODEL)

// ---------------- scratch (device globals; no runtime allocation) ----------------
__device__ float g_x [M_ROWS * D_MODEL];            // residual stream (B,S,D)
__device__ __nv_bfloat16 g_xn_h[M_ROWS * D_MODEL];  // layernorm out hi (bf16)
__device__ __nv_bfloat16 g_xn_l[M_ROWS * D_MODEL];  // layernorm out lo
__device__ __nv_bfloat16 g_qh[M_ROWS * D_MODEL];    // Q/8 hi (row-major)
__device__ __nv_bfloat16 g_ql[M_ROWS * D_MODEL];
__device__ __nv_bfloat16 g_kh[M_ROWS * D_MODEL];    // K hi
__device__ __nv_bfloat16 g_kl[M_ROWS * D_MODEL];
__device__ __nv_bfloat16 g_vth[D_MODEL * M_ROWS];   // V hi TRANSPOSED [dh_col][token]
__device__ __nv_bfloat16 g_vtl[D_MODEL * M_ROWS];
__device__ __nv_bfloat16 g_h_h[M_ROWS * FF_DIM];    // FF hidden hi
__device__ __nv_bfloat16 g_h_l[M_ROWS * FF_DIM];    // FF hidden lo
__device__ float g_p0[M_ROWS * D_MODEL];            // FF2 split-K partial 0
__device__ float g_p1[M_ROWS * D_MODEL];            // FF2 split-K partial 1
__device__ __nv_bfloat16 g_wth[W_TOTAL];            // weights transposed [N][K], hi
__device__ __nv_bfloat16 g_wtl[W_TOTAL];            // weights transposed [N][K], lo

// ---------------- helpers ----------------------------------------------------------
__device__ __forceinline__ void mma_bf16(float* d, const uint32_t* a, const uint32_t* b) {
    asm volatile(
        "mma.sync.aligned.m16n8k16.row.col.f32.bf16.bf16.f32 "
        "{%0,%1,%2,%3}, {%4,%5,%6,%7}, {%8,%9}, {%0,%1,%2,%3};"
        : "+f"(d[0]), "+f"(d[1]), "+f"(d[2]), "+f"(d[3])
        : "r"(a[0]), "r"(a[1]), "r"(a[2]), "r"(a[3]), "r"(b[0]), "r"(b[1]));
}

__device__ __forceinline__ void ldsm_x4(uint32_t* r, uint32_t addr) {
    asm volatile("ldmatrix.sync.aligned.m8n8.x4.shared.b16 {%0,%1,%2,%3}, [%4];"
                 : "=r"(r[0]), "=r"(r[1]), "=r"(r[2]), "=r"(r[3]) : "r"(addr));
}

__device__ __forceinline__ void split_bf16(float x, __nv_bfloat16& hi, __nv_bfloat16& lo) {
    hi = __float2bfloat16_rn(x);
    lo = __float2bfloat16_rn(x - __bfloat162float(hi));
}

__device__ __forceinline__ void cp_async16(uint32_t dst, const void* src) {
    asm volatile("cp.async.ca.shared.global [%0], [%1], 16;" :: "r"(dst), "l"(src));
}
__device__ __forceinline__ void cp_commit() {
    asm volatile("cp.async.commit_group;");
}
template<int N>
__device__ __forceinline__ void cp_wait() {
    asm volatile("cp.async.wait_group %0;" :: "n"(N));
}
__device__ __forceinline__ uint32_t smem_u32(const void* p) {
    return (uint32_t)__cvta_generic_to_shared(p);
}

// ---------------- weight transpose + bf16 split: W[K][N] -> Wt[N][K] hi/lo ---------
__global__ void wsplit_t_kernel(const float* __restrict__ src,
                                __nv_bfloat16* __restrict__ oh,
                                __nv_bfloat16* __restrict__ ol,
                                int K, int N) {
    __shared__ float tile[32][33];
    int l = blockIdx.z;
    src += (long)l * K * N;
    oh  += (long)l * N * K;
    ol  += (long)l * N * K;
    int n0 = blockIdx.x * 32, k0 = blockIdx.y * 32;
    int tx = threadIdx.x, ty = threadIdx.y;      // 32 x 8
    #pragma unroll
    for (int i = ty; i < 32; i += 8)
        tile[i][tx] = src[(long)(k0 + i) * N + n0 + tx];
    __syncthreads();
    #pragma unroll
    for (int i = ty; i < 32; i += 8) {
        float x = tile[tx][i];                   // src[k0+tx][n0+i]
        __nv_bfloat16 h, lo;
        split_bf16(x, h, lo);
        long o = (long)(n0 + i) * K + k0 + tx;
        oh[o] = h; ol[o] = lo;
    }
}

// ---------------- x = (src + pos) transposed (S,B,D) -> (B,S,D) ----------------
__global__ void add_pos_kernel(const float* __restrict__ src,
                               const float* __restrict__ pos,
                               float* __restrict__ x) {
    int idx = blockIdx.x * blockDim.x + threadIdx.x;
    if (idx >= M_ROWS * D_MODEL) return;
    int d = idx & (D_MODEL - 1);
    int m = idx >> 9;
    int b = m >> 10;
    int s = m & (S_LEN - 1);
    int src_i = ((s * BATCH + b) << 9) + d;
    x[idx] = src[src_i] + pos[src_i];
}

// ---------------- FF2 combine: x += p0 + p1 + bias --------------------------------
__global__ void ff2_combine_kernel(const float* __restrict__ p0,
                                   const float* __restrict__ p1,
                                   const float* __restrict__ bias,
                                   float* __restrict__ x) {
    int idx = blockIdx.x * blockDim.x + threadIdx.x;   // over M_ROWS*D/4
    if (idx >= M_ROWS * D_MODEL / 4) return;
    float4 a = ((const float4*)p0)[idx];
    float4 b = ((const float4*)p1)[idx];
    float4 v = ((const float4*)x)[idx];
    int c = (idx & 127) * 4;
    float4 bb = *(const float4*)(bias + c);
    v.x += a.x + b.x + bb.x;
    v.y += a.y + b.y + bb.y;
    v.z += a.z + b.z + bb.z;
    v.w += a.w + b.w + bb.w;
    ((float4*)x)[idx] = v;
}

// ---------------- layernorm -> split bf16 hi/lo output ---------------------------
__global__ void layernorm_split_kernel(const float* __restrict__ x,
                                       const float* __restrict__ gamma,
                                       const float* __restrict__ beta,
                                       __nv_bfloat16* __restrict__ yh,
                                       __nv_bfloat16* __restrict__ yl) {
    int row = blockIdx.x;
    int tid = threadIdx.x;                 // 128
    const float4* xr = (const float4*)(x + row * D_MODEL);
    float4 v = xr[tid];
    float s  = v.x + v.y + v.z + v.w;
    float ss = v.x*v.x + v.y*v.y + v.z*v.z + v.w*v.w;
    #pragma unroll
    for (int o = 16; o > 0; o >>= 1) {
        s  += __shfl_down_sync(0xffffffffu, s,  o);
        ss += __shfl_down_sync(0xffffffffu, ss, o);
    }
    __shared__ float shs[4], shss[4];
    __shared__ float s_mean, s_inv;
    int w = tid >> 5, lane = tid & 31;
    if (lane == 0) { shs[w] = s; shss[w] = ss; }
    __syncthreads();
    if (tid == 0) {
        float ts  = shs[0] + shs[1] + shs[2] + shs[3];
        float tss = shss[0] + shss[1] + shss[2] + shss[3];
        float mean = ts * (1.0f / D_MODEL);
        float var  = tss * (1.0f / D_MODEL) - mean * mean;
        s_mean = mean;
        s_inv  = rsqrtf(var + 1e-5f);
    }
    __syncthreads();
    float mean = s_mean, inv = s_inv;
    int c = tid * 4;
    float4 g = *(const float4*)(gamma + c);
    float4 bb = *(const float4*)(beta + c);
    float o0 = (v.x - mean) * inv * g.x + bb.x;
    float o1 = (v.y - mean) * inv * g.y + bb.y;
    float o2 = (v.z - mean) * inv * g.z + bb.z;
    float o3 = (v.w - mean) * inv * g.w + bb.w;
    __nv_bfloat16 h0,l0,h1,l1,h2,l2,h3,l3;
    split_bf16(o0, h0, l0); split_bf16(o1, h1, l1);
    split_bf16(o2, h2, l2); split_bf16(o3, h3, l3);
    __nv_bfloat162* yh2 = (__nv_bfloat162*)(yh + row * D_MODEL);
    __nv_bfloat162* yl2 = (__nv_bfloat162*)(yl + row * D_MODEL);
    yh2[tid * 2]     = __nv_bfloat162{h0, h1};
    yh2[tid * 2 + 1] = __nv_bfloat162{h2, h3};
    yl2[tid * 2]     = __nv_bfloat162{l0, l1};
    yl2[tid * 2 + 1] = __nv_bfloat162{l2, l3};
}

// ---------------- final layernorm with transpose back to (S,B,D) ----------------
__global__ void final_ln_kernel(const float* __restrict__ x,
                                const float* __restrict__ gamma,
                                const float* __restrict__ beta,
                                float* __restrict__ out) {
    int row = blockIdx.x;
    int tid = threadIdx.x;
    const float4* xr = (const float4*)(x + row * D_MODEL);
    float4 v = xr[tid];
    float s  = v.x + v.y + v.z + v.w;
    float ss = v.x*v.x + v.y*v.y + v.z*v.z + v.w*v.w;
    #pragma unroll
    for (int o = 16; o > 0; o >>= 1) {
        s  += __shfl_down_sync(0xffffffffu, s,  o);
        ss += __shfl_down_sync(0xffffffffu, ss, o);
    }
    __shared__ float shs[4], shss[4];
    __shared__ float s_mean, s_inv;
    int w = tid >> 5, lane = tid & 31;
    if (lane == 0) { shs[w] = s; shss[w] = ss; }
    __syncthreads();
    if (tid == 0) {
        float ts  = shs[0] + shs[1] + shs[2] + shs[3];
        float tss = shss[0] + shss[1] + shss[2] + shss[3];
        float mean = ts * (1.0f / D_MODEL);
        float var  = tss * (1.0f / D_MODEL) - mean * mean;
        s_mean = mean;
        s_inv  = rsqrtf(var + 1e-5f);
    }
    __syncthreads();
    float mean = s_mean, inv = s_inv;
    int c = tid * 4;
    float4 g = *(const float4*)(gamma + c);
    float4 bb = *(const float4*)(beta + c);
    float4 o;
    o.x = (v.x - mean) * inv * g.x + bb.x;
    o.y = (v.y - mean) * inv * g.y + bb.y;
    o.z = (v.z - mean) * inv * g.z + bb.z;
    o.w = (v.w - mean) * inv * g.w + bb.w;
    int b = row >> 10;
    int ss_ = row & (S_LEN - 1);
    ((float4*)(out + ((ss_ * BATCH + b) << 9)))[tid] = o;
}

// ---------------- split-BF16 3-term GEMM mainloop (m16n8k16 + ldmatrix) ------------
#define BM 128
#define BN 128
#define BK 32
#define SPAD 40                    // bf16 row stride: 80 B (conflict-free for LDSM)
#define TBUF (128 * SPAD)          // bf16 elems per buffer
#define BUFB (TBUF * 2)            // bytes per buffer
#define GEMM_SMEM (8 * TBUF * 2)   // bytes

// Pointers pre-offset to the k-range start; ldk = row stride; kIters = (#BK steps).
__device__ __forceinline__ void gemm_mainloop(const __nv_bfloat16* __restrict__ Ah,
                                              const __nv_bfloat16* __restrict__ Al,
                                              const __nv_bfloat16* __restrict__ Wh,
                                              const __nv_bfloat16* __restrict__ Wl,
                                              int ldk, int kIters, float acc[2][8][4]) {
    extern __shared__ __nv_bfloat16 smb[];
    __nv_bfloat16* Ash = smb;
    __nv_bfloat16* Asl = Ash + 2 * TBUF;
    __nv_bfloat16* Bsh = Asl + 2 * TBUF;
    __nv_bfloat16* Bsl = Bsh + 2 * TBUF;

    int tid  = threadIdx.x;
    int lane = tid & 31;
    int warp = tid >> 5;
    int warpM = warp >> 1;
    int warpN = warp & 1;
    int rowBase = blockIdx.y * BM;
    int colBase = blockIdx.x * BN;

    int lm8  = lane & 7;
    int bit3 = (lane >> 3) & 1;
    int bit4 = lane >> 4;
    uint32_t aOff = (uint32_t)(warpM * 32 + lm8 + 8 * bit3) * 80u + (uint32_t)bit4 * 16u;
    uint32_t bOff = (uint32_t)(warpN * 64 + lm8 + 8 * bit4) * 80u + (uint32_t)bit3 * 16u;
    uint32_t baseAh = smem_u32(Ash) + aOff;
    uint32_t baseAl = smem_u32(Asl) + aOff;
    uint32_t baseBh = smem_u32(Bsh) + bOff;
    uint32_t baseBl = smem_u32(Bsl) + bOff;

    int r0c = tid >> 2;
    int o0c = (tid & 3) * 8;
    int r1c = (tid + 256) >> 2;
    const __nv_bfloat16* Ag0 = Ah + (long)(rowBase + r0c) * ldk + o0c;
    const __nv_bfloat16* Ag1 = Ah + (long)(rowBase + r1c) * ldk + o0c;
    const __nv_bfloat16* Al0 = Al + (long)(rowBase + r0c) * ldk + o0c;
    const __nv_bfloat16* Al1 = Al + (long)(rowBase + r1c) * ldk + o0c;
    const __nv_bfloat16* Bg0 = Wh + (long)(colBase + r0c) * ldk + o0c;
    const __nv_bfloat16* Bg1 = Wh + (long)(colBase + r1c) * ldk + o0c;
    const __nv_bfloat16* Bl0 = Wl + (long)(colBase + r0c) * ldk + o0c;
    const __nv_bfloat16* Bl1 = Wl + (long)(colBase + r1c) * ldk + o0c;
    uint32_t dA0 = smem_u32(&Ash[r0c * SPAD + o0c]);
    uint32_t dA1 = smem_u32(&Ash[r1c * SPAD + o0c]);
    uint32_t dAl0 = smem_u32(&Asl[r0c * SPAD + o0c]);
    uint32_t dAl1 = smem_u32(&Asl[r1c * SPAD + o0c]);
    uint32_t dB0 = smem_u32(&Bsh[r0c * SPAD + o0c]);
    uint32_t dB1 = smem_u32(&Bsh[r1c * SPAD + o0c]);
    uint32_t dBl0 = smem_u32(&Bsl[r0c * SPAD + o0c]);
    uint32_t dBl1 = smem_u32(&Bsl[r1c * SPAD + o0c]);

    cp_async16(dA0, Ag0);  cp_async16(dA1, Ag1);
    cp_async16(dAl0, Al0); cp_async16(dAl1, Al1);
    cp_async16(dB0, Bg0);  cp_async16(dB1, Bg1);
    cp_async16(dBl0, Bl0); cp_async16(dBl1, Bl1);
    cp_commit();

    for (int it = 0; it < kIters; it++) {
        int cur = it & 1;
        int nxt = cur ^ 1;
        if (it + 1 < kIters) {
            int ka = (it + 1) * BK;
            int bo = nxt * BUFB;
            cp_async16(dA0 + bo, Ag0 + ka);  cp_async16(dA1 + bo, Ag1 + ka);
            cp_async16(dAl0 + bo, Al0 + ka); cp_async16(dAl1 + bo, Al1 + ka);
            cp_async16(dB0 + bo, Bg0 + ka);  cp_async16(dB1 + bo, Bg1 + ka);
            cp_async16(dBl0 + bo, Bl0 + ka); cp_async16(dBl1 + bo, Bl1 + ka);
            cp_commit();
            cp_wait<1>();
        } else {
            cp_wait<0>();
        }
        __syncthreads();

        uint32_t cb = (uint32_t)(cur * BUFB);
        #pragma unroll
        for (int ks = 0; ks < 2; ks++) {
            uint32_t ko = cb + ks * 32;
            uint32_t ahi[2][4], alo[2][4];
            ldsm_x4(ahi[0], baseAh + ko);
            ldsm_x4(ahi[1], baseAh + ko + 16 * 80);
            ldsm_x4(alo[0], baseAl + ko);
            ldsm_x4(alo[1], baseAl + ko + 16 * 80);
            #pragma unroll
            for (int h = 0; h < 4; h++) {
                uint32_t bh[4], bl[4];
                ldsm_x4(bh, baseBh + ko + h * (16 * 80));
                ldsm_x4(bl, baseBl + ko + h * (16 * 80));
                #pragma unroll
                for (int mi = 0; mi < 2; mi++) {
                    mma_bf16(acc[mi][2 * h],     ahi[mi], bl);
                    mma_bf16(acc[mi][2 * h],     alo[mi], bh);
                    mma_bf16(acc[mi][2 * h],     ahi[mi], bh);
                    mma_bf16(acc[mi][2 * h + 1], ahi[mi], bl + 2);
                    mma_bf16(acc[mi][2 * h + 1], alo[mi], bh + 2);
                    mma_bf16(acc[mi][2 * h + 1], ahi[mi], bh + 2);
                }
            }
        }
        __syncthreads();
    }
}

// ---- FF1 GEMM: relu + split-bf16 epilogue ----
__global__ __launch_bounds__(256, 2)
void ff1_gemm_kernel(const __nv_bfloat16* __restrict__ Ah, const __nv_bfloat16* __restrict__ Al,
                     const __nv_bfloat16* __restrict__ Wh, const __nv_bfloat16* __restrict__ Wl,
                     const float* __restrict__ bias,
                     __nv_bfloat16* __restrict__ Ch, __nv_bfloat16* __restrict__ Cl) {
    float acc[2][8][4];
    #pragma unroll
    for (int mi = 0; mi < 2; mi++)
        #pragma unroll
        for (int nj = 0; nj < 8; nj++)
            #pragma unroll
            for (int r = 0; r < 4; r++) acc[mi][nj][r] = 0.0f;
    gemm_mainloop(Ah, Al, Wh, Wl, D_MODEL, D_MODEL / BK, acc);

    const int N = FF_DIM;
    int lane = threadIdx.x & 31, warp = threadIdx.x >> 5;
    int warpM = warp >> 1, warpN = warp & 1;
    int g = lane >> 2, t = lane & 3;
    int rowBase = blockIdx.y * BM, colBase = blockIdx.x * BN;
    #pragma unroll
    for (int mi = 0; mi < 2; mi++) {
        int r0 = rowBase + warpM * 32 + mi * 16 + g;
        #pragma unroll
        for (int nj = 0; nj < 8; nj++) {
            int c = colBase + warpN * 64 + nj * 8 + t * 2;
            float b0 = bias[c], b1 = bias[c + 1];
            float v0 = fmaxf(acc[mi][nj][0] + b0, 0.0f);
            float v1 = fmaxf(acc[mi][nj][1] + b1, 0.0f);
            float v2 = fmaxf(acc[mi][nj][2] + b0, 0.0f);
            float v3 = fmaxf(acc[mi][nj][3] + b1, 0.0f);
            long o0 = (long)r0 * N + c;
            long o1 = (long)(r0 + 8) * N + c;
            __nv_bfloat16 h0,l0,h1,l1,h2,l2,h3,l3;
            split_bf16(v0, h0, l0); split_bf16(v1, h1, l1);
            split_bf16(v2, h2, l2); split_bf16(v3, h3, l3);
            *(__nv_bfloat162*)(Ch + o0) = __nv_bfloat162{h0, h1};
            *(__nv_bfloat162*)(Ch + o1) = __nv_bfloat162{h2, h3};
            *(__nv_bfloat162*)(Cl + o0) = __nv_bfloat162{l0, l1};
            *(__nv_bfloat162*)(Cl + o1) = __nv_bfloat162{l2, l3};
        }
    }
}

// ---- FF2 GEMM split-K: z = K-half; writes fp32 partials (no bias/residual) ----
__global__ __launch_bounds__(256, 2)
void ff2_splitk_kernel(const __nv_bfloat16* __restrict__ Ah, const __nv_bfloat16* __restrict__ Al,
                       const __nv_bfloat16* __restrict__ Wh, const __nv_bfloat16* __restrict__ Wl,
                       float* __restrict__ p0, float* __restrict__ p1) {
    int z = blockIdx.z;
    int kOff = z * (FF_DIM / 2);
    float* P = z ? p1 : p0;

    float acc[2][8][4];
    #pragma unroll
    for (int mi = 0; mi < 2; mi++)
        #pragma unroll
        for (int nj = 0; nj < 8; nj++)
            #pragma unroll
            for (int r = 0; r < 4; r++) acc[mi][nj][r] = 0.0f;
    gemm_mainloop(Ah + kOff, Al + kOff, Wh + kOff, Wl + kOff,
                  FF_DIM, (FF_DIM / 2) / BK, acc);

    const int N = D_MODEL;
    int lane = threadIdx.x & 31, warp = threadIdx.x >> 5;
    int warpM = warp >> 1, warpN = warp & 1;
    int g = lane >> 2, t = lane & 3;
    int rowBase = blockIdx.y * BM, colBase = blockIdx.x * BN;
    #pragma unroll
    for (int mi = 0; mi < 2; mi++) {
        int r0 = rowBase + warpM * 32 + mi * 16 + g;
        #pragma unroll
        for (int nj = 0; nj < 8; nj++) {
            int c = colBase + warpN * 64 + nj * 8 + t * 2;
            long o0 = (long)r0 * N + c;
            long o1 = (long)(r0 + 8) * N + c;
            P[o0] = acc[mi][nj][0]; P[o0 + 1] = acc[mi][nj][1];
            P[o1] = acc[mi][nj][2]; P[o1 + 1] = acc[mi][nj][3];
        }
    }
}

// ---- fused QKV GEMM: z selects weight; epilogue emits pre-split bf16 -------------
__global__ __launch_bounds__(256, 2)
void qkv_gemm_kernel(const __nv_bfloat16* __restrict__ Ah, const __nv_bfloat16* __restrict__ Al,
                     const __nv_bfloat16* __restrict__ Wh_base,
                     const __nv_bfloat16* __restrict__ Wl_base,
                     const float* __restrict__ bq, const float* __restrict__ bk,
                     const float* __restrict__ bv,
                     __nv_bfloat16* __restrict__ qh, __nv_bfloat16* __restrict__ ql,
                     __nv_bfloat16* __restrict__ kh, __nv_bfloat16* __restrict__ kl,
                     __nv_bfloat16* __restrict__ vth, __nv_bfloat16* __restrict__ vtl) {
    int z = blockIdx.z;
    const __nv_bfloat16* Wh = Wh_base + (long)z * (NLAYER * D_MODEL * D_MODEL);
    const __nv_bfloat16* Wl = Wl_base + (long)z * (NLAYER * D_MODEL * D_MODEL);
    const float* bias = (z == 0) ? bq : (z == 1) ? bk : bv;

    float acc[2][8][4];
    #pragma unroll
    for (int mi = 0; mi < 2; mi++)
        #pragma unroll
        for (int nj = 0; nj < 8; nj++)
            #pragma unroll
            for (int r = 0; r < 4; r++) acc[mi][nj][r] = 0.0f;
    gemm_mainloop(Ah, Al, Wh, Wl, D_MODEL, D_MODEL / BK, acc);

    int lane = threadIdx.x & 31, warp = threadIdx.x >> 5;
    int warpM = warp >> 1, warpN = warp & 1;
    int g = lane >> 2, t = lane & 3;
    int rowBase = blockIdx.y * BM, colBase = blockIdx.x * BN;
    float scale = (z == 0) ? 0.125f : 1.0f;

    #pragma unroll
    for (int mi = 0; mi < 2; mi++) {
        int r0 = rowBase + warpM * 32 + mi * 16 + g;
        #pragma unroll
        for (int nj = 0; nj < 8; nj++) {
            int c = colBase + warpN * 64 + nj * 8 + t * 2;
            float b0 = bias[c], b1 = bias[c + 1];
            float v0 = (acc[mi][nj][0] + b0) * scale;
            float v1 = (acc[mi][nj][1] + b1) * scale;
            float v2 = (acc[mi][nj][2] + b0) * scale;
            float v3 = (acc[mi][nj][3] + b1) * scale;
            __nv_bfloat16 h0,l0,h1,l1,h2,l2,h3,l3;
            split_bf16(v0, h0, l0); split_bf16(v1, h1, l1);
            split_bf16(v2, h2, l2); split_bf16(v3, h3, l3);
            if (z == 2) {
                long c0 = (long)c * M_ROWS, c1 = (long)(c + 1) * M_ROWS;
                vth[c0 + r0]     = h0; vth[c1 + r0]     = h1;
                vth[c0 + r0 + 8] = h2; vth[c1 + r0 + 8] = h3;
                vtl[c0 + r0]     = l0; vtl[c1 + r0]     = l1;
                vtl[c0 + r0 + 8] = l2; vtl[c1 + r0 + 8] = l3;
            } else {
                __nv_bfloat16* Ch = (z == 0) ? qh : kh;
                __nv_bfloat16* Cl = (z == 0) ? ql : kl;
                long o0 = (long)r0 * D_MODEL + c;
                long o1 = (long)(r0 + 8) * D_MODEL + c;
                *(__nv_bfloat162*)(Ch + o0) = __nv_bfloat162{h0, h1};
                *(__nv_bfloat162*)(Ch + o1) = __nv_bfloat162{h2, h3};
                *(__nv_bfloat162*)(Cl + o0) = __nv_bfloat162{l0, l1};
                *(__nv_bfloat162*)(Cl + o1) = __nv_bfloat162{l2, l3};
            }
        }
    }
}

// ---------------- split-bf16 flash attention (m16n8k16 + ldmatrix) ----------------
#define QPB 72   // bf16 row stride (144 B): conflict-free for LDSM
#define QPBB (QPB * 2)
#define ATT_SMEM ((2*128 + 2*64 + 2*64 + 2*128) * QPB * 2)   // 110592 B

__global__ __launch_bounds__(256, 2)
void attention_bf16_kernel(const __nv_bfloat16* __restrict__ qh,
                           const __nv_bfloat16* __restrict__ ql,
                           const __nv_bfloat16* __restrict__ kh,
                           const __nv_bfloat16* __restrict__ kl,
                           const __nv_bfloat16* __restrict__ vth,
                           const __nv_bfloat16* __restrict__ vtl,
                           float* __restrict__ x) {
    extern __shared__ __nv_bfloat16 smb[];
    __nv_bfloat16* Qh = smb;                 // [128][QPB]
    __nv_bfloat16* Ql = Qh + 128 * QPB;
    __nv_bfloat16* Kh = Ql + 128 * QPB;      // [64][QPB]
    __nv_bfloat16* Kl = Kh + 64 * QPB;
    __nv_bfloat16* Vh = Kl + 64 * QPB;       // [64 dh][QPB keys]
    __nv_bfloat16* Vl = Vh + 64 * QPB;
    __nv_bfloat16* Ph = Vl + 64 * QPB;       // [128][QPB]
    __nv_bfloat16* Pl = Ph + 128 * QPB;

    int tid = threadIdx.x;
    int lane = tid & 31, warp = tid >> 5;
    int g = lane >> 2, t = lane & 3;
    int bh = blockIdx.x;
    int b = bh >> 3, h = bh & 7;
    int qt = blockIdx.y;
    int qr = warp * 16;

    int lm8  = lane & 7;
    int bit3 = (lane >> 3) & 1;
    int bit4 = lane >> 4;
    uint32_t aOff = (uint32_t)(qr + lm8 + 8 * bit3) * QPBB + (uint32_t)bit4 * 16u;
    uint32_t bOff = (uint32_t)(lm8 + 8 * bit4) * QPBB + (uint32_t)bit3 * 16u;
    uint32_t baseQh = smem_u32(Qh) + aOff;
    uint32_t baseQl = smem_u32(Ql) + aOff;
    uint32_t basePh = smem_u32(Ph) + aOff;
    uint32_t basePl = smem_u32(Pl) + aOff;
    uint32_t baseKh = smem_u32(Kh) + bOff;
    uint32_t baseKl = smem_u32(Kl) + bOff;
    uint32_t baseVh = smem_u32(Vh) + bOff;
    uint32_t baseVl = smem_u32(Vl) + bOff;

    // ---- stage Q ----
    {
        long qbase = ((long)(b * S_LEN + qt * 128)) * D_MODEL + h * DHEAD;
        #pragma unroll
        for (int p = 0; p < 8; p++) {
            int id = p * 256 + tid;
            int arr = id >> 10;
            int rem = id & 1023;
            int row = rem >> 3, ck = rem & 7;
            const __nv_bfloat16* src = (arr ? ql : qh) + qbase + (long)row * D_MODEL + ck * 8;
            uint32_t dst = smem_u32(&(arr ? Ql : Qh)[row * QPB + ck * 8]);
            cp_async16(dst, src);
        }
        cp_commit();
    }

    float o[8][4];
    #pragma unroll
    for (int j = 0; j < 8; j++)
        #pragma unroll
        for (int r = 0; r < 4; r++) o[j][r] = 0.0f;
    float m0 = -1e30f, m1 = -1e30f, l0s = 0.0f, l1s = 0.0f;

    for (int kt = 0; kt < S_LEN / 64; kt++) {
        __syncthreads();
        // ---- stage K + Vt ----
        {
            long kbase = ((long)(b * S_LEN + kt * 64)) * D_MODEL + h * DHEAD;
            long vcol  = (long)b * S_LEN + kt * 64;
            #pragma unroll
            for (int p = 0; p < 8; p++) {
                int id = p * 256 + tid;
                int arr = id >> 9;
                int rem = id & 511;
                int row = rem >> 3, ck = rem & 7;
                const __nv_bfloat16* src;
                uint32_t dst;
                if (arr == 0) {
                    src = kh + kbase + (long)row * D_MODEL + ck * 8;
                    dst = smem_u32(&Kh[row * QPB + ck * 8]);
                } else if (arr == 1) {
                    src = kl + kbase + (long)row * D_MODEL + ck * 8;
                    dst = smem_u32(&Kl[row * QPB + ck * 8]);
                } else if (arr == 2) {
                    src = vth + (long)(h * DHEAD + row) * M_ROWS + vcol + ck * 8;
                    dst = smem_u32(&Vh[row * QPB + ck * 8]);
                } else {
                    src = vtl + (long)(h * DHEAD + row) * M_ROWS + vcol + ck * 8;
                    dst = smem_u32(&Vl[row * QPB + ck * 8]);
                }
                cp_async16(dst, src);
            }
            cp_commit();
        }
        cp_wait<0>();
        __syncthreads();

        // ---- S = (Q/8) @ K^T ----
        float s[8][4];
        #pragma unroll
        for (int j = 0; j < 8; j++)
            #pragma unroll
            for (int r = 0; r < 4; r++) s[j][r] = 0.0f;

        #pragma unroll
        for (int ks = 0; ks < 4; ks++) {
            uint32_t ko = ks * 32;
            uint32_t a_h[4], a_l[4];
            ldsm_x4(a_h, baseQh + ko);
            ldsm_x4(a_l, baseQl + ko);
            #pragma unroll
            for (int h4 = 0; h4 < 4; h4++) {
                uint32_t b_h[4], b_l[4];
                ldsm_x4(b_h, baseKh + ko + h4 * (16 * QPBB));
                ldsm_x4(b_l, baseKl + ko + h4 * (16 * QPBB));
                mma_bf16(s[2 * h4],     a_h, b_l);
                mma_bf16(s[2 * h4],     a_l, b_h);
                mma_bf16(s[2 * h4],     a_h, b_h);
                mma_bf16(s[2 * h4 + 1], a_h, b_l + 2);
                mma_bf16(s[2 * h4 + 1], a_l, b_h + 2);
                mma_bf16(s[2 * h4 + 1], a_h, b_h + 2);
            }
        }

        // ---- online softmax ----
        float mx0 = -1e30f, mx1 = -1e30f;
        #pragma unroll
        for (int j = 0; j < 8; j++) {
            mx0 = fmaxf(mx0, fmaxf(s[j][0], s[j][1]));
            mx1 = fmaxf(mx1, fmaxf(s[j][2], s[j][3]));
        }
        mx0 = fmaxf(mx0, __shfl_xor_sync(0xffffffffu, mx0, 1));
        mx0 = fmaxf(mx0, __shfl_xor_sync(0xffffffffu, mx0, 2));
        mx1 = fmaxf(mx1, __shfl_xor_sync(0xffffffffu, mx1, 1));
        mx1 = fmaxf(mx1, __shfl_xor_sync(0xffffffffu, mx1, 2));
        float mn0 = fmaxf(m0, mx0), mn1 = fmaxf(m1, mx1);
        float c0 = __expf(m0 - mn0), c1 = __expf(m1 - mn1);
        l0s *= c0; l1s *= c1;
        #pragma unroll
        for (int j = 0; j < 8; j++) {
            float p0 = __expf(s[j][0] - mn0);
            float p1 = __expf(s[j][1] - mn0);
            float p2 = __expf(s[j][2] - mn1);
            float p3 = __expf(s[j][3] - mn1);
            l0s += p0 + p1; l1s += p2 + p3;
            __nv_bfloat16 h0,lo0,h1,lo1,h2,lo2,h3,lo3;
            split_bf16(p0, h0, lo0); split_bf16(p1, h1, lo1);
            split_bf16(p2, h2, lo2); split_bf16(p3, h3, lo3);
            int cc = j * 8 + 2 * t;
            *(__nv_bfloat162*)&Ph[(qr + g) * QPB + cc]     = __nv_bfloat162{h0, h1};
            *(__nv_bfloat162*)&Ph[(qr + g + 8) * QPB + cc] = __nv_bfloat162{h2, h3};
            *(__nv_bfloat162*)&Pl[(qr + g) * QPB + cc]     = __nv_bfloat162{lo0, lo1};
            *(__nv_bfloat162*)&Pl[(qr + g + 8) * QPB + cc] = __nv_bfloat162{lo2, lo3};
            o[j][0] *= c0; o[j][1] *= c0; o[j][2] *= c1; o[j][3] *= c1;
        }
        m0 = mn0; m1 = mn1;
        __syncwarp();

        // ---- O += P @ V ----
        #pragma unroll
        for (int ks = 0; ks < 4; ks++) {
            uint32_t ko = ks * 32;
            uint32_t p_h[4], p_l[4];
            ldsm_x4(p_h, basePh + ko);
            ldsm_x4(p_l, basePl + ko);
            #pragma unroll
            for (int h4 = 0; h4 < 4; h4++) {
                uint32_t b_h[4], b_l[4];
                ldsm_x4(b_h, baseVh + ko + h4 * (16 * QPBB));
                ldsm_x4(b_l, baseVl + ko + h4 * (16 * QPBB));
                mma_bf16(o[2 * h4],     p_h, b_l);
                mma_bf16(o[2 * h4],     p_l, b_h);
                mma_bf16(o[2 * h4],     p_h, b_h);
                mma_bf16(o[2 * h4 + 1], p_h, b_l + 2);
                mma_bf16(o[2 * h4 + 1], p_l, b_h + 2);
                mma_bf16(o[2 * h4 + 1], p_h, b_h + 2);
            }
        }
    }

    // ---- finalize: x += O / l ----
    l0s += __shfl_xor_sync(0xffffffffu, l0s, 1);
    l0s += __shfl_xor_sync(0xffffffffu, l0s, 2);
    l1s += __shfl_xor_sync(0xffffffffu, l1s, 1);
    l1s += __shfl_xor_sync(0xffffffffu, l1s, 2);
    float i0 = 1.0f / l0s, i1 = 1.0f / l1s;

    float* xr0 = x + ((long)(b * S_LEN + qt * 128 + qr + g)     << 9) + h * DHEAD;
    float* xr1 = x + ((long)(b * S_LEN + qt * 128 + qr + g + 8) << 9) + h * DHEAD;
    #pragma unroll
    for (int j = 0; j < 8; j++) {
        int cc = j * 8 + 2 * t;
        float2 r0 = *(float2*)(xr0 + cc);
        r0.x += o[j][0] * i0; r0.y += o[j][1] * i0;
        *(float2*)(xr0 + cc) = r0;
        float2 r1 = *(float2*)(xr1 + cc);
        r1.x += o[j][2] * i1; r1.y += o[j][3] * i1;
        *(float2*)(xr1 + cc) = r1;
    }
}

// ---------------- host orchestration --------------------------------------------
extern "C" void kernel_launch(void* const* d_in, const int* in_sizes, int n_in,
                              void* d_out, int out_size) {
    const float* src   = (const float*)d_in[0];
    const float* pos   = (const float*)d_in[1];
    const float* Wq    = (const float*)d_in[2];
    const float* bq    = (const float*)d_in[3];
    const float* Wk    = (const float*)d_in[4];
    const float* bk    = (const float*)d_in[5];
    const float* Wv    = (const float*)d_in[6];
    const float* bv    = (const float*)d_in[7];
    const float* W1    = (const float*)d_in[8];
    const float* b1    = (const float*)d_in[9];
    const float* W2    = (const float*)d_in[10];
    const float* b2    = (const float*)d_in[11];
    const float* ln1_g = (const float*)d_in[12];
    const float* ln1_b = (const float*)d_in[13];
    const float* ln2_g = (const float*)d_in[14];
    const float* ln2_b = (const float*)d_in[15];
    const float* lnf_g = (const float*)d_in[16];
    const float* lnf_b = (const float*)d_in[17];
    float* out = (float*)d_out;

    float *px, *pp0, *pp1;
    __nv_bfloat16 *pxnh, *pxnl, *pqh, *pql, *pkh, *pkl, *pvth, *pvtl, *phh, *phl, *pwh, *pwl;
    cudaGetSymbolAddress((void**)&px,   g_x);
    cudaGetSymbolAddress((void**)&pp0,  g_p0);
    cudaGetSymbolAddress((void**)&pp1,  g_p1);
    cudaGetSymbolAddress((void**)&pxnh, g_xn_h);
    cudaGetSymbolAddress((void**)&pxnl, g_xn_l);
    cudaGetSymbolAddress((void**)&pqh,  g_qh);
    cudaGetSymbolAddress((void**)&pql,  g_ql);
    cudaGetSymbolAddress((void**)&pkh,  g_kh);
    cudaGetSymbolAddress((void**)&pkl,  g_kl);
    cudaGetSymbolAddress((void**)&pvth, g_vth);
    cudaGetSymbolAddress((void**)&pvtl, g_vtl);
    cudaGetSymbolAddress((void**)&phh,  g_h_h);
    cudaGetSymbolAddress((void**)&phl,  g_h_l);
    cudaGetSymbolAddress((void**)&pwh,  g_wth);
    cudaGetSymbolAddress((void**)&pwl,  g_wtl);

    cudaFuncSetAttribute(attention_bf16_kernel,
                         cudaFuncAttributeMaxDynamicSharedMemorySize, ATT_SMEM);
    cudaFuncSetAttribute(qkv_gemm_kernel,
                         cudaFuncAttributeMaxDynamicSharedMemorySize, GEMM_SMEM);
    cudaFuncSetAttribute(ff1_gemm_kernel,
                         cudaFuncAttributeMaxDynamicSharedMemorySize, GEMM_SMEM);
    cudaFuncSetAttribute(ff2_splitk_kernel,
                         cudaFuncAttributeMaxDynamicSharedMemorySize, GEMM_SMEM);

    // ---- transpose + bf16-split all weights ----
    {
        dim3 blk(32, 8);
        wsplit_t_kernel<<<dim3(D_MODEL / 32, D_MODEL / 32, NLAYER), blk>>>(
            Wq, pwh + WQ_OFF, pwl + WQ_OFF, D_MODEL, D_MODEL);
        wsplit_t_kernel<<<dim3(D_MODEL / 32, D_MODEL / 32, NLAYER), blk>>>(
            Wk, pwh + WK_OFF, pwl + WK_OFF, D_MODEL, D_MODEL);
        wsplit_t_kernel<<<dim3(D_MODEL / 32, D_MODEL / 32, NLAYER), blk>>>(
            Wv, pwh + WV_OFF, pwl + WV_OFF, D_MODEL, D_MODEL);
        wsplit_t_kernel<<<dim3(FF_DIM / 32, D_MODEL / 32, NLAYER), blk>>>(
            W1, pwh + W1_OFF, pwl + W1_OFF, D_MODEL, FF_DIM);
        wsplit_t_kernel<<<dim3(D_MODEL / 32, FF_DIM / 32, NLAYER), blk>>>(
            W2, pwh + W2_OFF, pwl + W2_OFF, FF_DIM, D_MODEL);
    }

    add_pos_kernel<<<(M_ROWS * D_MODEL + 255) / 256, 256>>>(src, pos, px);

    for (int l = 0; l < NLAYER; l++) {
        long wqkv = (long)l * D_MODEL * D_MODEL;
        long wff1 = (long)l * D_MODEL * FF_DIM;
        long wff2 = (long)l * FF_DIM * D_MODEL;

        // attention block
        layernorm_split_kernel<<<M_ROWS, 128>>>(px, ln1_g + l * D_MODEL, ln1_b + l * D_MODEL,
                                                pxnh, pxnl);
        qkv_gemm_kernel<<<dim3(D_MODEL / BN, M_ROWS / BM, 3), 256, GEMM_SMEM>>>(
            pxnh, pxnl, pwh + WQ_OFF + wqkv, pwl + WQ_OFF + wqkv,
            bq + l * D_MODEL, bk + l * D_MODEL, bv + l * D_MODEL,
            pqh, pql, pkh, pkl, pvth, pvtl);
        attention_bf16_kernel<<<dim3(BATCH * NHEAD, S_LEN / 128), 256, ATT_SMEM>>>(
            pqh, pql, pkh, pkl, pvth, pvtl, px);

        // feed-forward block
        layernorm_split_kernel<<<M_ROWS, 128>>>(px, ln2_g + l * D_MODEL, ln2_b + l * D_MODEL,
                                                pxnh, pxnl);
        ff1_gemm_kernel<<<dim3(FF_DIM / BN, M_ROWS / BM), 256, GEMM_SMEM>>>(
            pxnh, pxnl, pwh + W1_OFF + wff1, pwl + W1_OFF + wff1, b1 + l * FF_DIM,
            phh, phl);
        ff2_splitk_kernel<<<dim3(D_MODEL / BN, M_ROWS / BM, 2), 256, GEMM_SMEM>>>(
            phh, phl, pwh + W2_OFF + wff2, pwl + W2_OFF + wff2, pp0, pp1);
        ff2_combine_kernel<<<(M_ROWS * D_MODEL / 4 + 255) / 256, 256>>>(
            pp0, pp1, b2 + l * D_MODEL, px);
    }

    final_ln_kernel<<<M_ROWS, 128>>>(px, lnf_g, lnf_b, out);
}

// round 10
// speedup vs baseline: 5.3962x; 1.3016x over previous
#include <cuda_runtime.h>
#include <cuda_fp16.h>
#include <math.h>
#include <stdint.h>

#define D_MODEL 512
#define FF_DIM  2048
#define S_LEN   1024
#define BATCH   4
#define NLAYER  6
#define NHEAD   8
#define DHEAD   64
#define M_ROWS  (S_LEN * BATCH)   // 4096 token rows

// weight layout inside g_wt (element offsets; arrays are transposed [N][K], fp16 hi only)
#define WQ_OFF 0
#define WK_OFF (NLAYER * D_MODEL * D_MODEL)
#define WV_OFF (2 * NLAYER * D_MODEL * D_MODEL)
#define W1_OFF (3 * NLAYER * D_MODEL * D_MODEL)
#define W2_OFF (W1_OFF + NLAYER * D_MODEL * FF_DIM)
#define W_TOTAL (W2_OFF + NLAYER * FF_DIM * D_MODEL)

// ---------------- scratch (device globals; no runtime allocation) ----------------
__device__ float g_x [M_ROWS * D_MODEL];        // residual stream (B,S,D)
__device__ __half g_xn_h[M_ROWS * D_MODEL];     // layernorm out hi (fp16)
__device__ __half g_xn_l[M_ROWS * D_MODEL];     // layernorm out lo
__device__ __half g_qh[M_ROWS * D_MODEL];       // Q/8 hi (row-major)
__device__ __half g_ql[M_ROWS * D_MODEL];       // Q/8 lo
__device__ __half g_kh[M_ROWS * D_MODEL];       // K (single fp16, B-side)
__device__ __half g_vth[D_MODEL * M_ROWS];      // V TRANSPOSED [dh_col][token] (single fp16)
__device__ __half g_h_h[M_ROWS * FF_DIM];       // FF hidden hi
__device__ __half g_h_l[M_ROWS * FF_DIM];       // FF hidden lo
__device__ float g_p0[M_ROWS * D_MODEL];        // FF2 split-K partial 0
__device__ float g_p1[M_ROWS * D_MODEL];        // FF2 split-K partial 1
__device__ __half g_wt[W_TOTAL];                // weights transposed [N][K], fp16

// ---------------- helpers ----------------------------------------------------------
__device__ __forceinline__ void mma_fp16(float* d, const uint32_t* a, const uint32_t* b) {
    asm volatile(
        "mma.sync.aligned.m16n8k16.row.col.f32.f16.f16.f32 "
        "{%0,%1,%2,%3}, {%4,%5,%6,%7}, {%8,%9}, {%0,%1,%2,%3};"
        : "+f"(d[0]), "+f"(d[1]), "+f"(d[2]), "+f"(d[3])
        : "r"(a[0]), "r"(a[1]), "r"(a[2]), "r"(a[3]), "r"(b[0]), "r"(b[1]));
}

__device__ __forceinline__ void ldsm_x4(uint32_t* r, uint32_t addr) {
    asm volatile("ldmatrix.sync.aligned.m8n8.x4.shared.b16 {%0,%1,%2,%3}, [%4];"
                 : "=r"(r[0]), "=r"(r[1]), "=r"(r[2]), "=r"(r[3]) : "r"(addr));
}

__device__ __forceinline__ void split_fp16(float x, __half& hi, __half& lo) {
    hi = __float2half_rn(x);
    lo = __float2half_rn(x - __half2float(hi));
}

__device__ __forceinline__ void cp_async16(uint32_t dst, const void* src) {
    asm volatile("cp.async.ca.shared.global [%0], [%1], 16;" :: "r"(dst), "l"(src));
}
__device__ __forceinline__ void cp_commit() {
    asm volatile("cp.async.commit_group;");
}
template<int N>
__device__ __forceinline__ void cp_wait() {
    asm volatile("cp.async.wait_group %0;" :: "n"(N));
}
__device__ __forceinline__ uint32_t smem_u32(const void* p) {
    return (uint32_t)__cvta_generic_to_shared(p);
}

// ---------------- weight transpose + fp16: W[K][N] -> Wt[N][K] ---------------------
__global__ void wsplit_t_kernel(const float* __restrict__ src,
                                __half* __restrict__ oh,
                                int K, int N) {
    __shared__ float tile[32][33];
    int l = blockIdx.z;
    src += (long)l * K * N;
    oh  += (long)l * N * K;
    int n0 = blockIdx.x * 32, k0 = blockIdx.y * 32;
    int tx = threadIdx.x, ty = threadIdx.y;      // 32 x 8
    #pragma unroll
    for (int i = ty; i < 32; i += 8)
        tile[i][tx] = src[(long)(k0 + i) * N + n0 + tx];
    __syncthreads();
    #pragma unroll
    for (int i = ty; i < 32; i += 8) {
        float x = tile[tx][i];                   // src[k0+tx][n0+i]
        oh[(long)(n0 + i) * K + k0 + tx] = __float2half_rn(x);
    }
}

// ---------------- x = (src + pos) transposed (S,B,D) -> (B,S,D) ----------------
__global__ void add_pos_kernel(const float* __restrict__ src,
                               const float* __restrict__ pos,
                               float* __restrict__ x) {
    int idx = blockIdx.x * blockDim.x + threadIdx.x;
    if (idx >= M_ROWS * D_MODEL) return;
    int d = idx & (D_MODEL - 1);
    int m = idx >> 9;
    int b = m >> 10;
    int s = m & (S_LEN - 1);
    int src_i = ((s * BATCH + b) << 9) + d;
    x[idx] = src[src_i] + pos[src_i];
}

// ---------------- FF2 combine: x += p0 + p1 + bias --------------------------------
__global__ void ff2_combine_kernel(const float* __restrict__ p0,
                                   const float* __restrict__ p1,
                                   const float* __restrict__ bias,
                                   float* __restrict__ x) {
    int idx = blockIdx.x * blockDim.x + threadIdx.x;
    if (idx >= M_ROWS * D_MODEL / 4) return;
    float4 a = ((const float4*)p0)[idx];
    float4 b = ((const float4*)p1)[idx];
    float4 v = ((const float4*)x)[idx];
    int c = (idx & 127) * 4;
    float4 bb = *(const float4*)(bias + c);
    v.x += a.x + b.x + bb.x;
    v.y += a.y + b.y + bb.y;
    v.z += a.z + b.z + bb.z;
    v.w += a.w + b.w + bb.w;
    ((float4*)x)[idx] = v;
}

// ---------------- layernorm -> split fp16 hi/lo output ---------------------------
__global__ void layernorm_split_kernel(const float* __restrict__ x,
                                       const float* __restrict__ gamma,
                                       const float* __restrict__ beta,
                                       __half* __restrict__ yh,
                                       __half* __restrict__ yl) {
    int row = blockIdx.x;
    int tid = threadIdx.x;                 // 128
    const float4* xr = (const float4*)(x + row * D_MODEL);
    float4 v = xr[tid];
    float s  = v.x + v.y + v.z + v.w;
    float ss = v.x*v.x + v.y*v.y + v.z*v.z + v.w*v.w;
    #pragma unroll
    for (int o = 16; o > 0; o >>= 1) {
        s  += __shfl_down_sync(0xffffffffu, s,  o);
        ss += __shfl_down_sync(0xffffffffu, ss, o);
    }
    __shared__ float shs[4], shss[4];
    __shared__ float s_mean, s_inv;
    int w = tid >> 5, lane = tid & 31;
    if (lane == 0) { shs[w] = s; shss[w] = ss; }
    __syncthreads();
    if (tid == 0) {
        float ts  = shs[0] + shs[1] + shs[2] + shs[3];
        float tss = shss[0] + shss[1] + shss[2] + shss[3];
        float mean = ts * (1.0f / D_MODEL);
        float var  = tss * (1.0f / D_MODEL) - mean * mean;
        s_mean = mean;
        s_inv  = rsqrtf(var + 1e-5f);
    }
    __syncthreads();
    float mean = s_mean, inv = s_inv;
    int c = tid * 4;
    float4 g = *(const float4*)(gamma + c);
    float4 bb = *(const float4*)(beta + c);
    float o0 = (v.x - mean) * inv * g.x + bb.x;
    float o1 = (v.y - mean) * inv * g.y + bb.y;
    float o2 = (v.z - mean) * inv * g.z + bb.z;
    float o3 = (v.w - mean) * inv * g.w + bb.w;
    __half h0,l0,h1,l1,h2,l2,h3,l3;
    split_fp16(o0, h0, l0); split_fp16(o1, h1, l1);
    split_fp16(o2, h2, l2); split_fp16(o3, h3, l3);
    __half2* yh2 = (__half2*)(yh + row * D_MODEL);
    __half2* yl2 = (__half2*)(yl + row * D_MODEL);
    yh2[tid * 2]     = __halves2half2(h0, h1);
    yh2[tid * 2 + 1] = __halves2half2(h2, h3);
    yl2[tid * 2]     = __halves2half2(l0, l1);
    yl2[tid * 2 + 1] = __halves2half2(l2, l3);
}

// ---------------- final layernorm with transpose back to (S,B,D) ----------------
__global__ void final_ln_kernel(const float* __restrict__ x,
                                const float* __restrict__ gamma,
                                const float* __restrict__ beta,
                                float* __restrict__ out) {
    int row = blockIdx.x;
    int tid = threadIdx.x;
    const float4* xr = (const float4*)(x + row * D_MODEL);
    float4 v = xr[tid];
    float s  = v.x + v.y + v.z + v.w;
    float ss = v.x*v.x + v.y*v.y + v.z*v.z + v.w*v.w;
    #pragma unroll
    for (int o = 16; o > 0; o >>= 1) {
        s  += __shfl_down_sync(0xffffffffu, s,  o);
        ss += __shfl_down_sync(0xffffffffu, ss, o);
    }
    __shared__ float shs[4], shss[4];
    __shared__ float s_mean, s_inv;
    int w = tid >> 5, lane = tid & 31;
    if (lane == 0) { shs[w] = s; shss[w] = ss; }
    __syncthreads();
    if (tid == 0) {
        float ts  = shs[0] + shs[1] + shs[2] + shs[3];
        float tss = shss[0] + shss[1] + shss[2] + shss[3];
        float mean = ts * (1.0f / D_MODEL);
        float var  = tss * (1.0f / D_MODEL) - mean * mean;
        s_mean = mean;
        s_inv  = rsqrtf(var + 1e-5f);
    }
    __syncthreads();
    float mean = s_mean, inv = s_inv;
    int c = tid * 4;
    float4 g = *(const float4*)(gamma + c);
    float4 bb = *(const float4*)(beta + c);
    float4 o;
    o.x = (v.x - mean) * inv * g.x + bb.x;
    o.y = (v.y - mean) * inv * g.y + bb.y;
    o.z = (v.z - mean) * inv * g.z + bb.z;
    o.w = (v.w - mean) * inv * g.w + bb.w;
    int b = row >> 10;
    int ss_ = row & (S_LEN - 1);
    ((float4*)(out + ((ss_ * BATCH + b) << 9)))[tid] = o;
}

// ---------------- 2-term split-FP16 GEMM mainloop (m16n8k16 + ldmatrix) ------------
// C = (Ah + Al) @ Wh^T  (A split fp16, W single fp16). 128x128 tile, BK=32.
#define BM 128
#define BN 128
#define BK 32
#define SPAD 40                    // fp16 row stride: 80 B (conflict-free for LDSM)
#define TBUF (128 * SPAD)          // fp16 elems per buffer
#define BUFB (TBUF * 2)            // bytes per buffer
#define GEMM_SMEM (6 * TBUF * 2)   // 3 arrays x 2 buffers = 61440 bytes

__device__ __forceinline__ void gemm_mainloop(const __half* __restrict__ Ah,
                                              const __half* __restrict__ Al,
                                              const __half* __restrict__ Wh,
                                              int ldk, int kIters, float acc[2][8][4]) {
    extern __shared__ __half smh[];
    __half* Ash = smh;
    __half* Asl = Ash + 2 * TBUF;
    __half* Bsh = Asl + 2 * TBUF;

    int tid  = threadIdx.x;
    int lane = tid & 31;
    int warp = tid >> 5;
    int warpM = warp >> 1;
    int warpN = warp & 1;
    int rowBase = blockIdx.y * BM;
    int colBase = blockIdx.x * BN;

    int lm8  = lane & 7;
    int bit3 = (lane >> 3) & 1;
    int bit4 = lane >> 4;
    uint32_t aOff = (uint32_t)(warpM * 32 + lm8 + 8 * bit3) * 80u + (uint32_t)bit4 * 16u;
    uint32_t bOff = (uint32_t)(warpN * 64 + lm8 + 8 * bit4) * 80u + (uint32_t)bit3 * 16u;
    uint32_t baseAh = smem_u32(Ash) + aOff;
    uint32_t baseAl = smem_u32(Asl) + aOff;
    uint32_t baseBh = smem_u32(Bsh) + bOff;

    int r0c = tid >> 2;
    int o0c = (tid & 3) * 8;
    int r1c = (tid + 256) >> 2;
    const __half* Ag0 = Ah + (long)(rowBase + r0c) * ldk + o0c;
    const __half* Ag1 = Ah + (long)(rowBase + r1c) * ldk + o0c;
    const __half* Al0 = Al + (long)(rowBase + r0c) * ldk + o0c;
    const __half* Al1 = Al + (long)(rowBase + r1c) * ldk + o0c;
    const __half* Bg0 = Wh + (long)(colBase + r0c) * ldk + o0c;
    const __half* Bg1 = Wh + (long)(colBase + r1c) * ldk + o0c;
    uint32_t dA0 = smem_u32(&Ash[r0c * SPAD + o0c]);
    uint32_t dA1 = smem_u32(&Ash[r1c * SPAD + o0c]);
    uint32_t dAl0 = smem_u32(&Asl[r0c * SPAD + o0c]);
    uint32_t dAl1 = smem_u32(&Asl[r1c * SPAD + o0c]);
    uint32_t dB0 = smem_u32(&Bsh[r0c * SPAD + o0c]);
    uint32_t dB1 = smem_u32(&Bsh[r1c * SPAD + o0c]);

    cp_async16(dA0, Ag0);  cp_async16(dA1, Ag1);
    cp_async16(dAl0, Al0); cp_async16(dAl1, Al1);
    cp_async16(dB0, Bg0);  cp_async16(dB1, Bg1);
    cp_commit();

    for (int it = 0; it < kIters; it++) {
        int cur = it & 1;
        int nxt = cur ^ 1;
        if (it + 1 < kIters) {
            int ka = (it + 1) * BK;
            int bo = nxt * BUFB;
            cp_async16(dA0 + bo, Ag0 + ka);  cp_async16(dA1 + bo, Ag1 + ka);
            cp_async16(dAl0 + bo, Al0 + ka); cp_async16(dAl1 + bo, Al1 + ka);
            cp_async16(dB0 + bo, Bg0 + ka);  cp_async16(dB1 + bo, Bg1 + ka);
            cp_commit();
            cp_wait<1>();
        } else {
            cp_wait<0>();
        }
        __syncthreads();

        uint32_t cb = (uint32_t)(cur * BUFB);
        #pragma unroll
        for (int ks = 0; ks < 2; ks++) {
            uint32_t ko = cb + ks * 32;
            uint32_t ahi[2][4], alo[2][4];
            ldsm_x4(ahi[0], baseAh + ko);
            ldsm_x4(ahi[1], baseAh + ko + 16 * 80);
            ldsm_x4(alo[0], baseAl + ko);
            ldsm_x4(alo[1], baseAl + ko + 16 * 80);
            #pragma unroll
            for (int h = 0; h < 4; h++) {
                uint32_t bh[4];
                ldsm_x4(bh, baseBh + ko + h * (16 * 80));
                #pragma unroll
                for (int mi = 0; mi < 2; mi++) {
                    mma_fp16(acc[mi][2 * h],     ahi[mi], bh);
                    mma_fp16(acc[mi][2 * h],     alo[mi], bh);
                    mma_fp16(acc[mi][2 * h + 1], ahi[mi], bh + 2);
                    mma_fp16(acc[mi][2 * h + 1], alo[mi], bh + 2);
                }
            }
        }
        __syncthreads();
    }
}

// ---- FF1 GEMM: relu + split-fp16 epilogue ----
__global__ __launch_bounds__(256, 2)
void ff1_gemm_kernel(const __half* __restrict__ Ah, const __half* __restrict__ Al,
                     const __half* __restrict__ Wh,
                     const float* __restrict__ bias,
                     __half* __restrict__ Ch, __half* __restrict__ Cl) {
    float acc[2][8][4];
    #pragma unroll
    for (int mi = 0; mi < 2; mi++)
        #pragma unroll
        for (int nj = 0; nj < 8; nj++)
            #pragma unroll
            for (int r = 0; r < 4; r++) acc[mi][nj][r] = 0.0f;
    gemm_mainloop(Ah, Al, Wh, D_MODEL, D_MODEL / BK, acc);

    const int N = FF_DIM;
    int lane = threadIdx.x & 31, warp = threadIdx.x >> 5;
    int warpM = warp >> 1, warpN = warp & 1;
    int g = lane >> 2, t = lane & 3;
    int rowBase = blockIdx.y * BM, colBase = blockIdx.x * BN;
    #pragma unroll
    for (int mi = 0; mi < 2; mi++) {
        int r0 = rowBase + warpM * 32 + mi * 16 + g;
        #pragma unroll
        for (int nj = 0; nj < 8; nj++) {
            int c = colBase + warpN * 64 + nj * 8 + t * 2;
            float b0 = bias[c], b1 = bias[c + 1];
            float v0 = fmaxf(acc[mi][nj][0] + b0, 0.0f);
            float v1 = fmaxf(acc[mi][nj][1] + b1, 0.0f);
            float v2 = fmaxf(acc[mi][nj][2] + b0, 0.0f);
            float v3 = fmaxf(acc[mi][nj][3] + b1, 0.0f);
            long o0 = (long)r0 * N + c;
            long o1 = (long)(r0 + 8) * N + c;
            __half h0,l0,h1,l1,h2,l2,h3,l3;
            split_fp16(v0, h0, l0); split_fp16(v1, h1, l1);
            split_fp16(v2, h2, l2); split_fp16(v3, h3, l3);
            *(__half2*)(Ch + o0) = __halves2half2(h0, h1);
            *(__half2*)(Ch + o1) = __halves2half2(h2, h3);
            *(__half2*)(Cl + o0) = __halves2half2(l0, l1);
            *(__half2*)(Cl + o1) = __halves2half2(l2, l3);
        }
    }
}

// ---- FF2 GEMM split-K: z = K-half; writes fp32 partials ----
__global__ __launch_bounds__(256, 2)
void ff2_splitk_kernel(const __half* __restrict__ Ah, const __half* __restrict__ Al,
                       const __half* __restrict__ Wh,
                       float* __restrict__ p0, float* __restrict__ p1) {
    int z = blockIdx.z;
    int kOff = z * (FF_DIM / 2);
    float* P = z ? p1 : p0;

    float acc[2][8][4];
    #pragma unroll
    for (int mi = 0; mi < 2; mi++)
        #pragma unroll
        for (int nj = 0; nj < 8; nj++)
            #pragma unroll
            for (int r = 0; r < 4; r++) acc[mi][nj][r] = 0.0f;
    gemm_mainloop(Ah + kOff, Al + kOff, Wh + kOff, FF_DIM, (FF_DIM / 2) / BK, acc);

    const int N = D_MODEL;
    int lane = threadIdx.x & 31, warp = threadIdx.x >> 5;
    int warpM = warp >> 1, warpN = warp & 1;
    int g = lane >> 2, t = lane & 3;
    int rowBase = blockIdx.y * BM, colBase = blockIdx.x * BN;
    #pragma unroll
    for (int mi = 0; mi < 2; mi++) {
        int r0 = rowBase + warpM * 32 + mi * 16 + g;
        #pragma unroll
        for (int nj = 0; nj < 8; nj++) {
            int c = colBase + warpN * 64 + nj * 8 + t * 2;
            long o0 = (long)r0 * N + c;
            long o1 = (long)(r0 + 8) * N + c;
            P[o0] = acc[mi][nj][0]; P[o0 + 1] = acc[mi][nj][1];
            P[o1] = acc[mi][nj][2]; P[o1 + 1] = acc[mi][nj][3];
        }
    }
}

// ---- fused QKV GEMM: z=0 Q*0.125 split, z=1 K single, z=2 V single transposed ----
__global__ __launch_bounds__(256, 2)
void qkv_gemm_kernel(const __half* __restrict__ Ah, const __half* __restrict__ Al,
                     const __half* __restrict__ Wh_base,
                     const float* __restrict__ bq, const float* __restrict__ bk,
                     const float* __restrict__ bv,
                     __half* __restrict__ qh, __half* __restrict__ ql,
                     __half* __restrict__ kh, __half* __restrict__ vth) {
    int z = blockIdx.z;
    const __half* Wh = Wh_base + (long)z * (NLAYER * D_MODEL * D_MODEL);
    const float* bias = (z == 0) ? bq : (z == 1) ? bk : bv;

    float acc[2][8][4];
    #pragma unroll
    for (int mi = 0; mi < 2; mi++)
        #pragma unroll
        for (int nj = 0; nj < 8; nj++)
            #pragma unroll
            for (int r = 0; r < 4; r++) acc[mi][nj][r] = 0.0f;
    gemm_mainloop(Ah, Al, Wh, D_MODEL, D_MODEL / BK, acc);

    int lane = threadIdx.x & 31, warp = threadIdx.x >> 5;
    int warpM = warp >> 1, warpN = warp & 1;
    int g = lane >> 2, t = lane & 3;
    int rowBase = blockIdx.y * BM, colBase = blockIdx.x * BN;

    #pragma unroll
    for (int mi = 0; mi < 2; mi++) {
        int r0 = rowBase + warpM * 32 + mi * 16 + g;
        #pragma unroll
        for (int nj = 0; nj < 8; nj++) {
            int c = colBase + warpN * 64 + nj * 8 + t * 2;
            float b0 = bias[c], b1 = bias[c + 1];
            float v0 = acc[mi][nj][0] + b0;
            float v1 = acc[mi][nj][1] + b1;
            float v2 = acc[mi][nj][2] + b0;
            float v3 = acc[mi][nj][3] + b1;
            if (z == 0) {
                v0 *= 0.125f; v1 *= 0.125f; v2 *= 0.125f; v3 *= 0.125f;
                __half h0,l0,h1,l1,h2,l2,h3,l3;
                split_fp16(v0, h0, l0); split_fp16(v1, h1, l1);
                split_fp16(v2, h2, l2); split_fp16(v3, h3, l3);
                long o0 = (long)r0 * D_MODEL + c;
                long o1 = (long)(r0 + 8) * D_MODEL + c;
                *(__half2*)(qh + o0) = __halves2half2(h0, h1);
                *(__half2*)(qh + o1) = __halves2half2(h2, h3);
                *(__half2*)(ql + o0) = __halves2half2(l0, l1);
                *(__half2*)(ql + o1) = __halves2half2(l2, l3);
            } else if (z == 1) {
                long o0 = (long)r0 * D_MODEL + c;
                long o1 = (long)(r0 + 8) * D_MODEL + c;
                *(__half2*)(kh + o0) = __halves2half2(__float2half_rn(v0), __float2half_rn(v1));
                *(__half2*)(kh + o1) = __halves2half2(__float2half_rn(v2), __float2half_rn(v3));
            } else {
                long c0 = (long)c * M_ROWS, c1 = (long)(c + 1) * M_ROWS;
                vth[c0 + r0]     = __float2half_rn(v0);
                vth[c1 + r0]     = __float2half_rn(v1);
                vth[c0 + r0 + 8] = __float2half_rn(v2);
                vth[c1 + r0 + 8] = __float2half_rn(v3);
            }
        }
    }
}

// ---------------- 2-term split-fp16 flash attention (m16n8k16 + ldmatrix) ----------
// Q split (hi/lo), K single, V single, P split.
#define QPB 72   // fp16 row stride (144 B): conflict-free for LDSM
#define QPBB (QPB * 2)
#define ATT_SMEM ((2*128 + 64 + 64 + 2*128) * QPB * 2)   // 92160 B

__global__ __launch_bounds__(256, 2)
void attention_fp16_kernel(const __half* __restrict__ qh,
                           const __half* __restrict__ ql,
                           const __half* __restrict__ kh,
                           const __half* __restrict__ vth,
                           float* __restrict__ x) {
    extern __shared__ __half smh[];
    __half* Qh = smh;                    // [128][QPB]
    __half* Ql = Qh + 128 * QPB;
    __half* Kh = Ql + 128 * QPB;         // [64][QPB]
    __half* Vh = Kh + 64 * QPB;          // [64 dh][QPB keys]
    __half* Ph = Vh + 64 * QPB;          // [128][QPB]
    __half* Pl = Ph + 128 * QPB;

    int tid = threadIdx.x;
    int lane = tid & 31, warp = tid >> 5;
    int g = lane >> 2, t = lane & 3;
    int bh = blockIdx.x;
    int b = bh >> 3, h = bh & 7;
    int qt = blockIdx.y;
    int qr = warp * 16;

    int lm8  = lane & 7;
    int bit3 = (lane >> 3) & 1;
    int bit4 = lane >> 4;
    uint32_t aOff = (uint32_t)(qr + lm8 + 8 * bit3) * QPBB + (uint32_t)bit4 * 16u;
    uint32_t bOff = (uint32_t)(lm8 + 8 * bit4) * QPBB + (uint32_t)bit3 * 16u;
    uint32_t baseQh = smem_u32(Qh) + aOff;
    uint32_t baseQl = smem_u32(Ql) + aOff;
    uint32_t basePh = smem_u32(Ph) + aOff;
    uint32_t basePl = smem_u32(Pl) + aOff;
    uint32_t baseKh = smem_u32(Kh) + bOff;
    uint32_t baseVh = smem_u32(Vh) + bOff;

    // ---- stage Q (Qh, Ql: 2048 x 16B chunks) ----
    {
        long qbase = ((long)(b * S_LEN + qt * 128)) * D_MODEL + h * DHEAD;
        #pragma unroll
        for (int p = 0; p < 8; p++) {
            int id = p * 256 + tid;
            int arr = id >> 10;            // 0 = hi, 1 = lo
            int rem = id & 1023;
            int row = rem >> 3, ck = rem & 7;
            const __half* src = (arr ? ql : qh) + qbase + (long)row * D_MODEL + ck * 8;
            uint32_t dst = smem_u32(&(arr ? Ql : Qh)[row * QPB + ck * 8]);
            cp_async16(dst, src);
        }
        cp_commit();
    }

    float o[8][4];
    #pragma unroll
    for (int j = 0; j < 8; j++)
        #pragma unroll
        for (int r = 0; r < 4; r++) o[j][r] = 0.0f;
    float m0 = -1e30f, m1 = -1e30f, l0s = 0.0f, l1s = 0.0f;

    for (int kt = 0; kt < S_LEN / 64; kt++) {
        __syncthreads();
        // ---- stage K + Vt (1024 chunks) ----
        {
            long kbase = ((long)(b * S_LEN + kt * 64)) * D_MODEL + h * DHEAD;
            long vcol  = (long)b * S_LEN + kt * 64;
            #pragma unroll
            for (int p = 0; p < 4; p++) {
                int id = p * 256 + tid;
                int arr = id >> 9;         // 0=Kh 1=Vh
                int rem = id & 511;
                int row = rem >> 3, ck = rem & 7;
                const __half* src;
                uint32_t dst;
                if (arr == 0) {
                    src = kh + kbase + (long)row * D_MODEL + ck * 8;
                    dst = smem_u32(&Kh[row * QPB + ck * 8]);
                } else {
                    src = vth + (long)(h * DHEAD + row) * M_ROWS + vcol + ck * 8;
                    dst = smem_u32(&Vh[row * QPB + ck * 8]);
                }
                cp_async16(dst, src);
            }
            cp_commit();
        }
        cp_wait<0>();
        __syncthreads();

        // ---- S = (Q/8) @ K^T : 2-term ----
        float s[8][4];
        #pragma unroll
        for (int j = 0; j < 8; j++)
            #pragma unroll
            for (int r = 0; r < 4; r++) s[j][r] = 0.0f;

        #pragma unroll
        for (int ks = 0; ks < 4; ks++) {
            uint32_t ko = ks * 32;
            uint32_t a_h[4], a_l[4];
            ldsm_x4(a_h, baseQh + ko);
            ldsm_x4(a_l, baseQl + ko);
            #pragma unroll
            for (int h4 = 0; h4 < 4; h4++) {
                uint32_t b_h[4];
                ldsm_x4(b_h, baseKh + ko + h4 * (16 * QPBB));
                mma_fp16(s[2 * h4],     a_h, b_h);
                mma_fp16(s[2 * h4],     a_l, b_h);
                mma_fp16(s[2 * h4 + 1], a_h, b_h + 2);
                mma_fp16(s[2 * h4 + 1], a_l, b_h + 2);
            }
        }

        // ---- online softmax (warp-local rows) ----
        float mx0 = -1e30f, mx1 = -1e30f;
        #pragma unroll
        for (int j = 0; j < 8; j++) {
            mx0 = fmaxf(mx0, fmaxf(s[j][0], s[j][1]));
            mx1 = fmaxf(mx1, fmaxf(s[j][2], s[j][3]));
        }
        mx0 = fmaxf(mx0, __shfl_xor_sync(0xffffffffu, mx0, 1));
        mx0 = fmaxf(mx0, __shfl_xor_sync(0xffffffffu, mx0, 2));
        mx1 = fmaxf(mx1, __shfl_xor_sync(0xffffffffu, mx1, 1));
        mx1 = fmaxf(mx1, __shfl_xor_sync(0xffffffffu, mx1, 2));
        float mn0 = fmaxf(m0, mx0), mn1 = fmaxf(m1, mx1);
        float c0 = __expf(m0 - mn0), c1 = __expf(m1 - mn1);
        l0s *= c0; l1s *= c1;
        #pragma unroll
        for (int j = 0; j < 8; j++) {
            float p0 = __expf(s[j][0] - mn0);
            float p1 = __expf(s[j][1] - mn0);
            float p2 = __expf(s[j][2] - mn1);
            float p3 = __expf(s[j][3] - mn1);
            l0s += p0 + p1; l1s += p2 + p3;
            __half h0,lo0,h1,lo1,h2,lo2,h3,lo3;
            split_fp16(p0, h0, lo0); split_fp16(p1, h1, lo1);
            split_fp16(p2, h2, lo2); split_fp16(p3, h3, lo3);
            int cc = j * 8 + 2 * t;
            *(__half2*)&Ph[(qr + g) * QPB + cc]     = __halves2half2(h0, h1);
            *(__half2*)&Ph[(qr + g + 8) * QPB + cc] = __halves2half2(h2, h3);
            *(__half2*)&Pl[(qr + g) * QPB + cc]     = __halves2half2(lo0, lo1);
            *(__half2*)&Pl[(qr + g + 8) * QPB + cc] = __halves2half2(lo2, lo3);
            o[j][0] *= c0; o[j][1] *= c0; o[j][2] *= c1; o[j][3] *= c1;
        }
        m0 = mn0; m1 = mn1;
        __syncwarp();

        // ---- O += P @ V : 2-term ----
        #pragma unroll
        for (int ks = 0; ks < 4; ks++) {
            uint32_t ko = ks * 32;
            uint32_t p_h[4], p_l[4];
            ldsm_x4(p_h, basePh + ko);
            ldsm_x4(p_l, basePl + ko);
            #pragma unroll
            for (int h4 = 0; h4 < 4; h4++) {
                uint32_t b_h[4];
                ldsm_x4(b_h, baseVh + ko + h4 * (16 * QPBB));
                mma_fp16(o[2 * h4],     p_h, b_h);
                mma_fp16(o[2 * h4],     p_l, b_h);
                mma_fp16(o[2 * h4 + 1], p_h, b_h + 2);
                mma_fp16(o[2 * h4 + 1], p_l, b_h + 2);
            }
        }
    }

    // ---- finalize: x += O / l ----
    l0s += __shfl_xor_sync(0xffffffffu, l0s, 1);
    l0s += __shfl_xor_sync(0xffffffffu, l0s, 2);
    l1s += __shfl_xor_sync(0xffffffffu, l1s, 1);
    l1s += __shfl_xor_sync(0xffffffffu, l1s, 2);
    float i0 = 1.0f / l0s, i1 = 1.0f / l1s;

    float* xr0 = x + ((long)(b * S_LEN + qt * 128 + qr + g)     << 9) + h * DHEAD;
    float* xr1 = x + ((long)(b * S_LEN + qt * 128 + qr + g + 8) << 9) + h * DHEAD;
    #pragma unroll
    for (int j = 0; j < 8; j++) {
        int cc = j * 8 + 2 * t;
        float2 r0 = *(float2*)(xr0 + cc);
        r0.x += o[j][0] * i0; r0.y += o[j][1] * i0;
        *(float2*)(xr0 + cc) = r0;
        float2 r1 = *(float2*)(xr1 + cc);
        r1.x += o[j][2] * i1; r1.y += o[j][3] * i1;
        *(float2*)(xr1 + cc) = r1;
    }
}

// ---------------- host orchestration --------------------------------------------
extern "C" void kernel_launch(void* const* d_in, const int* in_sizes, int n_in,
                              void* d_out, int out_size) {
    const float* src   = (const float*)d_in[0];
    const float* pos   = (const float*)d_in[1];
    const float* Wq    = (const float*)d_in[2];
    const float* bq    = (const float*)d_in[3];
    const float* Wk    = (const float*)d_in[4];
    const float* bk    = (const float*)d_in[5];
    const float* Wv    = (const float*)d_in[6];
    const float* bv    = (const float*)d_in[7];
    const float* W1    = (const float*)d_in[8];
    const float* b1    = (const float*)d_in[9];
    const float* W2    = (const float*)d_in[10];
    const float* b2    = (const float*)d_in[11];
    const float* ln1_g = (const float*)d_in[12];
    const float* ln1_b = (const float*)d_in[13];
    const float* ln2_g = (const float*)d_in[14];
    const float* ln2_b = (const float*)d_in[15];
    const float* lnf_g = (const float*)d_in[16];
    const float* lnf_b = (const float*)d_in[17];
    float* out = (float*)d_out;

    float *px, *pp0, *pp1;
    __half *pxnh, *pxnl, *pqh, *pql, *pkh, *pvth, *phh, *phl, *pwt;
    cudaGetSymbolAddress((void**)&px,   g_x);
    cudaGetSymbolAddress((void**)&pp0,  g_p0);
    cudaGetSymbolAddress((void**)&pp1,  g_p1);
    cudaGetSymbolAddress((void**)&pxnh, g_xn_h);
    cudaGetSymbolAddress((void**)&pxnl, g_xn_l);
    cudaGetSymbolAddress((void**)&pqh,  g_qh);
    cudaGetSymbolAddress((void**)&pql,  g_ql);
    cudaGetSymbolAddress((void**)&pkh,  g_kh);
    cudaGetSymbolAddress((void**)&pvth, g_vth);
    cudaGetSymbolAddress((void**)&phh,  g_h_h);
    cudaGetSymbolAddress((void**)&phl,  g_h_l);
    cudaGetSymbolAddress((void**)&pwt,  g_wt);

    cudaFuncSetAttribute(attention_fp16_kernel,
                         cudaFuncAttributeMaxDynamicSharedMemorySize, ATT_SMEM);
    cudaFuncSetAttribute(qkv_gemm_kernel,
                         cudaFuncAttributeMaxDynamicSharedMemorySize, GEMM_SMEM);
    cudaFuncSetAttribute(ff1_gemm_kernel,
                         cudaFuncAttributeMaxDynamicSharedMemorySize, GEMM_SMEM);
    cudaFuncSetAttribute(ff2_splitk_kernel,
                         cudaFuncAttributeMaxDynamicSharedMemorySize, GEMM_SMEM);

    // ---- transpose + fp16 all weights: W[K][N] -> Wt[N][K] ----
    {
        dim3 blk(32, 8);
        wsplit_t_kernel<<<dim3(D_MODEL / 32, D_MODEL / 32, NLAYER), blk>>>(
            Wq, pwt + WQ_OFF, D_MODEL, D_MODEL);
        wsplit_t_kernel<<<dim3(D_MODEL / 32, D_MODEL / 32, NLAYER), blk>>>(
            Wk, pwt + WK_OFF, D_MODEL, D_MODEL);
        wsplit_t_kernel<<<dim3(D_MODEL / 32, D_MODEL / 32, NLAYER), blk>>>(
            Wv, pwt + WV_OFF, D_MODEL, D_MODEL);
        wsplit_t_kernel<<<dim3(FF_DIM / 32, D_MODEL / 32, NLAYER), blk>>>(
            W1, pwt + W1_OFF, D_MODEL, FF_DIM);
        wsplit_t_kernel<<<dim3(D_MODEL / 32, FF_DIM / 32, NLAYER), blk>>>(
            W2, pwt + W2_OFF, FF_DIM, D_MODEL);
    }

    add_pos_kernel<<<(M_ROWS * D_MODEL + 255) / 256, 256>>>(src, pos, px);

    for (int l = 0; l < NLAYER; l++) {
        long wqkv = (long)l * D_MODEL * D_MODEL;
        long wff1 = (long)l * D_MODEL * FF_DIM;
        long wff2 = (long)l * FF_DIM * D_MODEL;

        // attention block
        layernorm_split_kernel<<<M_ROWS, 128>>>(px, ln1_g + l * D_MODEL, ln1_b + l * D_MODEL,
                                                pxnh, pxnl);
        qkv_gemm_kernel<<<dim3(D_MODEL / BN, M_ROWS / BM, 3), 256, GEMM_SMEM>>>(
            pxnh, pxnl, pwt + WQ_OFF + wqkv,
            bq + l * D_MODEL, bk + l * D_MODEL, bv + l * D_MODEL,
            pqh, pql, pkh, pvth);
        attention_fp16_kernel<<<dim3(BATCH * NHEAD, S_LEN / 128), 256, ATT_SMEM>>>(
            pqh, pql, pkh, pvth, px);

        // feed-forward block
        layernorm_split_kernel<<<M_ROWS, 128>>>(px, ln2_g + l * D_MODEL, ln2_b + l * D_MODEL,
                                                pxnh, pxnl);
        ff1_gemm_kernel<<<dim3(FF_DIM / BN, M_ROWS / BM), 256, GEMM_SMEM>>>(
            pxnh, pxnl, pwt + W1_OFF + wff1, b1 + l * FF_DIM, phh, phl);
        ff2_splitk_kernel<<<dim3(D_MODEL / BN, M_ROWS / BM, 2), 256, GEMM_SMEM>>>(
            phh, phl, pwt + W2_OFF + wff2, pp0, pp1);
        ff2_combine_kernel<<<(M_ROWS * D_MODEL / 4 + 255) / 256, 256>>>(
            pp0, pp1, b2 + l * D_MODEL, px);
    }

    final_ln_kernel<<<M_ROWS, 128>>>(px, lnf_g, lnf_b, out);
}

// round 11
// speedup vs baseline: 5.9464x; 1.1020x over previous
#include <cuda_runtime.h>
#include <cuda_fp16.h>
#include <math.h>
#include <stdint.h>

#define D_MODEL 512
#define FF_DIM  2048
#define S_LEN   1024
#define BATCH   4
#define NLAYER  6
#define NHEAD   8
#define DHEAD   64
#define M_ROWS  (S_LEN * BATCH)   // 4096 token rows

// weight layout inside g_wt (element offsets; arrays are transposed [N][K], fp16)
#define WQ_OFF 0
#define WK_OFF (NLAYER * D_MODEL * D_MODEL)
#define WV_OFF (2 * NLAYER * D_MODEL * D_MODEL)
#define W1_OFF (3 * NLAYER * D_MODEL * D_MODEL)
#define W2_OFF (W1_OFF + NLAYER * D_MODEL * FF_DIM)
#define W_TOTAL (W2_OFF + NLAYER * FF_DIM * D_MODEL)

// ---------------- scratch (device globals; no runtime allocation) ----------------
__device__ float g_x [M_ROWS * D_MODEL];        // residual stream (B,S,D)
__device__ __half g_xn_h[M_ROWS * D_MODEL];     // layernorm out hi (fp16)
__device__ __half g_xn_l[M_ROWS * D_MODEL];     // layernorm out lo
__device__ __half g_qh[M_ROWS * D_MODEL];       // Q/8 hi (row-major)
__device__ __half g_ql[M_ROWS * D_MODEL];       // Q/8 lo
__device__ __half g_kh[M_ROWS * D_MODEL];       // K (single fp16, B-side)
__device__ __half g_vth[D_MODEL * M_ROWS];      // V TRANSPOSED [dh_col][token]
__device__ __half g_h_h[M_ROWS * FF_DIM];       // FF hidden hi
__device__ __half g_h_l[M_ROWS * FF_DIM];       // FF hidden lo
__device__ float g_p0[M_ROWS * D_MODEL];        // FF2 split-K partial 0
__device__ float g_p1[M_ROWS * D_MODEL];        // FF2 split-K partial 1
__device__ __half g_wt[W_TOTAL];                // weights transposed [N][K], fp16

// ---------------- helpers ----------------------------------------------------------
__device__ __forceinline__ void mma_fp16(float* d, const uint32_t* a, const uint32_t* b) {
    asm volatile(
        "mma.sync.aligned.m16n8k16.row.col.f32.f16.f16.f32 "
        "{%0,%1,%2,%3}, {%4,%5,%6,%7}, {%8,%9}, {%0,%1,%2,%3};"
        : "+f"(d[0]), "+f"(d[1]), "+f"(d[2]), "+f"(d[3])
        : "r"(a[0]), "r"(a[1]), "r"(a[2]), "r"(a[3]), "r"(b[0]), "r"(b[1]));
}

__device__ __forceinline__ void ldsm_x4(uint32_t* r, uint32_t addr) {
    asm volatile("ldmatrix.sync.aligned.m8n8.x4.shared.b16 {%0,%1,%2,%3}, [%4];"
                 : "=r"(r[0]), "=r"(r[1]), "=r"(r[2]), "=r"(r[3]) : "r"(addr));
}

__device__ __forceinline__ void split_fp16(float x, __half& hi, __half& lo) {
    hi = __float2half_rn(x);
    lo = __float2half_rn(x - __half2float(hi));
}

__device__ __forceinline__ void cp_async16(uint32_t dst, const void* src) {
    asm volatile("cp.async.ca.shared.global [%0], [%1], 16;" :: "r"(dst), "l"(src));
}
__device__ __forceinline__ void cp_commit() {
    asm volatile("cp.async.commit_group;");
}
template<int N>
__device__ __forceinline__ void cp_wait() {
    asm volatile("cp.async.wait_group %0;" :: "n"(N));
}
__device__ __forceinline__ uint32_t smem_u32(const void* p) {
    return (uint32_t)__cvta_generic_to_shared(p);
}

// ---------------- weight transpose + fp16: W[K][N] -> Wt[N][K] ---------------------
__global__ void wsplit_t_kernel(const float* __restrict__ src,
                                __half* __restrict__ oh,
                                int K, int N) {
    __shared__ float tile[32][33];
    int l = blockIdx.z;
    src += (long)l * K * N;
    oh  += (long)l * N * K;
    int n0 = blockIdx.x * 32, k0 = blockIdx.y * 32;
    int tx = threadIdx.x, ty = threadIdx.y;      // 32 x 8
    #pragma unroll
    for (int i = ty; i < 32; i += 8)
        tile[i][tx] = src[(long)(k0 + i) * N + n0 + tx];
    __syncthreads();
    #pragma unroll
    for (int i = ty; i < 32; i += 8) {
        float x = tile[tx][i];                   // src[k0+tx][n0+i]
        oh[(long)(n0 + i) * K + k0 + tx] = __float2half_rn(x);
    }
}

// ---------------- x = (src + pos) transposed (S,B,D) -> (B,S,D) ----------------
__global__ void add_pos_kernel(const float* __restrict__ src,
                               const float* __restrict__ pos,
                               float* __restrict__ x) {
    int idx = blockIdx.x * blockDim.x + threadIdx.x;
    if (idx >= M_ROWS * D_MODEL) return;
    int d = idx & (D_MODEL - 1);
    int m = idx >> 9;
    int b = m >> 10;
    int s = m & (S_LEN - 1);
    int src_i = ((s * BATCH + b) << 9) + d;
    x[idx] = src[src_i] + pos[src_i];
}

// ---------------- LN core (per-row block of 128 threads; v in registers) -----------
__device__ __forceinline__ void ln_stats(float4 v, float& mean, float& inv) {
    float s  = v.x + v.y + v.z + v.w;
    float ss = v.x*v.x + v.y*v.y + v.z*v.z + v.w*v.w;
    #pragma unroll
    for (int o = 16; o > 0; o >>= 1) {
        s  += __shfl_down_sync(0xffffffffu, s,  o);
        ss += __shfl_down_sync(0xffffffffu, ss, o);
    }
    __shared__ float shs[4], shss[4];
    __shared__ float s_mean, s_inv;
    int tid = threadIdx.x;
    int w = tid >> 5, lane = tid & 31;
    if (lane == 0) { shs[w] = s; shss[w] = ss; }
    __syncthreads();
    if (tid == 0) {
        float ts  = shs[0] + shs[1] + shs[2] + shs[3];
        float tss = shss[0] + shss[1] + shss[2] + shss[3];
        float m = ts * (1.0f / D_MODEL);
        float var = tss * (1.0f / D_MODEL) - m * m;
        s_mean = m;
        s_inv  = rsqrtf(var + 1e-5f);
    }
    __syncthreads();
    mean = s_mean; inv = s_inv;
}

__device__ __forceinline__ void ln_emit_split(float4 v, float mean, float inv,
                                              const float* gamma, const float* beta,
                                              __half* yh, __half* yl, int row) {
    int tid = threadIdx.x;
    int c = tid * 4;
    float4 g = *(const float4*)(gamma + c);
    float4 bb = *(const float4*)(beta + c);
    float o0 = (v.x - mean) * inv * g.x + bb.x;
    float o1 = (v.y - mean) * inv * g.y + bb.y;
    float o2 = (v.z - mean) * inv * g.z + bb.z;
    float o3 = (v.w - mean) * inv * g.w + bb.w;
    __half h0,l0,h1,l1,h2,l2,h3,l3;
    split_fp16(o0, h0, l0); split_fp16(o1, h1, l1);
    split_fp16(o2, h2, l2); split_fp16(o3, h3, l3);
    __half2* yh2 = (__half2*)(yh + row * D_MODEL);
    __half2* yl2 = (__half2*)(yl + row * D_MODEL);
    yh2[tid * 2]     = __halves2half2(h0, h1);
    yh2[tid * 2 + 1] = __halves2half2(h2, h3);
    yl2[tid * 2]     = __halves2half2(l0, l1);
    yl2[tid * 2 + 1] = __halves2half2(l2, l3);
}

// ---------------- layernorm -> split fp16 (standalone, for LN1(l=0) and LN2) ------
__global__ void layernorm_split_kernel(const float* __restrict__ x,
                                       const float* __restrict__ gamma,
                                       const float* __restrict__ beta,
                                       __half* __restrict__ yh,
                                       __half* __restrict__ yl) {
    int row = blockIdx.x;
    int tid = threadIdx.x;
    float4 v = ((const float4*)(x + row * D_MODEL))[tid];
    float mean, inv;
    ln_stats(v, mean, inv);
    ln_emit_split(v, mean, inv, gamma, beta, yh, yl, row);
}

// ---------------- fused FF2-combine + next-layer LN1 ------------------------------
__global__ void combine_ln_kernel(const float* __restrict__ p0,
                                  const float* __restrict__ p1,
                                  const float* __restrict__ bias,
                                  float* __restrict__ x,
                                  const float* __restrict__ gamma,
                                  const float* __restrict__ beta,
                                  __half* __restrict__ yh,
                                  __half* __restrict__ yl) {
    int row = blockIdx.x;
    int tid = threadIdx.x;
    int idx = row * 128 + tid;
    float4 a = ((const float4*)p0)[idx];
    float4 b = ((const float4*)p1)[idx];
    float4 v = ((const float4*)x)[idx];
    float4 bb = *(const float4*)(bias + tid * 4);
    v.x += a.x + b.x + bb.x;
    v.y += a.y + b.y + bb.y;
    v.z += a.z + b.z + bb.z;
    v.w += a.w + b.w + bb.w;
    ((float4*)x)[idx] = v;
    float mean, inv;
    ln_stats(v, mean, inv);
    ln_emit_split(v, mean, inv, gamma, beta, yh, yl, row);
}

// ---------------- fused FF2-combine + FINAL LN (transpose back to (S,B,D)) --------
__global__ void combine_final_kernel(const float* __restrict__ p0,
                                     const float* __restrict__ p1,
                                     const float* __restrict__ bias,
                                     const float* __restrict__ x,
                                     const float* __restrict__ gamma,
                                     const float* __restrict__ beta,
                                     float* __restrict__ out) {
    int row = blockIdx.x;                  // b*S + s
    int tid = threadIdx.x;
    int idx = row * 128 + tid;
    float4 a = ((const float4*)p0)[idx];
    float4 b = ((const float4*)p1)[idx];
    float4 v = ((const float4*)x)[idx];
    float4 bb = *(const float4*)(bias + tid * 4);
    v.x += a.x + b.x + bb.x;
    v.y += a.y + b.y + bb.y;
    v.z += a.z + b.z + bb.z;
    v.w += a.w + b.w + bb.w;
    float mean, inv;
    ln_stats(v, mean, inv);
    int c = tid * 4;
    float4 g = *(const float4*)(gamma + c);
    float4 be = *(const float4*)(beta + c);
    float4 o;
    o.x = (v.x - mean) * inv * g.x + be.x;
    o.y = (v.y - mean) * inv * g.y + be.y;
    o.z = (v.z - mean) * inv * g.z + be.z;
    o.w = (v.w - mean) * inv * g.w + be.w;
    int bb_ = row >> 10;
    int ss_ = row & (S_LEN - 1);
    ((float4*)(out + ((ss_ * BATCH + bb_) << 9)))[tid] = o;
}

// ---------------- 2-term split-FP16 GEMM mainloop (m16n8k16 + ldmatrix, BK=64) -----
#define BM 128
#define BN 128
#define BK 64
#define SPAD 72                    // fp16 row stride: 144 B (conflict-free for LDSM)
#define TBUF (128 * SPAD)          // fp16 elems per buffer
#define BUFB (TBUF * 2)            // bytes per buffer
#define GEMM_SMEM (6 * TBUF * 2)   // 3 arrays x 2 buffers = 110592 bytes

__device__ __forceinline__ void gemm_mainloop(const __half* __restrict__ Ah,
                                              const __half* __restrict__ Al,
                                              const __half* __restrict__ Wh,
                                              int ldk, int kIters, float acc[2][8][4]) {
    extern __shared__ __half smh[];
    __half* Ash = smh;
    __half* Asl = Ash + 2 * TBUF;
    __half* Bsh = Asl + 2 * TBUF;

    int tid  = threadIdx.x;
    int lane = tid & 31;
    int warp = tid >> 5;
    int warpM = warp >> 1;
    int warpN = warp & 1;
    int rowBase = blockIdx.y * BM;
    int colBase = blockIdx.x * BN;

    int lm8  = lane & 7;
    int bit3 = (lane >> 3) & 1;
    int bit4 = lane >> 4;
    uint32_t aOff = (uint32_t)(warpM * 32 + lm8 + 8 * bit3) * 144u + (uint32_t)bit4 * 16u;
    uint32_t bOff = (uint32_t)(warpN * 64 + lm8 + 8 * bit4) * 144u + (uint32_t)bit3 * 16u;
    uint32_t baseAh = smem_u32(Ash) + aOff;
    uint32_t baseAl = smem_u32(Asl) + aOff;
    uint32_t baseBh = smem_u32(Bsh) + bOff;

    // staging: 1024 x 16B chunks per array; thread does 4 chunks per array
    int r0c = tid >> 3;                // rows 0..31 (+32 per pass)
    int o0c = (tid & 7) * 8;           // fp16 offset within 64
    const __half* Ag = Ah + (long)(rowBase + r0c) * ldk + o0c;
    const __half* Alg = Al + (long)(rowBase + r0c) * ldk + o0c;
    const __half* Bg = Wh + (long)(colBase + r0c) * ldk + o0c;
    uint32_t dA = smem_u32(&Ash[r0c * SPAD + o0c]);
    uint32_t dAl = smem_u32(&Asl[r0c * SPAD + o0c]);
    uint32_t dB = smem_u32(&Bsh[r0c * SPAD + o0c]);
    const uint32_t rstep = 32u * SPAD * 2u;       // 32 rows in bytes
    const long gstep = 32l * ldk;

    #pragma unroll
    for (int p = 0; p < 4; p++) {
        cp_async16(dA + p * rstep, Ag + p * gstep);
        cp_async16(dAl + p * rstep, Alg + p * gstep);
        cp_async16(dB + p * rstep, Bg + p * gstep);
    }
    cp_commit();

    for (int it = 0; it < kIters; it++) {
        int cur = it & 1;
        int nxt = cur ^ 1;
        if (it + 1 < kIters) {
            int ka = (it + 1) * BK;
            uint32_t bo = (uint32_t)(nxt * BUFB);
            #pragma unroll
            for (int p = 0; p < 4; p++) {
                cp_async16(dA + bo + p * rstep, Ag + ka + p * gstep);
                cp_async16(dAl + bo + p * rstep, Alg + ka + p * gstep);
                cp_async16(dB + bo + p * rstep, Bg + ka + p * gstep);
            }
            cp_commit();
            cp_wait<1>();
        } else {
            cp_wait<0>();
        }
        __syncthreads();

        uint32_t cb = (uint32_t)(cur * BUFB);
        #pragma unroll
        for (int ks = 0; ks < 4; ks++) {
            uint32_t ko = cb + ks * 32;
            uint32_t ahi[2][4], alo[2][4];
            ldsm_x4(ahi[0], baseAh + ko);
            ldsm_x4(ahi[1], baseAh + ko + 16 * 144);
            ldsm_x4(alo[0], baseAl + ko);
            ldsm_x4(alo[1], baseAl + ko + 16 * 144);
            #pragma unroll
            for (int h = 0; h < 4; h++) {
                uint32_t bh[4];
                ldsm_x4(bh, baseBh + ko + h * (16 * 144));
                #pragma unroll
                for (int mi = 0; mi < 2; mi++) {
                    mma_fp16(acc[mi][2 * h],     ahi[mi], bh);
                    mma_fp16(acc[mi][2 * h],     alo[mi], bh);
                    mma_fp16(acc[mi][2 * h + 1], ahi[mi], bh + 2);
                    mma_fp16(acc[mi][2 * h + 1], alo[mi], bh + 2);
                }
            }
        }
        __syncthreads();
    }
}

// ---- FF1 GEMM: relu + split-fp16 epilogue ----
__global__ __launch_bounds__(256, 2)
void ff1_gemm_kernel(const __half* __restrict__ Ah, const __half* __restrict__ Al,
                     const __half* __restrict__ Wh,
                     const float* __restrict__ bias,
                     __half* __restrict__ Ch, __half* __restrict__ Cl) {
    float acc[2][8][4];
    #pragma unroll
    for (int mi = 0; mi < 2; mi++)
        #pragma unroll
        for (int nj = 0; nj < 8; nj++)
            #pragma unroll
            for (int r = 0; r < 4; r++) acc[mi][nj][r] = 0.0f;
    gemm_mainloop(Ah, Al, Wh, D_MODEL, D_MODEL / BK, acc);

    const int N = FF_DIM;
    int lane = threadIdx.x & 31, warp = threadIdx.x >> 5;
    int warpM = warp >> 1, warpN = warp & 1;
    int g = lane >> 2, t = lane & 3;
    int rowBase = blockIdx.y * BM, colBase = blockIdx.x * BN;
    #pragma unroll
    for (int mi = 0; mi < 2; mi++) {
        int r0 = rowBase + warpM * 32 + mi * 16 + g;
        #pragma unroll
        for (int nj = 0; nj < 8; nj++) {
            int c = colBase + warpN * 64 + nj * 8 + t * 2;
            float b0 = bias[c], b1 = bias[c + 1];
            float v0 = fmaxf(acc[mi][nj][0] + b0, 0.0f);
            float v1 = fmaxf(acc[mi][nj][1] + b1, 0.0f);
            float v2 = fmaxf(acc[mi][nj][2] + b0, 0.0f);
            float v3 = fmaxf(acc[mi][nj][3] + b1, 0.0f);
            long o0 = (long)r0 * N + c;
            long o1 = (long)(r0 + 8) * N + c;
            __half h0,l0,h1,l1,h2,l2,h3,l3;
            split_fp16(v0, h0, l0); split_fp16(v1, h1, l1);
            split_fp16(v2, h2, l2); split_fp16(v3, h3, l3);
            *(__half2*)(Ch + o0) = __halves2half2(h0, h1);
            *(__half2*)(Ch + o1) = __halves2half2(h2, h3);
            *(__half2*)(Cl + o0) = __halves2half2(l0, l1);
            *(__half2*)(Cl + o1) = __halves2half2(l2, l3);
        }
    }
}

// ---- FF2 GEMM split-K: z = K-half; writes fp32 partials ----
__global__ __launch_bounds__(256, 2)
void ff2_splitk_kernel(const __half* __restrict__ Ah, const __half* __restrict__ Al,
                       const __half* __restrict__ Wh,
                       float* __restrict__ p0, float* __restrict__ p1) {
    int z = blockIdx.z;
    int kOff = z * (FF_DIM / 2);
    float* P = z ? p1 : p0;

    float acc[2][8][4];
    #pragma unroll
    for (int mi = 0; mi < 2; mi++)
        #pragma unroll
        for (int nj = 0; nj < 8; nj++)
            #pragma unroll
            for (int r = 0; r < 4; r++) acc[mi][nj][r] = 0.0f;
    gemm_mainloop(Ah + kOff, Al + kOff, Wh + kOff, FF_DIM, (FF_DIM / 2) / BK, acc);

    const int N = D_MODEL;
    int lane = threadIdx.x & 31, warp = threadIdx.x >> 5;
    int warpM = warp >> 1, warpN = warp & 1;
    int g = lane >> 2, t = lane & 3;
    int rowBase = blockIdx.y * BM, colBase = blockIdx.x * BN;
    #pragma unroll
    for (int mi = 0; mi < 2; mi++) {
        int r0 = rowBase + warpM * 32 + mi * 16 + g;
        #pragma unroll
        for (int nj = 0; nj < 8; nj++) {
            int c = colBase + warpN * 64 + nj * 8 + t * 2;
            long o0 = (long)r0 * N + c;
            long o1 = (long)(r0 + 8) * N + c;
            P[o0] = acc[mi][nj][0]; P[o0 + 1] = acc[mi][nj][1];
            P[o1] = acc[mi][nj][2]; P[o1 + 1] = acc[mi][nj][3];
        }
    }
}

// ---- fused QKV GEMM: z=0 Q*0.125 split, z=1 K single, z=2 V single transposed ----
__global__ __launch_bounds__(256, 2)
void qkv_gemm_kernel(const __half* __restrict__ Ah, const __half* __restrict__ Al,
                     const __half* __restrict__ Wh_base,
                     const float* __restrict__ bq, const float* __restrict__ bk,
                     const float* __restrict__ bv,
                     __half* __restrict__ qh, __half* __restrict__ ql,
                     __half* __restrict__ kh, __half* __restrict__ vth) {
    int z = blockIdx.z;
    const __half* Wh = Wh_base + (long)z * (NLAYER * D_MODEL * D_MODEL);
    const float* bias = (z == 0) ? bq : (z == 1) ? bk : bv;

    float acc[2][8][4];
    #pragma unroll
    for (int mi = 0; mi < 2; mi++)
        #pragma unroll
        for (int nj = 0; nj < 8; nj++)
            #pragma unroll
            for (int r = 0; r < 4; r++) acc[mi][nj][r] = 0.0f;
    gemm_mainloop(Ah, Al, Wh, D_MODEL, D_MODEL / BK, acc);

    int lane = threadIdx.x & 31, warp = threadIdx.x >> 5;
    int warpM = warp >> 1, warpN = warp & 1;
    int g = lane >> 2, t = lane & 3;
    int rowBase = blockIdx.y * BM, colBase = blockIdx.x * BN;

    #pragma unroll
    for (int mi = 0; mi < 2; mi++) {
        int r0 = rowBase + warpM * 32 + mi * 16 + g;
        #pragma unroll
        for (int nj = 0; nj < 8; nj++) {
            int c = colBase + warpN * 64 + nj * 8 + t * 2;
            float b0 = bias[c], b1 = bias[c + 1];
            float v0 = acc[mi][nj][0] + b0;
            float v1 = acc[mi][nj][1] + b1;
            float v2 = acc[mi][nj][2] + b0;
            float v3 = acc[mi][nj][3] + b1;
            if (z == 0) {
                v0 *= 0.125f; v1 *= 0.125f; v2 *= 0.125f; v3 *= 0.125f;
                __half h0,l0,h1,l1,h2,l2,h3,l3;
                split_fp16(v0, h0, l0); split_fp16(v1, h1, l1);
                split_fp16(v2, h2, l2); split_fp16(v3, h3, l3);
                long o0 = (long)r0 * D_MODEL + c;
                long o1 = (long)(r0 + 8) * D_MODEL + c;
                *(__half2*)(qh + o0) = __halves2half2(h0, h1);
                *(__half2*)(qh + o1) = __halves2half2(h2, h3);
                *(__half2*)(ql + o0) = __halves2half2(l0, l1);
                *(__half2*)(ql + o1) = __halves2half2(l2, l3);
            } else if (z == 1) {
                long o0 = (long)r0 * D_MODEL + c;
                long o1 = (long)(r0 + 8) * D_MODEL + c;
                *(__half2*)(kh + o0) = __halves2half2(__float2half_rn(v0), __float2half_rn(v1));
                *(__half2*)(kh + o1) = __halves2half2(__float2half_rn(v2), __float2half_rn(v3));
            } else {
                long c0 = (long)c * M_ROWS, c1 = (long)(c + 1) * M_ROWS;
                vth[c0 + r0]     = __float2half_rn(v0);
                vth[c1 + r0]     = __float2half_rn(v1);
                vth[c0 + r0 + 8] = __float2half_rn(v2);
                vth[c1 + r0 + 8] = __float2half_rn(v3);
            }
        }
    }
}

// ---------------- 2-term split-fp16 flash attention (m16n8k16 + ldmatrix) ----------
#define QPB 72   // fp16 row stride (144 B): conflict-free for LDSM
#define QPBB (QPB * 2)
#define ATT_SMEM ((2*128 + 64 + 64 + 2*128) * QPB * 2)   // 92160 B

__global__ __launch_bounds__(256, 2)
void attention_fp16_kernel(const __half* __restrict__ qh,
                           const __half* __restrict__ ql,
                           const __half* __restrict__ kh,
                           const __half* __restrict__ vth,
                           float* __restrict__ x) {
    extern __shared__ __half smh[];
    __half* Qh = smh;
    __half* Ql = Qh + 128 * QPB;
    __half* Kh = Ql + 128 * QPB;
    __half* Vh = Kh + 64 * QPB;
    __half* Ph = Vh + 64 * QPB;
    __half* Pl = Ph + 128 * QPB;

    int tid = threadIdx.x;
    int lane = tid & 31, warp = tid >> 5;
    int g = lane >> 2, t = lane & 3;
    int bh = blockIdx.x;
    int b = bh >> 3, h = bh & 7;
    int qt = blockIdx.y;
    int qr = warp * 16;

    int lm8  = lane & 7;
    int bit3 = (lane >> 3) & 1;
    int bit4 = lane >> 4;
    uint32_t aOff = (uint32_t)(qr + lm8 + 8 * bit3) * QPBB + (uint32_t)bit4 * 16u;
    uint32_t bOff = (uint32_t)(lm8 + 8 * bit4) * QPBB + (uint32_t)bit3 * 16u;
    uint32_t baseQh = smem_u32(Qh) + aOff;
    uint32_t baseQl = smem_u32(Ql) + aOff;
    uint32_t basePh = smem_u32(Ph) + aOff;
    uint32_t basePl = smem_u32(Pl) + aOff;
    uint32_t baseKh = smem_u32(Kh) + bOff;
    uint32_t baseVh = smem_u32(Vh) + bOff;

    // ---- stage Q ----
    {
        long qbase = ((long)(b * S_LEN + qt * 128)) * D_MODEL + h * DHEAD;
        #pragma unroll
        for (int p = 0; p < 8; p++) {
            int id = p * 256 + tid;
            int arr = id >> 10;
            int rem = id & 1023;
            int row = rem >> 3, ck = rem & 7;
            const __half* src = (arr ? ql : qh) + qbase + (long)row * D_MODEL + ck * 8;
            uint32_t dst = smem_u32(&(arr ? Ql : Qh)[row * QPB + ck * 8]);
            cp_async16(dst, src);
        }
        cp_commit();
    }

    float o[8][4];
    #pragma unroll
    for (int j = 0; j < 8; j++)
        #pragma unroll
        for (int r = 0; r < 4; r++) o[j][r] = 0.0f;
    float m0 = -1e30f, m1 = -1e30f, l0s = 0.0f, l1s = 0.0f;

    for (int kt = 0; kt < S_LEN / 64; kt++) {
        __syncthreads();
        {
            long kbase = ((long)(b * S_LEN + kt * 64)) * D_MODEL + h * DHEAD;
            long vcol  = (long)b * S_LEN + kt * 64;
            #pragma unroll
            for (int p = 0; p < 4; p++) {
                int id = p * 256 + tid;
                int arr = id >> 9;
                int rem = id & 511;
                int row = rem >> 3, ck = rem & 7;
                const __half* src;
                uint32_t dst;
                if (arr == 0) {
                    src = kh + kbase + (long)row * D_MODEL + ck * 8;
                    dst = smem_u32(&Kh[row * QPB + ck * 8]);
                } else {
                    src = vth + (long)(h * DHEAD + row) * M_ROWS + vcol + ck * 8;
                    dst = smem_u32(&Vh[row * QPB + ck * 8]);
                }
                cp_async16(dst, src);
            }
            cp_commit();
        }
        cp_wait<0>();
        __syncthreads();

        // ---- S = (Q/8) @ K^T : 2-term ----
        float s[8][4];
        #pragma unroll
        for (int j = 0; j < 8; j++)
            #pragma unroll
            for (int r = 0; r < 4; r++) s[j][r] = 0.0f;

        #pragma unroll
        for (int ks = 0; ks < 4; ks++) {
            uint32_t ko = ks * 32;
            uint32_t a_h[4], a_l[4];
            ldsm_x4(a_h, baseQh + ko);
            ldsm_x4(a_l, baseQl + ko);
            #pragma unroll
            for (int h4 = 0; h4 < 4; h4++) {
                uint32_t b_h[4];
                ldsm_x4(b_h, baseKh + ko + h4 * (16 * QPBB));
                mma_fp16(s[2 * h4],     a_h, b_h);
                mma_fp16(s[2 * h4],     a_l, b_h);
                mma_fp16(s[2 * h4 + 1], a_h, b_h + 2);
                mma_fp16(s[2 * h4 + 1], a_l, b_h + 2);
            }
        }

        // ---- online softmax ----
        float mx0 = -1e30f, mx1 = -1e30f;
        #pragma unroll
        for (int j = 0; j < 8; j++) {
            mx0 = fmaxf(mx0, fmaxf(s[j][0], s[j][1]));
            mx1 = fmaxf(mx1, fmaxf(s[j][2], s[j][3]));
        }
        mx0 = fmaxf(mx0, __shfl_xor_sync(0xffffffffu, mx0, 1));
        mx0 = fmaxf(mx0, __shfl_xor_sync(0xffffffffu, mx0, 2));
        mx1 = fmaxf(mx1, __shfl_xor_sync(0xffffffffu, mx1, 1));
        mx1 = fmaxf(mx1, __shfl_xor_sync(0xffffffffu, mx1, 2));
        float mn0 = fmaxf(m0, mx0), mn1 = fmaxf(m1, mx1);
        float c0 = __expf(m0 - mn0), c1 = __expf(m1 - mn1);
        l0s *= c0; l1s *= c1;
        #pragma unroll
        for (int j = 0; j < 8; j++) {
            float p0 = __expf(s[j][0] - mn0);
            float p1 = __expf(s[j][1] - mn0);
            float p2 = __expf(s[j][2] - mn1);
            float p3 = __expf(s[j][3] - mn1);
            l0s += p0 + p1; l1s += p2 + p3;
            __half h0,lo0,h1,lo1,h2,lo2,h3,lo3;
            split_fp16(p0, h0, lo0); split_fp16(p1, h1, lo1);
            split_fp16(p2, h2, lo2); split_fp16(p3, h3, lo3);
            int cc = j * 8 + 2 * t;
            *(__half2*)&Ph[(qr + g) * QPB + cc]     = __halves2half2(h0, h1);
            *(__half2*)&Ph[(qr + g + 8) * QPB + cc] = __halves2half2(h2, h3);
            *(__half2*)&Pl[(qr + g) * QPB + cc]     = __halves2half2(lo0, lo1);
            *(__half2*)&Pl[(qr + g + 8) * QPB + cc] = __halves2half2(lo2, lo3);
            o[j][0] *= c0; o[j][1] *= c0; o[j][2] *= c1; o[j][3] *= c1;
        }
        m0 = mn0; m1 = mn1;
        __syncwarp();

        // ---- O += P @ V : 2-term ----
        #pragma unroll
        for (int ks = 0; ks < 4; ks++) {
            uint32_t ko = ks * 32;
            uint32_t p_h[4], p_l[4];
            ldsm_x4(p_h, basePh + ko);
            ldsm_x4(p_l, basePl + ko);
            #pragma unroll
            for (int h4 = 0; h4 < 4; h4++) {
                uint32_t b_h[4];
                ldsm_x4(b_h, baseVh + ko + h4 * (16 * QPBB));
                mma_fp16(o[2 * h4],     p_h, b_h);
                mma_fp16(o[2 * h4],     p_l, b_h);
                mma_fp16(o[2 * h4 + 1], p_h, b_h + 2);
                mma_fp16(o[2 * h4 + 1], p_l, b_h + 2);
            }
        }
    }

    // ---- finalize: x += O / l ----
    l0s += __shfl_xor_sync(0xffffffffu, l0s, 1);
    l0s += __shfl_xor_sync(0xffffffffu, l0s, 2);
    l1s += __shfl_xor_sync(0xffffffffu, l1s, 1);
    l1s += __shfl_xor_sync(0xffffffffu, l1s, 2);
    float i0 = 1.0f / l0s, i1 = 1.0f / l1s;

    float* xr0 = x + ((long)(b * S_LEN + qt * 128 + qr + g)     << 9) + h * DHEAD;
    float* xr1 = x + ((long)(b * S_LEN + qt * 128 + qr + g + 8) << 9) + h * DHEAD;
    #pragma unroll
    for (int j = 0; j < 8; j++) {
        int cc = j * 8 + 2 * t;
        float2 r0 = *(float2*)(xr0 + cc);
        r0.x += o[j][0] * i0; r0.y += o[j][1] * i0;
        *(float2*)(xr0 + cc) = r0;
        float2 r1 = *(float2*)(xr1 + cc);
        r1.x += o[j][2] * i1; r1.y += o[j][3] * i1;
        *(float2*)(xr1 + cc) = r1;
    }
}

// ---------------- host orchestration --------------------------------------------
extern "C" void kernel_launch(void* const* d_in, const int* in_sizes, int n_in,
                              void* d_out, int out_size) {
    const float* src   = (const float*)d_in[0];
    const float* pos   = (const float*)d_in[1];
    const float* Wq    = (const float*)d_in[2];
    const float* bq    = (const float*)d_in[3];
    const float* Wk    = (const float*)d_in[4];
    const float* bk    = (const float*)d_in[5];
    const float* Wv    = (const float*)d_in[6];
    const float* bv    = (const float*)d_in[7];
    const float* W1    = (const float*)d_in[8];
    const float* b1    = (const float*)d_in[9];
    const float* W2    = (const float*)d_in[10];
    const float* b2    = (const float*)d_in[11];
    const float* ln1_g = (const float*)d_in[12];
    const float* ln1_b = (const float*)d_in[13];
    const float* ln2_g = (const float*)d_in[14];
    const float* ln2_b = (const float*)d_in[15];
    const float* lnf_g = (const float*)d_in[16];
    const float* lnf_b = (const float*)d_in[17];
    float* out = (float*)d_out;

    float *px, *pp0, *pp1;
    __half *pxnh, *pxnl, *pqh, *pql, *pkh, *pvth, *phh, *phl, *pwt;
    cudaGetSymbolAddress((void**)&px,   g_x);
    cudaGetSymbolAddress((void**)&pp0,  g_p0);
    cudaGetSymbolAddress((void**)&pp1,  g_p1);
    cudaGetSymbolAddress((void**)&pxnh, g_xn_h);
    cudaGetSymbolAddress((void**)&pxnl, g_xn_l);
    cudaGetSymbolAddress((void**)&pqh,  g_qh);
    cudaGetSymbolAddress((void**)&pql,  g_ql);
    cudaGetSymbolAddress((void**)&pkh,  g_kh);
    cudaGetSymbolAddress((void**)&pvth, g_vth);
    cudaGetSymbolAddress((void**)&phh,  g_h_h);
    cudaGetSymbolAddress((void**)&phl,  g_h_l);
    cudaGetSymbolAddress((void**)&pwt,  g_wt);

    cudaFuncSetAttribute(attention_fp16_kernel,
                         cudaFuncAttributeMaxDynamicSharedMemorySize, ATT_SMEM);
    cudaFuncSetAttribute(qkv_gemm_kernel,
                         cudaFuncAttributeMaxDynamicSharedMemorySize, GEMM_SMEM);
    cudaFuncSetAttribute(ff1_gemm_kernel,
                         cudaFuncAttributeMaxDynamicSharedMemorySize, GEMM_SMEM);
    cudaFuncSetAttribute(ff2_splitk_kernel,
                         cudaFuncAttributeMaxDynamicSharedMemorySize, GEMM_SMEM);

    // ---- transpose + fp16 all weights: W[K][N] -> Wt[N][K] ----
    {
        dim3 blk(32, 8);
        wsplit_t_kernel<<<dim3(D_MODEL / 32, D_MODEL / 32, NLAYER), blk>>>(
            Wq, pwt + WQ_OFF, D_MODEL, D_MODEL);
        wsplit_t_kernel<<<dim3(D_MODEL / 32, D_MODEL / 32, NLAYER), blk>>>(
            Wk, pwt + WK_OFF, D_MODEL, D_MODEL);
        wsplit_t_kernel<<<dim3(D_MODEL / 32, D_MODEL / 32, NLAYER), blk>>>(
            Wv, pwt + WV_OFF, D_MODEL, D_MODEL);
        wsplit_t_kernel<<<dim3(FF_DIM / 32, D_MODEL / 32, NLAYER), blk>>>(
            W1, pwt + W1_OFF, D_MODEL, FF_DIM);
        wsplit_t_kernel<<<dim3(D_MODEL / 32, FF_DIM / 32, NLAYER), blk>>>(
            W2, pwt + W2_OFF, FF_DIM, D_MODEL);
    }

    add_pos_kernel<<<(M_ROWS * D_MODEL + 255) / 256, 256>>>(src, pos, px);
    layernorm_split_kernel<<<M_ROWS, 128>>>(px, ln1_g, ln1_b, pxnh, pxnl);

    for (int l = 0; l < NLAYER; l++) {
        long wqkv = (long)l * D_MODEL * D_MODEL;
        long wff1 = (long)l * D_MODEL * FF_DIM;
        long wff2 = (long)l * FF_DIM * D_MODEL;

        // attention block (xn already holds LN1 output)
        qkv_gemm_kernel<<<dim3(D_MODEL / BN, M_ROWS / BM, 3), 256, GEMM_SMEM>>>(
            pxnh, pxnl, pwt + WQ_OFF + wqkv,
            bq + l * D_MODEL, bk + l * D_MODEL, bv + l * D_MODEL,
            pqh, pql, pkh, pvth);
        attention_fp16_kernel<<<dim3(BATCH * NHEAD, S_LEN / 128), 256, ATT_SMEM>>>(
            pqh, pql, pkh, pvth, px);

        // feed-forward block
        layernorm_split_kernel<<<M_ROWS, 128>>>(px, ln2_g + l * D_MODEL, ln2_b + l * D_MODEL,
                                                pxnh, pxnl);
        ff1_gemm_kernel<<<dim3(FF_DIM / BN, M_ROWS / BM), 256, GEMM_SMEM>>>(
            pxnh, pxnl, pwt + W1_OFF + wff1, b1 + l * FF_DIM, phh, phl);
        ff2_splitk_kernel<<<dim3(D_MODEL / BN, M_ROWS / BM, 2), 256, GEMM_SMEM>>>(
            phh, phl, pwt + W2_OFF + wff2, pp0, pp1);

        if (l < NLAYER - 1) {
            // fused: x += partials + bias, then next layer's LN1 -> xn
            combine_ln_kernel<<<M_ROWS, 128>>>(
                pp0, pp1, b2 + l * D_MODEL, px,
                ln1_g + (l + 1) * D_MODEL, ln1_b + (l + 1) * D_MODEL, pxnh, pxnl);
        } else {
            // fused: x += partials + bias, then FINAL LN with transpose to out
            combine_final_kernel<<<M_ROWS, 128>>>(
                pp0, pp1, b2 + l * D_MODEL, px, lnf_g, lnf_b, out);
        }
    }
}

// round 12
// speedup vs baseline: 6.0331x; 1.0146x over previous
#include <cuda_runtime.h>
#include <cuda_fp16.h>
#include <math.h>
#include <stdint.h>

#define D_MODEL 512
#define FF_DIM  2048
#define S_LEN   1024
#define BATCH   4
#define NLAYER  6
#define NHEAD   8
#define DHEAD   64
#define M_ROWS  (S_LEN * BATCH)   // 4096 token rows

// weight layout inside g_wt (element offsets; arrays are transposed [N][K], fp16)
#define WQ_OFF 0
#define WK_OFF (NLAYER * D_MODEL * D_MODEL)
#define WV_OFF (2 * NLAYER * D_MODEL * D_MODEL)
#define W1_OFF (3 * NLAYER * D_MODEL * D_MODEL)
#define W2_OFF (W1_OFF + NLAYER * D_MODEL * FF_DIM)
#define W_TOTAL (W2_OFF + NLAYER * FF_DIM * D_MODEL)

// ---------------- scratch (device globals; no runtime allocation) ----------------
__device__ float g_x [M_ROWS * D_MODEL];        // residual stream (B,S,D)
__device__ __half g_xn_h[M_ROWS * D_MODEL];     // layernorm out hi (fp16)
__device__ __half g_xn_l[M_ROWS * D_MODEL];     // layernorm out lo
__device__ __half g_qh[M_ROWS * D_MODEL];       // Q/8 hi (row-major)
__device__ __half g_ql[M_ROWS * D_MODEL];       // Q/8 lo
__device__ __half g_kh[M_ROWS * D_MODEL];       // K (single fp16, B-side)
__device__ __half g_vth[D_MODEL * M_ROWS];      // V TRANSPOSED [dh_col][token]
__device__ __half g_h_h[M_ROWS * FF_DIM];       // FF hidden hi
__device__ __half g_h_l[M_ROWS * FF_DIM];       // FF hidden lo
__device__ float g_p0[M_ROWS * D_MODEL];        // FF2 split-K partial 0
__device__ float g_p1[M_ROWS * D_MODEL];        // FF2 split-K partial 1
__device__ __half g_wt[W_TOTAL];                // weights transposed [N][K], fp16

// ---------------- helpers ----------------------------------------------------------
__device__ __forceinline__ void mma_fp16(float* d, const uint32_t* a, const uint32_t* b) {
    asm volatile(
        "mma.sync.aligned.m16n8k16.row.col.f32.f16.f16.f32 "
        "{%0,%1,%2,%3}, {%4,%5,%6,%7}, {%8,%9}, {%0,%1,%2,%3};"
        : "+f"(d[0]), "+f"(d[1]), "+f"(d[2]), "+f"(d[3])
        : "r"(a[0]), "r"(a[1]), "r"(a[2]), "r"(a[3]), "r"(b[0]), "r"(b[1]));
}

__device__ __forceinline__ void ldsm_x4(uint32_t* r, uint32_t addr) {
    asm volatile("ldmatrix.sync.aligned.m8n8.x4.shared.b16 {%0,%1,%2,%3}, [%4];"
                 : "=r"(r[0]), "=r"(r[1]), "=r"(r[2]), "=r"(r[3]) : "r"(addr));
}

__device__ __forceinline__ void split_fp16(float x, __half& hi, __half& lo) {
    hi = __float2half_rn(x);
    lo = __float2half_rn(x - __half2float(hi));
}

__device__ __forceinline__ void cp_async16(uint32_t dst, const void* src) {
    asm volatile("cp.async.ca.shared.global [%0], [%1], 16;" :: "r"(dst), "l"(src));
}
__device__ __forceinline__ void cp_commit() {
    asm volatile("cp.async.commit_group;");
}
template<int N>
__device__ __forceinline__ void cp_wait() {
    asm volatile("cp.async.wait_group %0;" :: "n"(N));
}
__device__ __forceinline__ uint32_t smem_u32(const void* p) {
    return (uint32_t)__cvta_generic_to_shared(p);
}

// ---------------- weight transpose + fp16 body: W[K][N] tile -> Wt[N][K] ----------
__device__ __forceinline__ void wsplit_body(const float* __restrict__ src,
                                            __half* __restrict__ oh, int K, int N) {
    __shared__ float tile[32][33];
    int n0 = blockIdx.x * 32, k0 = blockIdx.y * 32;
    int tx = threadIdx.x, ty = threadIdx.y;      // 32 x 8
    #pragma unroll
    for (int i = ty; i < 32; i += 8)
        tile[i][tx] = src[(long)(k0 + i) * N + n0 + tx];
    __syncthreads();
    int tid = ty * 32 + tx;        // 0..255
    int p = tid & 15;              // half2 index along K
    int i0 = tid >> 4;             // 0..15
    #pragma unroll
    for (int rep = 0; rep < 2; rep++) {
        int i = i0 + rep * 16;
        __half2 v = __floats2half2_rn(tile[2 * p][i], tile[2 * p + 1][i]);
        *(__half2*)(oh + (long)(n0 + i) * K + k0 + 2 * p) = v;
    }
}

// merged Q/K/V weight transpose: z = which*NLAYER + layer
__global__ void wsplit_qkv_kernel(const float* __restrict__ Wq,
                                  const float* __restrict__ Wk,
                                  const float* __restrict__ Wv,
                                  __half* __restrict__ wt) {
    int z = blockIdx.z;
    int which = z / NLAYER, l = z % NLAYER;
    const float* src = ((which == 0) ? Wq : (which == 1) ? Wk : Wv)
                       + (long)l * D_MODEL * D_MODEL;
    __half* oh = wt + (long)which * (NLAYER * D_MODEL * D_MODEL)
                    + (long)l * D_MODEL * D_MODEL;
    wsplit_body(src, oh, D_MODEL, D_MODEL);
}

__global__ void wsplit_t_kernel(const float* __restrict__ src,
                                __half* __restrict__ oh, int K, int N) {
    int l = blockIdx.z;
    wsplit_body(src + (long)l * K * N, oh + (long)l * N * K, K, N);
}

// ---------------- LN core (per-row block of 128 threads; v in registers) -----------
__device__ __forceinline__ void ln_stats(float4 v, float& mean, float& inv) {
    float s  = v.x + v.y + v.z + v.w;
    float ss = v.x*v.x + v.y*v.y + v.z*v.z + v.w*v.w;
    #pragma unroll
    for (int o = 16; o > 0; o >>= 1) {
        s  += __shfl_down_sync(0xffffffffu, s,  o);
        ss += __shfl_down_sync(0xffffffffu, ss, o);
    }
    __shared__ float shs[4], shss[4];
    __shared__ float s_mean, s_inv;
    int tid = threadIdx.x;
    int w = tid >> 5, lane = tid & 31;
    if (lane == 0) { shs[w] = s; shss[w] = ss; }
    __syncthreads();
    if (tid == 0) {
        float ts  = shs[0] + shs[1] + shs[2] + shs[3];
        float tss = shss[0] + shss[1] + shss[2] + shss[3];
        float m = ts * (1.0f / D_MODEL);
        float var = tss * (1.0f / D_MODEL) - m * m;
        s_mean = m;
        s_inv  = rsqrtf(var + 1e-5f);
    }
    __syncthreads();
    mean = s_mean; inv = s_inv;
}

__device__ __forceinline__ void ln_emit_split(float4 v, float mean, float inv,
                                              const float* gamma, const float* beta,
                                              __half* yh, __half* yl, int row) {
    int tid = threadIdx.x;
    int c = tid * 4;
    float4 g = *(const float4*)(gamma + c);
    float4 bb = *(const float4*)(beta + c);
    float o0 = (v.x - mean) * inv * g.x + bb.x;
    float o1 = (v.y - mean) * inv * g.y + bb.y;
    float o2 = (v.z - mean) * inv * g.z + bb.z;
    float o3 = (v.w - mean) * inv * g.w + bb.w;
    __half h0,l0,h1,l1,h2,l2,h3,l3;
    split_fp16(o0, h0, l0); split_fp16(o1, h1, l1);
    split_fp16(o2, h2, l2); split_fp16(o3, h3, l3);
    __half2* yh2 = (__half2*)(yh + row * D_MODEL);
    __half2* yl2 = (__half2*)(yl + row * D_MODEL);
    yh2[tid * 2]     = __halves2half2(h0, h1);
    yh2[tid * 2 + 1] = __halves2half2(h2, h3);
    yl2[tid * 2]     = __halves2half2(l0, l1);
    yl2[tid * 2 + 1] = __halves2half2(l2, l3);
}

// ---------------- fused add_pos + LN1(layer 0) -------------------------------------
__global__ void add_pos_ln_kernel(const float* __restrict__ src,
                                  const float* __restrict__ pos,
                                  float* __restrict__ x,
                                  const float* __restrict__ gamma,
                                  const float* __restrict__ beta,
                                  __half* __restrict__ yh,
                                  __half* __restrict__ yl) {
    int row = blockIdx.x;              // b*S + s
    int tid = threadIdx.x;
    int b = row >> 10, s = row & (S_LEN - 1);
    long si = ((long)(s * BATCH + b)) << 9;
    float4 v = ((const float4*)(src + si))[tid];
    float4 q = ((const float4*)(pos + si))[tid];
    v.x += q.x; v.y += q.y; v.z += q.z; v.w += q.w;
    ((float4*)(x + (long)row * D_MODEL))[tid] = v;
    float mean, inv;
    ln_stats(v, mean, inv);
    ln_emit_split(v, mean, inv, gamma, beta, yh, yl, row);
}

// ---------------- layernorm -> split fp16 (standalone, for LN2) --------------------
__global__ void layernorm_split_kernel(const float* __restrict__ x,
                                       const float* __restrict__ gamma,
                                       const float* __restrict__ beta,
                                       __half* __restrict__ yh,
                                       __half* __restrict__ yl) {
    int row = blockIdx.x;
    int tid = threadIdx.x;
    float4 v = ((const float4*)(x + row * D_MODEL))[tid];
    float mean, inv;
    ln_stats(v, mean, inv);
    ln_emit_split(v, mean, inv, gamma, beta, yh, yl, row);
}

// ---------------- fused FF2-combine + next-layer LN1 ------------------------------
__global__ void combine_ln_kernel(const float* __restrict__ p0,
                                  const float* __restrict__ p1,
                                  const float* __restrict__ bias,
                                  float* __restrict__ x,
                                  const float* __restrict__ gamma,
                                  const float* __restrict__ beta,
                                  __half* __restrict__ yh,
                                  __half* __restrict__ yl) {
    int row = blockIdx.x;
    int tid = threadIdx.x;
    int idx = row * 128 + tid;
    float4 a = ((const float4*)p0)[idx];
    float4 b = ((const float4*)p1)[idx];
    float4 v = ((const float4*)x)[idx];
    float4 bb = *(const float4*)(bias + tid * 4);
    v.x += a.x + b.x + bb.x;
    v.y += a.y + b.y + bb.y;
    v.z += a.z + b.z + bb.z;
    v.w += a.w + b.w + bb.w;
    ((float4*)x)[idx] = v;
    float mean, inv;
    ln_stats(v, mean, inv);
    ln_emit_split(v, mean, inv, gamma, beta, yh, yl, row);
}

// ---------------- fused FF2-combine + FINAL LN (transpose back to (S,B,D)) --------
__global__ void combine_final_kernel(const float* __restrict__ p0,
                                     const float* __restrict__ p1,
                                     const float* __restrict__ bias,
                                     const float* __restrict__ x,
                                     const float* __restrict__ gamma,
                                     const float* __restrict__ beta,
                                     float* __restrict__ out) {
    int row = blockIdx.x;
    int tid = threadIdx.x;
    int idx = row * 128 + tid;
    float4 a = ((const float4*)p0)[idx];
    float4 b = ((const float4*)p1)[idx];
    float4 v = ((const float4*)x)[idx];
    float4 bb = *(const float4*)(bias + tid * 4);
    v.x += a.x + b.x + bb.x;
    v.y += a.y + b.y + bb.y;
    v.z += a.z + b.z + bb.z;
    v.w += a.w + b.w + bb.w;
    float mean, inv;
    ln_stats(v, mean, inv);
    int c = tid * 4;
    float4 g = *(const float4*)(gamma + c);
    float4 be = *(const float4*)(beta + c);
    float4 o;
    o.x = (v.x - mean) * inv * g.x + be.x;
    o.y = (v.y - mean) * inv * g.y + be.y;
    o.z = (v.z - mean) * inv * g.z + be.z;
    o.w = (v.w - mean) * inv * g.w + be.w;
    int bb_ = row >> 10;
    int ss_ = row & (S_LEN - 1);
    ((float4*)(out + ((ss_ * BATCH + bb_) << 9)))[tid] = o;
}

// ---------------- 2-term split-FP16 GEMM mainloop (m16n8k16 + ldmatrix, BK=64) -----
#define BM 128
#define BN 128
#define BK 64
#define SPAD 72                    // fp16 row stride: 144 B (conflict-free for LDSM)
#define TBUF (128 * SPAD)          // fp16 elems per buffer
#define BUFB (TBUF * 2)            // bytes per buffer
#define GEMM_SMEM (6 * TBUF * 2)   // 3 arrays x 2 buffers = 110592 bytes

__device__ __forceinline__ void gemm_mainloop(const __half* __restrict__ Ah,
                                              const __half* __restrict__ Al,
                                              const __half* __restrict__ Wh,
                                              int ldk, int kIters, float acc[2][8][4]) {
    extern __shared__ __half smh[];
    __half* Ash = smh;
    __half* Asl = Ash + 2 * TBUF;
    __half* Bsh = Asl + 2 * TBUF;

    int tid  = threadIdx.x;
    int lane = tid & 31;
    int warp = tid >> 5;
    int warpM = warp >> 1;
    int warpN = warp & 1;
    int rowBase = blockIdx.y * BM;
    int colBase = blockIdx.x * BN;

    int lm8  = lane & 7;
    int bit3 = (lane >> 3) & 1;
    int bit4 = lane >> 4;
    uint32_t aOff = (uint32_t)(warpM * 32 + lm8 + 8 * bit3) * 144u + (uint32_t)bit4 * 16u;
    uint32_t bOff = (uint32_t)(warpN * 64 + lm8 + 8 * bit4) * 144u + (uint32_t)bit3 * 16u;
    uint32_t baseAh = smem_u32(Ash) + aOff;
    uint32_t baseAl = smem_u32(Asl) + aOff;
    uint32_t baseBh = smem_u32(Bsh) + bOff;

    int r0c = tid >> 3;
    int o0c = (tid & 7) * 8;
    const __half* Ag = Ah + (long)(rowBase + r0c) * ldk + o0c;
    const __half* Alg = Al + (long)(rowBase + r0c) * ldk + o0c;
    const __half* Bg = Wh + (long)(colBase + r0c) * ldk + o0c;
    uint32_t dA = smem_u32(&Ash[r0c * SPAD + o0c]);
    uint32_t dAl = smem_u32(&Asl[r0c * SPAD + o0c]);
    uint32_t dB = smem_u32(&Bsh[r0c * SPAD + o0c]);
    const uint32_t rstep = 32u * SPAD * 2u;
    const long gstep = 32l * ldk;

    #pragma unroll
    for (int p = 0; p < 4; p++) {
        cp_async16(dA + p * rstep, Ag + p * gstep);
        cp_async16(dAl + p * rstep, Alg + p * gstep);
        cp_async16(dB + p * rstep, Bg + p * gstep);
    }
    cp_commit();

    for (int it = 0; it < kIters; it++) {
        int cur = it & 1;
        int nxt = cur ^ 1;
        if (it + 1 < kIters) {
            int ka = (it + 1) * BK;
            uint32_t bo = (uint32_t)(nxt * BUFB);
            #pragma unroll
            for (int p = 0; p < 4; p++) {
                cp_async16(dA + bo + p * rstep, Ag + ka + p * gstep);
                cp_async16(dAl + bo + p * rstep, Alg + ka + p * gstep);
                cp_async16(dB + bo + p * rstep, Bg + ka + p * gstep);
            }
            cp_commit();
            cp_wait<1>();
        } else {
            cp_wait<0>();
        }
        __syncthreads();

        uint32_t cb = (uint32_t)(cur * BUFB);
        #pragma unroll
        for (int ks = 0; ks < 4; ks++) {
            uint32_t ko = cb + ks * 32;
            uint32_t ahi[2][4], alo[2][4];
            ldsm_x4(ahi[0], baseAh + ko);
            ldsm_x4(ahi[1], baseAh + ko + 16 * 144);
            ldsm_x4(alo[0], baseAl + ko);
            ldsm_x4(alo[1], baseAl + ko + 16 * 144);
            #pragma unroll
            for (int h = 0; h < 4; h++) {
                uint32_t bh[4];
                ldsm_x4(bh, baseBh + ko + h * (16 * 144));
                #pragma unroll
                for (int mi = 0; mi < 2; mi++) {
                    mma_fp16(acc[mi][2 * h],     ahi[mi], bh);
                    mma_fp16(acc[mi][2 * h],     alo[mi], bh);
                    mma_fp16(acc[mi][2 * h + 1], ahi[mi], bh + 2);
                    mma_fp16(acc[mi][2 * h + 1], alo[mi], bh + 2);
                }
            }
        }
        __syncthreads();
    }
}

// ---- FF1 GEMM: relu + split-fp16 epilogue ----
__global__ __launch_bounds__(256, 2)
void ff1_gemm_kernel(const __half* __restrict__ Ah, const __half* __restrict__ Al,
                     const __half* __restrict__ Wh,
                     const float* __restrict__ bias,
                     __half* __restrict__ Ch, __half* __restrict__ Cl) {
    float acc[2][8][4];
    #pragma unroll
    for (int mi = 0; mi < 2; mi++)
        #pragma unroll
        for (int nj = 0; nj < 8; nj++)
            #pragma unroll
            for (int r = 0; r < 4; r++) acc[mi][nj][r] = 0.0f;
    gemm_mainloop(Ah, Al, Wh, D_MODEL, D_MODEL / BK, acc);

    const int N = FF_DIM;
    int lane = threadIdx.x & 31, warp = threadIdx.x >> 5;
    int warpM = warp >> 1, warpN = warp & 1;
    int g = lane >> 2, t = lane & 3;
    int rowBase = blockIdx.y * BM, colBase = blockIdx.x * BN;
    #pragma unroll
    for (int mi = 0; mi < 2; mi++) {
        int r0 = rowBase + warpM * 32 + mi * 16 + g;
        #pragma unroll
        for (int nj = 0; nj < 8; nj++) {
            int c = colBase + warpN * 64 + nj * 8 + t * 2;
            float b0 = bias[c], b1 = bias[c + 1];
            float v0 = fmaxf(acc[mi][nj][0] + b0, 0.0f);
            float v1 = fmaxf(acc[mi][nj][1] + b1, 0.0f);
            float v2 = fmaxf(acc[mi][nj][2] + b0, 0.0f);
            float v3 = fmaxf(acc[mi][nj][3] + b1, 0.0f);
            long o0 = (long)r0 * N + c;
            long o1 = (long)(r0 + 8) * N + c;
            __half h0,l0,h1,l1,h2,l2,h3,l3;
            split_fp16(v0, h0, l0); split_fp16(v1, h1, l1);
            split_fp16(v2, h2, l2); split_fp16(v3, h3, l3);
            *(__half2*)(Ch + o0) = __halves2half2(h0, h1);
            *(__half2*)(Ch + o1) = __halves2half2(h2, h3);
            *(__half2*)(Cl + o0) = __halves2half2(l0, l1);
            *(__half2*)(Cl + o1) = __halves2half2(l2, l3);
        }
    }
}

// ---- FF2 GEMM split-K: z = K-half; writes fp32 partials ----
__global__ __launch_bounds__(256, 2)
void ff2_splitk_kernel(const __half* __restrict__ Ah, const __half* __restrict__ Al,
                       const __half* __restrict__ Wh,
                       float* __restrict__ p0, float* __restrict__ p1) {
    int z = blockIdx.z;
    int kOff = z * (FF_DIM / 2);
    float* P = z ? p1 : p0;

    float acc[2][8][4];
    #pragma unroll
    for (int mi = 0; mi < 2; mi++)
        #pragma unroll
        for (int nj = 0; nj < 8; nj++)
            #pragma unroll
            for (int r = 0; r < 4; r++) acc[mi][nj][r] = 0.0f;
    gemm_mainloop(Ah + kOff, Al + kOff, Wh + kOff, FF_DIM, (FF_DIM / 2) / BK, acc);

    const int N = D_MODEL;
    int lane = threadIdx.x & 31, warp = threadIdx.x >> 5;
    int warpM = warp >> 1, warpN = warp & 1;
    int g = lane >> 2, t = lane & 3;
    int rowBase = blockIdx.y * BM, colBase = blockIdx.x * BN;
    #pragma unroll
    for (int mi = 0; mi < 2; mi++) {
        int r0 = rowBase + warpM * 32 + mi * 16 + g;
        #pragma unroll
        for (int nj = 0; nj < 8; nj++) {
            int c = colBase + warpN * 64 + nj * 8 + t * 2;
            long o0 = (long)r0 * N + c;
            long o1 = (long)(r0 + 8) * N + c;
            P[o0] = acc[mi][nj][0]; P[o0 + 1] = acc[mi][nj][1];
            P[o1] = acc[mi][nj][2]; P[o1 + 1] = acc[mi][nj][3];
        }
    }
}

// ---- fused QKV GEMM: z=0 Q*0.125 split, z=1 K single, z=2 V single transposed ----
__global__ __launch_bounds__(256, 2)
void qkv_gemm_kernel(const __half* __restrict__ Ah, const __half* __restrict__ Al,
                     const __half* __restrict__ Wh_base,
                     const float* __restrict__ bq, const float* __restrict__ bk,
                     const float* __restrict__ bv,
                     __half* __restrict__ qh, __half* __restrict__ ql,
                     __half* __restrict__ kh, __half* __restrict__ vth) {
    int z = blockIdx.z;
    const __half* Wh = Wh_base + (long)z * (NLAYER * D_MODEL * D_MODEL);
    const float* bias = (z == 0) ? bq : (z == 1) ? bk : bv;

    float acc[2][8][4];
    #pragma unroll
    for (int mi = 0; mi < 2; mi++)
        #pragma unroll
        for (int nj = 0; nj < 8; nj++)
            #pragma unroll
            for (int r = 0; r < 4; r++) acc[mi][nj][r] = 0.0f;
    gemm_mainloop(Ah, Al, Wh, D_MODEL, D_MODEL / BK, acc);

    int lane = threadIdx.x & 31, warp = threadIdx.x >> 5;
    int warpM = warp >> 1, warpN = warp & 1;
    int g = lane >> 2, t = lane & 3;
    int rowBase = blockIdx.y * BM, colBase = blockIdx.x * BN;

    #pragma unroll
    for (int mi = 0; mi < 2; mi++) {
        int r0 = rowBase + warpM * 32 + mi * 16 + g;
        #pragma unroll
        for (int nj = 0; nj < 8; nj++) {
            int c = colBase + warpN * 64 + nj * 8 + t * 2;
            float b0 = bias[c], b1 = bias[c + 1];
            float v0 = acc[mi][nj][0] + b0;
            float v1 = acc[mi][nj][1] + b1;
            float v2 = acc[mi][nj][2] + b0;
            float v3 = acc[mi][nj][3] + b1;
            if (z == 0) {
                v0 *= 0.125f; v1 *= 0.125f; v2 *= 0.125f; v3 *= 0.125f;
                __half h0,l0,h1,l1,h2,l2,h3,l3;
                split_fp16(v0, h0, l0); split_fp16(v1, h1, l1);
                split_fp16(v2, h2, l2); split_fp16(v3, h3, l3);
                long o0 = (long)r0 * D_MODEL + c;
                long o1 = (long)(r0 + 8) * D_MODEL + c;
                *(__half2*)(qh + o0) = __halves2half2(h0, h1);
                *(__half2*)(qh + o1) = __halves2half2(h2, h3);
                *(__half2*)(ql + o0) = __halves2half2(l0, l1);
                *(__half2*)(ql + o1) = __halves2half2(l2, l3);
            } else if (z == 1) {
                long o0 = (long)r0 * D_MODEL + c;
                long o1 = (long)(r0 + 8) * D_MODEL + c;
                *(__half2*)(kh + o0) = __halves2half2(__float2half_rn(v0), __float2half_rn(v1));
                *(__half2*)(kh + o1) = __halves2half2(__float2half_rn(v2), __float2half_rn(v3));
            } else {
                long c0 = (long)c * M_ROWS, c1 = (long)(c + 1) * M_ROWS;
                vth[c0 + r0]     = __float2half_rn(v0);
                vth[c1 + r0]     = __float2half_rn(v1);
                vth[c0 + r0 + 8] = __float2half_rn(v2);
                vth[c1 + r0 + 8] = __float2half_rn(v3);
            }
        }
    }
}

// ---------------- 2-term split-fp16 flash attention (double-buffered KV) -----------
#define QPB 72   // fp16 row stride (144 B): conflict-free for LDSM
#define QPBB (QPB * 2)
#define KVBUF (64 * QPB)                                   // one K or V tile (elems)
#define ATT_SMEM ((2*128 + 2*64 + 2*64 + 2*128) * QPB * 2) // 110592 B

__global__ __launch_bounds__(256, 2)
void attention_fp16_kernel(const __half* __restrict__ qh,
                           const __half* __restrict__ ql,
                           const __half* __restrict__ kh,
                           const __half* __restrict__ vth,
                           float* __restrict__ x) {
    extern __shared__ __half smh[];
    __half* Qh = smh;                    // [128][QPB]
    __half* Ql = Qh + 128 * QPB;
    __half* Kh = Ql + 128 * QPB;         // [2][64][QPB]
    __half* Vh = Kh + 2 * KVBUF;         // [2][64 dh][QPB keys]
    __half* Ph = Vh + 2 * KVBUF;         // [128][QPB]
    __half* Pl = Ph + 128 * QPB;

    int tid = threadIdx.x;
    int lane = tid & 31, warp = tid >> 5;
    int g = lane >> 2, t = lane & 3;
    int bh = blockIdx.x;
    int b = bh >> 3, h = bh & 7;
    int qt = blockIdx.y;
    int qr = warp * 16;

    int lm8  = lane & 7;
    int bit3 = (lane >> 3) & 1;
    int bit4 = lane >> 4;
    uint32_t aOff = (uint32_t)(qr + lm8 + 8 * bit3) * QPBB + (uint32_t)bit4 * 16u;
    uint32_t bOff = (uint32_t)(lm8 + 8 * bit4) * QPBB + (uint32_t)bit3 * 16u;
    uint32_t baseQh = smem_u32(Qh) + aOff;
    uint32_t baseQl = smem_u32(Ql) + aOff;
    uint32_t basePh = smem_u32(Ph) + aOff;
    uint32_t basePl = smem_u32(Pl) + aOff;
    uint32_t baseKh = smem_u32(Kh) + bOff;
    uint32_t baseVh = smem_u32(Vh) + bOff;

    long kbase0 = ((long)(b * S_LEN)) * D_MODEL + h * DHEAD;
    long vcol0  = (long)b * S_LEN;

    // ---- stage Q (group 0) ----
    {
        long qbase = ((long)(b * S_LEN + qt * 128)) * D_MODEL + h * DHEAD;
        #pragma unroll
        for (int p = 0; p < 8; p++) {
            int id = p * 256 + tid;
            int arr = id >> 10;
            int rem = id & 1023;
            int row = rem >> 3, ck = rem & 7;
            const __half* src = (arr ? ql : qh) + qbase + (long)row * D_MODEL + ck * 8;
            uint32_t dst = smem_u32(&(arr ? Ql : Qh)[row * QPB + ck * 8]);
            cp_async16(dst, src);
        }
        cp_commit();
    }

    // KV staging lambda-like macro via explicit code; stage tile kt into buffer ib
    int s_row = (tid & 511) >> 3;     // shared across passes
    int s_ck  = tid & 7;
    // each thread handles 4 chunks: 2 arrays x 2 passes
    // (computed inline below)

    // ---- stage KV tile 0 into buffer 0 (group 1) ----
    {
        long kbase = kbase0;          // kt = 0
        long vcol  = vcol0;
        #pragma unroll
        for (int p = 0; p < 4; p++) {
            int id = p * 256 + tid;
            int arr = id >> 9;
            int rem = id & 511;
            int row = rem >> 3, ck = rem & 7;
            const __half* src;
            uint32_t dst;
            if (arr == 0) {
                src = kh + kbase + (long)row * D_MODEL + ck * 8;
                dst = smem_u32(&Kh[row * QPB + ck * 8]);
            } else {
                src = vth + (long)(h * DHEAD + row) * M_ROWS + vcol + ck * 8;
                dst = smem_u32(&Vh[row * QPB + ck * 8]);
            }
            cp_async16(dst, src);
        }
        cp_commit();
    }

    float o[8][4];
    #pragma unroll
    for (int j = 0; j < 8; j++)
        #pragma unroll
        for (int r = 0; r < 4; r++) o[j][r] = 0.0f;
    float m0 = -1e30f, m1 = -1e30f, l0s = 0.0f, l1s = 0.0f;

    for (int kt = 0; kt < S_LEN / 64; kt++) {
        int cur = kt & 1;
        // stage next tile into the other buffer (its previous readers finished
        // at the end-of-iteration barrier of kt-1)
        if (kt + 1 < S_LEN / 64) {
            long kbase = kbase0 + (long)(kt + 1) * 64 * D_MODEL;
            long vcol  = vcol0 + (kt + 1) * 64;
            int ib = cur ^ 1;
            #pragma unroll
            for (int p = 0; p < 4; p++) {
                int id = p * 256 + tid;
                int arr = id >> 9;
                int rem = id & 511;
                int row = rem >> 3, ck = rem & 7;
                const __half* src;
                uint32_t dst;
                if (arr == 0) {
                    src = kh + kbase + (long)row * D_MODEL + ck * 8;
                    dst = smem_u32(&Kh[ib * KVBUF + row * QPB + ck * 8]);
                } else {
                    src = vth + (long)(h * DHEAD + row) * M_ROWS + vcol + ck * 8;
                    dst = smem_u32(&Vh[ib * KVBUF + row * QPB + ck * 8]);
                }
                cp_async16(dst, src);
            }
            cp_commit();
            cp_wait<1>();
        } else {
            cp_wait<0>();
        }
        __syncthreads();

        uint32_t kvoff = (uint32_t)(cur * KVBUF * 2);   // bytes

        // ---- S = (Q/8) @ K^T : 2-term ----
        float s[8][4];
        #pragma unroll
        for (int j = 0; j < 8; j++)
            #pragma unroll
            for (int r = 0; r < 4; r++) s[j][r] = 0.0f;

        #pragma unroll
        for (int ks = 0; ks < 4; ks++) {
            uint32_t ko = ks * 32;
            uint32_t a_h[4], a_l[4];
            ldsm_x4(a_h, baseQh + ko);
            ldsm_x4(a_l, baseQl + ko);
            #pragma unroll
            for (int h4 = 0; h4 < 4; h4++) {
                uint32_t b_h[4];
                ldsm_x4(b_h, baseKh + kvoff + ko + h4 * (16 * QPBB));
                mma_fp16(s[2 * h4],     a_h, b_h);
                mma_fp16(s[2 * h4],     a_l, b_h);
                mma_fp16(s[2 * h4 + 1], a_h, b_h + 2);
                mma_fp16(s[2 * h4 + 1], a_l, b_h + 2);
            }
        }

        // ---- online softmax ----
        float mx0 = -1e30f, mx1 = -1e30f;
        #pragma unroll
        for (int j = 0; j < 8; j++) {
            mx0 = fmaxf(mx0, fmaxf(s[j][0], s[j][1]));
            mx1 = fmaxf(mx1, fmaxf(s[j][2], s[j][3]));
        }
        mx0 = fmaxf(mx0, __shfl_xor_sync(0xffffffffu, mx0, 1));
        mx0 = fmaxf(mx0, __shfl_xor_sync(0xffffffffu, mx0, 2));
        mx1 = fmaxf(mx1, __shfl_xor_sync(0xffffffffu, mx1, 1));
        mx1 = fmaxf(mx1, __shfl_xor_sync(0xffffffffu, mx1, 2));
        float mn0 = fmaxf(m0, mx0), mn1 = fmaxf(m1, mx1);
        float c0 = __expf(m0 - mn0), c1 = __expf(m1 - mn1);
        l0s *= c0; l1s *= c1;
        #pragma unroll
        for (int j = 0; j < 8; j++) {
            float p0 = __expf(s[j][0] - mn0);
            float p1 = __expf(s[j][1] - mn0);
            float p2 = __expf(s[j][2] - mn1);
            float p3 = __expf(s[j][3] - mn1);
            l0s += p0 + p1; l1s += p2 + p3;
            __half h0,lo0,h1,lo1,h2,lo2,h3,lo3;
            split_fp16(p0, h0, lo0); split_fp16(p1, h1, lo1);
            split_fp16(p2, h2, lo2); split_fp16(p3, h3, lo3);
            int cc = j * 8 + 2 * t;
            *(__half2*)&Ph[(qr + g) * QPB + cc]     = __halves2half2(h0, h1);
            *(__half2*)&Ph[(qr + g + 8) * QPB + cc] = __halves2half2(h2, h3);
            *(__half2*)&Pl[(qr + g) * QPB + cc]     = __halves2half2(lo0, lo1);
            *(__half2*)&Pl[(qr + g + 8) * QPB + cc] = __halves2half2(lo2, lo3);
            o[j][0] *= c0; o[j][1] *= c0; o[j][2] *= c1; o[j][3] *= c1;
        }
        m0 = mn0; m1 = mn1;
        __syncwarp();

        // ---- O += P @ V : 2-term ----
        #pragma unroll
        for (int ks = 0; ks < 4; ks++) {
            uint32_t ko = ks * 32;
            uint32_t p_h[4], p_l[4];
            ldsm_x4(p_h, basePh + ko);
            ldsm_x4(p_l, basePl + ko);
            #pragma unroll
            for (int h4 = 0; h4 < 4; h4++) {
                uint32_t b_h[4];
                ldsm_x4(b_h, baseVh + kvoff + ko + h4 * (16 * QPBB));
                mma_fp16(o[2 * h4],     p_h, b_h);
                mma_fp16(o[2 * h4],     p_l, b_h);
                mma_fp16(o[2 * h4 + 1], p_h, b_h + 2);
                mma_fp16(o[2 * h4 + 1], p_l, b_h + 2);
            }
        }
        __syncthreads();   // all reads of buffer `cur` done before it is re-staged
    }

    // ---- finalize: x += O / l ----
    l0s += __shfl_xor_sync(0xffffffffu, l0s, 1);
    l0s += __shfl_xor_sync(0xffffffffu, l0s, 2);
    l1s += __shfl_xor_sync(0xffffffffu, l1s, 1);
    l1s += __shfl_xor_sync(0xffffffffu, l1s, 2);
    float i0 = 1.0f / l0s, i1 = 1.0f / l1s;

    float* xr0 = x + ((long)(b * S_LEN + qt * 128 + qr + g)     << 9) + h * DHEAD;
    float* xr1 = x + ((long)(b * S_LEN + qt * 128 + qr + g + 8) << 9) + h * DHEAD;
    #pragma unroll
    for (int j = 0; j < 8; j++) {
        int cc = j * 8 + 2 * t;
        float2 r0 = *(float2*)(xr0 + cc);
        r0.x += o[j][0] * i0; r0.y += o[j][1] * i0;
        *(float2*)(xr0 + cc) = r0;
        float2 r1 = *(float2*)(xr1 + cc);
        r1.x += o[j][2] * i1; r1.y += o[j][3] * i1;
        *(float2*)(xr1 + cc) = r1;
    }
}

// ---------------- host orchestration --------------------------------------------
extern "C" void kernel_launch(void* const* d_in, const int* in_sizes, int n_in,
                              void* d_out, int out_size) {
    const float* src   = (const float*)d_in[0];
    const float* pos   = (const float*)d_in[1];
    const float* Wq    = (const float*)d_in[2];
    const float* bq    = (const float*)d_in[3];
    const float* Wk    = (const float*)d_in[4];
    const float* bk    = (const float*)d_in[5];
    const float* Wv    = (const float*)d_in[6];
    const float* bv    = (const float*)d_in[7];
    const float* W1    = (const float*)d_in[8];
    const float* b1    = (const float*)d_in[9];
    const float* W2    = (const float*)d_in[10];
    const float* b2    = (const float*)d_in[11];
    const float* ln1_g = (const float*)d_in[12];
    const float* ln1_b = (const float*)d_in[13];
    const float* ln2_g = (const float*)d_in[14];
    const float* ln2_b = (const float*)d_in[15];
    const float* lnf_g = (const float*)d_in[16];
    const float* lnf_b = (const float*)d_in[17];
    float* out = (float*)d_out;

    float *px, *pp0, *pp1;
    __half *pxnh, *pxnl, *pqh, *pql, *pkh, *pvth, *phh, *phl, *pwt;
    cudaGetSymbolAddress((void**)&px,   g_x);
    cudaGetSymbolAddress((void**)&pp0,  g_p0);
    cudaGetSymbolAddress((void**)&pp1,  g_p1);
    cudaGetSymbolAddress((void**)&pxnh, g_xn_h);
    cudaGetSymbolAddress((void**)&pxnl, g_xn_l);
    cudaGetSymbolAddress((void**)&pqh,  g_qh);
    cudaGetSymbolAddress((void**)&pql,  g_ql);
    cudaGetSymbolAddress((void**)&pkh,  g_kh);
    cudaGetSymbolAddress((void**)&pvth, g_vth);
    cudaGetSymbolAddress((void**)&phh,  g_h_h);
    cudaGetSymbolAddress((void**)&phl,  g_h_l);
    cudaGetSymbolAddress((void**)&pwt,  g_wt);

    cudaFuncSetAttribute(attention_fp16_kernel,
                         cudaFuncAttributeMaxDynamicSharedMemorySize, ATT_SMEM);
    cudaFuncSetAttribute(qkv_gemm_kernel,
                         cudaFuncAttributeMaxDynamicSharedMemorySize, GEMM_SMEM);
    cudaFuncSetAttribute(ff1_gemm_kernel,
                         cudaFuncAttributeMaxDynamicSharedMemorySize, GEMM_SMEM);
    cudaFuncSetAttribute(ff2_splitk_kernel,
                         cudaFuncAttributeMaxDynamicSharedMemorySize, GEMM_SMEM);

    // ---- transpose + fp16 all weights: W[K][N] -> Wt[N][K] ----
    {
        dim3 blk(32, 8);
        wsplit_qkv_kernel<<<dim3(D_MODEL / 32, D_MODEL / 32, 3 * NLAYER), blk>>>(
            Wq, Wk, Wv, pwt);
        wsplit_t_kernel<<<dim3(FF_DIM / 32, D_MODEL / 32, NLAYER), blk>>>(
            W1, pwt + W1_OFF, D_MODEL, FF_DIM);
        wsplit_t_kernel<<<dim3(D_MODEL / 32, FF_DIM / 32, NLAYER), blk>>>(
            W2, pwt + W2_OFF, FF_DIM, D_MODEL);
    }

    // fused add_pos + LN1(layer 0)
    add_pos_ln_kernel<<<M_ROWS, 128>>>(src, pos, px, ln1_g, ln1_b, pxnh, pxnl);

    for (int l = 0; l < NLAYER; l++) {
        long wqkv = (long)l * D_MODEL * D_MODEL;
        long wff1 = (long)l * D_MODEL * FF_DIM;
        long wff2 = (long)l * FF_DIM * D_MODEL;

        // attention block (xn already holds LN1 output)
        qkv_gemm_kernel<<<dim3(D_MODEL / BN, M_ROWS / BM, 3), 256, GEMM_SMEM>>>(
            pxnh, pxnl, pwt + WQ_OFF + wqkv,
            bq + l * D_MODEL, bk + l * D_MODEL, bv + l * D_MODEL,
            pqh, pql, pkh, pvth);
        attention_fp16_kernel<<<dim3(BATCH * NHEAD, S_LEN / 128), 256, ATT_SMEM>>>(
            pqh, pql, pkh, pvth, px);

        // feed-forward block
        layernorm_split_kernel<<<M_ROWS, 128>>>(px, ln2_g + l * D_MODEL, ln2_b + l * D_MODEL,
                                                pxnh, pxnl);
        ff1_gemm_kernel<<<dim3(FF_DIM / BN, M_ROWS / BM), 256, GEMM_SMEM>>>(
            pxnh, pxnl, pwt + W1_OFF + wff1, b1 + l * FF_DIM, phh, phl);
        ff2_splitk_kernel<<<dim3(D_MODEL / BN, M_ROWS / BM, 2), 256, GEMM_SMEM>>>(
            phh, phl, pwt + W2_OFF + wff2, pp0, pp1);

        if (l < NLAYER - 1) {
            combine_ln_kernel<<<M_ROWS, 128>>>(
                pp0, pp1, b2 + l * D_MODEL, px,
                ln1_g + (l + 1) * D_MODEL, ln1_b + (l + 1) * D_MODEL, pxnh, pxnl);
        } else {
            combine_final_kernel<<<M_ROWS, 128>>>(
                pp0, pp1, b2 + l * D_MODEL, px, lnf_g, lnf_b, out);
        }
    }
}

// round 13
// speedup vs baseline: 7.3221x; 1.2137x over previous
#include <cuda_runtime.h>
#include <cuda_fp16.h>
#include <math.h>
#include <stdint.h>

#define D_MODEL 512
#define FF_DIM  2048
#define S_LEN   1024
#define BATCH   4
#define NLAYER  6
#define NHEAD   8
#define DHEAD   64
#define M_ROWS  (S_LEN * BATCH)   // 4096 token rows

// weight layout inside g_wt (element offsets; arrays are transposed [N][K], fp16)
#define WQ_OFF 0
#define WK_OFF (NLAYER * D_MODEL * D_MODEL)
#define WV_OFF (2 * NLAYER * D_MODEL * D_MODEL)
#define W1_OFF (3 * NLAYER * D_MODEL * D_MODEL)
#define W2_OFF (W1_OFF + NLAYER * D_MODEL * FF_DIM)
#define W_TOTAL (W2_OFF + NLAYER * FF_DIM * D_MODEL)

// ---------------- scratch (device globals; no runtime allocation) ----------------
__device__ float g_x [M_ROWS * D_MODEL];        // residual stream (B,S,D)
__device__ __half g_xn_h[M_ROWS * D_MODEL];     // layernorm out hi (fp16)
__device__ __half g_xn_l[M_ROWS * D_MODEL];     // layernorm out lo
__device__ __half g_qh[M_ROWS * D_MODEL];       // Q/8 hi (row-major)
__device__ __half g_ql[M_ROWS * D_MODEL];       // Q/8 lo
__device__ __half g_kh[M_ROWS * D_MODEL];       // K (single fp16, B-side)
__device__ __half g_vth[D_MODEL * M_ROWS];      // V TRANSPOSED [dh_col][token]
__device__ __half g_h_h[M_ROWS * FF_DIM];       // FF hidden (single fp16)
__device__ float g_p0[M_ROWS * D_MODEL];        // FF2 split-K partial 0
__device__ float g_p1[M_ROWS * D_MODEL];        // FF2 split-K partial 1
__device__ __half g_wt[W_TOTAL];                // weights transposed [N][K], fp16

// ---------------- helpers ----------------------------------------------------------
__device__ __forceinline__ void mma_fp16(float* d, const uint32_t* a, const uint32_t* b) {
    asm volatile(
        "mma.sync.aligned.m16n8k16.row.col.f32.f16.f16.f32 "
        "{%0,%1,%2,%3}, {%4,%5,%6,%7}, {%8,%9}, {%0,%1,%2,%3};"
        : "+f"(d[0]), "+f"(d[1]), "+f"(d[2]), "+f"(d[3])
        : "r"(a[0]), "r"(a[1]), "r"(a[2]), "r"(a[3]), "r"(b[0]), "r"(b[1]));
}

__device__ __forceinline__ void ldsm_x4(uint32_t* r, uint32_t addr) {
    asm volatile("ldmatrix.sync.aligned.m8n8.x4.shared.b16 {%0,%1,%2,%3}, [%4];"
                 : "=r"(r[0]), "=r"(r[1]), "=r"(r[2]), "=r"(r[3]) : "r"(addr));
}

__device__ __forceinline__ void split_fp16(float x, __half& hi, __half& lo) {
    hi = __float2half_rn(x);
    lo = __float2half_rn(x - __half2float(hi));
}

__device__ __forceinline__ void cp_async16(uint32_t dst, const void* src) {
    asm volatile("cp.async.ca.shared.global [%0], [%1], 16;" :: "r"(dst), "l"(src));
}
__device__ __forceinline__ void cp_commit() {
    asm volatile("cp.async.commit_group;");
}
template<int N>
__device__ __forceinline__ void cp_wait() {
    asm volatile("cp.async.wait_group %0;" :: "n"(N));
}
__device__ __forceinline__ uint32_t smem_u32(const void* p) {
    return (uint32_t)__cvta_generic_to_shared(p);
}

// ---------------- weight transpose + fp16 body: W[K][N] tile -> Wt[N][K] ----------
__device__ __forceinline__ void wsplit_body(const float* __restrict__ src,
                                            __half* __restrict__ oh, int K, int N) {
    __shared__ float tile[32][33];
    int n0 = blockIdx.x * 32, k0 = blockIdx.y * 32;
    int tx = threadIdx.x, ty = threadIdx.y;      // 32 x 8
    #pragma unroll
    for (int i = ty; i < 32; i += 8)
        tile[i][tx] = src[(long)(k0 + i) * N + n0 + tx];
    __syncthreads();
    int tid = ty * 32 + tx;
    int p = tid & 15;
    int i0 = tid >> 4;
    #pragma unroll
    for (int rep = 0; rep < 2; rep++) {
        int i = i0 + rep * 16;
        __half2 v = __floats2half2_rn(tile[2 * p][i], tile[2 * p + 1][i]);
        *(__half2*)(oh + (long)(n0 + i) * K + k0 + 2 * p) = v;
    }
}

__global__ void wsplit_qkv_kernel(const float* __restrict__ Wq,
                                  const float* __restrict__ Wk,
                                  const float* __restrict__ Wv,
                                  __half* __restrict__ wt) {
    int z = blockIdx.z;
    int which = z / NLAYER, l = z % NLAYER;
    const float* src = ((which == 0) ? Wq : (which == 1) ? Wk : Wv)
                       + (long)l * D_MODEL * D_MODEL;
    __half* oh = wt + (long)which * (NLAYER * D_MODEL * D_MODEL)
                    + (long)l * D_MODEL * D_MODEL;
    wsplit_body(src, oh, D_MODEL, D_MODEL);
}

__global__ void wsplit_t_kernel(const float* __restrict__ src,
                                __half* __restrict__ oh, int K, int N) {
    int l = blockIdx.z;
    wsplit_body(src + (long)l * K * N, oh + (long)l * N * K, K, N);
}

// ---------------- LN core ----------------------------------------------------------
__device__ __forceinline__ void ln_stats(float4 v, float& mean, float& inv) {
    float s  = v.x + v.y + v.z + v.w;
    float ss = v.x*v.x + v.y*v.y + v.z*v.z + v.w*v.w;
    #pragma unroll
    for (int o = 16; o > 0; o >>= 1) {
        s  += __shfl_down_sync(0xffffffffu, s,  o);
        ss += __shfl_down_sync(0xffffffffu, ss, o);
    }
    __shared__ float shs[4], shss[4];
    __shared__ float s_mean, s_inv;
    int tid = threadIdx.x;
    int w = tid >> 5, lane = tid & 31;
    if (lane == 0) { shs[w] = s; shss[w] = ss; }
    __syncthreads();
    if (tid == 0) {
        float ts  = shs[0] + shs[1] + shs[2] + shs[3];
        float tss = shss[0] + shss[1] + shss[2] + shss[3];
        float m = ts * (1.0f / D_MODEL);
        float var = tss * (1.0f / D_MODEL) - m * m;
        s_mean = m;
        s_inv  = rsqrtf(var + 1e-5f);
    }
    __syncthreads();
    mean = s_mean; inv = s_inv;
}

__device__ __forceinline__ void ln_emit_split(float4 v, float mean, float inv,
                                              const float* gamma, const float* beta,
                                              __half* yh, __half* yl, int row) {
    int tid = threadIdx.x;
    int c = tid * 4;
    float4 g = *(const float4*)(gamma + c);
    float4 bb = *(const float4*)(beta + c);
    float o0 = (v.x - mean) * inv * g.x + bb.x;
    float o1 = (v.y - mean) * inv * g.y + bb.y;
    float o2 = (v.z - mean) * inv * g.z + bb.z;
    float o3 = (v.w - mean) * inv * g.w + bb.w;
    __half h0,l0,h1,l1,h2,l2,h3,l3;
    split_fp16(o0, h0, l0); split_fp16(o1, h1, l1);
    split_fp16(o2, h2, l2); split_fp16(o3, h3, l3);
    __half2* yh2 = (__half2*)(yh + row * D_MODEL);
    __half2* yl2 = (__half2*)(yl + row * D_MODEL);
    yh2[tid * 2]     = __halves2half2(h0, h1);
    yh2[tid * 2 + 1] = __halves2half2(h2, h3);
    yl2[tid * 2]     = __halves2half2(l0, l1);
    yl2[tid * 2 + 1] = __halves2half2(l2, l3);
}

// ---------------- fused add_pos + LN1(layer 0) -------------------------------------
__global__ void add_pos_ln_kernel(const float* __restrict__ src,
                                  const float* __restrict__ pos,
                                  float* __restrict__ x,
                                  const float* __restrict__ gamma,
                                  const float* __restrict__ beta,
                                  __half* __restrict__ yh,
                                  __half* __restrict__ yl) {
    int row = blockIdx.x;
    int tid = threadIdx.x;
    int b = row >> 10, s = row & (S_LEN - 1);
    long si = ((long)(s * BATCH + b)) << 9;
    float4 v = ((const float4*)(src + si))[tid];
    float4 q = ((const float4*)(pos + si))[tid];
    v.x += q.x; v.y += q.y; v.z += q.z; v.w += q.w;
    ((float4*)(x + (long)row * D_MODEL))[tid] = v;
    float mean, inv;
    ln_stats(v, mean, inv);
    ln_emit_split(v, mean, inv, gamma, beta, yh, yl, row);
}

// ---------------- layernorm -> split fp16 (standalone, for LN2) --------------------
__global__ void layernorm_split_kernel(const float* __restrict__ x,
                                       const float* __restrict__ gamma,
                                       const float* __restrict__ beta,
                                       __half* __restrict__ yh,
                                       __half* __restrict__ yl) {
    int row = blockIdx.x;
    int tid = threadIdx.x;
    float4 v = ((const float4*)(x + row * D_MODEL))[tid];
    float mean, inv;
    ln_stats(v, mean, inv);
    ln_emit_split(v, mean, inv, gamma, beta, yh, yl, row);
}

// ---------------- fused FF2-combine + next-layer LN1 ------------------------------
__global__ void combine_ln_kernel(const float* __restrict__ p0,
                                  const float* __restrict__ p1,
                                  const float* __restrict__ bias,
                                  float* __restrict__ x,
                                  const float* __restrict__ gamma,
                                  const float* __restrict__ beta,
                                  __half* __restrict__ yh,
                                  __half* __restrict__ yl) {
    int row = blockIdx.x;
    int tid = threadIdx.x;
    int idx = row * 128 + tid;
    float4 a = ((const float4*)p0)[idx];
    float4 b = ((const float4*)p1)[idx];
    float4 v = ((const float4*)x)[idx];
    float4 bb = *(const float4*)(bias + tid * 4);
    v.x += a.x + b.x + bb.x;
    v.y += a.y + b.y + bb.y;
    v.z += a.z + b.z + bb.z;
    v.w += a.w + b.w + bb.w;
    ((float4*)x)[idx] = v;
    float mean, inv;
    ln_stats(v, mean, inv);
    ln_emit_split(v, mean, inv, gamma, beta, yh, yl, row);
}

// ---------------- fused FF2-combine + FINAL LN (transpose back to (S,B,D)) --------
__global__ void combine_final_kernel(const float* __restrict__ p0,
                                     const float* __restrict__ p1,
                                     const float* __restrict__ bias,
                                     const float* __restrict__ x,
                                     const float* __restrict__ gamma,
                                     const float* __restrict__ beta,
                                     float* __restrict__ out) {
    int row = blockIdx.x;
    int tid = threadIdx.x;
    int idx = row * 128 + tid;
    float4 a = ((const float4*)p0)[idx];
    float4 b = ((const float4*)p1)[idx];
    float4 v = ((const float4*)x)[idx];
    float4 bb = *(const float4*)(bias + tid * 4);
    v.x += a.x + b.x + bb.x;
    v.y += a.y + b.y + bb.y;
    v.z += a.z + b.z + bb.z;
    v.w += a.w + b.w + bb.w;
    float mean, inv;
    ln_stats(v, mean, inv);
    int c = tid * 4;
    float4 g = *(const float4*)(gamma + c);
    float4 be = *(const float4*)(beta + c);
    float4 o;
    o.x = (v.x - mean) * inv * g.x + be.x;
    o.y = (v.y - mean) * inv * g.y + be.y;
    o.z = (v.z - mean) * inv * g.z + be.z;
    o.w = (v.w - mean) * inv * g.w + be.w;
    int bb_ = row >> 10;
    int ss_ = row & (S_LEN - 1);
    ((float4*)(out + ((ss_ * BATCH + bb_) << 9)))[tid] = o;
}

// ---------------- split-FP16 GEMM mainloop (m16n8k16 + ldmatrix, BK=64) ------------
// TERMS=2: C=(Ah+Al)@W^T (A split). TERMS=1: C=Ah@W^T (plain fp16 A).
#define BM 128
#define BN 128
#define BK 64
#define SPAD 72                    // fp16 row stride: 144 B (conflict-free for LDSM)
#define TBUF (128 * SPAD)          // fp16 elems per buffer
#define BUFB (TBUF * 2)            // bytes per buffer
#define GEMM_SMEM2 (6 * TBUF * 2)  // 110592 bytes (TERMS=2)
#define GEMM_SMEM1 (4 * TBUF * 2)  // 73728 bytes (TERMS=1)

template<int TERMS>
__device__ __forceinline__ void gemm_mainloop(const __half* __restrict__ Ah,
                                              const __half* __restrict__ Al,
                                              const __half* __restrict__ Wh,
                                              int ldk, int kIters, float acc[2][8][4]) {
    extern __shared__ __half smh[];
    __half* Ash = smh;
    __half* Asl = Ash + 2 * TBUF;              // only used when TERMS==2
    __half* Bsh = Ash + 2 * TBUF * TERMS;

    int tid  = threadIdx.x;
    int lane = tid & 31;
    int warp = tid >> 5;
    int warpM = warp >> 1;
    int warpN = warp & 1;
    int rowBase = blockIdx.y * BM;
    int colBase = blockIdx.x * BN;

    int lm8  = lane & 7;
    int bit3 = (lane >> 3) & 1;
    int bit4 = lane >> 4;
    uint32_t aOff = (uint32_t)(warpM * 32 + lm8 + 8 * bit3) * 144u + (uint32_t)bit4 * 16u;
    uint32_t bOff = (uint32_t)(warpN * 64 + lm8 + 8 * bit4) * 144u + (uint32_t)bit3 * 16u;
    uint32_t baseAh = smem_u32(Ash) + aOff;
    uint32_t baseAl = smem_u32(Asl) + aOff;
    uint32_t baseBh = smem_u32(Bsh) + bOff;

    int r0c = tid >> 3;
    int o0c = (tid & 7) * 8;
    const __half* Ag = Ah + (long)(rowBase + r0c) * ldk + o0c;
    const __half* Alg = (TERMS == 2) ? Al + (long)(rowBase + r0c) * ldk + o0c : nullptr;
    const __half* Bg = Wh + (long)(colBase + r0c) * ldk + o0c;
    uint32_t dA = smem_u32(&Ash[r0c * SPAD + o0c]);
    uint32_t dAl = smem_u32(&Asl[r0c * SPAD + o0c]);
    uint32_t dB = smem_u32(&Bsh[r0c * SPAD + o0c]);
    const uint32_t rstep = 32u * SPAD * 2u;
    const long gstep = 32l * ldk;

    #pragma unroll
    for (int p = 0; p < 4; p++) {
        cp_async16(dA + p * rstep, Ag + p * gstep);
        if (TERMS == 2) cp_async16(dAl + p * rstep, Alg + p * gstep);
        cp_async16(dB + p * rstep, Bg + p * gstep);
    }
    cp_commit();

    for (int it = 0; it < kIters; it++) {
        int cur = it & 1;
        int nxt = cur ^ 1;
        if (it + 1 < kIters) {
            int ka = (it + 1) * BK;
            uint32_t bo = (uint32_t)(nxt * BUFB);
            #pragma unroll
            for (int p = 0; p < 4; p++) {
                cp_async16(dA + bo + p * rstep, Ag + ka + p * gstep);
                if (TERMS == 2) cp_async16(dAl + bo + p * rstep, Alg + ka + p * gstep);
                cp_async16(dB + bo + p * rstep, Bg + ka + p * gstep);
            }
            cp_commit();
            cp_wait<1>();
        } else {
            cp_wait<0>();
        }
        __syncthreads();

        uint32_t cb = (uint32_t)(cur * BUFB);
        #pragma unroll
        for (int ks = 0; ks < 4; ks++) {
            uint32_t ko = cb + ks * 32;
            uint32_t ahi[2][4], alo[2][4];
            ldsm_x4(ahi[0], baseAh + ko);
            ldsm_x4(ahi[1], baseAh + ko + 16 * 144);
            if (TERMS == 2) {
                ldsm_x4(alo[0], baseAl + ko);
                ldsm_x4(alo[1], baseAl + ko + 16 * 144);
            }
            #pragma unroll
            for (int h = 0; h < 4; h++) {
                uint32_t bh[4];
                ldsm_x4(bh, baseBh + ko + h * (16 * 144));
                #pragma unroll
                for (int mi = 0; mi < 2; mi++) {
                    mma_fp16(acc[mi][2 * h],     ahi[mi], bh);
                    if (TERMS == 2) mma_fp16(acc[mi][2 * h], alo[mi], bh);
                    mma_fp16(acc[mi][2 * h + 1], ahi[mi], bh + 2);
                    if (TERMS == 2) mma_fp16(acc[mi][2 * h + 1], alo[mi], bh + 2);
                }
            }
        }
        __syncthreads();
    }
}

// ---- FF1 GEMM: relu + single-fp16 hidden epilogue ----
__global__ __launch_bounds__(256, 2)
void ff1_gemm_kernel(const __half* __restrict__ Ah, const __half* __restrict__ Al,
                     const __half* __restrict__ Wh,
                     const float* __restrict__ bias,
                     __half* __restrict__ Ch) {
    float acc[2][8][4];
    #pragma unroll
    for (int mi = 0; mi < 2; mi++)
        #pragma unroll
        for (int nj = 0; nj < 8; nj++)
            #pragma unroll
            for (int r = 0; r < 4; r++) acc[mi][nj][r] = 0.0f;
    gemm_mainloop<2>(Ah, Al, Wh, D_MODEL, D_MODEL / BK, acc);

    const int N = FF_DIM;
    int lane = threadIdx.x & 31, warp = threadIdx.x >> 5;
    int warpM = warp >> 1, warpN = warp & 1;
    int g = lane >> 2, t = lane & 3;
    int rowBase = blockIdx.y * BM, colBase = blockIdx.x * BN;
    #pragma unroll
    for (int mi = 0; mi < 2; mi++) {
        int r0 = rowBase + warpM * 32 + mi * 16 + g;
        #pragma unroll
        for (int nj = 0; nj < 8; nj++) {
            int c = colBase + warpN * 64 + nj * 8 + t * 2;
            float b0 = bias[c], b1 = bias[c + 1];
            float v0 = fmaxf(acc[mi][nj][0] + b0, 0.0f);
            float v1 = fmaxf(acc[mi][nj][1] + b1, 0.0f);
            float v2 = fmaxf(acc[mi][nj][2] + b0, 0.0f);
            float v3 = fmaxf(acc[mi][nj][3] + b1, 0.0f);
            long o0 = (long)r0 * N + c;
            long o1 = (long)(r0 + 8) * N + c;
            *(__half2*)(Ch + o0) = __halves2half2(__float2half_rn(v0), __float2half_rn(v1));
            *(__half2*)(Ch + o1) = __halves2half2(__float2half_rn(v2), __float2half_rn(v3));
        }
    }
}

// ---- FF2 GEMM split-K (1-term fp16 A): z = K-half; writes fp32 partials ----
__global__ __launch_bounds__(256, 2)
void ff2_splitk_kernel(const __half* __restrict__ Ah,
                       const __half* __restrict__ Wh,
                       float* __restrict__ p0, float* __restrict__ p1) {
    int z = blockIdx.z;
    int kOff = z * (FF_DIM / 2);
    float* P = z ? p1 : p0;

    float acc[2][8][4];
    #pragma unroll
    for (int mi = 0; mi < 2; mi++)
        #pragma unroll
        for (int nj = 0; nj < 8; nj++)
            #pragma unroll
            for (int r = 0; r < 4; r++) acc[mi][nj][r] = 0.0f;
    gemm_mainloop<1>(Ah + kOff, nullptr, Wh + kOff, FF_DIM, (FF_DIM / 2) / BK, acc);

    const int N = D_MODEL;
    int lane = threadIdx.x & 31, warp = threadIdx.x >> 5;
    int warpM = warp >> 1, warpN = warp & 1;
    int g = lane >> 2, t = lane & 3;
    int rowBase = blockIdx.y * BM, colBase = blockIdx.x * BN;
    #pragma unroll
    for (int mi = 0; mi < 2; mi++) {
        int r0 = rowBase + warpM * 32 + mi * 16 + g;
        #pragma unroll
        for (int nj = 0; nj < 8; nj++) {
            int c = colBase + warpN * 64 + nj * 8 + t * 2;
            long o0 = (long)r0 * N + c;
            long o1 = (long)(r0 + 8) * N + c;
            P[o0] = acc[mi][nj][0]; P[o0 + 1] = acc[mi][nj][1];
            P[o1] = acc[mi][nj][2]; P[o1 + 1] = acc[mi][nj][3];
        }
    }
}

// ---- fused QKV GEMM: z=0 Q*0.125 split, z=1 K single, z=2 V single transposed ----
__global__ __launch_bounds__(256, 2)
void qkv_gemm_kernel(const __half* __restrict__ Ah, const __half* __restrict__ Al,
                     const __half* __restrict__ Wh_base,
                     const float* __restrict__ bq, const float* __restrict__ bk,
                     const float* __restrict__ bv,
                     __half* __restrict__ qh, __half* __restrict__ ql,
                     __half* __restrict__ kh, __half* __restrict__ vth) {
    int z = blockIdx.z;
    const __half* Wh = Wh_base + (long)z * (NLAYER * D_MODEL * D_MODEL);
    const float* bias = (z == 0) ? bq : (z == 1) ? bk : bv;

    float acc[2][8][4];
    #pragma unroll
    for (int mi = 0; mi < 2; mi++)
        #pragma unroll
        for (int nj = 0; nj < 8; nj++)
            #pragma unroll
            for (int r = 0; r < 4; r++) acc[mi][nj][r] = 0.0f;
    gemm_mainloop<2>(Ah, Al, Wh, D_MODEL, D_MODEL / BK, acc);

    int lane = threadIdx.x & 31, warp = threadIdx.x >> 5;
    int warpM = warp >> 1, warpN = warp & 1;
    int g = lane >> 2, t = lane & 3;
    int rowBase = blockIdx.y * BM, colBase = blockIdx.x * BN;

    #pragma unroll
    for (int mi = 0; mi < 2; mi++) {
        int r0 = rowBase + warpM * 32 + mi * 16 + g;
        #pragma unroll
        for (int nj = 0; nj < 8; nj++) {
            int c = colBase + warpN * 64 + nj * 8 + t * 2;
            float b0 = bias[c], b1 = bias[c + 1];
            float v0 = acc[mi][nj][0] + b0;
            float v1 = acc[mi][nj][1] + b1;
            float v2 = acc[mi][nj][2] + b0;
            float v3 = acc[mi][nj][3] + b1;
            if (z == 0) {
                v0 *= 0.125f; v1 *= 0.125f; v2 *= 0.125f; v3 *= 0.125f;
                __half h0,l0,h1,l1,h2,l2,h3,l3;
                split_fp16(v0, h0, l0); split_fp16(v1, h1, l1);
                split_fp16(v2, h2, l2); split_fp16(v3, h3, l3);
                long o0 = (long)r0 * D_MODEL + c;
                long o1 = (long)(r0 + 8) * D_MODEL + c;
                *(__half2*)(qh + o0) = __halves2half2(h0, h1);
                *(__half2*)(qh + o1) = __halves2half2(h2, h3);
                *(__half2*)(ql + o0) = __halves2half2(l0, l1);
                *(__half2*)(ql + o1) = __halves2half2(l2, l3);
            } else if (z == 1) {
                long o0 = (long)r0 * D_MODEL + c;
                long o1 = (long)(r0 + 8) * D_MODEL + c;
                *(__half2*)(kh + o0) = __halves2half2(__float2half_rn(v0), __float2half_rn(v1));
                *(__half2*)(kh + o1) = __halves2half2(__float2half_rn(v2), __float2half_rn(v3));
            } else {
                long c0 = (long)c * M_ROWS, c1 = (long)(c + 1) * M_ROWS;
                vth[c0 + r0]     = __float2half_rn(v0);
                vth[c1 + r0]     = __float2half_rn(v1);
                vth[c0 + r0 + 8] = __float2half_rn(v2);
                vth[c1 + r0 + 8] = __float2half_rn(v3);
            }
        }
    }
}

// ---------------- flash attention: 2-term QK^T, 1-term PV (m16n8k16 + ldmatrix) ----
#define QPB 72   // fp16 row stride (144 B): conflict-free for LDSM
#define QPBB (QPB * 2)
#define ATT_SMEM ((2*128 + 64 + 64 + 128) * QPB * 2)   // 69120 B

__global__ __launch_bounds__(256, 2)
void attention_fp16_kernel(const __half* __restrict__ qh,
                           const __half* __restrict__ ql,
                           const __half* __restrict__ kh,
                           const __half* __restrict__ vth,
                           float* __restrict__ x) {
    extern __shared__ __half smh[];
    __half* Qh = smh;                    // [128][QPB]
    __half* Ql = Qh + 128 * QPB;
    __half* Kh = Ql + 128 * QPB;         // [64][QPB]
    __half* Vh = Kh + 64 * QPB;          // [64 dh][QPB keys]
    __half* Ph = Vh + 64 * QPB;          // [128][QPB]

    int tid = threadIdx.x;
    int lane = tid & 31, warp = tid >> 5;
    int g = lane >> 2, t = lane & 3;
    int bh = blockIdx.x;
    int b = bh >> 3, h = bh & 7;
    int qt = blockIdx.y;
    int qr = warp * 16;

    int lm8  = lane & 7;
    int bit3 = (lane >> 3) & 1;
    int bit4 = lane >> 4;
    uint32_t aOff = (uint32_t)(qr + lm8 + 8 * bit3) * QPBB + (uint32_t)bit4 * 16u;
    uint32_t bOff = (uint32_t)(lm8 + 8 * bit4) * QPBB + (uint32_t)bit3 * 16u;
    uint32_t baseQh = smem_u32(Qh) + aOff;
    uint32_t baseQl = smem_u32(Ql) + aOff;
    uint32_t basePh = smem_u32(Ph) + aOff;
    uint32_t baseKh = smem_u32(Kh) + bOff;
    uint32_t baseVh = smem_u32(Vh) + bOff;

    // ---- stage Q ----
    {
        long qbase = ((long)(b * S_LEN + qt * 128)) * D_MODEL + h * DHEAD;
        #pragma unroll
        for (int p = 0; p < 8; p++) {
            int id = p * 256 + tid;
            int arr = id >> 10;
            int rem = id & 1023;
            int row = rem >> 3, ck = rem & 7;
            const __half* src = (arr ? ql : qh) + qbase + (long)row * D_MODEL + ck * 8;
            uint32_t dst = smem_u32(&(arr ? Ql : Qh)[row * QPB + ck * 8]);
            cp_async16(dst, src);
        }
        cp_commit();
    }

    float o[8][4];
    #pragma unroll
    for (int j = 0; j < 8; j++)
        #pragma unroll
        for (int r = 0; r < 4; r++) o[j][r] = 0.0f;
    float m0 = -1e30f, m1 = -1e30f, l0s = 0.0f, l1s = 0.0f;

    for (int kt = 0; kt < S_LEN / 64; kt++) {
        __syncthreads();
        {
            long kbase = ((long)(b * S_LEN + kt * 64)) * D_MODEL + h * DHEAD;
            long vcol  = (long)b * S_LEN + kt * 64;
            #pragma unroll
            for (int p = 0; p < 4; p++) {
                int id = p * 256 + tid;
                int arr = id >> 9;
                int rem = id & 511;
                int row = rem >> 3, ck = rem & 7;
                const __half* src;
                uint32_t dst;
                if (arr == 0) {
                    src = kh + kbase + (long)row * D_MODEL + ck * 8;
                    dst = smem_u32(&Kh[row * QPB + ck * 8]);
                } else {
                    src = vth + (long)(h * DHEAD + row) * M_ROWS + vcol + ck * 8;
                    dst = smem_u32(&Vh[row * QPB + ck * 8]);
                }
                cp_async16(dst, src);
            }
            cp_commit();
        }
        cp_wait<0>();
        __syncthreads();

        // ---- S = (Q/8) @ K^T : 2-term ----
        float s[8][4];
        #pragma unroll
        for (int j = 0; j < 8; j++)
            #pragma unroll
            for (int r = 0; r < 4; r++) s[j][r] = 0.0f;

        #pragma unroll
        for (int ks = 0; ks < 4; ks++) {
            uint32_t ko = ks * 32;
            uint32_t a_h[4], a_l[4];
            ldsm_x4(a_h, baseQh + ko);
            ldsm_x4(a_l, baseQl + ko);
            #pragma unroll
            for (int h4 = 0; h4 < 4; h4++) {
                uint32_t b_h[4];
                ldsm_x4(b_h, baseKh + ko + h4 * (16 * QPBB));
                mma_fp16(s[2 * h4],     a_h, b_h);
                mma_fp16(s[2 * h4],     a_l, b_h);
                mma_fp16(s[2 * h4 + 1], a_h, b_h + 2);
                mma_fp16(s[2 * h4 + 1], a_l, b_h + 2);
            }
        }

        // ---- online softmax ----
        float mx0 = -1e30f, mx1 = -1e30f;
        #pragma unroll
        for (int j = 0; j < 8; j++) {
            mx0 = fmaxf(mx0, fmaxf(s[j][0], s[j][1]));
            mx1 = fmaxf(mx1, fmaxf(s[j][2], s[j][3]));
        }
        mx0 = fmaxf(mx0, __shfl_xor_sync(0xffffffffu, mx0, 1));
        mx0 = fmaxf(mx0, __shfl_xor_sync(0xffffffffu, mx0, 2));
        mx1 = fmaxf(mx1, __shfl_xor_sync(0xffffffffu, mx1, 1));
        mx1 = fmaxf(mx1, __shfl_xor_sync(0xffffffffu, mx1, 2));
        float mn0 = fmaxf(m0, mx0), mn1 = fmaxf(m1, mx1);
        float c0 = __expf(m0 - mn0), c1 = __expf(m1 - mn1);
        l0s *= c0; l1s *= c1;
        #pragma unroll
        for (int j = 0; j < 8; j++) {
            float p0 = __expf(s[j][0] - mn0);
            float p1 = __expf(s[j][1] - mn0);
            float p2 = __expf(s[j][2] - mn1);
            float p3 = __expf(s[j][3] - mn1);
            l0s += p0 + p1; l1s += p2 + p3;
            int cc = j * 8 + 2 * t;
            *(__half2*)&Ph[(qr + g) * QPB + cc]     = __floats2half2_rn(p0, p1);
            *(__half2*)&Ph[(qr + g + 8) * QPB + cc] = __floats2half2_rn(p2, p3);
            o[j][0] *= c0; o[j][1] *= c0; o[j][2] *= c1; o[j][3] *= c1;
        }
        m0 = mn0; m1 = mn1;
        __syncwarp();

        // ---- O += P @ V : 1-term ----
        #pragma unroll
        for (int ks = 0; ks < 4; ks++) {
            uint32_t ko = ks * 32;
            uint32_t p_h[4];
            ldsm_x4(p_h, basePh + ko);
            #pragma unroll
            for (int h4 = 0; h4 < 4; h4++) {
                uint32_t b_h[4];
                ldsm_x4(b_h, baseVh + ko + h4 * (16 * QPBB));
                mma_fp16(o[2 * h4],     p_h, b_h);
                mma_fp16(o[2 * h4 + 1], p_h, b_h + 2);
            }
        }
    }

    // ---- finalize: x += O / l ----
    l0s += __shfl_xor_sync(0xffffffffu, l0s, 1);
    l0s += __shfl_xor_sync(0xffffffffu, l0s, 2);
    l1s += __shfl_xor_sync(0xffffffffu, l1s, 1);
    l1s += __shfl_xor_sync(0xffffffffu, l1s, 2);
    float i0 = 1.0f / l0s, i1 = 1.0f / l1s;

    float* xr0 = x + ((long)(b * S_LEN + qt * 128 + qr + g)     << 9) + h * DHEAD;
    float* xr1 = x + ((long)(b * S_LEN + qt * 128 + qr + g + 8) << 9) + h * DHEAD;
    #pragma unroll
    for (int j = 0; j < 8; j++) {
        int cc = j * 8 + 2 * t;
        float2 r0 = *(float2*)(xr0 + cc);
        r0.x += o[j][0] * i0; r0.y += o[j][1] * i0;
        *(float2*)(xr0 + cc) = r0;
        float2 r1 = *(float2*)(xr1 + cc);
        r1.x += o[j][2] * i1; r1.y += o[j][3] * i1;
        *(float2*)(xr1 + cc) = r1;
    }
}

// ---------------- host orchestration --------------------------------------------
extern "C" void kernel_launch(void* const* d_in, const int* in_sizes, int n_in,
                              void* d_out, int out_size) {
    const float* src   = (const float*)d_in[0];
    const float* pos   = (const float*)d_in[1];
    const float* Wq    = (const float*)d_in[2];
    const float* bq    = (const float*)d_in[3];
    const float* Wk    = (const float*)d_in[4];
    const float* bk    = (const float*)d_in[5];
    const float* Wv    = (const float*)d_in[6];
    const float* bv    = (const float*)d_in[7];
    const float* W1    = (const float*)d_in[8];
    const float* b1    = (const float*)d_in[9];
    const float* W2    = (const float*)d_in[10];
    const float* b2    = (const float*)d_in[11];
    const float* ln1_g = (const float*)d_in[12];
    const float* ln1_b = (const float*)d_in[13];
    const float* ln2_g = (const float*)d_in[14];
    const float* ln2_b = (const float*)d_in[15];
    const float* lnf_g = (const float*)d_in[16];
    const float* lnf_b = (const float*)d_in[17];
    float* out = (float*)d_out;

    float *px, *pp0, *pp1;
    __half *pxnh, *pxnl, *pqh, *pql, *pkh, *pvth, *phh, *pwt;
    cudaGetSymbolAddress((void**)&px,   g_x);
    cudaGetSymbolAddress((void**)&pp0,  g_p0);
    cudaGetSymbolAddress((void**)&pp1,  g_p1);
    cudaGetSymbolAddress((void**)&pxnh, g_xn_h);
    cudaGetSymbolAddress((void**)&pxnl, g_xn_l);
    cudaGetSymbolAddress((void**)&pqh,  g_qh);
    cudaGetSymbolAddress((void**)&pql,  g_ql);
    cudaGetSymbolAddress((void**)&pkh,  g_kh);
    cudaGetSymbolAddress((void**)&pvth, g_vth);
    cudaGetSymbolAddress((void**)&phh,  g_h_h);
    cudaGetSymbolAddress((void**)&pwt,  g_wt);

    cudaFuncSetAttribute(attention_fp16_kernel,
                         cudaFuncAttributeMaxDynamicSharedMemorySize, ATT_SMEM);
    cudaFuncSetAttribute(qkv_gemm_kernel,
                         cudaFuncAttributeMaxDynamicSharedMemorySize, GEMM_SMEM2);
    cudaFuncSetAttribute(ff1_gemm_kernel,
                         cudaFuncAttributeMaxDynamicSharedMemorySize, GEMM_SMEM2);
    cudaFuncSetAttribute(ff2_splitk_kernel,
                         cudaFuncAttributeMaxDynamicSharedMemorySize, GEMM_SMEM1);

    // ---- transpose + fp16 all weights: W[K][N] -> Wt[N][K] ----
    {
        dim3 blk(32, 8);
        wsplit_qkv_kernel<<<dim3(D_MODEL / 32, D_MODEL / 32, 3 * NLAYER), blk>>>(
            Wq, Wk, Wv, pwt);
        wsplit_t_kernel<<<dim3(FF_DIM / 32, D_MODEL / 32, NLAYER), blk>>>(
            W1, pwt + W1_OFF, D_MODEL, FF_DIM);
        wsplit_t_kernel<<<dim3(D_MODEL / 32, FF_DIM / 32, NLAYER), blk>>>(
            W2, pwt + W2_OFF, FF_DIM, D_MODEL);
    }

    // fused add_pos + LN1(layer 0)
    add_pos_ln_kernel<<<M_ROWS, 128>>>(src, pos, px, ln1_g, ln1_b, pxnh, pxnl);

    for (int l = 0; l < NLAYER; l++) {
        long wqkv = (long)l * D_MODEL * D_MODEL;
        long wff1 = (long)l * D_MODEL * FF_DIM;
        long wff2 = (long)l * FF_DIM * D_MODEL;

        // attention block (xn already holds LN1 output)
        qkv_gemm_kernel<<<dim3(D_MODEL / BN, M_ROWS / BM, 3), 256, GEMM_SMEM2>>>(
            pxnh, pxnl, pwt + WQ_OFF + wqkv,
            bq + l * D_MODEL, bk + l * D_MODEL, bv + l * D_MODEL,
            pqh, pql, pkh, pvth);
        attention_fp16_kernel<<<dim3(BATCH * NHEAD, S_LEN / 128), 256, ATT_SMEM>>>(
            pqh, pql, pkh, pvth, px);

        // feed-forward block
        layernorm_split_kernel<<<M_ROWS, 128>>>(px, ln2_g + l * D_MODEL, ln2_b + l * D_MODEL,
                                                pxnh, pxnl);
        ff1_gemm_kernel<<<dim3(FF_DIM / BN, M_ROWS / BM), 256, GEMM_SMEM2>>>(
            pxnh, pxnl, pwt + W1_OFF + wff1, b1 + l * FF_DIM, phh);
        ff2_splitk_kernel<<<dim3(D_MODEL / BN, M_ROWS / BM, 2), 256, GEMM_SMEM1>>>(
            phh, pwt + W2_OFF + wff2, pp0, pp1);

        if (l < NLAYER - 1) {
            combine_ln_kernel<<<M_ROWS, 128>>>(
                pp0, pp1, b2 + l * D_MODEL, px,
                ln1_g + (l + 1) * D_MODEL, ln1_b + (l + 1) * D_MODEL, pxnh, pxnl);
        } else {
            combine_final_kernel<<<M_ROWS, 128>>>(
                pp0, pp1, b2 + l * D_MODEL, px, lnf_g, lnf_b, out);
        }
    }
}

// round 14
// speedup vs baseline: 9.0583x; 1.2371x over previous
#include <cuda_runtime.h>
#include <cuda_fp16.h>
#include <math.h>
#include <stdint.h>

#define D_MODEL 512
#define FF_DIM  2048
#define S_LEN   1024
#define BATCH   4
#define NLAYER  6
#define NHEAD   8
#define DHEAD   64
#define M_ROWS  (S_LEN * BATCH)   // 4096 token rows

// weight layout inside g_wt (element offsets; arrays are transposed [N][K], fp16)
#define WQ_OFF 0
#define WK_OFF (NLAYER * D_MODEL * D_MODEL)
#define WV_OFF (2 * NLAYER * D_MODEL * D_MODEL)
#define W1_OFF (3 * NLAYER * D_MODEL * D_MODEL)
#define W2_OFF (W1_OFF + NLAYER * D_MODEL * FF_DIM)
#define W_TOTAL (W2_OFF + NLAYER * FF_DIM * D_MODEL)

// ---------------- scratch (device globals; no runtime allocation) ----------------
__device__ float g_x [M_ROWS * D_MODEL];        // residual stream (B,S,D)
__device__ __half g_xn[M_ROWS * D_MODEL];       // layernorm out (single fp16)
__device__ __half g_qh[M_ROWS * D_MODEL];       // Q/8 hi (row-major)
__device__ __half g_ql[M_ROWS * D_MODEL];       // Q/8 lo
__device__ __half g_kh[M_ROWS * D_MODEL];       // K (single fp16, B-side)
__device__ __half g_vth[D_MODEL * M_ROWS];      // V TRANSPOSED [dh_col][token]
__device__ __half g_h_h[M_ROWS * FF_DIM];       // FF hidden (single fp16)
__device__ float g_p0[M_ROWS * D_MODEL];        // FF2 split-K partial 0
__device__ float g_p1[M_ROWS * D_MODEL];        // FF2 split-K partial 1
__device__ __half g_wt[W_TOTAL];                // weights transposed [N][K], fp16

// ---------------- helpers ----------------------------------------------------------
__device__ __forceinline__ void mma_fp16(float* d, const uint32_t* a, const uint32_t* b) {
    asm volatile(
        "mma.sync.aligned.m16n8k16.row.col.f32.f16.f16.f32 "
        "{%0,%1,%2,%3}, {%4,%5,%6,%7}, {%8,%9}, {%0,%1,%2,%3};"
        : "+f"(d[0]), "+f"(d[1]), "+f"(d[2]), "+f"(d[3])
        : "r"(a[0]), "r"(a[1]), "r"(a[2]), "r"(a[3]), "r"(b[0]), "r"(b[1]));
}

__device__ __forceinline__ void ldsm_x4(uint32_t* r, uint32_t addr) {
    asm volatile("ldmatrix.sync.aligned.m8n8.x4.shared.b16 {%0,%1,%2,%3}, [%4];"
                 : "=r"(r[0]), "=r"(r[1]), "=r"(r[2]), "=r"(r[3]) : "r"(addr));
}

__device__ __forceinline__ void split_fp16(float x, __half& hi, __half& lo) {
    hi = __float2half_rn(x);
    lo = __float2half_rn(x - __half2float(hi));
}

__device__ __forceinline__ void cp_async16(uint32_t dst, const void* src) {
    asm volatile("cp.async.ca.shared.global [%0], [%1], 16;" :: "r"(dst), "l"(src));
}
__device__ __forceinline__ void cp_commit() {
    asm volatile("cp.async.commit_group;");
}
template<int N>
__device__ __forceinline__ void cp_wait() {
    asm volatile("cp.async.wait_group %0;" :: "n"(N));
}
__device__ __forceinline__ uint32_t smem_u32(const void* p) {
    return (uint32_t)__cvta_generic_to_shared(p);
}

// ---------------- weight transpose + fp16 body: W[K][N] tile -> Wt[N][K] ----------
__device__ __forceinline__ void wsplit_body(const float* __restrict__ src,
                                            __half* __restrict__ oh, int K, int N) {
    __shared__ float tile[32][33];
    int n0 = blockIdx.x * 32, k0 = blockIdx.y * 32;
    int tx = threadIdx.x, ty = threadIdx.y;      // 32 x 8
    #pragma unroll
    for (int i = ty; i < 32; i += 8)
        tile[i][tx] = src[(long)(k0 + i) * N + n0 + tx];
    __syncthreads();
    int tid = ty * 32 + tx;
    int p = tid & 15;
    int i0 = tid >> 4;
    #pragma unroll
    for (int rep = 0; rep < 2; rep++) {
        int i = i0 + rep * 16;
        __half2 v = __floats2half2_rn(tile[2 * p][i], tile[2 * p + 1][i]);
        *(__half2*)(oh + (long)(n0 + i) * K + k0 + 2 * p) = v;
    }
}

__global__ void wsplit_qkv_kernel(const float* __restrict__ Wq,
                                  const float* __restrict__ Wk,
                                  const float* __restrict__ Wv,
                                  __half* __restrict__ wt) {
    int z = blockIdx.z;
    int which = z / NLAYER, l = z % NLAYER;
    const float* src = ((which == 0) ? Wq : (which == 1) ? Wk : Wv)
                       + (long)l * D_MODEL * D_MODEL;
    __half* oh = wt + (long)which * (NLAYER * D_MODEL * D_MODEL)
                    + (long)l * D_MODEL * D_MODEL;
    wsplit_body(src, oh, D_MODEL, D_MODEL);
}

__global__ void wsplit_t_kernel(const float* __restrict__ src,
                                __half* __restrict__ oh, int K, int N) {
    int l = blockIdx.z;
    wsplit_body(src + (long)l * K * N, oh + (long)l * N * K, K, N);
}

// ---------------- LN core ----------------------------------------------------------
__device__ __forceinline__ void ln_stats(float4 v, float& mean, float& inv) {
    float s  = v.x + v.y + v.z + v.w;
    float ss = v.x*v.x + v.y*v.y + v.z*v.z + v.w*v.w;
    #pragma unroll
    for (int o = 16; o > 0; o >>= 1) {
        s  += __shfl_down_sync(0xffffffffu, s,  o);
        ss += __shfl_down_sync(0xffffffffu, ss, o);
    }
    __shared__ float shs[4], shss[4];
    __shared__ float s_mean, s_inv;
    int tid = threadIdx.x;
    int w = tid >> 5, lane = tid & 31;
    if (lane == 0) { shs[w] = s; shss[w] = ss; }
    __syncthreads();
    if (tid == 0) {
        float ts  = shs[0] + shs[1] + shs[2] + shs[3];
        float tss = shss[0] + shss[1] + shss[2] + shss[3];
        float m = ts * (1.0f / D_MODEL);
        float var = tss * (1.0f / D_MODEL) - m * m;
        s_mean = m;
        s_inv  = rsqrtf(var + 1e-5f);
    }
    __syncthreads();
    mean = s_mean; inv = s_inv;
}

__device__ __forceinline__ void ln_emit(float4 v, float mean, float inv,
                                        const float* gamma, const float* beta,
                                        __half* y, int row) {
    int tid = threadIdx.x;
    int c = tid * 4;
    float4 g = *(const float4*)(gamma + c);
    float4 bb = *(const float4*)(beta + c);
    float o0 = (v.x - mean) * inv * g.x + bb.x;
    float o1 = (v.y - mean) * inv * g.y + bb.y;
    float o2 = (v.z - mean) * inv * g.z + bb.z;
    float o3 = (v.w - mean) * inv * g.w + bb.w;
    __half2* y2 = (__half2*)(y + row * D_MODEL);
    y2[tid * 2]     = __floats2half2_rn(o0, o1);
    y2[tid * 2 + 1] = __floats2half2_rn(o2, o3);
}

// ---------------- fused add_pos + LN1(layer 0) -------------------------------------
__global__ void add_pos_ln_kernel(const float* __restrict__ src,
                                  const float* __restrict__ pos,
                                  float* __restrict__ x,
                                  const float* __restrict__ gamma,
                                  const float* __restrict__ beta,
                                  __half* __restrict__ y) {
    int row = blockIdx.x;
    int tid = threadIdx.x;
    int b = row >> 10, s = row & (S_LEN - 1);
    long si = ((long)(s * BATCH + b)) << 9;
    float4 v = ((const float4*)(src + si))[tid];
    float4 q = ((const float4*)(pos + si))[tid];
    v.x += q.x; v.y += q.y; v.z += q.z; v.w += q.w;
    ((float4*)(x + (long)row * D_MODEL))[tid] = v;
    float mean, inv;
    ln_stats(v, mean, inv);
    ln_emit(v, mean, inv, gamma, beta, y, row);
}

// ---------------- layernorm -> fp16 (standalone, for LN2) --------------------------
__global__ void layernorm_kernel(const float* __restrict__ x,
                                 const float* __restrict__ gamma,
                                 const float* __restrict__ beta,
                                 __half* __restrict__ y) {
    int row = blockIdx.x;
    int tid = threadIdx.x;
    float4 v = ((const float4*)(x + row * D_MODEL))[tid];
    float mean, inv;
    ln_stats(v, mean, inv);
    ln_emit(v, mean, inv, gamma, beta, y, row);
}

// ---------------- fused FF2-combine + next-layer LN1 ------------------------------
__global__ void combine_ln_kernel(const float* __restrict__ p0,
                                  const float* __restrict__ p1,
                                  const float* __restrict__ bias,
                                  float* __restrict__ x,
                                  const float* __restrict__ gamma,
                                  const float* __restrict__ beta,
                                  __half* __restrict__ y) {
    int row = blockIdx.x;
    int tid = threadIdx.x;
    int idx = row * 128 + tid;
    float4 a = ((const float4*)p0)[idx];
    float4 b = ((const float4*)p1)[idx];
    float4 v = ((const float4*)x)[idx];
    float4 bb = *(const float4*)(bias + tid * 4);
    v.x += a.x + b.x + bb.x;
    v.y += a.y + b.y + bb.y;
    v.z += a.z + b.z + bb.z;
    v.w += a.w + b.w + bb.w;
    ((float4*)x)[idx] = v;
    float mean, inv;
    ln_stats(v, mean, inv);
    ln_emit(v, mean, inv, gamma, beta, y, row);
}

// ---------------- fused FF2-combine + FINAL LN (transpose back to (S,B,D)) --------
__global__ void combine_final_kernel(const float* __restrict__ p0,
                                     const float* __restrict__ p1,
                                     const float* __restrict__ bias,
                                     const float* __restrict__ x,
                                     const float* __restrict__ gamma,
                                     const float* __restrict__ beta,
                                     float* __restrict__ out) {
    int row = blockIdx.x;
    int tid = threadIdx.x;
    int idx = row * 128 + tid;
    float4 a = ((const float4*)p0)[idx];
    float4 b = ((const float4*)p1)[idx];
    float4 v = ((const float4*)x)[idx];
    float4 bb = *(const float4*)(bias + tid * 4);
    v.x += a.x + b.x + bb.x;
    v.y += a.y + b.y + bb.y;
    v.z += a.z + b.z + bb.z;
    v.w += a.w + b.w + bb.w;
    float mean, inv;
    ln_stats(v, mean, inv);
    int c = tid * 4;
    float4 g = *(const float4*)(gamma + c);
    float4 be = *(const float4*)(beta + c);
    float4 o;
    o.x = (v.x - mean) * inv * g.x + be.x;
    o.y = (v.y - mean) * inv * g.y + be.y;
    o.z = (v.z - mean) * inv * g.z + be.z;
    o.w = (v.w - mean) * inv * g.w + be.w;
    int bb_ = row >> 10;
    int ss_ = row & (S_LEN - 1);
    ((float4*)(out + ((ss_ * BATCH + bb_) << 9)))[tid] = o;
}

// ---------------- 1-term FP16 GEMM mainloop (m16n8k16 + ldmatrix, BK=64) -----------
#define BM 128
#define BN 128
#define BK 64
#define SPAD 72                    // fp16 row stride: 144 B (conflict-free for LDSM)
#define TBUF (128 * SPAD)          // fp16 elems per buffer
#define BUFB (TBUF * 2)            // bytes per buffer
#define GEMM_SMEM (4 * TBUF * 2)   // 2 arrays x 2 buffers = 73728 bytes

__device__ __forceinline__ void gemm_mainloop(const __half* __restrict__ Ah,
                                              const __half* __restrict__ Wh,
                                              int ldk, int kIters, float acc[2][8][4]) {
    extern __shared__ __half smh[];
    __half* Ash = smh;
    __half* Bsh = Ash + 2 * TBUF;

    int tid  = threadIdx.x;
    int lane = tid & 31;
    int warp = tid >> 5;
    int warpM = warp >> 1;
    int warpN = warp & 1;
    int rowBase = blockIdx.y * BM;
    int colBase = blockIdx.x * BN;

    int lm8  = lane & 7;
    int bit3 = (lane >> 3) & 1;
    int bit4 = lane >> 4;
    uint32_t aOff = (uint32_t)(warpM * 32 + lm8 + 8 * bit3) * 144u + (uint32_t)bit4 * 16u;
    uint32_t bOff = (uint32_t)(warpN * 64 + lm8 + 8 * bit4) * 144u + (uint32_t)bit3 * 16u;
    uint32_t baseAh = smem_u32(Ash) + aOff;
    uint32_t baseBh = smem_u32(Bsh) + bOff;

    int r0c = tid >> 3;
    int o0c = (tid & 7) * 8;
    const __half* Ag = Ah + (long)(rowBase + r0c) * ldk + o0c;
    const __half* Bg = Wh + (long)(colBase + r0c) * ldk + o0c;
    uint32_t dA = smem_u32(&Ash[r0c * SPAD + o0c]);
    uint32_t dB = smem_u32(&Bsh[r0c * SPAD + o0c]);
    const uint32_t rstep = 32u * SPAD * 2u;
    const long gstep = 32l * ldk;

    #pragma unroll
    for (int p = 0; p < 4; p++) {
        cp_async16(dA + p * rstep, Ag + p * gstep);
        cp_async16(dB + p * rstep, Bg + p * gstep);
    }
    cp_commit();

    for (int it = 0; it < kIters; it++) {
        int cur = it & 1;
        int nxt = cur ^ 1;
        if (it + 1 < kIters) {
            int ka = (it + 1) * BK;
            uint32_t bo = (uint32_t)(nxt * BUFB);
            #pragma unroll
            for (int p = 0; p < 4; p++) {
                cp_async16(dA + bo + p * rstep, Ag + ka + p * gstep);
                cp_async16(dB + bo + p * rstep, Bg + ka + p * gstep);
            }
            cp_commit();
            cp_wait<1>();
        } else {
            cp_wait<0>();
        }
        __syncthreads();

        uint32_t cb = (uint32_t)(cur * BUFB);
        #pragma unroll
        for (int ks = 0; ks < 4; ks++) {
            uint32_t ko = cb + ks * 32;
            uint32_t ahi[2][4];
            ldsm_x4(ahi[0], baseAh + ko);
            ldsm_x4(ahi[1], baseAh + ko + 16 * 144);
            #pragma unroll
            for (int h = 0; h < 4; h++) {
                uint32_t bh[4];
                ldsm_x4(bh, baseBh + ko + h * (16 * 144));
                #pragma unroll
                for (int mi = 0; mi < 2; mi++) {
                    mma_fp16(acc[mi][2 * h],     ahi[mi], bh);
                    mma_fp16(acc[mi][2 * h + 1], ahi[mi], bh + 2);
                }
            }
        }
        __syncthreads();
    }
}

// ---- FF1 GEMM: relu + single-fp16 hidden epilogue ----
__global__ __launch_bounds__(256, 2)
void ff1_gemm_kernel(const __half* __restrict__ xn,
                     const __half* __restrict__ Wh,
                     const float* __restrict__ bias,
                     __half* __restrict__ Ch) {
    float acc[2][8][4];
    #pragma unroll
    for (int mi = 0; mi < 2; mi++)
        #pragma unroll
        for (int nj = 0; nj < 8; nj++)
            #pragma unroll
            for (int r = 0; r < 4; r++) acc[mi][nj][r] = 0.0f;
    gemm_mainloop(xn, Wh, D_MODEL, D_MODEL / BK, acc);

    const int N = FF_DIM;
    int lane = threadIdx.x & 31, warp = threadIdx.x >> 5;
    int warpM = warp >> 1, warpN = warp & 1;
    int g = lane >> 2, t = lane & 3;
    int rowBase = blockIdx.y * BM, colBase = blockIdx.x * BN;
    #pragma unroll
    for (int mi = 0; mi < 2; mi++) {
        int r0 = rowBase + warpM * 32 + mi * 16 + g;
        #pragma unroll
        for (int nj = 0; nj < 8; nj++) {
            int c = colBase + warpN * 64 + nj * 8 + t * 2;
            float b0 = bias[c], b1 = bias[c + 1];
            float v0 = fmaxf(acc[mi][nj][0] + b0, 0.0f);
            float v1 = fmaxf(acc[mi][nj][1] + b1, 0.0f);
            float v2 = fmaxf(acc[mi][nj][2] + b0, 0.0f);
            float v3 = fmaxf(acc[mi][nj][3] + b1, 0.0f);
            long o0 = (long)r0 * N + c;
            long o1 = (long)(r0 + 8) * N + c;
            *(__half2*)(Ch + o0) = __halves2half2(__float2half_rn(v0), __float2half_rn(v1));
            *(__half2*)(Ch + o1) = __halves2half2(__float2half_rn(v2), __float2half_rn(v3));
        }
    }
}

// ---- FF2 GEMM split-K: z = K-half; writes fp32 partials ----
__global__ __launch_bounds__(256, 2)
void ff2_splitk_kernel(const __half* __restrict__ Ah,
                       const __half* __restrict__ Wh,
                       float* __restrict__ p0, float* __restrict__ p1) {
    int z = blockIdx.z;
    int kOff = z * (FF_DIM / 2);
    float* P = z ? p1 : p0;

    float acc[2][8][4];
    #pragma unroll
    for (int mi = 0; mi < 2; mi++)
        #pragma unroll
        for (int nj = 0; nj < 8; nj++)
            #pragma unroll
            for (int r = 0; r < 4; r++) acc[mi][nj][r] = 0.0f;
    gemm_mainloop(Ah + kOff, Wh + kOff, FF_DIM, (FF_DIM / 2) / BK, acc);

    const int N = D_MODEL;
    int lane = threadIdx.x & 31, warp = threadIdx.x >> 5;
    int warpM = warp >> 1, warpN = warp & 1;
    int g = lane >> 2, t = lane & 3;
    int rowBase = blockIdx.y * BM, colBase = blockIdx.x * BN;
    #pragma unroll
    for (int mi = 0; mi < 2; mi++) {
        int r0 = rowBase + warpM * 32 + mi * 16 + g;
        #pragma unroll
        for (int nj = 0; nj < 8; nj++) {
            int c = colBase + warpN * 64 + nj * 8 + t * 2;
            long o0 = (long)r0 * N + c;
            long o1 = (long)(r0 + 8) * N + c;
            P[o0] = acc[mi][nj][0]; P[o0 + 1] = acc[mi][nj][1];
            P[o1] = acc[mi][nj][2]; P[o1 + 1] = acc[mi][nj][3];
        }
    }
}

// ---- fused QKV GEMM: z=0 Q*0.125 split-output, z=1 K single, z=2 V transposed ----
__global__ __launch_bounds__(256, 2)
void qkv_gemm_kernel(const __half* __restrict__ xn,
                     const __half* __restrict__ Wh_base,
                     const float* __restrict__ bq, const float* __restrict__ bk,
                     const float* __restrict__ bv,
                     __half* __restrict__ qh, __half* __restrict__ ql,
                     __half* __restrict__ kh, __half* __restrict__ vth) {
    int z = blockIdx.z;
    const __half* Wh = Wh_base + (long)z * (NLAYER * D_MODEL * D_MODEL);
    const float* bias = (z == 0) ? bq : (z == 1) ? bk : bv;

    float acc[2][8][4];
    #pragma unroll
    for (int mi = 0; mi < 2; mi++)
        #pragma unroll
        for (int nj = 0; nj < 8; nj++)
            #pragma unroll
            for (int r = 0; r < 4; r++) acc[mi][nj][r] = 0.0f;
    gemm_mainloop(xn, Wh, D_MODEL, D_MODEL / BK, acc);

    int lane = threadIdx.x & 31, warp = threadIdx.x >> 5;
    int warpM = warp >> 1, warpN = warp & 1;
    int g = lane >> 2, t = lane & 3;
    int rowBase = blockIdx.y * BM, colBase = blockIdx.x * BN;

    #pragma unroll
    for (int mi = 0; mi < 2; mi++) {
        int r0 = rowBase + warpM * 32 + mi * 16 + g;
        #pragma unroll
        for (int nj = 0; nj < 8; nj++) {
            int c = colBase + warpN * 64 + nj * 8 + t * 2;
            float b0 = bias[c], b1 = bias[c + 1];
            float v0 = acc[mi][nj][0] + b0;
            float v1 = acc[mi][nj][1] + b1;
            float v2 = acc[mi][nj][2] + b0;
            float v3 = acc[mi][nj][3] + b1;
            if (z == 0) {
                v0 *= 0.125f; v1 *= 0.125f; v2 *= 0.125f; v3 *= 0.125f;
                __half h0,l0,h1,l1,h2,l2,h3,l3;
                split_fp16(v0, h0, l0); split_fp16(v1, h1, l1);
                split_fp16(v2, h2, l2); split_fp16(v3, h3, l3);
                long o0 = (long)r0 * D_MODEL + c;
                long o1 = (long)(r0 + 8) * D_MODEL + c;
                *(__half2*)(qh + o0) = __halves2half2(h0, h1);
                *(__half2*)(qh + o1) = __halves2half2(h2, h3);
                *(__half2*)(ql + o0) = __halves2half2(l0, l1);
                *(__half2*)(ql + o1) = __halves2half2(l2, l3);
            } else if (z == 1) {
                long o0 = (long)r0 * D_MODEL + c;
                long o1 = (long)(r0 + 8) * D_MODEL + c;
                *(__half2*)(kh + o0) = __halves2half2(__float2half_rn(v0), __float2half_rn(v1));
                *(__half2*)(kh + o1) = __halves2half2(__float2half_rn(v2), __float2half_rn(v3));
            } else {
                long c0 = (long)c * M_ROWS, c1 = (long)(c + 1) * M_ROWS;
                vth[c0 + r0]     = __float2half_rn(v0);
                vth[c1 + r0]     = __float2half_rn(v1);
                vth[c0 + r0 + 8] = __float2half_rn(v2);
                vth[c1 + r0 + 8] = __float2half_rn(v3);
            }
        }
    }
}

// ---------------- flash attention: 2-term QK^T, 1-term PV (m16n8k16 + ldmatrix) ----
#define QPB 72   // fp16 row stride (144 B): conflict-free for LDSM
#define QPBB (QPB * 2)
#define ATT_SMEM ((2*128 + 64 + 64 + 128) * QPB * 2)   // 69120 B

__global__ __launch_bounds__(256, 2)
void attention_fp16_kernel(const __half* __restrict__ qh,
                           const __half* __restrict__ ql,
                           const __half* __restrict__ kh,
                           const __half* __restrict__ vth,
                           float* __restrict__ x) {
    extern __shared__ __half smh[];
    __half* Qh = smh;                    // [128][QPB]
    __half* Ql = Qh + 128 * QPB;
    __half* Kh = Ql + 128 * QPB;         // [64][QPB]
    __half* Vh = Kh + 64 * QPB;          // [64 dh][QPB keys]
    __half* Ph = Vh + 64 * QPB;          // [128][QPB]

    int tid = threadIdx.x;
    int lane = tid & 31, warp = tid >> 5;
    int g = lane >> 2, t = lane & 3;
    int bh = blockIdx.x;
    int b = bh >> 3, h = bh & 7;
    int qt = blockIdx.y;
    int qr = warp * 16;

    int lm8  = lane & 7;
    int bit3 = (lane >> 3) & 1;
    int bit4 = lane >> 4;
    uint32_t aOff = (uint32_t)(qr + lm8 + 8 * bit3) * QPBB + (uint32_t)bit4 * 16u;
    uint32_t bOff = (uint32_t)(lm8 + 8 * bit4) * QPBB + (uint32_t)bit3 * 16u;
    uint32_t baseQh = smem_u32(Qh) + aOff;
    uint32_t baseQl = smem_u32(Ql) + aOff;
    uint32_t basePh = smem_u32(Ph) + aOff;
    uint32_t baseKh = smem_u32(Kh) + bOff;
    uint32_t baseVh = smem_u32(Vh) + bOff;

    // ---- stage Q ----
    {
        long qbase = ((long)(b * S_LEN + qt * 128)) * D_MODEL + h * DHEAD;
        #pragma unroll
        for (int p = 0; p < 8; p++) {
            int id = p * 256 + tid;
            int arr = id >> 10;
            int rem = id & 1023;
            int row = rem >> 3, ck = rem & 7;
            const __half* src = (arr ? ql : qh) + qbase + (long)row * D_MODEL + ck * 8;
            uint32_t dst = smem_u32(&(arr ? Ql : Qh)[row * QPB + ck * 8]);
            cp_async16(dst, src);
        }
        cp_commit();
    }

    float o[8][4];
    #pragma unroll
    for (int j = 0; j < 8; j++)
        #pragma unroll
        for (int r = 0; r < 4; r++) o[j][r] = 0.0f;
    float m0 = -1e30f, m1 = -1e30f, l0s = 0.0f, l1s = 0.0f;

    for (int kt = 0; kt < S_LEN / 64; kt++) {
        __syncthreads();
        {
            long kbase = ((long)(b * S_LEN + kt * 64)) * D_MODEL + h * DHEAD;
            long vcol  = (long)b * S_LEN + kt * 64;
            #pragma unroll
            for (int p = 0; p < 4; p++) {
                int id = p * 256 + tid;
                int arr = id >> 9;
                int rem = id & 511;
                int row = rem >> 3, ck = rem & 7;
                const __half* src;
                uint32_t dst;
                if (arr == 0) {
                    src = kh + kbase + (long)row * D_MODEL + ck * 8;
                    dst = smem_u32(&Kh[row * QPB + ck * 8]);
                } else {
                    src = vth + (long)(h * DHEAD + row) * M_ROWS + vcol + ck * 8;
                    dst = smem_u32(&Vh[row * QPB + ck * 8]);
                }
                cp_async16(dst, src);
            }
            cp_commit();
        }
        cp_wait<0>();
        __syncthreads();

        // ---- S = (Q/8) @ K^T : 2-term ----
        float s[8][4];
        #pragma unroll
        for (int j = 0; j < 8; j++)
            #pragma unroll
            for (int r = 0; r < 4; r++) s[j][r] = 0.0f;

        #pragma unroll
        for (int ks = 0; ks < 4; ks++) {
            uint32_t ko = ks * 32;
            uint32_t a_h[4], a_l[4];
            ldsm_x4(a_h, baseQh + ko);
            ldsm_x4(a_l, baseQl + ko);
            #pragma unroll
            for (int h4 = 0; h4 < 4; h4++) {
                uint32_t b_h[4];
                ldsm_x4(b_h, baseKh + ko + h4 * (16 * QPBB));
                mma_fp16(s[2 * h4],     a_h, b_h);
                mma_fp16(s[2 * h4],     a_l, b_h);
                mma_fp16(s[2 * h4 + 1], a_h, b_h + 2);
                mma_fp16(s[2 * h4 + 1], a_l, b_h + 2);
            }
        }

        // ---- online softmax ----
        float mx0 = -1e30f, mx1 = -1e30f;
        #pragma unroll
        for (int j = 0; j < 8; j++) {
            mx0 = fmaxf(mx0, fmaxf(s[j][0], s[j][1]));
            mx1 = fmaxf(mx1, fmaxf(s[j][2], s[j][3]));
        }
        mx0 = fmaxf(mx0, __shfl_xor_sync(0xffffffffu, mx0, 1));
        mx0 = fmaxf(mx0, __shfl_xor_sync(0xffffffffu, mx0, 2));
        mx1 = fmaxf(mx1, __shfl_xor_sync(0xffffffffu, mx1, 1));
        mx1 = fmaxf(mx1, __shfl_xor_sync(0xffffffffu, mx1, 2));
        float mn0 = fmaxf(m0, mx0), mn1 = fmaxf(m1, mx1);
        float c0 = __expf(m0 - mn0), c1 = __expf(m1 - mn1);
        l0s *= c0; l1s *= c1;
        #pragma unroll
        for (int j = 0; j < 8; j++) {
            float p0 = __expf(s[j][0] - mn0);
            float p1 = __expf(s[j][1] - mn0);
            float p2 = __expf(s[j][2] - mn1);
            float p3 = __expf(s[j][3] - mn1);
            l0s += p0 + p1; l1s += p2 + p3;
            int cc = j * 8 + 2 * t;
            *(__half2*)&Ph[(qr + g) * QPB + cc]     = __floats2half2_rn(p0, p1);
            *(__half2*)&Ph[(qr + g + 8) * QPB + cc] = __floats2half2_rn(p2, p3);
            o[j][0] *= c0; o[j][1] *= c0; o[j][2] *= c1; o[j][3] *= c1;
        }
        m0 = mn0; m1 = mn1;
        __syncwarp();

        // ---- O += P @ V : 1-term ----
        #pragma unroll
        for (int ks = 0; ks < 4; ks++) {
            uint32_t ko = ks * 32;
            uint32_t p_h[4];
            ldsm_x4(p_h, basePh + ko);
            #pragma unroll
            for (int h4 = 0; h4 < 4; h4++) {
                uint32_t b_h[4];
                ldsm_x4(b_h, baseVh + ko + h4 * (16 * QPBB));
                mma_fp16(o[2 * h4],     p_h, b_h);
                mma_fp16(o[2 * h4 + 1], p_h, b_h + 2);
            }
        }
    }

    // ---- finalize: x += O / l ----
    l0s += __shfl_xor_sync(0xffffffffu, l0s, 1);
    l0s += __shfl_xor_sync(0xffffffffu, l0s, 2);
    l1s += __shfl_xor_sync(0xffffffffu, l1s, 1);
    l1s += __shfl_xor_sync(0xffffffffu, l1s, 2);
    float i0 = 1.0f / l0s, i1 = 1.0f / l1s;

    float* xr0 = x + ((long)(b * S_LEN + qt * 128 + qr + g)     << 9) + h * DHEAD;
    float* xr1 = x + ((long)(b * S_LEN + qt * 128 + qr + g + 8) << 9) + h * DHEAD;
    #pragma unroll
    for (int j = 0; j < 8; j++) {
        int cc = j * 8 + 2 * t;
        float2 r0 = *(float2*)(xr0 + cc);
        r0.x += o[j][0] * i0; r0.y += o[j][1] * i0;
        *(float2*)(xr0 + cc) = r0;
        float2 r1 = *(float2*)(xr1 + cc);
        r1.x += o[j][2] * i1; r1.y += o[j][3] * i1;
        *(float2*)(xr1 + cc) = r1;
    }
}

// ---------------- host orchestration --------------------------------------------
extern "C" void kernel_launch(void* const* d_in, const int* in_sizes, int n_in,
                              void* d_out, int out_size) {
    const float* src   = (const float*)d_in[0];
    const float* pos   = (const float*)d_in[1];
    const float* Wq    = (const float*)d_in[2];
    const float* bq    = (const float*)d_in[3];
    const float* Wk    = (const float*)d_in[4];
    const float* bk    = (const float*)d_in[5];
    const float* Wv    = (const float*)d_in[6];
    const float* bv    = (const float*)d_in[7];
    const float* W1    = (const float*)d_in[8];
    const float* b1    = (const float*)d_in[9];
    const float* W2    = (const float*)d_in[10];
    const float* b2    = (const float*)d_in[11];
    const float* ln1_g = (const float*)d_in[12];
    const float* ln1_b = (const float*)d_in[13];
    const float* ln2_g = (const float*)d_in[14];
    const float* ln2_b = (const float*)d_in[15];
    const float* lnf_g = (const float*)d_in[16];
    const float* lnf_b = (const float*)d_in[17];
    float* out = (float*)d_out;

    float *px, *pp0, *pp1;
    __half *pxn, *pqh, *pql, *pkh, *pvth, *phh, *pwt;
    cudaGetSymbolAddress((void**)&px,   g_x);
    cudaGetSymbolAddress((void**)&pp0,  g_p0);
    cudaGetSymbolAddress((void**)&pp1,  g_p1);
    cudaGetSymbolAddress((void**)&pxn,  g_xn);
    cudaGetSymbolAddress((void**)&pqh,  g_qh);
    cudaGetSymbolAddress((void**)&pql,  g_ql);
    cudaGetSymbolAddress((void**)&pkh,  g_kh);
    cudaGetSymbolAddress((void**)&pvth, g_vth);
    cudaGetSymbolAddress((void**)&phh,  g_h_h);
    cudaGetSymbolAddress((void**)&pwt,  g_wt);

    cudaFuncSetAttribute(attention_fp16_kernel,
                         cudaFuncAttributeMaxDynamicSharedMemorySize, ATT_SMEM);
    cudaFuncSetAttribute(qkv_gemm_kernel,
                         cudaFuncAttributeMaxDynamicSharedMemorySize, GEMM_SMEM);
    cudaFuncSetAttribute(ff1_gemm_kernel,
                         cudaFuncAttributeMaxDynamicSharedMemorySize, GEMM_SMEM);
    cudaFuncSetAttribute(ff2_splitk_kernel,
                         cudaFuncAttributeMaxDynamicSharedMemorySize, GEMM_SMEM);

    // ---- transpose + fp16 all weights: W[K][N] -> Wt[N][K] ----
    {
        dim3 blk(32, 8);
        wsplit_qkv_kernel<<<dim3(D_MODEL / 32, D_MODEL / 32, 3 * NLAYER), blk>>>(
            Wq, Wk, Wv, pwt);
        wsplit_t_kernel<<<dim3(FF_DIM / 32, D_MODEL / 32, NLAYER), blk>>>(
            W1, pwt + W1_OFF, D_MODEL, FF_DIM);
        wsplit_t_kernel<<<dim3(D_MODEL / 32, FF_DIM / 32, NLAYER), blk>>>(
            W2, pwt + W2_OFF, FF_DIM, D_MODEL);
    }

    // fused add_pos + LN1(layer 0)
    add_pos_ln_kernel<<<M_ROWS, 128>>>(src, pos, px, ln1_g, ln1_b, pxn);

    for (int l = 0; l < NLAYER; l++) {
        long wqkv = (long)l * D_MODEL * D_MODEL;
        long wff1 = (long)l * D_MODEL * FF_DIM;
        long wff2 = (long)l * FF_DIM * D_MODEL;

        // attention block (xn already holds LN1 output)
        qkv_gemm_kernel<<<dim3(D_MODEL / BN, M_ROWS / BM, 3), 256, GEMM_SMEM>>>(
            pxn, pwt + WQ_OFF + wqkv,
            bq + l * D_MODEL, bk + l * D_MODEL, bv + l * D_MODEL,
            pqh, pql, pkh, pvth);
        attention_fp16_kernel<<<dim3(BATCH * NHEAD, S_LEN / 128), 256, ATT_SMEM>>>(
            pqh, pql, pkh, pvth, px);

        // feed-forward block
        layernorm_kernel<<<M_ROWS, 128>>>(px, ln2_g + l * D_MODEL, ln2_b + l * D_MODEL, pxn);
        ff1_gemm_kernel<<<dim3(FF_DIM / BN, M_ROWS / BM), 256, GEMM_SMEM>>>(
            pxn, pwt + W1_OFF + wff1, b1 + l * FF_DIM, phh);
        ff2_splitk_kernel<<<dim3(D_MODEL / BN, M_ROWS / BM, 2), 256, GEMM_SMEM>>>(
            phh, pwt + W2_OFF + wff2, pp0, pp1);

        if (l < NLAYER - 1) {
            combine_ln_kernel<<<M_ROWS, 128>>>(
                pp0, pp1, b2 + l * D_MODEL, px,
                ln1_g + (l + 1) * D_MODEL, ln1_b + (l + 1) * D_MODEL, pxn);
        } else {
            combine_final_kernel<<<M_ROWS, 128>>>(
                pp0, pp1, b2 + l * D_MODEL, px, lnf_g, lnf_b, out);
        }
    }
}